// round 4
// baseline (speedup 1.0000x reference)
#include <cuda_runtime.h>
#include <cstdint>

// ---------------------------------------------------------------------------
// Problem constants
// ---------------------------------------------------------------------------
namespace {
constexpr int NB   = 2048;
constexpr int SPOT = 1024;
constexpr int IMG  = 1024;
constexpr int PROJ = 256;
constexpr int NH   = 8;
constexpr int DH   = 64;
constexpr int INNER = 512;
constexpr int MLPD = 2048;
constexpr int QKVW = 1536;
constexpr int NL   = 2;
}

// ---------------------------------------------------------------------------
// Scratch: fp32
// ---------------------------------------------------------------------------
__device__ float g_spot  [NB * SPOT];
__device__ float g_tmp   [NB * SPOT];
__device__ float g_S     [(size_t)NH * NB * NB];
__device__ float g_pimg  [NB * PROJ];
__device__ float g_pspot [NB * PROJ];
__device__ float g_logits[NB * NB];
__device__ float g_tgt   [NB * NB];
__device__ float g_rowp  [NB];
__device__ float g_colp  [NB];

// ---------------------------------------------------------------------------
// Scratch: bf16 hi/lo (stored as uint16)
// ---------------------------------------------------------------------------
__device__ uint16_t g_hbuf_h[NB * SPOT],  g_hbuf_l[NB * SPOT];
__device__ uint16_t g_qkv_h [NB * QKVW],  g_qkv_l [NB * QKVW];
__device__ uint16_t g_attn_h[NB * INNER], g_attn_l[NB * INNER];
__device__ uint16_t g_mlp_h [NB * MLPD],  g_mlp_l [NB * MLPD];
__device__ uint16_t g_P_h[(size_t)NH * NB * NB], g_P_l[(size_t)NH * NB * NB];
__device__ uint16_t g_eimg_h [NB * PROJ], g_eimg_l [NB * PROJ];
__device__ uint16_t g_espot_h[NB * PROJ], g_espot_l[NB * PROJ];
__device__ uint16_t g_pg_h   [NB * PROJ], g_pg_l   [NB * PROJ];
__device__ uint16_t g_cat_h[NB * 2 * PROJ], g_cat_l[NB * 2 * PROJ];
__device__ uint16_t g_imgf_h[NB * IMG], g_imgf_l[NB * IMG];
// weights bf16
__device__ uint16_t g_wqkv_h[NL * SPOT * QKVW], g_wqkv_l[NL * SPOT * QKVW];
__device__ uint16_t g_wo_h  [NL * INNER * SPOT], g_wo_l [NL * INNER * SPOT];
__device__ uint16_t g_w1_h  [NL * SPOT * MLPD],  g_w1_l [NL * SPOT * MLPD];
__device__ uint16_t g_w2_h  [NL * MLPD * SPOT],  g_w2_l [NL * MLPD * SPOT];
__device__ uint16_t g_wip_h [IMG * PROJ],  g_wip_l[IMG * PROJ];
__device__ uint16_t g_wif_h [PROJ * PROJ], g_wif_l[PROJ * PROJ];
__device__ uint16_t g_wsp_h [SPOT * PROJ], g_wsp_l[SPOT * PROJ];
__device__ uint16_t g_wsf_h [PROJ * PROJ], g_wsf_l[PROJ * PROJ];

// ---------------------------------------------------------------------------
// Helpers
// ---------------------------------------------------------------------------
__device__ __forceinline__ uint32_t smem_u32(const void* p) {
    uint32_t a;
    asm("{ .reg .u64 t; cvta.to.shared.u64 t, %1; cvt.u32.u64 %0, t; }"
        : "=r"(a) : "l"(p));
    return a;
}
__device__ __forceinline__ unsigned long long gptr(const void* p) {
    return (unsigned long long)__cvta_generic_to_global(p);
}
__device__ __forceinline__ float gelu_f(float x) {
    return 0.5f * x * (1.0f + erff(x * 0.7071067811865475f));
}
// split fp32 pair -> packed bf16x2 hi and lo (f0 in low half)
__device__ __forceinline__ void split2(float f0, float f1, uint32_t& hi, uint32_t& lo) {
    asm("cvt.rn.bf16x2.f32 %0, %1, %2;" : "=r"(hi) : "f"(f1), "f"(f0));
    float h0 = __uint_as_float(hi << 16);
    float h1 = __uint_as_float(hi & 0xFFFF0000u);
    float l0 = f0 - h0, l1 = f1 - h1;
    asm("cvt.rn.bf16x2.f32 %0, %1, %2;" : "=r"(lo) : "f"(l1), "f"(l0));
}

#define CP16(dst, src) \
    asm volatile("cp.async.cg.shared.global [%0], [%1], 16;" :: "r"(dst), "l"(src))
#define CP_COMMIT() asm volatile("cp.async.commit_group;" ::: "memory")
#define CP_WAIT2()  asm volatile("cp.async.wait_group 2;" ::: "memory")

#define LDSM_X4(r, a)                                                          \
    asm volatile("ldmatrix.sync.aligned.m8n8.x4.shared.b16 {%0,%1,%2,%3}, [%4];" \
        : "=r"((r)[0]), "=r"((r)[1]), "=r"((r)[2]), "=r"((r)[3]) : "r"(a))
#define LDSM_X2(r, a)                                                          \
    asm volatile("ldmatrix.sync.aligned.m8n8.x2.shared.b16 {%0,%1}, [%2];"     \
        : "=r"((r)[0]), "=r"((r)[1]) : "r"(a))
#define LDSM_X2T(r, a)                                                         \
    asm volatile("ldmatrix.sync.aligned.m8n8.x2.trans.shared.b16 {%0,%1}, [%2];" \
        : "=r"((r)[0]), "=r"((r)[1]) : "r"(a))
#define MMA16816(d, a, b)                                                      \
    asm volatile("mma.sync.aligned.m16n8k16.row.col.f32.bf16.bf16.f32 "        \
        "{%0,%1,%2,%3}, {%4,%5,%6,%7}, {%8,%9}, {%0,%1,%2,%3};"                \
        : "+f"((d)[0]), "+f"((d)[1]), "+f"((d)[2]), "+f"((d)[3])               \
        : "r"((a)[0]), "r"((a)[1]), "r"((a)[2]), "r"((a)[3]),                  \
          "r"((b)[0]), "r"((b)[1]))

// ---------------------------------------------------------------------------
// Pure-bf16 split GEMM with 4-stage cp.async pipeline.
//   D = epi( scale * (Ah+Al) @ op(Bh+Bl) ) via 3 MMA passes (h*h + h*l + l*h)
//   A: [M,K] bf16 hi/lo, lda elems. B: BNAT ? [N,K] : [K,N] bf16 hi/lo.
//   EPI: 0 none, 1 +bias, 2 +bias+gelu, 3 +bias+res(fp32)
//   OUT bits: 1 = fp32 C, 2 = bf16 Ch/Cl, 4 = gelu before bf16 split only
// ---------------------------------------------------------------------------
template<int NT, bool BNAT, int EPI, int OUT>
__global__ __launch_bounds__(256) void gemm_bf(
    const uint16_t* __restrict__ Ah, const uint16_t* __restrict__ Al,
    int lda, long long az,
    const uint16_t* __restrict__ Bh, const uint16_t* __restrict__ Bl,
    int ldb, long long bz,
    const float* __restrict__ bias, const float* __restrict__ res,
    float* __restrict__ C, uint16_t* __restrict__ Ch, uint16_t* __restrict__ Cl,
    int ldc, long long cz, int K, float scale)
{
    constexpr int WARPS_N = NT / 32;
    constexpr int WARPS_M = 8 / WARPS_N;
    constexpr int WM = 128 / WARPS_M;
    constexpr int MT = WM / 16;
    constexpr int ABYTES = 128 * 80;                       // stride 40 bf16
    constexpr int BROWB  = BNAT ? 80 : (NT + 8) * 2;
    constexpr int BBYTES = BNAT ? NT * 80 : 32 * (NT + 8) * 2;
    constexpr int STAGE  = 2 * ABYTES + 2 * BBYTES;
    constexpr int STAGES = 4;
    constexpr int BSEGS  = BNAT ? NT * 4 : 32 * (NT / 8);  // 16B segs per buf
    constexpr int BIT    = BSEGS / 256;

    extern __shared__ __align__(128) char smm[];
    const uint32_t sb = smem_u32(smm);
    const int tid = threadIdx.x, lane = tid & 31, wid = tid >> 5;
    const int wm = wid / WARPS_N, wn = wid % WARPS_N;
    const int bm = blockIdx.y * 128, bn = blockIdx.x * NT;

    const uint16_t* Abh = Ah + (size_t)blockIdx.z * az + (size_t)bm * lda;
    const uint16_t* Abl = Al + (size_t)blockIdx.z * az + (size_t)bm * lda;
    const uint16_t* Bbh = Bh + (size_t)blockIdx.z * bz;
    const uint16_t* Bbl = Bl + (size_t)blockIdx.z * bz;

    float acc[MT][4][4];
    #pragma unroll
    for (int mt = 0; mt < MT; mt++)
        #pragma unroll
        for (int nt = 0; nt < 4; nt++)
            #pragma unroll
            for (int r = 0; r < 4; r++) acc[mt][nt][r] = 0.f;

    const int NC = K >> 5;

    auto issue = [&](int c, int s) {
        const uint32_t st = sb + s * STAGE;
        const int k0 = c << 5;
        #pragma unroll
        for (int j = 0; j < 2; j++) {
            int idx = tid + j * 256;
            int row = idx >> 2, seg = idx & 3;
            size_t so = (size_t)row * lda + k0 + seg * 8;
            uint32_t d = st + row * 80 + seg * 16;
            CP16(d, gptr(Abh + so));
            CP16(d + ABYTES, gptr(Abl + so));
        }
        #pragma unroll
        for (int j = 0; j < BIT; j++) {
            int idx = tid + j * 256;
            if (BNAT) {
                int row = idx >> 2, seg = idx & 3;
                size_t so = (size_t)(bn + row) * ldb + k0 + seg * 8;
                uint32_t d = st + 2 * ABYTES + row * 80 + seg * 16;
                CP16(d, gptr(Bbh + so));
                CP16(d + BBYTES, gptr(Bbl + so));
            } else {
                int row = idx / (NT / 8), seg = idx % (NT / 8);
                size_t so = (size_t)(k0 + row) * ldb + bn + seg * 8;
                uint32_t d = st + 2 * ABYTES + row * BROWB + seg * 16;
                CP16(d, gptr(Bbh + so));
                CP16(d + BBYTES, gptr(Bbl + so));
            }
        }
    };

    // prologue: fill STAGES-1 stages (empty commits keep group ordering valid)
    #pragma unroll
    for (int s = 0; s < STAGES - 1; s++) {
        if (s < NC) issue(s, s);
        CP_COMMIT();
    }

    for (int c = 0; c < NC; c++) {
        CP_WAIT2();
        __syncthreads();
        {
            int cn = c + STAGES - 1;
            if (cn < NC) issue(cn, cn % STAGES);
            CP_COMMIT();
        }
        // ---- compute stage c%STAGES
        const uint32_t abh_ = sb + (c % STAGES) * STAGE;
        const uint32_t abl_ = abh_ + ABYTES;
        const uint32_t bbh_ = abh_ + 2 * ABYTES;
        const uint32_t bbl_ = bbh_ + BBYTES;
        #pragma unroll
        for (int ks = 0; ks < 2; ks++) {
            uint32_t afh[MT][4], afl[MT][4], bfh[4][2], bfl[4][2];
            #pragma unroll
            for (int mt = 0; mt < MT; mt++) {
                uint32_t off = ((wm * WM + mt * 16 + (lane & 15)) * 40 +
                                ks * 16 + ((lane >> 4) << 3)) << 1;
                LDSM_X4(afh[mt], abh_ + off);
                LDSM_X4(afl[mt], abl_ + off);
            }
            #pragma unroll
            for (int nt = 0; nt < 4; nt++) {
                if (BNAT) {
                    uint32_t off = ((wn * 32 + nt * 8 + (lane & 7)) * 40 +
                                    ks * 16 + (((lane >> 3) & 1) << 3)) << 1;
                    LDSM_X2(bfh[nt], bbh_ + off);
                    LDSM_X2(bfl[nt], bbl_ + off);
                } else {
                    uint32_t off = ((ks * 16 + (lane & 15)) * (NT + 8) +
                                    wn * 32 + nt * 8) << 1;
                    LDSM_X2T(bfh[nt], bbh_ + off);
                    LDSM_X2T(bfl[nt], bbl_ + off);
                }
            }
            #pragma unroll
            for (int nt = 0; nt < 4; nt++)
                #pragma unroll
                for (int mt = 0; mt < MT; mt++) {
                    MMA16816(acc[mt][nt], afh[mt], bfh[nt]);
                    MMA16816(acc[mt][nt], afh[mt], bfl[nt]);
                    MMA16816(acc[mt][nt], afl[mt], bfh[nt]);
                }
        }
    }

    // ---- epilogue
    const int gid = lane >> 2, tig = lane & 3;
    #pragma unroll
    for (int mt = 0; mt < MT; mt++) {
        #pragma unroll
        for (int nt = 0; nt < 4; nt++) {
            int r0  = bm + wm * WM + mt * 16 + gid;
            int col = bn + wn * 32 + nt * 8 + tig * 2;
            float2 v0 = make_float2(acc[mt][nt][0] * scale, acc[mt][nt][1] * scale);
            float2 v1 = make_float2(acc[mt][nt][2] * scale, acc[mt][nt][3] * scale);
            if (EPI >= 1) {
                float2 bb = *reinterpret_cast<const float2*>(&bias[col]);
                v0.x += bb.x; v0.y += bb.y; v1.x += bb.x; v1.y += bb.y;
            }
            if (EPI == 2) {
                v0.x = gelu_f(v0.x); v0.y = gelu_f(v0.y);
                v1.x = gelu_f(v1.x); v1.y = gelu_f(v1.y);
            }
            if (EPI == 3) {
                float2 ra = *reinterpret_cast<const float2*>(
                    &res[(size_t)r0 * ldc + col]);
                float2 rb = *reinterpret_cast<const float2*>(
                    &res[(size_t)(r0 + 8) * ldc + col]);
                v0.x += ra.x; v0.y += ra.y; v1.x += rb.x; v1.y += rb.y;
            }
            size_t o0 = (size_t)r0 * ldc + col + (size_t)blockIdx.z * cz;
            size_t o1 = (size_t)(r0 + 8) * ldc + col + (size_t)blockIdx.z * cz;
            if (OUT & 1) {
                *reinterpret_cast<float2*>(&C[o0]) = v0;
                *reinterpret_cast<float2*>(&C[o1]) = v1;
            }
            if (OUT & 2) {
                float a0 = v0.x, a1 = v0.y, b0 = v1.x, b1 = v1.y;
                if (OUT & 4) {
                    a0 = gelu_f(a0); a1 = gelu_f(a1);
                    b0 = gelu_f(b0); b1 = gelu_f(b1);
                }
                uint32_t h, l;
                split2(a0, a1, h, l);
                *reinterpret_cast<uint32_t*>(&Ch[o0]) = h;
                *reinterpret_cast<uint32_t*>(&Cl[o0]) = l;
                split2(b0, b1, h, l);
                *reinterpret_cast<uint32_t*>(&Ch[o1]) = h;
                *reinterpret_cast<uint32_t*>(&Cl[o1]) = l;
            }
        }
    }
}

// ---------------------------------------------------------------------------
// Reductions
// ---------------------------------------------------------------------------
__device__ __forceinline__ float blk_sum256(float v, float* sh) {
    int t = threadIdx.x;
    sh[t] = v; __syncthreads();
    #pragma unroll
    for (int s = 128; s >= 1; s >>= 1) {
        if (t < s) sh[t] += sh[t + s];
        __syncthreads();
    }
    float r = sh[0]; __syncthreads();
    return r;
}
__device__ __forceinline__ float blk_max256(float v, float* sh) {
    int t = threadIdx.x;
    sh[t] = v; __syncthreads();
    #pragma unroll
    for (int s = 128; s >= 1; s >>= 1) {
        if (t < s) sh[t] = fmaxf(sh[t], sh[t + s]);
        __syncthreads();
    }
    float r = sh[0]; __syncthreads();
    return r;
}

// ---------------------------------------------------------------------------
// Elementwise kernels
// ---------------------------------------------------------------------------
__global__ __launch_bounds__(256) void conv_bf(
    const float* __restrict__ x, uint16_t* __restrict__ h,
    uint16_t* __restrict__ l, int n2)
{
    int i = blockIdx.x * 256 + threadIdx.x;
    if (i < n2) {
        float2 v = reinterpret_cast<const float2*>(x)[i];
        uint32_t hh, ll;
        split2(v.x, v.y, hh, ll);
        reinterpret_cast<uint32_t*>(h)[i] = hh;
        reinterpret_cast<uint32_t*>(l)[i] = ll;
    }
}

__global__ __launch_bounds__(256) void embed_kernel(
    const float* __restrict__ expr, const float* __restrict__ xt,
    const float* __restrict__ yt, const int* __restrict__ xi,
    const int* __restrict__ yi, float* __restrict__ out)
{
    int row = blockIdx.x;
    size_t xo = (size_t)xi[row] * SPOT;
    size_t yo = (size_t)yi[row] * SPOT;
    size_t ro = (size_t)row * SPOT;
    for (int j = threadIdx.x; j < SPOT; j += 256)
        out[ro + j] = expr[ro + j] + xt[xo + j] + yt[yo + j];
}

// LayerNorm fp32 -> split bf16
template<int N>
__global__ __launch_bounds__(256) void ln_bf(
    const float* __restrict__ x, const float* __restrict__ g,
    const float* __restrict__ b, uint16_t* __restrict__ oh,
    uint16_t* __restrict__ ol)
{
    __shared__ float sh[256];
    constexpr int NPAIR = N / 2;
    constexpr int NP = (NPAIR + 255) / 256;
    int row = blockIdx.x, tid = threadIdx.x;
    const float2* xr = reinterpret_cast<const float2*>(x + (size_t)row * N);
    float2 v[NP];
    float s = 0.f;
    #pragma unroll
    for (int i = 0; i < NP; i++) {
        int p = i * 256 + tid;
        if (p < NPAIR) { v[i] = xr[p]; s += v[i].x + v[i].y; }
        else v[i] = make_float2(0.f, 0.f);
    }
    s = blk_sum256(s, sh);
    float mean = s / N, ss = 0.f;
    #pragma unroll
    for (int i = 0; i < NP; i++) {
        int p = i * 256 + tid;
        if (p < NPAIR) {
            float dx = v[i].x - mean, dy = v[i].y - mean;
            ss += dx * dx + dy * dy;
        }
    }
    ss = blk_sum256(ss, sh);
    float rstd = rsqrtf(ss / N + 1e-5f);
    uint32_t* OH = reinterpret_cast<uint32_t*>(oh + (size_t)row * N);
    uint32_t* OL = reinterpret_cast<uint32_t*>(ol + (size_t)row * N);
    #pragma unroll
    for (int i = 0; i < NP; i++) {
        int p = i * 256 + tid;
        if (p < NPAIR) {
            float2 gg = reinterpret_cast<const float2*>(g)[p];
            float2 bb = reinterpret_cast<const float2*>(b)[p];
            float y0 = (v[i].x - mean) * rstd * gg.x + bb.x;
            float y1 = (v[i].y - mean) * rstd * gg.y + bb.y;
            uint32_t h, l;
            split2(y0, y1, h, l);
            OH[p] = h; OL[p] = l;
        }
    }
}

// softmax fp32 row -> split bf16 (attention P)
__global__ __launch_bounds__(256) void softmax_bf(
    const float* __restrict__ S, uint16_t* __restrict__ ph,
    uint16_t* __restrict__ pl)
{
    __shared__ float sh[256];
    size_t row = blockIdx.x;
    int tid = threadIdx.x;
    const float4* r = reinterpret_cast<const float4*>(S + row * NB);
    float4 a = r[tid * 2], b = r[tid * 2 + 1];
    float mx = fmaxf(fmaxf(fmaxf(a.x, a.y), fmaxf(a.z, a.w)),
                     fmaxf(fmaxf(b.x, b.y), fmaxf(b.z, b.w)));
    mx = blk_max256(mx, sh);
    a.x = __expf(a.x - mx); a.y = __expf(a.y - mx);
    a.z = __expf(a.z - mx); a.w = __expf(a.w - mx);
    b.x = __expf(b.x - mx); b.y = __expf(b.y - mx);
    b.z = __expf(b.z - mx); b.w = __expf(b.w - mx);
    float s = a.x + a.y + a.z + a.w + b.x + b.y + b.z + b.w;
    s = blk_sum256(s, sh);
    float inv = 1.f / s;
    uint32_t* PH = reinterpret_cast<uint32_t*>(ph + row * NB) + tid * 4;
    uint32_t* PL = reinterpret_cast<uint32_t*>(pl + row * NB) + tid * 4;
    uint32_t h, l;
    split2(a.x * inv, a.y * inv, h, l); PH[0] = h; PL[0] = l;
    split2(a.z * inv, a.w * inv, h, l); PH[1] = h; PL[1] = l;
    split2(b.x * inv, b.y * inv, h, l); PH[2] = h; PL[2] = l;
    split2(b.z * inv, b.w * inv, h, l); PH[3] = h; PL[3] = l;
}

// softmax fp32 in place (targets)
__global__ __launch_bounds__(256) void softmax_rows(float* __restrict__ x)
{
    __shared__ float sh[256];
    size_t row = blockIdx.x;
    int tid = threadIdx.x;
    float* r = x + row * NB;
    float v[8];
    float mx = -1e30f;
    #pragma unroll
    for (int i = 0; i < 8; i++) { v[i] = r[i * 256 + tid]; mx = fmaxf(mx, v[i]); }
    mx = blk_max256(mx, sh);
    float s = 0.f;
    #pragma unroll
    for (int i = 0; i < 8; i++) { v[i] = __expf(v[i] - mx); s += v[i]; }
    s = blk_sum256(s, sh);
    float inv = 1.f / s;
    #pragma unroll
    for (int i = 0; i < 8; i++) r[i * 256 + tid] = v[i] * inv;
}

__global__ __launch_bounds__(256) void pack_bf(
    const uint16_t* __restrict__ ih, const uint16_t* __restrict__ il,
    const uint16_t* __restrict__ eh, const uint16_t* __restrict__ el,
    uint16_t* __restrict__ ch, uint16_t* __restrict__ cl)
{
    int row = blockIdx.x, tid = threadIdx.x;   // 256 uint32 per row
    const uint32_t* IH = reinterpret_cast<const uint32_t*>(ih + (size_t)row * PROJ);
    const uint32_t* IL = reinterpret_cast<const uint32_t*>(il + (size_t)row * PROJ);
    const uint32_t* EH = reinterpret_cast<const uint32_t*>(eh + (size_t)row * PROJ);
    const uint32_t* EL = reinterpret_cast<const uint32_t*>(el + (size_t)row * PROJ);
    uint32_t vh, vl;
    if (tid < 128) { vh = IH[tid]; vl = IL[tid]; }
    else           { vh = EH[tid - 128]; vl = EL[tid - 128]; }
    reinterpret_cast<uint32_t*>(ch + (size_t)row * 2 * PROJ)[tid] = vh;
    reinterpret_cast<uint32_t*>(cl + (size_t)row * 2 * PROJ)[tid] = vl;
}

__global__ __launch_bounds__(256) void rowloss_kernel(
    const float* __restrict__ logits, const float* __restrict__ tgt,
    float* __restrict__ rowp)
{
    __shared__ float sh[256];
    int row = blockIdx.x, tid = threadIdx.x;
    const float* lr = logits + (size_t)row * NB;
    const float* tr = tgt    + (size_t)row * NB;
    float lv[8], tv[8];
    float mx = -1e30f;
    #pragma unroll
    for (int i = 0; i < 8; i++) {
        lv[i] = lr[i * 256 + tid];
        tv[i] = tr[i * 256 + tid];
        mx = fmaxf(mx, lv[i]);
    }
    mx = blk_max256(mx, sh);
    float se = 0.f, dot = 0.f;
    #pragma unroll
    for (int i = 0; i < 8; i++) { se += __expf(lv[i] - mx); dot += tv[i] * lv[i]; }
    se  = blk_sum256(se, sh);
    dot = blk_sum256(dot, sh);
    if (tid == 0) rowp[row] = 0.5f * (mx + logf(se) - dot);
}

__global__ __launch_bounds__(256) void colloss_kernel(
    const float* __restrict__ logits, const float* __restrict__ tgt,
    float* __restrict__ colp)
{
    __shared__ float smx[256], sse[256], sts[256], stdot[256];
    int tid = threadIdx.x;
    int c = blockIdx.x * 64 + (tid & 63);
    int ry = tid >> 6;
    float mx = -1e30f, se = 0.f, ts = 0.f, td = 0.f;
    for (int r = ry; r < NB; r += 4) {
        float l = logits[(size_t)r * NB + c];
        float t = tgt   [(size_t)r * NB + c];
        if (l > mx) { se = se * __expf(mx - l) + 1.f; mx = l; }
        else        { se += __expf(l - mx); }
        ts += t;
        td += t * l;
    }
    smx[tid] = mx; sse[tid] = se; sts[tid] = ts; stdot[tid] = td;
    __syncthreads();
    if (ry == 0) {
        #pragma unroll
        for (int k = 1; k < 4; k++) {
            int o = tid + k * 64;
            float m2 = smx[o], s2 = sse[o];
            float m = fmaxf(mx, m2);
            se = se * __expf(mx - m) + s2 * __expf(m2 - m);
            mx = m;
            ts += sts[o];
            td += stdot[o];
        }
        colp[c] = 0.5f * (ts * (mx + logf(se)) - td);
    }
}

__global__ __launch_bounds__(256) void final_reduce(
    const float* __restrict__ a, const float* __restrict__ b,
    float* __restrict__ out)
{
    __shared__ float sh[256];
    int tid = threadIdx.x;
    float s = 0.f;
    for (int i = tid; i < NB; i += 256) s += a[i] + b[i];
    s = blk_sum256(s, sh);
    if (tid == 0) out[0] = s * (1.0f / NB);
}

// ---------------------------------------------------------------------------
// Host launch
// ---------------------------------------------------------------------------
namespace {
constexpr int SMEM_STD = 4 * (2 * 128 * 80 + 2 * 32 * (128 + 8) * 2); // 151552
constexpr int SMEM_NAT = 4 * (2 * 128 * 80 + 2 * 128 * 80);           // 163840
constexpr int SMEM_PV  = 4 * (2 * 128 * 80 + 2 * 32 * (64 + 8) * 2);  // 118784
}

#define SYM(var, sym) cudaGetSymbolAddress((void**)&var, sym)

extern "C" void kernel_launch(void* const* d_in, const int* in_sizes, int n_in,
                              void* d_out, int out_size)
{
    (void)in_sizes; (void)n_in; (void)out_size;
    const float* image_features = (const float*)d_in[0];
    const float* expression     = (const float*)d_in[1];
    const float* x_table        = (const float*)d_in[2];
    const float* y_table        = (const float*)d_in[3];
    const float* ln1_g          = (const float*)d_in[4];
    const float* ln1_b          = (const float*)d_in[5];
    const float* w_qkv          = (const float*)d_in[6];
    const float* w_o            = (const float*)d_in[7];
    const float* b_o            = (const float*)d_in[8];
    const float* ln2_g          = (const float*)d_in[9];
    const float* ln2_b          = (const float*)d_in[10];
    const float* w1             = (const float*)d_in[11];
    const float* b1             = (const float*)d_in[12];
    const float* w2             = (const float*)d_in[13];
    const float* b2             = (const float*)d_in[14];
    const float* img_proj_w     = (const float*)d_in[15];
    const float* img_proj_b     = (const float*)d_in[16];
    const float* img_fc_w       = (const float*)d_in[17];
    const float* img_fc_b       = (const float*)d_in[18];
    const float* img_ln_g       = (const float*)d_in[19];
    const float* img_ln_b       = (const float*)d_in[20];
    const float* spot_proj_w    = (const float*)d_in[21];
    const float* spot_proj_b    = (const float*)d_in[22];
    const float* spot_fc_w      = (const float*)d_in[23];
    const float* spot_fc_b      = (const float*)d_in[24];
    const float* spot_ln_g      = (const float*)d_in[25];
    const float* spot_ln_b      = (const float*)d_in[26];
    const int*   x_idx          = (const int*)d_in[27];
    const int*   y_idx          = (const int*)d_in[28];
    float* out = (float*)d_out;

    float *spot, *tmp, *S, *pimg, *pspot, *logits, *tgt, *rowp, *colp;
    SYM(spot, g_spot); SYM(tmp, g_tmp); SYM(S, g_S);
    SYM(pimg, g_pimg); SYM(pspot, g_pspot);
    SYM(logits, g_logits); SYM(tgt, g_tgt); SYM(rowp, g_rowp); SYM(colp, g_colp);

    uint16_t *hbh, *hbl, *qkh, *qkl, *ath, *atl, *mph, *mpl, *Ph, *Pl;
    uint16_t *eih, *eil, *esh, *esl, *pgh, *pgl, *cth, *ctl, *ifh, *ifl;
    SYM(hbh, g_hbuf_h); SYM(hbl, g_hbuf_l);
    SYM(qkh, g_qkv_h);  SYM(qkl, g_qkv_l);
    SYM(ath, g_attn_h); SYM(atl, g_attn_l);
    SYM(mph, g_mlp_h);  SYM(mpl, g_mlp_l);
    SYM(Ph, g_P_h);     SYM(Pl, g_P_l);
    SYM(eih, g_eimg_h); SYM(eil, g_eimg_l);
    SYM(esh, g_espot_h); SYM(esl, g_espot_l);
    SYM(pgh, g_pg_h);   SYM(pgl, g_pg_l);
    SYM(cth, g_cat_h);  SYM(ctl, g_cat_l);
    SYM(ifh, g_imgf_h); SYM(ifl, g_imgf_l);

    uint16_t *wqh, *wql, *woh, *wol, *w1h, *w1l, *w2h, *w2l;
    uint16_t *iph, *ipl, *ifch, *ifcl, *sph, *spl, *sfh, *sfl;
    SYM(wqh, g_wqkv_h); SYM(wql, g_wqkv_l);
    SYM(woh, g_wo_h);   SYM(wol, g_wo_l);
    SYM(w1h, g_w1_h);   SYM(w1l, g_w1_l);
    SYM(w2h, g_w2_h);   SYM(w2l, g_w2_l);
    SYM(iph, g_wip_h);  SYM(ipl, g_wip_l);
    SYM(ifch, g_wif_h); SYM(ifcl, g_wif_l);
    SYM(sph, g_wsp_h);  SYM(spl, g_wsp_l);
    SYM(sfh, g_wsf_h);  SYM(sfl, g_wsf_l);

    auto kQKV  = gemm_bf<128, false, 0, 2>;
    auto kSqk  = gemm_bf<128, true,  0, 1>;
    auto kPV   = gemm_bf<64,  false, 0, 2>;
    auto kRes  = gemm_bf<128, false, 3, 1>;
    auto kMlp1 = gemm_bf<128, false, 2, 2>;
    auto kProj = gemm_bf<128, false, 1, 7>;
    cudaFuncSetAttribute(kQKV,  cudaFuncAttributeMaxDynamicSharedMemorySize, SMEM_STD);
    cudaFuncSetAttribute(kSqk,  cudaFuncAttributeMaxDynamicSharedMemorySize, SMEM_NAT);
    cudaFuncSetAttribute(kPV,   cudaFuncAttributeMaxDynamicSharedMemorySize, SMEM_PV);
    cudaFuncSetAttribute(kRes,  cudaFuncAttributeMaxDynamicSharedMemorySize, SMEM_STD);
    cudaFuncSetAttribute(kMlp1, cudaFuncAttributeMaxDynamicSharedMemorySize, SMEM_STD);
    cudaFuncSetAttribute(kProj, cudaFuncAttributeMaxDynamicSharedMemorySize, SMEM_STD);

    // ---- convert weights + image features (per-launch, deterministic)
    auto CONV = [&](const float* src, uint16_t* h, uint16_t* l, int n) {
        conv_bf<<<(n / 2 + 255) / 256, 256>>>(src, h, l, n / 2);
    };
    CONV(w_qkv, wqh, wql, NL * SPOT * QKVW);
    CONV(w_o,   woh, wol, NL * INNER * SPOT);
    CONV(w1,    w1h, w1l, NL * SPOT * MLPD);
    CONV(w2,    w2h, w2l, NL * MLPD * SPOT);
    CONV(img_proj_w, iph, ipl, IMG * PROJ);
    CONV(img_fc_w, ifch, ifcl, PROJ * PROJ);
    CONV(spot_proj_w, sph, spl, SPOT * PROJ);
    CONV(spot_fc_w, sfh, sfl, PROJ * PROJ);
    CONV(image_features, ifh, ifl, NB * IMG);

    const long long SZ = (long long)NB * NB;

    // ---- embedding
    embed_kernel<<<NB, 256>>>(expression, x_table, y_table, x_idx, y_idx, spot);

    // ---- transformer layers
    for (int l = 0; l < NL; l++) {
        uint16_t* wqh_l = wqh + (size_t)l * SPOT * QKVW;
        uint16_t* wql_l = wql + (size_t)l * SPOT * QKVW;
        uint16_t* woh_l = woh + (size_t)l * INNER * SPOT;
        uint16_t* wol_l = wol + (size_t)l * INNER * SPOT;
        uint16_t* w1h_l = w1h + (size_t)l * SPOT * MLPD;
        uint16_t* w1l_l = w1l + (size_t)l * SPOT * MLPD;
        uint16_t* w2h_l = w2h + (size_t)l * MLPD * SPOT;
        uint16_t* w2l_l = w2l + (size_t)l * MLPD * SPOT;

        ln_bf<SPOT><<<NB, 256>>>(spot, ln1_g + l * SPOT, ln1_b + l * SPOT, hbh, hbl);
        kQKV<<<dim3(QKVW / 128, NB / 128, 1), 256, SMEM_STD>>>(
            hbh, hbl, SPOT, 0, wqh_l, wql_l, QKVW, 0, nullptr, nullptr,
            nullptr, qkh, qkl, QKVW, 0, SPOT, 1.f);
        kSqk<<<dim3(NB / 128, NB / 128, NH), 256, SMEM_NAT>>>(
            qkh, qkl, QKVW, 64, qkh + INNER, qkl + INNER, QKVW, 64,
            nullptr, nullptr, S, nullptr, nullptr, NB, SZ, DH, 0.125f);
        softmax_bf<<<NH * NB, 256>>>(S, Ph, Pl);
        kPV<<<dim3(1, NB / 128, NH), 256, SMEM_PV>>>(
            Ph, Pl, NB, SZ, qkh + 2 * INNER, qkl + 2 * INNER, QKVW, 64,
            nullptr, nullptr, nullptr, ath, atl, INNER, 64, NB, 1.f);
        kRes<<<dim3(SPOT / 128, NB / 128, 1), 256, SMEM_STD>>>(
            ath, atl, INNER, 0, woh_l, wol_l, SPOT, 0,
            b_o + l * SPOT, spot, spot, nullptr, nullptr, SPOT, 0, INNER, 1.f);
        ln_bf<SPOT><<<NB, 256>>>(spot, ln2_g + l * SPOT, ln2_b + l * SPOT, hbh, hbl);
        kMlp1<<<dim3(MLPD / 128, NB / 128, 1), 256, SMEM_STD>>>(
            hbh, hbl, SPOT, 0, w1h_l, w1l_l, MLPD, 0,
            b1 + l * MLPD, nullptr, nullptr, mph, mpl, MLPD, 0, SPOT, 1.f);
        kRes<<<dim3(SPOT / 128, NB / 128, 1), 256, SMEM_STD>>>(
            mph, mpl, MLPD, 0, w2h_l, w2l_l, SPOT, 0,
            b2 + l * SPOT, spot, spot, nullptr, nullptr, SPOT, 0, MLPD, 1.f);
    }

    // ---- projection heads
    kProj<<<dim3(PROJ / 128, NB / 128, 1), 256, SMEM_STD>>>(
        ifh, ifl, IMG, 0, iph, ipl, PROJ, 0,
        img_proj_b, nullptr, pimg, pgh, pgl, PROJ, 0, IMG, 1.f);
    kRes<<<dim3(PROJ / 128, NB / 128, 1), 256, SMEM_STD>>>(
        pgh, pgl, PROJ, 0, ifch, ifcl, PROJ, 0,
        img_fc_b, pimg, tmp, nullptr, nullptr, PROJ, 0, PROJ, 1.f);
    ln_bf<PROJ><<<NB, 256>>>(tmp, img_ln_g, img_ln_b, eih, eil);

    CONV(spot, hbh, hbl, NB * SPOT);   // spot -> bf16 for spot head
    kProj<<<dim3(PROJ / 128, NB / 128, 1), 256, SMEM_STD>>>(
        hbh, hbl, SPOT, 0, sph, spl, PROJ, 0,
        spot_proj_b, nullptr, pspot, pgh, pgl, PROJ, 0, SPOT, 1.f);
    kRes<<<dim3(PROJ / 128, NB / 128, 1), 256, SMEM_STD>>>(
        pgh, pgl, PROJ, 0, sfh, sfl, PROJ, 0,
        spot_fc_b, pspot, tmp, nullptr, nullptr, PROJ, 0, PROJ, 1.f);
    ln_bf<PROJ><<<NB, 256>>>(tmp, spot_ln_g, spot_ln_b, esh, esl);

    // ---- loss
    pack_bf<<<NB, 256>>>(eih, eil, esh, esl, cth, ctl);
    kSqk<<<dim3(NB / 128, NB / 128, 1), 256, SMEM_NAT>>>(
        esh, esl, PROJ, 0, eih, eil, PROJ, 0,
        nullptr, nullptr, logits, nullptr, nullptr, NB, 0, PROJ, 1.f);
    kSqk<<<dim3(NB / 128, NB / 128, 1), 256, SMEM_NAT>>>(
        cth, ctl, 2 * PROJ, 0, cth, ctl, 2 * PROJ, 0,
        nullptr, nullptr, tgt, nullptr, nullptr, NB, 0, 2 * PROJ, 0.5f);
    softmax_rows<<<NB, 256>>>(tgt);
    rowloss_kernel<<<NB, 256>>>(logits, tgt, rowp);
    colloss_kernel<<<NB / 64, 256>>>(logits, tgt, colp);
    final_reduce<<<1, 256>>>(rowp, colp, out);
}

// round 5
// speedup vs baseline: 1.0339x; 1.0339x over previous
#include <cuda_runtime.h>
#include <cstdint>

// ---------------------------------------------------------------------------
// Problem constants
// ---------------------------------------------------------------------------
namespace {
constexpr int NB   = 2048;
constexpr int SPOT = 1024;
constexpr int IMG  = 1024;
constexpr int PROJ = 256;
constexpr int NH   = 8;
constexpr int DH   = 64;
constexpr int INNER = 512;
constexpr int MLPD = 2048;
constexpr int QKVW = 1536;
constexpr int NL   = 2;
}

// ---------------------------------------------------------------------------
// Scratch: fp32
// ---------------------------------------------------------------------------
__device__ float g_spot  [NB * SPOT];
__device__ float g_tmp   [NB * SPOT];
__device__ float g_S     [(size_t)NH * NB * NB];
__device__ float g_pimg  [NB * PROJ];
__device__ float g_pspot [NB * PROJ];
__device__ float g_logits[NB * NB];
__device__ float g_tgt   [NB * NB];
__device__ float g_rowp  [NB];
__device__ float g_colp  [NB];

// ---------------------------------------------------------------------------
// Scratch: bf16 hi/lo (stored as uint16)
// ---------------------------------------------------------------------------
__device__ uint16_t g_hbuf_h[NB * SPOT],  g_hbuf_l[NB * SPOT];
__device__ uint16_t g_qkv_h [NB * QKVW],  g_qkv_l [NB * QKVW];
__device__ uint16_t g_attn_h[NB * INNER], g_attn_l[NB * INNER];
__device__ uint16_t g_mlp_h [NB * MLPD],  g_mlp_l [NB * MLPD];
__device__ uint16_t g_P_h[(size_t)NH * NB * NB], g_P_l[(size_t)NH * NB * NB];
__device__ uint16_t g_eimg_h [NB * PROJ], g_eimg_l [NB * PROJ];
__device__ uint16_t g_espot_h[NB * PROJ], g_espot_l[NB * PROJ];
__device__ uint16_t g_pg_h   [NB * PROJ], g_pg_l   [NB * PROJ];
__device__ uint16_t g_cat_h[NB * 2 * PROJ], g_cat_l[NB * 2 * PROJ];
__device__ uint16_t g_imgf_h[NB * IMG], g_imgf_l[NB * IMG];
// weights bf16
__device__ uint16_t g_wqkv_h[NL * SPOT * QKVW], g_wqkv_l[NL * SPOT * QKVW];
__device__ uint16_t g_wo_h  [NL * INNER * SPOT], g_wo_l [NL * INNER * SPOT];
__device__ uint16_t g_w1_h  [NL * SPOT * MLPD],  g_w1_l [NL * SPOT * MLPD];
__device__ uint16_t g_w2_h  [NL * MLPD * SPOT],  g_w2_l [NL * MLPD * SPOT];
__device__ uint16_t g_wip_h [IMG * PROJ],  g_wip_l[IMG * PROJ];
__device__ uint16_t g_wif_h [PROJ * PROJ], g_wif_l[PROJ * PROJ];
__device__ uint16_t g_wsp_h [SPOT * PROJ], g_wsp_l[SPOT * PROJ];
__device__ uint16_t g_wsf_h [PROJ * PROJ], g_wsf_l[PROJ * PROJ];

// ---------------------------------------------------------------------------
// Helpers
// ---------------------------------------------------------------------------
__device__ __forceinline__ uint32_t smem_u32(const void* p) {
    uint32_t a;
    asm("{ .reg .u64 t; cvta.to.shared.u64 t, %1; cvt.u32.u64 %0, t; }"
        : "=r"(a) : "l"(p));
    return a;
}
__device__ __forceinline__ unsigned long long gptr(const void* p) {
    return (unsigned long long)__cvta_generic_to_global(p);
}
__device__ __forceinline__ float gelu_f(float x) {
    return 0.5f * x * (1.0f + erff(x * 0.7071067811865475f));
}
// split fp32 pair -> packed bf16x2 hi and lo (f0 in low half)
__device__ __forceinline__ void split2(float f0, float f1, uint32_t& hi, uint32_t& lo) {
    asm("cvt.rn.bf16x2.f32 %0, %1, %2;" : "=r"(hi) : "f"(f1), "f"(f0));
    float h0 = __uint_as_float(hi << 16);
    float h1 = __uint_as_float(hi & 0xFFFF0000u);
    float l0 = f0 - h0, l1 = f1 - h1;
    asm("cvt.rn.bf16x2.f32 %0, %1, %2;" : "=r"(lo) : "f"(l1), "f"(l0));
}

#define CP16(dst, src) \
    asm volatile("cp.async.cg.shared.global [%0], [%1], 16;" :: "r"(dst), "l"(src))
#define CP_COMMIT() asm volatile("cp.async.commit_group;" ::: "memory")
#define CP_WAIT2()  asm volatile("cp.async.wait_group 2;" ::: "memory")

#define LDSM_X4(r, a)                                                          \
    asm volatile("ldmatrix.sync.aligned.m8n8.x4.shared.b16 {%0,%1,%2,%3}, [%4];" \
        : "=r"((r)[0]), "=r"((r)[1]), "=r"((r)[2]), "=r"((r)[3]) : "r"(a))
#define LDSM_X2(r, a)                                                          \
    asm volatile("ldmatrix.sync.aligned.m8n8.x2.shared.b16 {%0,%1}, [%2];"     \
        : "=r"((r)[0]), "=r"((r)[1]) : "r"(a))
#define LDSM_X2T(r, a)                                                         \
    asm volatile("ldmatrix.sync.aligned.m8n8.x2.trans.shared.b16 {%0,%1}, [%2];" \
        : "=r"((r)[0]), "=r"((r)[1]) : "r"(a))
#define MMA16816(d, a, b)                                                      \
    asm volatile("mma.sync.aligned.m16n8k16.row.col.f32.bf16.bf16.f32 "        \
        "{%0,%1,%2,%3}, {%4,%5,%6,%7}, {%8,%9}, {%0,%1,%2,%3};"                \
        : "+f"((d)[0]), "+f"((d)[1]), "+f"((d)[2]), "+f"((d)[3])               \
        : "r"((a)[0]), "r"((a)[1]), "r"((a)[2]), "r"((a)[3]),                  \
          "r"((b)[0]), "r"((b)[1]))

// ---------------------------------------------------------------------------
// Pure-bf16 split GEMM. 512 threads (16 warps, 4 per SMSP), warp grid 4x4,
// warp tile 32 x (NT/4). 4-stage cp.async pipeline, BK=32.
//   D = epi( scale * (Ah+Al) @ op(Bh+Bl) ) via 3 MMA passes (hh + hl + lh)
//   A: [M,K] bf16 hi/lo. B: BNAT ? [N,K] : [K,N] bf16 hi/lo.
//   EPI: 0 none, 1 +bias, 2 +bias+gelu, 3 +bias+res(fp32)
//   OUT bits: 1 = fp32 C, 2 = bf16 Ch/Cl, 4 = gelu before bf16 split only
// ---------------------------------------------------------------------------
template<int NT, bool BNAT, int EPI, int OUT>
__global__ __launch_bounds__(512) void gemm_bf(
    const uint16_t* __restrict__ Ah, const uint16_t* __restrict__ Al,
    int lda, long long az,
    const uint16_t* __restrict__ Bh, const uint16_t* __restrict__ Bl,
    int ldb, long long bz,
    const float* __restrict__ bias, const float* __restrict__ res,
    float* __restrict__ C, uint16_t* __restrict__ Ch, uint16_t* __restrict__ Cl,
    int ldc, long long cz, int K, float scale)
{
    constexpr int WNC = NT / 4;                 // cols per warp (32 or 16)
    constexpr int NTL = WNC / 8;                // n-tiles per warp (4 or 2)
    constexpr int MT  = 2;                      // m16 tiles per warp (WM=32)
    constexpr int ABYTES = 128 * 80;            // bf16, row stride 40 elems
    constexpr int BROWB  = BNAT ? 80 : (NT + 8) * 2;
    constexpr int BBYTES = BNAT ? NT * 80 : 32 * (NT + 8) * 2;
    constexpr int STAGE  = 2 * ABYTES + 2 * BBYTES;
    constexpr int STAGES = 4;
    constexpr int BSEGS  = BNAT ? NT * 4 : 32 * (NT / 8);

    extern __shared__ __align__(128) char smm[];
    const uint32_t sb = smem_u32(smm);
    const int tid = threadIdx.x, lane = tid & 31, wid = tid >> 5;
    const int wm = wid >> 2, wn = wid & 3;
    const int bm = blockIdx.y * 128, bn = blockIdx.x * NT;

    const uint16_t* Abh = Ah + (size_t)blockIdx.z * az + (size_t)bm * lda;
    const uint16_t* Abl = Al + (size_t)blockIdx.z * az + (size_t)bm * lda;
    const uint16_t* Bbh = Bh + (size_t)blockIdx.z * bz;
    const uint16_t* Bbl = Bl + (size_t)blockIdx.z * bz;

    float acc[MT][NTL][4];
    #pragma unroll
    for (int mt = 0; mt < MT; mt++)
        #pragma unroll
        for (int nt = 0; nt < NTL; nt++)
            #pragma unroll
            for (int r = 0; r < 4; r++) acc[mt][nt][r] = 0.f;

    const int NC = K >> 5;

    auto issue = [&](int c, int s) {
        const uint32_t st = sb + s * STAGE;
        const int k0 = c << 5;
        {   // A: 512 segs of 16B per buffer — one per thread
            int row = tid >> 2, seg = tid & 3;
            size_t so = (size_t)row * lda + k0 + seg * 8;
            uint32_t d = st + row * 80 + seg * 16;
            CP16(d, gptr(Abh + so));
            CP16(d + ABYTES, gptr(Abl + so));
        }
        if (BSEGS == 512 || tid < BSEGS) {
            if (BNAT) {
                int row = tid >> 2, seg = tid & 3;
                size_t so = (size_t)(bn + row) * ldb + k0 + seg * 8;
                uint32_t d = st + 2 * ABYTES + row * 80 + seg * 16;
                CP16(d, gptr(Bbh + so));
                CP16(d + BBYTES, gptr(Bbl + so));
            } else {
                int row = tid / (NT / 8), seg = tid % (NT / 8);
                size_t so = (size_t)(k0 + row) * ldb + bn + seg * 8;
                uint32_t d = st + 2 * ABYTES + row * BROWB + seg * 16;
                CP16(d, gptr(Bbh + so));
                CP16(d + BBYTES, gptr(Bbl + so));
            }
        }
    };

    #pragma unroll
    for (int s = 0; s < STAGES - 1; s++) {
        if (s < NC) issue(s, s);
        CP_COMMIT();
    }

    for (int c = 0; c < NC; c++) {
        CP_WAIT2();
        __syncthreads();
        {
            int cn = c + STAGES - 1;
            if (cn < NC) issue(cn, cn % STAGES);
            CP_COMMIT();
        }
        const uint32_t abh_ = sb + (c % STAGES) * STAGE;
        const uint32_t abl_ = abh_ + ABYTES;
        const uint32_t bbh_ = abh_ + 2 * ABYTES;
        const uint32_t bbl_ = bbh_ + BBYTES;
        #pragma unroll
        for (int ks = 0; ks < 2; ks++) {
            uint32_t afh[MT][4], afl[MT][4], bfh[NTL][2], bfl[NTL][2];
            #pragma unroll
            for (int mt = 0; mt < MT; mt++) {
                uint32_t off = ((wm * 32 + mt * 16 + (lane & 15)) * 40 +
                                ks * 16 + ((lane >> 4) << 3)) << 1;
                LDSM_X4(afh[mt], abh_ + off);
                LDSM_X4(afl[mt], abl_ + off);
            }
            #pragma unroll
            for (int nt = 0; nt < NTL; nt++) {
                if (BNAT) {
                    uint32_t off = ((wn * WNC + nt * 8 + (lane & 7)) * 40 +
                                    ks * 16 + (((lane >> 3) & 1) << 3)) << 1;
                    LDSM_X2(bfh[nt], bbh_ + off);
                    LDSM_X2(bfl[nt], bbl_ + off);
                } else {
                    uint32_t off = ((ks * 16 + (lane & 15)) * (NT + 8) +
                                    wn * WNC + nt * 8) << 1;
                    LDSM_X2T(bfh[nt], bbh_ + off);
                    LDSM_X2T(bfl[nt], bbl_ + off);
                }
            }
            #pragma unroll
            for (int nt = 0; nt < NTL; nt++)
                #pragma unroll
                for (int mt = 0; mt < MT; mt++) {
                    MMA16816(acc[mt][nt], afh[mt], bfh[nt]);
                    MMA16816(acc[mt][nt], afh[mt], bfl[nt]);
                    MMA16816(acc[mt][nt], afl[mt], bfh[nt]);
                }
        }
    }

    // ---- epilogue
    const int gid = lane >> 2, tig = lane & 3;
    #pragma unroll
    for (int mt = 0; mt < MT; mt++) {
        #pragma unroll
        for (int nt = 0; nt < NTL; nt++) {
            int r0  = bm + wm * 32 + mt * 16 + gid;
            int col = bn + wn * WNC + nt * 8 + tig * 2;
            float2 v0 = make_float2(acc[mt][nt][0] * scale, acc[mt][nt][1] * scale);
            float2 v1 = make_float2(acc[mt][nt][2] * scale, acc[mt][nt][3] * scale);
            if (EPI >= 1) {
                float2 bb = *reinterpret_cast<const float2*>(&bias[col]);
                v0.x += bb.x; v0.y += bb.y; v1.x += bb.x; v1.y += bb.y;
            }
            if (EPI == 2) {
                v0.x = gelu_f(v0.x); v0.y = gelu_f(v0.y);
                v1.x = gelu_f(v1.x); v1.y = gelu_f(v1.y);
            }
            if (EPI == 3) {
                float2 ra = *reinterpret_cast<const float2*>(
                    &res[(size_t)r0 * ldc + col]);
                float2 rb = *reinterpret_cast<const float2*>(
                    &res[(size_t)(r0 + 8) * ldc + col]);
                v0.x += ra.x; v0.y += ra.y; v1.x += rb.x; v1.y += rb.y;
            }
            size_t o0 = (size_t)r0 * ldc + col + (size_t)blockIdx.z * cz;
            size_t o1 = (size_t)(r0 + 8) * ldc + col + (size_t)blockIdx.z * cz;
            if (OUT & 1) {
                *reinterpret_cast<float2*>(&C[o0]) = v0;
                *reinterpret_cast<float2*>(&C[o1]) = v1;
            }
            if (OUT & 2) {
                float a0 = v0.x, a1 = v0.y, b0 = v1.x, b1 = v1.y;
                if (OUT & 4) {
                    a0 = gelu_f(a0); a1 = gelu_f(a1);
                    b0 = gelu_f(b0); b1 = gelu_f(b1);
                }
                uint32_t h, l;
                split2(a0, a1, h, l);
                *reinterpret_cast<uint32_t*>(&Ch[o0]) = h;
                *reinterpret_cast<uint32_t*>(&Cl[o0]) = l;
                split2(b0, b1, h, l);
                *reinterpret_cast<uint32_t*>(&Ch[o1]) = h;
                *reinterpret_cast<uint32_t*>(&Cl[o1]) = l;
            }
        }
    }
}

// ---------------------------------------------------------------------------
// Reductions
// ---------------------------------------------------------------------------
__device__ __forceinline__ float blk_sum256(float v, float* sh) {
    int t = threadIdx.x;
    sh[t] = v; __syncthreads();
    #pragma unroll
    for (int s = 128; s >= 1; s >>= 1) {
        if (t < s) sh[t] += sh[t + s];
        __syncthreads();
    }
    float r = sh[0]; __syncthreads();
    return r;
}
__device__ __forceinline__ float blk_max256(float v, float* sh) {
    int t = threadIdx.x;
    sh[t] = v; __syncthreads();
    #pragma unroll
    for (int s = 128; s >= 1; s >>= 1) {
        if (t < s) sh[t] = fmaxf(sh[t], sh[t + s]);
        __syncthreads();
    }
    float r = sh[0]; __syncthreads();
    return r;
}

// ---------------------------------------------------------------------------
// Elementwise kernels
// ---------------------------------------------------------------------------
__global__ __launch_bounds__(256) void conv_bf(
    const float* __restrict__ x, uint16_t* __restrict__ h,
    uint16_t* __restrict__ l, int n2)
{
    int i = blockIdx.x * 256 + threadIdx.x;
    if (i < n2) {
        float2 v = reinterpret_cast<const float2*>(x)[i];
        uint32_t hh, ll;
        split2(v.x, v.y, hh, ll);
        reinterpret_cast<uint32_t*>(h)[i] = hh;
        reinterpret_cast<uint32_t*>(l)[i] = ll;
    }
}

__global__ __launch_bounds__(256) void embed_kernel(
    const float* __restrict__ expr, const float* __restrict__ xt,
    const float* __restrict__ yt, const int* __restrict__ xi,
    const int* __restrict__ yi, float* __restrict__ out)
{
    int row = blockIdx.x;
    size_t xo = (size_t)xi[row] * SPOT;
    size_t yo = (size_t)yi[row] * SPOT;
    size_t ro = (size_t)row * SPOT;
    for (int j = threadIdx.x; j < SPOT; j += 256)
        out[ro + j] = expr[ro + j] + xt[xo + j] + yt[yo + j];
}

// LayerNorm fp32 -> split bf16
template<int N>
__global__ __launch_bounds__(256) void ln_bf(
    const float* __restrict__ x, const float* __restrict__ g,
    const float* __restrict__ b, uint16_t* __restrict__ oh,
    uint16_t* __restrict__ ol)
{
    __shared__ float sh[256];
    constexpr int NPAIR = N / 2;
    constexpr int NP = (NPAIR + 255) / 256;
    int row = blockIdx.x, tid = threadIdx.x;
    const float2* xr = reinterpret_cast<const float2*>(x + (size_t)row * N);
    float2 v[NP];
    float s = 0.f;
    #pragma unroll
    for (int i = 0; i < NP; i++) {
        int p = i * 256 + tid;
        if (p < NPAIR) { v[i] = xr[p]; s += v[i].x + v[i].y; }
        else v[i] = make_float2(0.f, 0.f);
    }
    s = blk_sum256(s, sh);
    float mean = s / N, ss = 0.f;
    #pragma unroll
    for (int i = 0; i < NP; i++) {
        int p = i * 256 + tid;
        if (p < NPAIR) {
            float dx = v[i].x - mean, dy = v[i].y - mean;
            ss += dx * dx + dy * dy;
        }
    }
    ss = blk_sum256(ss, sh);
    float rstd = rsqrtf(ss / N + 1e-5f);
    uint32_t* OH = reinterpret_cast<uint32_t*>(oh + (size_t)row * N);
    uint32_t* OL = reinterpret_cast<uint32_t*>(ol + (size_t)row * N);
    #pragma unroll
    for (int i = 0; i < NP; i++) {
        int p = i * 256 + tid;
        if (p < NPAIR) {
            float2 gg = reinterpret_cast<const float2*>(g)[p];
            float2 bb = reinterpret_cast<const float2*>(b)[p];
            float y0 = (v[i].x - mean) * rstd * gg.x + bb.x;
            float y1 = (v[i].y - mean) * rstd * gg.y + bb.y;
            uint32_t h, l;
            split2(y0, y1, h, l);
            OH[p] = h; OL[p] = l;
        }
    }
}

// softmax fp32 row -> split bf16 (attention P)
__global__ __launch_bounds__(256) void softmax_bf(
    const float* __restrict__ S, uint16_t* __restrict__ ph,
    uint16_t* __restrict__ pl)
{
    __shared__ float sh[256];
    size_t row = blockIdx.x;
    int tid = threadIdx.x;
    const float4* r = reinterpret_cast<const float4*>(S + row * NB);
    float4 a = r[tid * 2], b = r[tid * 2 + 1];
    float mx = fmaxf(fmaxf(fmaxf(a.x, a.y), fmaxf(a.z, a.w)),
                     fmaxf(fmaxf(b.x, b.y), fmaxf(b.z, b.w)));
    mx = blk_max256(mx, sh);
    a.x = __expf(a.x - mx); a.y = __expf(a.y - mx);
    a.z = __expf(a.z - mx); a.w = __expf(a.w - mx);
    b.x = __expf(b.x - mx); b.y = __expf(b.y - mx);
    b.z = __expf(b.z - mx); b.w = __expf(b.w - mx);
    float s = a.x + a.y + a.z + a.w + b.x + b.y + b.z + b.w;
    s = blk_sum256(s, sh);
    float inv = 1.f / s;
    uint32_t* PH = reinterpret_cast<uint32_t*>(ph + row * NB) + tid * 4;
    uint32_t* PL = reinterpret_cast<uint32_t*>(pl + row * NB) + tid * 4;
    uint32_t h, l;
    split2(a.x * inv, a.y * inv, h, l); PH[0] = h; PL[0] = l;
    split2(a.z * inv, a.w * inv, h, l); PH[1] = h; PL[1] = l;
    split2(b.x * inv, b.y * inv, h, l); PH[2] = h; PL[2] = l;
    split2(b.z * inv, b.w * inv, h, l); PH[3] = h; PL[3] = l;
}

// softmax fp32 in place (targets)
__global__ __launch_bounds__(256) void softmax_rows(float* __restrict__ x)
{
    __shared__ float sh[256];
    size_t row = blockIdx.x;
    int tid = threadIdx.x;
    float* r = x + row * NB;
    float v[8];
    float mx = -1e30f;
    #pragma unroll
    for (int i = 0; i < 8; i++) { v[i] = r[i * 256 + tid]; mx = fmaxf(mx, v[i]); }
    mx = blk_max256(mx, sh);
    float s = 0.f;
    #pragma unroll
    for (int i = 0; i < 8; i++) { v[i] = __expf(v[i] - mx); s += v[i]; }
    s = blk_sum256(s, sh);
    float inv = 1.f / s;
    #pragma unroll
    for (int i = 0; i < 8; i++) r[i * 256 + tid] = v[i] * inv;
}

__global__ __launch_bounds__(256) void pack_bf(
    const uint16_t* __restrict__ ih, const uint16_t* __restrict__ il,
    const uint16_t* __restrict__ eh, const uint16_t* __restrict__ el,
    uint16_t* __restrict__ ch, uint16_t* __restrict__ cl)
{
    int row = blockIdx.x, tid = threadIdx.x;
    const uint32_t* IH = reinterpret_cast<const uint32_t*>(ih + (size_t)row * PROJ);
    const uint32_t* IL = reinterpret_cast<const uint32_t*>(il + (size_t)row * PROJ);
    const uint32_t* EH = reinterpret_cast<const uint32_t*>(eh + (size_t)row * PROJ);
    const uint32_t* EL = reinterpret_cast<const uint32_t*>(el + (size_t)row * PROJ);
    uint32_t vh, vl;
    if (tid < 128) { vh = IH[tid]; vl = IL[tid]; }
    else           { vh = EH[tid - 128]; vl = EL[tid - 128]; }
    reinterpret_cast<uint32_t*>(ch + (size_t)row * 2 * PROJ)[tid] = vh;
    reinterpret_cast<uint32_t*>(cl + (size_t)row * 2 * PROJ)[tid] = vl;
}

__global__ __launch_bounds__(256) void rowloss_kernel(
    const float* __restrict__ logits, const float* __restrict__ tgt,
    float* __restrict__ rowp)
{
    __shared__ float sh[256];
    int row = blockIdx.x, tid = threadIdx.x;
    const float* lr = logits + (size_t)row * NB;
    const float* tr = tgt    + (size_t)row * NB;
    float lv[8], tv[8];
    float mx = -1e30f;
    #pragma unroll
    for (int i = 0; i < 8; i++) {
        lv[i] = lr[i * 256 + tid];
        tv[i] = tr[i * 256 + tid];
        mx = fmaxf(mx, lv[i]);
    }
    mx = blk_max256(mx, sh);
    float se = 0.f, dot = 0.f;
    #pragma unroll
    for (int i = 0; i < 8; i++) { se += __expf(lv[i] - mx); dot += tv[i] * lv[i]; }
    se  = blk_sum256(se, sh);
    dot = blk_sum256(dot, sh);
    if (tid == 0) rowp[row] = 0.5f * (mx + logf(se) - dot);
}

__global__ __launch_bounds__(256) void colloss_kernel(
    const float* __restrict__ logits, const float* __restrict__ tgt,
    float* __restrict__ colp)
{
    __shared__ float smx[256], sse[256], sts[256], stdot[256];
    int tid = threadIdx.x;
    int c = blockIdx.x * 64 + (tid & 63);
    int ry = tid >> 6;
    float mx = -1e30f, se = 0.f, ts = 0.f, td = 0.f;
    for (int r = ry; r < NB; r += 4) {
        float l = logits[(size_t)r * NB + c];
        float t = tgt   [(size_t)r * NB + c];
        if (l > mx) { se = se * __expf(mx - l) + 1.f; mx = l; }
        else        { se += __expf(l - mx); }
        ts += t;
        td += t * l;
    }
    smx[tid] = mx; sse[tid] = se; sts[tid] = ts; stdot[tid] = td;
    __syncthreads();
    if (ry == 0) {
        #pragma unroll
        for (int k = 1; k < 4; k++) {
            int o = tid + k * 64;
            float m2 = smx[o], s2 = sse[o];
            float m = fmaxf(mx, m2);
            se = se * __expf(mx - m) + s2 * __expf(m2 - m);
            mx = m;
            ts += sts[o];
            td += stdot[o];
        }
        colp[c] = 0.5f * (ts * (mx + logf(se)) - td);
    }
}

__global__ __launch_bounds__(256) void final_reduce(
    const float* __restrict__ a, const float* __restrict__ b,
    float* __restrict__ out)
{
    __shared__ float sh[256];
    int tid = threadIdx.x;
    float s = 0.f;
    for (int i = tid; i < NB; i += 256) s += a[i] + b[i];
    s = blk_sum256(s, sh);
    if (tid == 0) out[0] = s * (1.0f / NB);
}

// ---------------------------------------------------------------------------
// Host launch
// ---------------------------------------------------------------------------
namespace {
constexpr int SMEM_STD = 4 * (2 * 128 * 80 + 2 * 32 * (128 + 8) * 2); // 151552
constexpr int SMEM_NAT = 4 * (2 * 128 * 80 + 2 * 128 * 80);           // 163840
constexpr int SMEM_PV  = 4 * (2 * 128 * 80 + 2 * 32 * (64 + 8) * 2);  // 118784
}

#define SYM(var, sym) cudaGetSymbolAddress((void**)&var, sym)

extern "C" void kernel_launch(void* const* d_in, const int* in_sizes, int n_in,
                              void* d_out, int out_size)
{
    (void)in_sizes; (void)n_in; (void)out_size;
    const float* image_features = (const float*)d_in[0];
    const float* expression     = (const float*)d_in[1];
    const float* x_table        = (const float*)d_in[2];
    const float* y_table        = (const float*)d_in[3];
    const float* ln1_g          = (const float*)d_in[4];
    const float* ln1_b          = (const float*)d_in[5];
    const float* w_qkv          = (const float*)d_in[6];
    const float* w_o            = (const float*)d_in[7];
    const float* b_o            = (const float*)d_in[8];
    const float* ln2_g          = (const float*)d_in[9];
    const float* ln2_b          = (const float*)d_in[10];
    const float* w1             = (const float*)d_in[11];
    const float* b1             = (const float*)d_in[12];
    const float* w2             = (const float*)d_in[13];
    const float* b2             = (const float*)d_in[14];
    const float* img_proj_w     = (const float*)d_in[15];
    const float* img_proj_b     = (const float*)d_in[16];
    const float* img_fc_w       = (const float*)d_in[17];
    const float* img_fc_b       = (const float*)d_in[18];
    const float* img_ln_g       = (const float*)d_in[19];
    const float* img_ln_b       = (const float*)d_in[20];
    const float* spot_proj_w    = (const float*)d_in[21];
    const float* spot_proj_b    = (const float*)d_in[22];
    const float* spot_fc_w      = (const float*)d_in[23];
    const float* spot_fc_b      = (const float*)d_in[24];
    const float* spot_ln_g      = (const float*)d_in[25];
    const float* spot_ln_b      = (const float*)d_in[26];
    const int*   x_idx          = (const int*)d_in[27];
    const int*   y_idx          = (const int*)d_in[28];
    float* out = (float*)d_out;

    float *spot, *tmp, *S, *pimg, *pspot, *logits, *tgt, *rowp, *colp;
    SYM(spot, g_spot); SYM(tmp, g_tmp); SYM(S, g_S);
    SYM(pimg, g_pimg); SYM(pspot, g_pspot);
    SYM(logits, g_logits); SYM(tgt, g_tgt); SYM(rowp, g_rowp); SYM(colp, g_colp);

    uint16_t *hbh, *hbl, *qkh, *qkl, *ath, *atl, *mph, *mpl, *Ph, *Pl;
    uint16_t *eih, *eil, *esh, *esl, *pgh, *pgl, *cth, *ctl, *ifh, *ifl;
    SYM(hbh, g_hbuf_h); SYM(hbl, g_hbuf_l);
    SYM(qkh, g_qkv_h);  SYM(qkl, g_qkv_l);
    SYM(ath, g_attn_h); SYM(atl, g_attn_l);
    SYM(mph, g_mlp_h);  SYM(mpl, g_mlp_l);
    SYM(Ph, g_P_h);     SYM(Pl, g_P_l);
    SYM(eih, g_eimg_h); SYM(eil, g_eimg_l);
    SYM(esh, g_espot_h); SYM(esl, g_espot_l);
    SYM(pgh, g_pg_h);   SYM(pgl, g_pg_l);
    SYM(cth, g_cat_h);  SYM(ctl, g_cat_l);
    SYM(ifh, g_imgf_h); SYM(ifl, g_imgf_l);

    uint16_t *wqh, *wql, *woh, *wol, *w1h, *w1l, *w2h, *w2l;
    uint16_t *iph, *ipl, *ifch, *ifcl, *sph, *spl, *sfh, *sfl;
    SYM(wqh, g_wqkv_h); SYM(wql, g_wqkv_l);
    SYM(woh, g_wo_h);   SYM(wol, g_wo_l);
    SYM(w1h, g_w1_h);   SYM(w1l, g_w1_l);
    SYM(w2h, g_w2_h);   SYM(w2l, g_w2_l);
    SYM(iph, g_wip_h);  SYM(ipl, g_wip_l);
    SYM(ifch, g_wif_h); SYM(ifcl, g_wif_l);
    SYM(sph, g_wsp_h);  SYM(spl, g_wsp_l);
    SYM(sfh, g_wsf_h);  SYM(sfl, g_wsf_l);

    auto kQKV  = gemm_bf<128, false, 0, 2>;
    auto kSqk  = gemm_bf<128, true,  0, 1>;
    auto kPV   = gemm_bf<64,  false, 0, 2>;
    auto kRes  = gemm_bf<128, false, 3, 1>;
    auto kMlp1 = gemm_bf<128, false, 2, 2>;
    auto kProj = gemm_bf<128, false, 1, 7>;
    cudaFuncSetAttribute(kQKV,  cudaFuncAttributeMaxDynamicSharedMemorySize, SMEM_STD);
    cudaFuncSetAttribute(kSqk,  cudaFuncAttributeMaxDynamicSharedMemorySize, SMEM_NAT);
    cudaFuncSetAttribute(kPV,   cudaFuncAttributeMaxDynamicSharedMemorySize, SMEM_PV);
    cudaFuncSetAttribute(kRes,  cudaFuncAttributeMaxDynamicSharedMemorySize, SMEM_STD);
    cudaFuncSetAttribute(kMlp1, cudaFuncAttributeMaxDynamicSharedMemorySize, SMEM_STD);
    cudaFuncSetAttribute(kProj, cudaFuncAttributeMaxDynamicSharedMemorySize, SMEM_STD);

    auto CONV = [&](const float* src, uint16_t* h, uint16_t* l, int n) {
        conv_bf<<<(n / 2 + 255) / 256, 256>>>(src, h, l, n / 2);
    };
    CONV(w_qkv, wqh, wql, NL * SPOT * QKVW);
    CONV(w_o,   woh, wol, NL * INNER * SPOT);
    CONV(w1,    w1h, w1l, NL * SPOT * MLPD);
    CONV(w2,    w2h, w2l, NL * MLPD * SPOT);
    CONV(img_proj_w, iph, ipl, IMG * PROJ);
    CONV(img_fc_w, ifch, ifcl, PROJ * PROJ);
    CONV(spot_proj_w, sph, spl, SPOT * PROJ);
    CONV(spot_fc_w, sfh, sfl, PROJ * PROJ);
    CONV(image_features, ifh, ifl, NB * IMG);

    const long long SZ = (long long)NB * NB;

    embed_kernel<<<NB, 256>>>(expression, x_table, y_table, x_idx, y_idx, spot);

    for (int l = 0; l < NL; l++) {
        uint16_t* wqh_l = wqh + (size_t)l * SPOT * QKVW;
        uint16_t* wql_l = wql + (size_t)l * SPOT * QKVW;
        uint16_t* woh_l = woh + (size_t)l * INNER * SPOT;
        uint16_t* wol_l = wol + (size_t)l * INNER * SPOT;
        uint16_t* w1h_l = w1h + (size_t)l * SPOT * MLPD;
        uint16_t* w1l_l = w1l + (size_t)l * SPOT * MLPD;
        uint16_t* w2h_l = w2h + (size_t)l * MLPD * SPOT;
        uint16_t* w2l_l = w2l + (size_t)l * MLPD * SPOT;

        ln_bf<SPOT><<<NB, 256>>>(spot, ln1_g + l * SPOT, ln1_b + l * SPOT, hbh, hbl);
        kQKV<<<dim3(QKVW / 128, NB / 128, 1), 512, SMEM_STD>>>(
            hbh, hbl, SPOT, 0, wqh_l, wql_l, QKVW, 0, nullptr, nullptr,
            nullptr, qkh, qkl, QKVW, 0, SPOT, 1.f);
        kSqk<<<dim3(NB / 128, NB / 128, NH), 512, SMEM_NAT>>>(
            qkh, qkl, QKVW, 64, qkh + INNER, qkl + INNER, QKVW, 64,
            nullptr, nullptr, S, nullptr, nullptr, NB, SZ, DH, 0.125f);
        softmax_bf<<<NH * NB, 256>>>(S, Ph, Pl);
        kPV<<<dim3(1, NB / 128, NH), 512, SMEM_PV>>>(
            Ph, Pl, NB, SZ, qkh + 2 * INNER, qkl + 2 * INNER, QKVW, 64,
            nullptr, nullptr, nullptr, ath, atl, INNER, 64, NB, 1.f);
        kRes<<<dim3(SPOT / 128, NB / 128, 1), 512, SMEM_STD>>>(
            ath, atl, INNER, 0, woh_l, wol_l, SPOT, 0,
            b_o + l * SPOT, spot, spot, nullptr, nullptr, SPOT, 0, INNER, 1.f);
        ln_bf<SPOT><<<NB, 256>>>(spot, ln2_g + l * SPOT, ln2_b + l * SPOT, hbh, hbl);
        kMlp1<<<dim3(MLPD / 128, NB / 128, 1), 512, SMEM_STD>>>(
            hbh, hbl, SPOT, 0, w1h_l, w1l_l, MLPD, 0,
            b1 + l * MLPD, nullptr, nullptr, mph, mpl, MLPD, 0, SPOT, 1.f);
        kRes<<<dim3(SPOT / 128, NB / 128, 1), 512, SMEM_STD>>>(
            mph, mpl, MLPD, 0, w2h_l, w2l_l, SPOT, 0,
            b2 + l * SPOT, spot, spot, nullptr, nullptr, SPOT, 0, MLPD, 1.f);
    }

    kProj<<<dim3(PROJ / 128, NB / 128, 1), 512, SMEM_STD>>>(
        ifh, ifl, IMG, 0, iph, ipl, PROJ, 0,
        img_proj_b, nullptr, pimg, pgh, pgl, PROJ, 0, IMG, 1.f);
    kRes<<<dim3(PROJ / 128, NB / 128, 1), 512, SMEM_STD>>>(
        pgh, pgl, PROJ, 0, ifch, ifcl, PROJ, 0,
        img_fc_b, pimg, tmp, nullptr, nullptr, PROJ, 0, PROJ, 1.f);
    ln_bf<PROJ><<<NB, 256>>>(tmp, img_ln_g, img_ln_b, eih, eil);

    CONV(spot, hbh, hbl, NB * SPOT);
    kProj<<<dim3(PROJ / 128, NB / 128, 1), 512, SMEM_STD>>>(
        hbh, hbl, SPOT, 0, sph, spl, PROJ, 0,
        spot_proj_b, nullptr, pspot, pgh, pgl, PROJ, 0, SPOT, 1.f);
    kRes<<<dim3(PROJ / 128, NB / 128, 1), 512, SMEM_STD>>>(
        pgh, pgl, PROJ, 0, sfh, sfl, PROJ, 0,
        spot_fc_b, pspot, tmp, nullptr, nullptr, PROJ, 0, PROJ, 1.f);
    ln_bf<PROJ><<<NB, 256>>>(tmp, spot_ln_g, spot_ln_b, esh, esl);

    pack_bf<<<NB, 256>>>(eih, eil, esh, esl, cth, ctl);
    kSqk<<<dim3(NB / 128, NB / 128, 1), 512, SMEM_NAT>>>(
        esh, esl, PROJ, 0, eih, eil, PROJ, 0,
        nullptr, nullptr, logits, nullptr, nullptr, NB, 0, PROJ, 1.f);
    kSqk<<<dim3(NB / 128, NB / 128, 1), 512, SMEM_NAT>>>(
        cth, ctl, 2 * PROJ, 0, cth, ctl, 2 * PROJ, 0,
        nullptr, nullptr, tgt, nullptr, nullptr, NB, 0, 2 * PROJ, 0.5f);
    softmax_rows<<<NB, 256>>>(tgt);
    rowloss_kernel<<<NB, 256>>>(logits, tgt, rowp);
    colloss_kernel<<<NB / 64, 256>>>(logits, tgt, colp);
    final_reduce<<<1, 256>>>(rowp, colp, out);
}

// round 7
// speedup vs baseline: 1.2299x; 1.1896x over previous
#include <cuda_runtime.h>
#include <cstdint>

// ---------------------------------------------------------------------------
// Problem constants
// ---------------------------------------------------------------------------
namespace {
constexpr int NB   = 2048;
constexpr int SPOT = 1024;
constexpr int IMG  = 1024;
constexpr int PROJ = 256;
constexpr int NH   = 8;
constexpr int DH   = 64;
constexpr int INNER = 512;
constexpr int MLPD = 2048;
constexpr int QKVW = 1536;
constexpr int NL   = 2;
}

// ---------------------------------------------------------------------------
// Scratch: fp32
// ---------------------------------------------------------------------------
__device__ float g_spot  [NB * SPOT];
__device__ float g_tmp   [NB * SPOT];
__device__ float g_pimg  [NB * PROJ];
__device__ float g_pspot [NB * PROJ];
__device__ float g_logits[NB * NB];
__device__ float g_tgt   [NB * NB];
__device__ float g_rowp  [NB];
__device__ float g_colp  [NB];

// ---------------------------------------------------------------------------
// Scratch: bf16 hi/lo
// ---------------------------------------------------------------------------
__device__ uint16_t g_hbuf_h[NB * SPOT],  g_hbuf_l[NB * SPOT];
__device__ uint16_t g_qkv_h [NB * QKVW],  g_qkv_l [NB * QKVW];
__device__ uint16_t g_attn_h[NB * INNER], g_attn_l[NB * INNER];
__device__ uint16_t g_mlp_h [NB * MLPD],  g_mlp_l [NB * MLPD];
__device__ uint16_t g_eimg_h [NB * PROJ], g_eimg_l [NB * PROJ];
__device__ uint16_t g_espot_h[NB * PROJ], g_espot_l[NB * PROJ];
__device__ uint16_t g_pg_h   [NB * PROJ], g_pg_l   [NB * PROJ];
__device__ uint16_t g_cat_h[NB * 2 * PROJ], g_cat_l[NB * 2 * PROJ];
__device__ uint16_t g_imgf_h[NB * IMG], g_imgf_l[NB * IMG];
// weights bf16
__device__ uint16_t g_wqkv_h[NL * SPOT * QKVW], g_wqkv_l[NL * SPOT * QKVW];
__device__ uint16_t g_wo_h  [NL * INNER * SPOT], g_wo_l [NL * INNER * SPOT];
__device__ uint16_t g_w1_h  [NL * SPOT * MLPD],  g_w1_l [NL * SPOT * MLPD];
__device__ uint16_t g_w2_h  [NL * MLPD * SPOT],  g_w2_l [NL * MLPD * SPOT];
__device__ uint16_t g_wip_h [IMG * PROJ],  g_wip_l[IMG * PROJ];
__device__ uint16_t g_wif_h [PROJ * PROJ], g_wif_l[PROJ * PROJ];
__device__ uint16_t g_wsp_h [SPOT * PROJ], g_wsp_l[SPOT * PROJ];
__device__ uint16_t g_wsf_h [PROJ * PROJ], g_wsf_l[PROJ * PROJ];

// ---------------------------------------------------------------------------
// Helpers
// ---------------------------------------------------------------------------
__device__ __forceinline__ uint32_t smem_u32(const void* p) {
    uint32_t a;
    asm("{ .reg .u64 t; cvta.to.shared.u64 t, %1; cvt.u32.u64 %0, t; }"
        : "=r"(a) : "l"(p));
    return a;
}
__device__ __forceinline__ unsigned long long gptr(const void* p) {
    return (unsigned long long)__cvta_generic_to_global(p);
}
__device__ __forceinline__ float gelu_f(float x) {
    return 0.5f * x * (1.0f + erff(x * 0.7071067811865475f));
}
__device__ __forceinline__ void split2(float f0, float f1, uint32_t& hi, uint32_t& lo) {
    asm("cvt.rn.bf16x2.f32 %0, %1, %2;" : "=r"(hi) : "f"(f1), "f"(f0));
    float h0 = __uint_as_float(hi << 16);
    float h1 = __uint_as_float(hi & 0xFFFF0000u);
    float l0 = f0 - h0, l1 = f1 - h1;
    asm("cvt.rn.bf16x2.f32 %0, %1, %2;" : "=r"(lo) : "f"(l1), "f"(l0));
}

#define CP16(dst, src) \
    asm volatile("cp.async.cg.shared.global [%0], [%1], 16;" :: "r"(dst), "l"(src))
#define CP_COMMIT() asm volatile("cp.async.commit_group;" ::: "memory")
#define CP_WAIT2()  asm volatile("cp.async.wait_group 2;" ::: "memory")
#define CP_WAIT1()  asm volatile("cp.async.wait_group 1;" ::: "memory")
#define CP_WAIT0()  asm volatile("cp.async.wait_group 0;" ::: "memory")

#define LDSM_X4(r, a)                                                          \
    asm volatile("ldmatrix.sync.aligned.m8n8.x4.shared.b16 {%0,%1,%2,%3}, [%4];" \
        : "=r"((r)[0]), "=r"((r)[1]), "=r"((r)[2]), "=r"((r)[3]) : "r"(a))
#define LDSM_X4T(r, a)                                                         \
    asm volatile("ldmatrix.sync.aligned.m8n8.x4.trans.shared.b16 {%0,%1,%2,%3}, [%4];" \
        : "=r"((r)[0]), "=r"((r)[1]), "=r"((r)[2]), "=r"((r)[3]) : "r"(a))
#define LDSM_X2(r, a)                                                          \
    asm volatile("ldmatrix.sync.aligned.m8n8.x2.shared.b16 {%0,%1}, [%2];"     \
        : "=r"((r)[0]), "=r"((r)[1]) : "r"(a))
#define LDSM_X2T(r, a)                                                         \
    asm volatile("ldmatrix.sync.aligned.m8n8.x2.trans.shared.b16 {%0,%1}, [%2];" \
        : "=r"((r)[0]), "=r"((r)[1]) : "r"(a))
#define MMA16816(d, a, b)                                                      \
    asm volatile("mma.sync.aligned.m16n8k16.row.col.f32.bf16.bf16.f32 "        \
        "{%0,%1,%2,%3}, {%4,%5,%6,%7}, {%8,%9}, {%0,%1,%2,%3};"                \
        : "+f"((d)[0]), "+f"((d)[1]), "+f"((d)[2]), "+f"((d)[3])               \
        : "r"((a)[0]), "r"((a)[1]), "r"((a)[2]), "r"((a)[3]),                  \
          "r"((b)[0]), "r"((b)[1]))

// ---------------------------------------------------------------------------
// Pure-bf16 split GEMM. 512 threads, 4-stage cp.async (unchanged from R5).
// ---------------------------------------------------------------------------
template<int NT, bool BNAT, int EPI, int OUT>
__global__ __launch_bounds__(512) void gemm_bf(
    const uint16_t* __restrict__ Ah, const uint16_t* __restrict__ Al,
    int lda, long long az,
    const uint16_t* __restrict__ Bh, const uint16_t* __restrict__ Bl,
    int ldb, long long bz,
    const float* __restrict__ bias, const float* __restrict__ res,
    float* __restrict__ C, uint16_t* __restrict__ Ch, uint16_t* __restrict__ Cl,
    int ldc, long long cz, int K, float scale)
{
    constexpr int WNC = NT / 4;
    constexpr int NTL = WNC / 8;
    constexpr int MT  = 2;
    constexpr int ABYTES = 128 * 80;
    constexpr int BROWB  = BNAT ? 80 : (NT + 8) * 2;
    constexpr int BBYTES = BNAT ? NT * 80 : 32 * (NT + 8) * 2;
    constexpr int STAGE  = 2 * ABYTES + 2 * BBYTES;
    constexpr int STAGES = 4;
    constexpr int BSEGS  = BNAT ? NT * 4 : 32 * (NT / 8);

    extern __shared__ __align__(128) char smm[];
    const uint32_t sb = smem_u32(smm);
    const int tid = threadIdx.x, lane = tid & 31, wid = tid >> 5;
    const int wm = wid >> 2, wn = wid & 3;
    const int bm = blockIdx.y * 128, bn = blockIdx.x * NT;

    const uint16_t* Abh = Ah + (size_t)blockIdx.z * az + (size_t)bm * lda;
    const uint16_t* Abl = Al + (size_t)blockIdx.z * az + (size_t)bm * lda;
    const uint16_t* Bbh = Bh + (size_t)blockIdx.z * bz;
    const uint16_t* Bbl = Bl + (size_t)blockIdx.z * bz;

    float acc[MT][NTL][4];
    #pragma unroll
    for (int mt = 0; mt < MT; mt++)
        #pragma unroll
        for (int nt = 0; nt < NTL; nt++)
            #pragma unroll
            for (int r = 0; r < 4; r++) acc[mt][nt][r] = 0.f;

    const int NC = K >> 5;

    auto issue = [&](int c, int s) {
        const uint32_t st = sb + s * STAGE;
        const int k0 = c << 5;
        {
            int row = tid >> 2, seg = tid & 3;
            size_t so = (size_t)row * lda + k0 + seg * 8;
            uint32_t d = st + row * 80 + seg * 16;
            CP16(d, gptr(Abh + so));
            CP16(d + ABYTES, gptr(Abl + so));
        }
        if (BSEGS == 512 || tid < BSEGS) {
            if (BNAT) {
                int row = tid >> 2, seg = tid & 3;
                size_t so = (size_t)(bn + row) * ldb + k0 + seg * 8;
                uint32_t d = st + 2 * ABYTES + row * 80 + seg * 16;
                CP16(d, gptr(Bbh + so));
                CP16(d + BBYTES, gptr(Bbl + so));
            } else {
                int row = tid / (NT / 8), seg = tid % (NT / 8);
                size_t so = (size_t)(k0 + row) * ldb + bn + seg * 8;
                uint32_t d = st + 2 * ABYTES + row * BROWB + seg * 16;
                CP16(d, gptr(Bbh + so));
                CP16(d + BBYTES, gptr(Bbl + so));
            }
        }
    };

    #pragma unroll
    for (int s = 0; s < STAGES - 1; s++) {
        if (s < NC) issue(s, s);
        CP_COMMIT();
    }

    for (int c = 0; c < NC; c++) {
        CP_WAIT2();
        __syncthreads();
        {
            int cn = c + STAGES - 1;
            if (cn < NC) issue(cn, cn % STAGES);
            CP_COMMIT();
        }
        const uint32_t abh_ = sb + (c % STAGES) * STAGE;
        const uint32_t abl_ = abh_ + ABYTES;
        const uint32_t bbh_ = abh_ + 2 * ABYTES;
        const uint32_t bbl_ = bbh_ + BBYTES;
        #pragma unroll
        for (int ks = 0; ks < 2; ks++) {
            uint32_t afh[MT][4], afl[MT][4], bfh[NTL][2], bfl[NTL][2];
            #pragma unroll
            for (int mt = 0; mt < MT; mt++) {
                uint32_t off = ((wm * 32 + mt * 16 + (lane & 15)) * 40 +
                                ks * 16 + ((lane >> 4) << 3)) << 1;
                LDSM_X4(afh[mt], abh_ + off);
                LDSM_X4(afl[mt], abl_ + off);
            }
            #pragma unroll
            for (int nt = 0; nt < NTL; nt++) {
                if (BNAT) {
                    uint32_t off = ((wn * WNC + nt * 8 + (lane & 7)) * 40 +
                                    ks * 16 + (((lane >> 3) & 1) << 3)) << 1;
                    LDSM_X2(bfh[nt], bbh_ + off);
                    LDSM_X2(bfl[nt], bbl_ + off);
                } else {
                    uint32_t off = ((ks * 16 + (lane & 15)) * (NT + 8) +
                                    wn * WNC + nt * 8) << 1;
                    LDSM_X2T(bfh[nt], bbh_ + off);
                    LDSM_X2T(bfl[nt], bbl_ + off);
                }
            }
            #pragma unroll
            for (int nt = 0; nt < NTL; nt++)
                #pragma unroll
                for (int mt = 0; mt < MT; mt++) {
                    MMA16816(acc[mt][nt], afh[mt], bfh[nt]);
                    MMA16816(acc[mt][nt], afh[mt], bfl[nt]);
                    MMA16816(acc[mt][nt], afl[mt], bfh[nt]);
                }
        }
    }

    const int gid = lane >> 2, tig = lane & 3;
    #pragma unroll
    for (int mt = 0; mt < MT; mt++) {
        #pragma unroll
        for (int nt = 0; nt < NTL; nt++) {
            int r0  = bm + wm * 32 + mt * 16 + gid;
            int col = bn + wn * WNC + nt * 8 + tig * 2;
            float2 v0 = make_float2(acc[mt][nt][0] * scale, acc[mt][nt][1] * scale);
            float2 v1 = make_float2(acc[mt][nt][2] * scale, acc[mt][nt][3] * scale);
            if (EPI >= 1) {
                float2 bb = *reinterpret_cast<const float2*>(&bias[col]);
                v0.x += bb.x; v0.y += bb.y; v1.x += bb.x; v1.y += bb.y;
            }
            if (EPI == 2) {
                v0.x = gelu_f(v0.x); v0.y = gelu_f(v0.y);
                v1.x = gelu_f(v1.x); v1.y = gelu_f(v1.y);
            }
            if (EPI == 3) {
                float2 ra = *reinterpret_cast<const float2*>(
                    &res[(size_t)r0 * ldc + col]);
                float2 rb = *reinterpret_cast<const float2*>(
                    &res[(size_t)(r0 + 8) * ldc + col]);
                v0.x += ra.x; v0.y += ra.y; v1.x += rb.x; v1.y += rb.y;
            }
            size_t o0 = (size_t)r0 * ldc + col + (size_t)blockIdx.z * cz;
            size_t o1 = (size_t)(r0 + 8) * ldc + col + (size_t)blockIdx.z * cz;
            if (OUT & 1) {
                *reinterpret_cast<float2*>(&C[o0]) = v0;
                *reinterpret_cast<float2*>(&C[o1]) = v1;
            }
            if (OUT & 2) {
                float a0 = v0.x, a1 = v0.y, b0 = v1.x, b1 = v1.y;
                if (OUT & 4) {
                    a0 = gelu_f(a0); a1 = gelu_f(a1);
                    b0 = gelu_f(b0); b1 = gelu_f(b1);
                }
                uint32_t h, l;
                split2(a0, a1, h, l);
                *reinterpret_cast<uint32_t*>(&Ch[o0]) = h;
                *reinterpret_cast<uint32_t*>(&Cl[o0]) = l;
                split2(b0, b1, h, l);
                *reinterpret_cast<uint32_t*>(&Ch[o1]) = h;
                *reinterpret_cast<uint32_t*>(&Cl[o1]) = l;
            }
        }
    }
}

// ---------------------------------------------------------------------------
// Fused flash attention (split-bf16 mma). Block = 128 queries x 1 head,
// 256 threads (8 warps); warp owns 16 query rows. K/V tiles of 128 keys
// double-buffered via cp.async. Row stride 72 elems (144B) for full DH=64
// rows (16B-aligned, ldmatrix conflict-free).
// ---------------------------------------------------------------------------
__global__ __launch_bounds__(256) void flash_attn(
    const uint16_t* __restrict__ qh, const uint16_t* __restrict__ ql,
    uint16_t* __restrict__ oh, uint16_t* __restrict__ ol)
{
    constexpr int RS = 72;              // row stride in elements
    constexpr int TB = 128 * RS * 2;    // bytes per tile buffer (18432)
    constexpr int KVSTAGE = 4 * TB;     // Kh,Kl,Vh,Vl
    extern __shared__ __align__(128) char smm[];
    const uint32_t sb  = smem_u32(smm);
    const uint32_t sQh = sb, sQl = sb + TB;
    const int tid = threadIdx.x, lane = tid & 31, w = tid >> 5;
    const int q0 = blockIdx.x * 128;
    const int h  = blockIdx.y;
    const int g = lane >> 2, t = lane & 3;

    // Q tile -> smem: 128 rows x 8 segs(16B) per buffer
    #pragma unroll
    for (int j = 0; j < 4; j++) {
        int idx = tid + j * 256;
        int row = idx >> 3, seg = idx & 7;
        size_t so = (size_t)(q0 + row) * QKVW + h * 64 + seg * 8;
        uint32_t d = sb + row * (RS * 2) + seg * 16;
        CP16(d, gptr(qh + so));
        CP16(d + TB, gptr(ql + so));
    }
    auto issueKV = [&](int kt, int s) {
        uint32_t st = sb + 2 * TB + s * KVSTAGE;
        int tok0 = kt * 128;
        #pragma unroll
        for (int j = 0; j < 4; j++) {
            int idx = tid + j * 256;
            int row = idx >> 3, seg = idx & 7;
            size_t soK = (size_t)(tok0 + row) * QKVW + INNER + h * 64 + seg * 8;
            uint32_t dK = st + row * (RS * 2) + seg * 16;
            CP16(dK, gptr(qh + soK));
            CP16(dK + TB, gptr(ql + soK));
            size_t soV = soK + INNER;
            uint32_t dV = st + 2 * TB + row * (RS * 2) + seg * 16;
            CP16(dV, gptr(qh + soV));
            CP16(dV + TB, gptr(ql + soV));
        }
    };
    issueKV(0, 0);
    CP_COMMIT();

    float O[8][4];
    #pragma unroll
    for (int jt = 0; jt < 8; jt++)
        #pragma unroll
        for (int r = 0; r < 4; r++) O[jt][r] = 0.f;
    float m0 = -1e30f, m1 = -1e30f, l0 = 0.f, l1 = 0.f;

    for (int kt = 0; kt < NB / 128; kt++) {
        if (kt + 1 < NB / 128) {
            issueKV(kt + 1, (kt + 1) & 1);
            CP_COMMIT();
            CP_WAIT1();
        } else {
            CP_WAIT0();
        }
        __syncthreads();
        const uint32_t st  = sb + 2 * TB + (kt & 1) * KVSTAGE;
        const uint32_t sKh = st, sKl = st + TB;
        const uint32_t sVh = st + 2 * TB, sVl = st + 3 * TB;

        // ---- S = Q @ K^T (3-pass split), warp tile 16 x 128
        float sacc[16][4];
        #pragma unroll
        for (int j = 0; j < 16; j++)
            #pragma unroll
            for (int r = 0; r < 4; r++) sacc[j][r] = 0.f;

        #pragma unroll
        for (int kc = 0; kc < 4; kc++) {
            uint32_t aqh[4], aql[4];
            uint32_t aoff = ((w * 16 + (lane & 15)) * RS +
                             kc * 16 + ((lane >> 4) << 3)) << 1;
            LDSM_X4(aqh, sQh + aoff);
            LDSM_X4(aql, sQl + aoff);
            #pragma unroll
            for (int jp = 0; jp < 8; jp++) {
                uint32_t rh[4], rl[4];
                uint32_t boff = ((jp * 16 + (lane & 15)) * RS +
                                 kc * 16 + ((lane >> 4) << 3)) << 1;
                LDSM_X4(rh, sKh + boff);   // {n0k0, n1k0, n0k8, n1k8}
                LDSM_X4(rl, sKl + boff);
                uint32_t bh0[2] = {rh[0], rh[2]}, bh1[2] = {rh[1], rh[3]};
                uint32_t bl0[2] = {rl[0], rl[2]}, bl1[2] = {rl[1], rl[3]};
                MMA16816(sacc[2 * jp],     aqh, bh0);
                MMA16816(sacc[2 * jp],     aqh, bl0);
                MMA16816(sacc[2 * jp],     aql, bh0);
                MMA16816(sacc[2 * jp + 1], aqh, bh1);
                MMA16816(sacc[2 * jp + 1], aqh, bl1);
                MMA16816(sacc[2 * jp + 1], aql, bh1);
            }
        }

        // ---- online softmax (rows g and g+8 of warp tile)
        float mx0 = m0, mx1 = m1;
        #pragma unroll
        for (int j = 0; j < 16; j++) {
            sacc[j][0] *= 0.125f; sacc[j][1] *= 0.125f;
            sacc[j][2] *= 0.125f; sacc[j][3] *= 0.125f;
            mx0 = fmaxf(mx0, fmaxf(sacc[j][0], sacc[j][1]));
            mx1 = fmaxf(mx1, fmaxf(sacc[j][2], sacc[j][3]));
        }
        mx0 = fmaxf(mx0, __shfl_xor_sync(0xffffffffu, mx0, 1));
        mx0 = fmaxf(mx0, __shfl_xor_sync(0xffffffffu, mx0, 2));
        mx1 = fmaxf(mx1, __shfl_xor_sync(0xffffffffu, mx1, 1));
        mx1 = fmaxf(mx1, __shfl_xor_sync(0xffffffffu, mx1, 2));
        float a0 = __expf(m0 - mx0), a1 = __expf(m1 - mx1);
        m0 = mx0; m1 = mx1;
        float s0 = 0.f, s1 = 0.f;
        #pragma unroll
        for (int j = 0; j < 16; j++) {
            sacc[j][0] = __expf(sacc[j][0] - m0); s0 += sacc[j][0];
            sacc[j][1] = __expf(sacc[j][1] - m0); s0 += sacc[j][1];
            sacc[j][2] = __expf(sacc[j][2] - m1); s1 += sacc[j][2];
            sacc[j][3] = __expf(sacc[j][3] - m1); s1 += sacc[j][3];
        }
        s0 += __shfl_xor_sync(0xffffffffu, s0, 1);
        s0 += __shfl_xor_sync(0xffffffffu, s0, 2);
        s1 += __shfl_xor_sync(0xffffffffu, s1, 1);
        s1 += __shfl_xor_sync(0xffffffffu, s1, 2);
        l0 = l0 * a0 + s0;
        l1 = l1 * a1 + s1;
        #pragma unroll
        for (int jt = 0; jt < 8; jt++) {
            O[jt][0] *= a0; O[jt][1] *= a0;
            O[jt][2] *= a1; O[jt][3] *= a1;
        }

        // ---- O += P @ V (3-pass split); P packed from sacc in registers
        #pragma unroll
        for (int kc = 0; kc < 8; kc++) {
            uint32_t ah[4], al[4];
            split2(sacc[2 * kc][0],     sacc[2 * kc][1],     ah[0], al[0]);
            split2(sacc[2 * kc][2],     sacc[2 * kc][3],     ah[1], al[1]);
            split2(sacc[2 * kc + 1][0], sacc[2 * kc + 1][1], ah[2], al[2]);
            split2(sacc[2 * kc + 1][2], sacc[2 * kc + 1][3], ah[3], al[3]);
            #pragma unroll
            for (int jp = 0; jp < 4; jp++) {
                uint32_t rh[4], rl[4];
                uint32_t boff = ((kc * 16 + (lane & 15)) * RS +
                                 jp * 16 + ((lane >> 4) << 3)) << 1;
                LDSM_X4T(rh, sVh + boff);  // {n0k0, n0k8, n1k0, n1k8}
                LDSM_X4T(rl, sVl + boff);
                uint32_t bh0[2] = {rh[0], rh[1]}, bh1[2] = {rh[2], rh[3]};
                uint32_t bl0[2] = {rl[0], rl[1]}, bl1[2] = {rl[2], rl[3]};
                MMA16816(O[2 * jp],     ah, bh0);
                MMA16816(O[2 * jp],     ah, bl0);
                MMA16816(O[2 * jp],     al, bh0);
                MMA16816(O[2 * jp + 1], ah, bh1);
                MMA16816(O[2 * jp + 1], ah, bl1);
                MMA16816(O[2 * jp + 1], al, bh1);
            }
        }
        __syncthreads();
    }

    // ---- normalize + store split bf16
    float i0 = 1.f / l0, i1 = 1.f / l1;
    #pragma unroll
    for (int jt = 0; jt < 8; jt++) {
        uint32_t hh, ll;
        size_t o0 = (size_t)(q0 + w * 16 + g) * INNER + h * 64 + jt * 8 + t * 2;
        split2(O[jt][0] * i0, O[jt][1] * i0, hh, ll);
        *reinterpret_cast<uint32_t*>(oh + o0) = hh;
        *reinterpret_cast<uint32_t*>(ol + o0) = ll;
        size_t o1 = o0 + (size_t)8 * INNER;
        split2(O[jt][2] * i1, O[jt][3] * i1, hh, ll);
        *reinterpret_cast<uint32_t*>(oh + o1) = hh;
        *reinterpret_cast<uint32_t*>(ol + o1) = ll;
    }
}

// ---------------------------------------------------------------------------
// Reductions
// ---------------------------------------------------------------------------
__device__ __forceinline__ float blk_sum256(float v, float* sh) {
    int t = threadIdx.x;
    sh[t] = v; __syncthreads();
    #pragma unroll
    for (int s = 128; s >= 1; s >>= 1) {
        if (t < s) sh[t] += sh[t + s];
        __syncthreads();
    }
    float r = sh[0]; __syncthreads();
    return r;
}
__device__ __forceinline__ float blk_max256(float v, float* sh) {
    int t = threadIdx.x;
    sh[t] = v; __syncthreads();
    #pragma unroll
    for (int s = 128; s >= 1; s >>= 1) {
        if (t < s) sh[t] = fmaxf(sh[t], sh[t + s]);
        __syncthreads();
    }
    float r = sh[0]; __syncthreads();
    return r;
}

// ---------------------------------------------------------------------------
// Elementwise kernels
// ---------------------------------------------------------------------------
__global__ __launch_bounds__(256) void conv_bf(
    const float* __restrict__ x, uint16_t* __restrict__ h,
    uint16_t* __restrict__ l, int n2)
{
    int i = blockIdx.x * 256 + threadIdx.x;
    if (i < n2) {
        float2 v = reinterpret_cast<const float2*>(x)[i];
        uint32_t hh, ll;
        split2(v.x, v.y, hh, ll);
        reinterpret_cast<uint32_t*>(h)[i] = hh;
        reinterpret_cast<uint32_t*>(l)[i] = ll;
    }
}

__global__ __launch_bounds__(256) void embed_kernel(
    const float* __restrict__ expr, const float* __restrict__ xt,
    const float* __restrict__ yt, const int* __restrict__ xi,
    const int* __restrict__ yi, float* __restrict__ out)
{
    int row = blockIdx.x;
    size_t xo = (size_t)xi[row] * SPOT;
    size_t yo = (size_t)yi[row] * SPOT;
    size_t ro = (size_t)row * SPOT;
    for (int j = threadIdx.x; j < SPOT; j += 256)
        out[ro + j] = expr[ro + j] + xt[xo + j] + yt[yo + j];
}

template<int N>
__global__ __launch_bounds__(256) void ln_bf(
    const float* __restrict__ x, const float* __restrict__ g,
    const float* __restrict__ b, uint16_t* __restrict__ oh,
    uint16_t* __restrict__ ol)
{
    __shared__ float sh[256];
    constexpr int NPAIR = N / 2;
    constexpr int NP = (NPAIR + 255) / 256;
    int row = blockIdx.x, tid = threadIdx.x;
    const float2* xr = reinterpret_cast<const float2*>(x + (size_t)row * N);
    float2 v[NP];
    float s = 0.f;
    #pragma unroll
    for (int i = 0; i < NP; i++) {
        int p = i * 256 + tid;
        if (p < NPAIR) { v[i] = xr[p]; s += v[i].x + v[i].y; }
        else v[i] = make_float2(0.f, 0.f);
    }
    s = blk_sum256(s, sh);
    float mean = s / N, ss = 0.f;
    #pragma unroll
    for (int i = 0; i < NP; i++) {
        int p = i * 256 + tid;
        if (p < NPAIR) {
            float dx = v[i].x - mean, dy = v[i].y - mean;
            ss += dx * dx + dy * dy;
        }
    }
    ss = blk_sum256(ss, sh);
    float rstd = rsqrtf(ss / N + 1e-5f);
    uint32_t* OH = reinterpret_cast<uint32_t*>(oh + (size_t)row * N);
    uint32_t* OL = reinterpret_cast<uint32_t*>(ol + (size_t)row * N);
    #pragma unroll
    for (int i = 0; i < NP; i++) {
        int p = i * 256 + tid;
        if (p < NPAIR) {
            float2 gg = reinterpret_cast<const float2*>(g)[p];
            float2 bb = reinterpret_cast<const float2*>(b)[p];
            float y0 = (v[i].x - mean) * rstd * gg.x + bb.x;
            float y1 = (v[i].y - mean) * rstd * gg.y + bb.y;
            uint32_t h, l;
            split2(y0, y1, h, l);
            OH[p] = h; OL[p] = l;
        }
    }
}

__global__ __launch_bounds__(256) void softmax_rows(float* __restrict__ x)
{
    __shared__ float sh[256];
    size_t row = blockIdx.x;
    int tid = threadIdx.x;
    float* r = x + row * NB;
    float v[8];
    float mx = -1e30f;
    #pragma unroll
    for (int i = 0; i < 8; i++) { v[i] = r[i * 256 + tid]; mx = fmaxf(mx, v[i]); }
    mx = blk_max256(mx, sh);
    float s = 0.f;
    #pragma unroll
    for (int i = 0; i < 8; i++) { v[i] = __expf(v[i] - mx); s += v[i]; }
    s = blk_sum256(s, sh);
    float inv = 1.f / s;
    #pragma unroll
    for (int i = 0; i < 8; i++) r[i * 256 + tid] = v[i] * inv;
}

__global__ __launch_bounds__(256) void pack_bf(
    const uint16_t* __restrict__ ih, const uint16_t* __restrict__ il,
    const uint16_t* __restrict__ eh, const uint16_t* __restrict__ el,
    uint16_t* __restrict__ ch, uint16_t* __restrict__ cl)
{
    int row = blockIdx.x, tid = threadIdx.x;
    const uint32_t* IH = reinterpret_cast<const uint32_t*>(ih + (size_t)row * PROJ);
    const uint32_t* IL = reinterpret_cast<const uint32_t*>(il + (size_t)row * PROJ);
    const uint32_t* EH = reinterpret_cast<const uint32_t*>(eh + (size_t)row * PROJ);
    const uint32_t* EL = reinterpret_cast<const uint32_t*>(el + (size_t)row * PROJ);
    uint32_t vh, vl;
    if (tid < 128) { vh = IH[tid]; vl = IL[tid]; }
    else           { vh = EH[tid - 128]; vl = EL[tid - 128]; }
    reinterpret_cast<uint32_t*>(ch + (size_t)row * 2 * PROJ)[tid] = vh;
    reinterpret_cast<uint32_t*>(cl + (size_t)row * 2 * PROJ)[tid] = vl;
}

__global__ __launch_bounds__(256) void rowloss_kernel(
    const float* __restrict__ logits, const float* __restrict__ tgt,
    float* __restrict__ rowp)
{
    __shared__ float sh[256];
    int row = blockIdx.x, tid = threadIdx.x;
    const float* lr = logits + (size_t)row * NB;
    const float* tr = tgt    + (size_t)row * NB;
    float lv[8], tv[8];
    float mx = -1e30f;
    #pragma unroll
    for (int i = 0; i < 8; i++) {
        lv[i] = lr[i * 256 + tid];
        tv[i] = tr[i * 256 + tid];
        mx = fmaxf(mx, lv[i]);
    }
    mx = blk_max256(mx, sh);
    float se = 0.f, dot = 0.f;
    #pragma unroll
    for (int i = 0; i < 8; i++) { se += __expf(lv[i] - mx); dot += tv[i] * lv[i]; }
    se  = blk_sum256(se, sh);
    dot = blk_sum256(dot, sh);
    if (tid == 0) rowp[row] = 0.5f * (mx + logf(se) - dot);
}

__global__ __launch_bounds__(256) void colloss_kernel(
    const float* __restrict__ logits, const float* __restrict__ tgt,
    float* __restrict__ colp)
{
    __shared__ float smx[256], sse[256], sts[256], stdot[256];
    int tid = threadIdx.x;
    int c = blockIdx.x * 64 + (tid & 63);
    int ry = tid >> 6;
    float mx = -1e30f, se = 0.f, ts = 0.f, td = 0.f;
    for (int r = ry; r < NB; r += 4) {
        float l = logits[(size_t)r * NB + c];
        float t = tgt   [(size_t)r * NB + c];
        if (l > mx) { se = se * __expf(mx - l) + 1.f; mx = l; }
        else        { se += __expf(l - mx); }
        ts += t;
        td += t * l;
    }
    smx[tid] = mx; sse[tid] = se; sts[tid] = ts; stdot[tid] = td;
    __syncthreads();
    if (ry == 0) {
        #pragma unroll
        for (int k = 1; k < 4; k++) {
            int o = tid + k * 64;
            float m2 = smx[o], s2 = sse[o];
            float m = fmaxf(mx, m2);
            se = se * __expf(mx - m) + s2 * __expf(m2 - m);
            mx = m;
            ts += sts[o];
            td += stdot[o];
        }
        colp[c] = 0.5f * (ts * (mx + logf(se)) - td);
    }
}

__global__ __launch_bounds__(256) void final_reduce(
    const float* __restrict__ a, const float* __restrict__ b,
    float* __restrict__ out)
{
    __shared__ float sh[256];
    int tid = threadIdx.x;
    float s = 0.f;
    for (int i = tid; i < NB; i += 256) s += a[i] + b[i];
    s = blk_sum256(s, sh);
    if (tid == 0) out[0] = s * (1.0f / NB);
}

// ---------------------------------------------------------------------------
// Host launch
// ---------------------------------------------------------------------------
namespace {
constexpr int SMEM_STD = 4 * (2 * 128 * 80 + 2 * 32 * (128 + 8) * 2); // 151552
constexpr int SMEM_NAT = 4 * (2 * 128 * 80 + 2 * 128 * 80);           // 163840
constexpr int SMEM_FLASH = 2 * (128 * 72 * 2) + 2 * 4 * (128 * 72 * 2); // 184320
}

#define SYM(var, sym) cudaGetSymbolAddress((void**)&var, sym)

extern "C" void kernel_launch(void* const* d_in, const int* in_sizes, int n_in,
                              void* d_out, int out_size)
{
    (void)in_sizes; (void)n_in; (void)out_size;
    const float* image_features = (const float*)d_in[0];
    const float* expression     = (const float*)d_in[1];
    const float* x_table        = (const float*)d_in[2];
    const float* y_table        = (const float*)d_in[3];
    const float* ln1_g          = (const float*)d_in[4];
    const float* ln1_b          = (const float*)d_in[5];
    const float* w_qkv          = (const float*)d_in[6];
    const float* w_o            = (const float*)d_in[7];
    const float* b_o            = (const float*)d_in[8];
    const float* ln2_g          = (const float*)d_in[9];
    const float* ln2_b          = (const float*)d_in[10];
    const float* w1             = (const float*)d_in[11];
    const float* b1             = (const float*)d_in[12];
    const float* w2             = (const float*)d_in[13];
    const float* b2             = (const float*)d_in[14];
    const float* img_proj_w     = (const float*)d_in[15];
    const float* img_proj_b     = (const float*)d_in[16];
    const float* img_fc_w       = (const float*)d_in[17];
    const float* img_fc_b       = (const float*)d_in[18];
    const float* img_ln_g       = (const float*)d_in[19];
    const float* img_ln_b       = (const float*)d_in[20];
    const float* spot_proj_w    = (const float*)d_in[21];
    const float* spot_proj_b    = (const float*)d_in[22];
    const float* spot_fc_w      = (const float*)d_in[23];
    const float* spot_fc_b      = (const float*)d_in[24];
    const float* spot_ln_g      = (const float*)d_in[25];
    const float* spot_ln_b      = (const float*)d_in[26];
    const int*   x_idx          = (const int*)d_in[27];
    const int*   y_idx          = (const int*)d_in[28];
    float* out = (float*)d_out;

    float *spot, *tmp, *pimg, *pspot, *logits, *tgt, *rowp, *colp;
    SYM(spot, g_spot); SYM(tmp, g_tmp);
    SYM(pimg, g_pimg); SYM(pspot, g_pspot);
    SYM(logits, g_logits); SYM(tgt, g_tgt); SYM(rowp, g_rowp); SYM(colp, g_colp);

    uint16_t *hbh, *hbl, *qkh, *qkl, *ath, *atl, *mph, *mpl;
    uint16_t *eih, *eil, *esh, *esl, *pgh, *pgl, *cth, *ctl, *ifh, *ifl;
    SYM(hbh, g_hbuf_h); SYM(hbl, g_hbuf_l);
    SYM(qkh, g_qkv_h);  SYM(qkl, g_qkv_l);
    SYM(ath, g_attn_h); SYM(atl, g_attn_l);
    SYM(mph, g_mlp_h);  SYM(mpl, g_mlp_l);
    SYM(eih, g_eimg_h); SYM(eil, g_eimg_l);
    SYM(esh, g_espot_h); SYM(esl, g_espot_l);
    SYM(pgh, g_pg_h);   SYM(pgl, g_pg_l);
    SYM(cth, g_cat_h);  SYM(ctl, g_cat_l);
    SYM(ifh, g_imgf_h); SYM(ifl, g_imgf_l);

    uint16_t *wqh, *wql, *woh, *wol, *w1h, *w1l, *w2h, *w2l;
    uint16_t *iph, *ipl, *ifch, *ifcl, *sph, *spl, *sfh, *sfl;
    SYM(wqh, g_wqkv_h); SYM(wql, g_wqkv_l);
    SYM(woh, g_wo_h);   SYM(wol, g_wo_l);
    SYM(w1h, g_w1_h);   SYM(w1l, g_w1_l);
    SYM(w2h, g_w2_h);   SYM(w2l, g_w2_l);
    SYM(iph, g_wip_h);  SYM(ipl, g_wip_l);
    SYM(ifch, g_wif_h); SYM(ifcl, g_wif_l);
    SYM(sph, g_wsp_h);  SYM(spl, g_wsp_l);
    SYM(sfh, g_wsf_h);  SYM(sfl, g_wsf_l);

    auto kQKV  = gemm_bf<128, false, 0, 2>;
    auto kSqk  = gemm_bf<128, true,  0, 1>;
    auto kRes  = gemm_bf<128, false, 3, 1>;
    auto kMlp1 = gemm_bf<128, false, 2, 2>;
    auto kProj = gemm_bf<128, false, 1, 7>;
    cudaFuncSetAttribute(kQKV,  cudaFuncAttributeMaxDynamicSharedMemorySize, SMEM_STD);
    cudaFuncSetAttribute(kSqk,  cudaFuncAttributeMaxDynamicSharedMemorySize, SMEM_NAT);
    cudaFuncSetAttribute(kRes,  cudaFuncAttributeMaxDynamicSharedMemorySize, SMEM_STD);
    cudaFuncSetAttribute(kMlp1, cudaFuncAttributeMaxDynamicSharedMemorySize, SMEM_STD);
    cudaFuncSetAttribute(kProj, cudaFuncAttributeMaxDynamicSharedMemorySize, SMEM_STD);
    cudaFuncSetAttribute(flash_attn,
                         cudaFuncAttributeMaxDynamicSharedMemorySize, SMEM_FLASH);

    auto CONV = [&](const float* src, uint16_t* h, uint16_t* l, int n) {
        conv_bf<<<(n / 2 + 255) / 256, 256>>>(src, h, l, n / 2);
    };
    CONV(w_qkv, wqh, wql, NL * SPOT * QKVW);
    CONV(w_o,   woh, wol, NL * INNER * SPOT);
    CONV(w1,    w1h, w1l, NL * SPOT * MLPD);
    CONV(w2,    w2h, w2l, NL * MLPD * SPOT);
    CONV(img_proj_w, iph, ipl, IMG * PROJ);
    CONV(img_fc_w, ifch, ifcl, PROJ * PROJ);
    CONV(spot_proj_w, sph, spl, SPOT * PROJ);
    CONV(spot_fc_w, sfh, sfl, PROJ * PROJ);
    CONV(image_features, ifh, ifl, NB * IMG);

    embed_kernel<<<NB, 256>>>(expression, x_table, y_table, x_idx, y_idx, spot);

    for (int l = 0; l < NL; l++) {
        uint16_t* wqh_l = wqh + (size_t)l * SPOT * QKVW;
        uint16_t* wql_l = wql + (size_t)l * SPOT * QKVW;
        uint16_t* woh_l = woh + (size_t)l * INNER * SPOT;
        uint16_t* wol_l = wol + (size_t)l * INNER * SPOT;
        uint16_t* w1h_l = w1h + (size_t)l * SPOT * MLPD;
        uint16_t* w1l_l = w1l + (size_t)l * SPOT * MLPD;
        uint16_t* w2h_l = w2h + (size_t)l * MLPD * SPOT;
        uint16_t* w2l_l = w2l + (size_t)l * MLPD * SPOT;

        ln_bf<SPOT><<<NB, 256>>>(spot, ln1_g + l * SPOT, ln1_b + l * SPOT, hbh, hbl);
        kQKV<<<dim3(QKVW / 128, NB / 128, 1), 512, SMEM_STD>>>(
            hbh, hbl, SPOT, 0, wqh_l, wql_l, QKVW, 0, nullptr, nullptr,
            nullptr, qkh, qkl, QKVW, 0, SPOT, 1.f);
        flash_attn<<<dim3(NB / 128, NH), 256, SMEM_FLASH>>>(qkh, qkl, ath, atl);
        kRes<<<dim3(SPOT / 128, NB / 128, 1), 512, SMEM_STD>>>(
            ath, atl, INNER, 0, woh_l, wol_l, SPOT, 0,
            b_o + l * SPOT, spot, spot, nullptr, nullptr, SPOT, 0, INNER, 1.f);
        ln_bf<SPOT><<<NB, 256>>>(spot, ln2_g + l * SPOT, ln2_b + l * SPOT, hbh, hbl);
        kMlp1<<<dim3(MLPD / 128, NB / 128, 1), 512, SMEM_STD>>>(
            hbh, hbl, SPOT, 0, w1h_l, w1l_l, MLPD, 0,
            b1 + l * MLPD, nullptr, nullptr, mph, mpl, MLPD, 0, SPOT, 1.f);
        kRes<<<dim3(SPOT / 128, NB / 128, 1), 512, SMEM_STD>>>(
            mph, mpl, MLPD, 0, w2h_l, w2l_l, SPOT, 0,
            b2 + l * SPOT, spot, spot, nullptr, nullptr, SPOT, 0, MLPD, 1.f);
    }

    kProj<<<dim3(PROJ / 128, NB / 128, 1), 512, SMEM_STD>>>(
        ifh, ifl, IMG, 0, iph, ipl, PROJ, 0,
        img_proj_b, nullptr, pimg, pgh, pgl, PROJ, 0, IMG, 1.f);
    kRes<<<dim3(PROJ / 128, NB / 128, 1), 512, SMEM_STD>>>(
        pgh, pgl, PROJ, 0, ifch, ifcl, PROJ, 0,
        img_fc_b, pimg, tmp, nullptr, nullptr, PROJ, 0, PROJ, 1.f);
    ln_bf<PROJ><<<NB, 256>>>(tmp, img_ln_g, img_ln_b, eih, eil);

    CONV(spot, hbh, hbl, NB * SPOT);
    kProj<<<dim3(PROJ / 128, NB / 128, 1), 512, SMEM_STD>>>(
        hbh, hbl, SPOT, 0, sph, spl, PROJ, 0,
        spot_proj_b, nullptr, pspot, pgh, pgl, PROJ, 0, SPOT, 1.f);
    kRes<<<dim3(PROJ / 128, NB / 128, 1), 512, SMEM_STD>>>(
        pgh, pgl, PROJ, 0, sfh, sfl, PROJ, 0,
        spot_fc_b, pspot, tmp, nullptr, nullptr, PROJ, 0, PROJ, 1.f);
    ln_bf<PROJ><<<NB, 256>>>(tmp, spot_ln_g, spot_ln_b, esh, esl);

    pack_bf<<<NB, 256>>>(eih, eil, esh, esl, cth, ctl);
    kSqk<<<dim3(NB / 128, NB / 128, 1), 512, SMEM_NAT>>>(
        esh, esl, PROJ, 0, eih, eil, PROJ, 0,
        nullptr, nullptr, logits, nullptr, nullptr, NB, 0, PROJ, 1.f);
    kSqk<<<dim3(NB / 128, NB / 128, 1), 512, SMEM_NAT>>>(
        cth, ctl, 2 * PROJ, 0, cth, ctl, 2 * PROJ, 0,
        nullptr, nullptr, tgt, nullptr, nullptr, NB, 0, 2 * PROJ, 0.5f);
    softmax_rows<<<NB, 256>>>(tgt);
    rowloss_kernel<<<NB, 256>>>(logits, tgt, rowp);
    colloss_kernel<<<NB / 64, 256>>>(logits, tgt, colp);
    final_reduce<<<1, 256>>>(rowp, colp, out);
}

// round 8
// speedup vs baseline: 1.2695x; 1.0322x over previous
#include <cuda_runtime.h>
#include <cstdint>

// ---------------------------------------------------------------------------
// Problem constants
// ---------------------------------------------------------------------------
namespace {
constexpr int NB   = 2048;
constexpr int SPOT = 1024;
constexpr int IMG  = 1024;
constexpr int PROJ = 256;
constexpr int NH   = 8;
constexpr int DH   = 64;
constexpr int INNER = 512;
constexpr int MLPD = 2048;
constexpr int QKVW = 1536;
constexpr int NL   = 2;
}

// ---------------------------------------------------------------------------
// Scratch: fp32
// ---------------------------------------------------------------------------
__device__ float g_spot  [NB * SPOT];
__device__ float g_tmp   [NB * SPOT];
__device__ float g_pimg  [NB * PROJ];
__device__ float g_pspot [NB * PROJ];
__device__ float g_logits[NB * NB];
__device__ float g_tgt   [NB * NB];
__device__ float g_rowp  [NB];
__device__ float g_colp  [NB];

// ---------------------------------------------------------------------------
// Scratch: bf16 hi/lo
// ---------------------------------------------------------------------------
__device__ uint16_t g_hbuf_h[NB * SPOT],  g_hbuf_l[NB * SPOT];
__device__ uint16_t g_qkv_h [NB * QKVW],  g_qkv_l [NB * QKVW];
__device__ uint16_t g_attn_h[NB * INNER], g_attn_l[NB * INNER];
__device__ uint16_t g_mlp_h [NB * MLPD],  g_mlp_l [NB * MLPD];
__device__ uint16_t g_eimg_h [NB * PROJ], g_eimg_l [NB * PROJ];
__device__ uint16_t g_espot_h[NB * PROJ], g_espot_l[NB * PROJ];
__device__ uint16_t g_pg_h   [NB * PROJ], g_pg_l   [NB * PROJ];
__device__ uint16_t g_cat_h[NB * 2 * PROJ], g_cat_l[NB * 2 * PROJ];
__device__ uint16_t g_imgf_h[NB * IMG], g_imgf_l[NB * IMG];
// weights bf16
__device__ uint16_t g_wqkv_h[NL * SPOT * QKVW], g_wqkv_l[NL * SPOT * QKVW];
__device__ uint16_t g_wo_h  [NL * INNER * SPOT], g_wo_l [NL * INNER * SPOT];
__device__ uint16_t g_w1_h  [NL * SPOT * MLPD],  g_w1_l [NL * SPOT * MLPD];
__device__ uint16_t g_w2_h  [NL * MLPD * SPOT],  g_w2_l [NL * MLPD * SPOT];
__device__ uint16_t g_wip_h [IMG * PROJ],  g_wip_l[IMG * PROJ];
__device__ uint16_t g_wif_h [PROJ * PROJ], g_wif_l[PROJ * PROJ];
__device__ uint16_t g_wsp_h [SPOT * PROJ], g_wsp_l[SPOT * PROJ];
__device__ uint16_t g_wsf_h [PROJ * PROJ], g_wsf_l[PROJ * PROJ];

// ---------------------------------------------------------------------------
// Helpers
// ---------------------------------------------------------------------------
__device__ __forceinline__ uint32_t smem_u32(const void* p) {
    uint32_t a;
    asm("{ .reg .u64 t; cvta.to.shared.u64 t, %1; cvt.u32.u64 %0, t; }"
        : "=r"(a) : "l"(p));
    return a;
}
__device__ __forceinline__ unsigned long long gptr(const void* p) {
    return (unsigned long long)__cvta_generic_to_global(p);
}
__device__ __forceinline__ float gelu_f(float x) {
    return 0.5f * x * (1.0f + erff(x * 0.7071067811865475f));
}
__device__ __forceinline__ void split2(float f0, float f1, uint32_t& hi, uint32_t& lo) {
    asm("cvt.rn.bf16x2.f32 %0, %1, %2;" : "=r"(hi) : "f"(f1), "f"(f0));
    float h0 = __uint_as_float(hi << 16);
    float h1 = __uint_as_float(hi & 0xFFFF0000u);
    float l0 = f0 - h0, l1 = f1 - h1;
    asm("cvt.rn.bf16x2.f32 %0, %1, %2;" : "=r"(lo) : "f"(l1), "f"(l0));
}

#define CP16(dst, src) \
    asm volatile("cp.async.cg.shared.global [%0], [%1], 16;" :: "r"(dst), "l"(src))
#define CP_COMMIT() asm volatile("cp.async.commit_group;" ::: "memory")
#define CP_WAIT1()  asm volatile("cp.async.wait_group 1;" ::: "memory")
#define CP_WAIT0()  asm volatile("cp.async.wait_group 0;" ::: "memory")

#define LDSM_X4(r, a)                                                          \
    asm volatile("ldmatrix.sync.aligned.m8n8.x4.shared.b16 {%0,%1,%2,%3}, [%4];" \
        : "=r"((r)[0]), "=r"((r)[1]), "=r"((r)[2]), "=r"((r)[3]) : "r"(a))
#define LDSM_X4T(r, a)                                                         \
    asm volatile("ldmatrix.sync.aligned.m8n8.x4.trans.shared.b16 {%0,%1,%2,%3}, [%4];" \
        : "=r"((r)[0]), "=r"((r)[1]), "=r"((r)[2]), "=r"((r)[3]) : "r"(a))
#define LDSM_X2(r, a)                                                          \
    asm volatile("ldmatrix.sync.aligned.m8n8.x2.shared.b16 {%0,%1}, [%2];"     \
        : "=r"((r)[0]), "=r"((r)[1]) : "r"(a))
#define LDSM_X2T(r, a)                                                         \
    asm volatile("ldmatrix.sync.aligned.m8n8.x2.trans.shared.b16 {%0,%1}, [%2];" \
        : "=r"((r)[0]), "=r"((r)[1]) : "r"(a))
#define MMA16816(d, a, b)                                                      \
    asm volatile("mma.sync.aligned.m16n8k16.row.col.f32.bf16.bf16.f32 "        \
        "{%0,%1,%2,%3}, {%4,%5,%6,%7}, {%8,%9}, {%0,%1,%2,%3};"                \
        : "+f"((d)[0]), "+f"((d)[1]), "+f"((d)[2]), "+f"((d)[3])               \
        : "r"((a)[0]), "r"((a)[1]), "r"((a)[2]), "r"((a)[3]),                  \
          "r"((b)[0]), "r"((b)[1]))

// ---------------------------------------------------------------------------
// Pure-bf16 split GEMM. 512 threads (16 warps, warp grid 4x4, warp tile 32x32),
// BK=64 chunks, 3-stage cp.async pipeline (wait_group 1).
//   D = epi( scale * (Ah+Al) @ op(Bh+Bl) ) via 3 MMA passes (hh + hl + lh)
//   A: [M,K] bf16 hi/lo. B: BNAT ? [N,K] : [K,N] bf16 hi/lo. NT = 128.
//   EPI: 0 none, 1 +bias, 2 +bias+gelu, 3 +bias+res(fp32)
//   OUT bits: 1 = fp32 C, 2 = bf16 Ch/Cl, 4 = gelu before bf16 split only
// ---------------------------------------------------------------------------
template<int NT, bool BNAT, int EPI, int OUT>
__global__ __launch_bounds__(512) void gemm_bf(
    const uint16_t* __restrict__ Ah, const uint16_t* __restrict__ Al,
    int lda, long long az,
    const uint16_t* __restrict__ Bh, const uint16_t* __restrict__ Bl,
    int ldb, long long bz,
    const float* __restrict__ bias, const float* __restrict__ res,
    float* __restrict__ C, uint16_t* __restrict__ Ch, uint16_t* __restrict__ Cl,
    int ldc, long long cz, int K, float scale)
{
    constexpr int WNC = NT / 4;                // 32
    constexpr int NTL = WNC / 8;               // 4
    constexpr int MT  = 2;
    constexpr int RS  = 72;                    // A row stride (elems), BK=64+8
    constexpr int ABYTES = 128 * RS * 2;       // 18432 per buffer
    constexpr int BRS  = BNAT ? RS : (NT + 8); // B row stride (elems)
    constexpr int BROWS = BNAT ? NT : 64;
    constexpr int BBYTES = BROWS * BRS * 2;
    constexpr int STAGE  = 2 * ABYTES + 2 * BBYTES;
    constexpr int STAGES = 3;

    extern __shared__ __align__(128) char smm[];
    const uint32_t sb = smem_u32(smm);
    const int tid = threadIdx.x, lane = tid & 31, wid = tid >> 5;
    const int wm = wid >> 2, wn = wid & 3;
    const int bm = blockIdx.y * 128, bn = blockIdx.x * NT;

    const uint16_t* Abh = Ah + (size_t)blockIdx.z * az + (size_t)bm * lda;
    const uint16_t* Abl = Al + (size_t)blockIdx.z * az + (size_t)bm * lda;
    const uint16_t* Bbh = Bh + (size_t)blockIdx.z * bz;
    const uint16_t* Bbl = Bl + (size_t)blockIdx.z * bz;

    float acc[MT][NTL][4];
    #pragma unroll
    for (int mt = 0; mt < MT; mt++)
        #pragma unroll
        for (int nt = 0; nt < NTL; nt++)
            #pragma unroll
            for (int r = 0; r < 4; r++) acc[mt][nt][r] = 0.f;

    const int NC = K >> 6;   // BK = 64

    auto issue = [&](int c, int s) {
        const uint32_t st = sb + s * STAGE;
        const int k0 = c << 6;
        // A: 128 rows x 8 segs(16B) per buffer = 1024 segs -> 2/thread
        #pragma unroll
        for (int j = 0; j < 2; j++) {
            int idx = tid + j * 512;
            int row = idx >> 3, seg = idx & 7;
            size_t so = (size_t)row * lda + k0 + seg * 8;
            uint32_t d = st + row * (RS * 2) + seg * 16;
            CP16(d, gptr(Abh + so));
            CP16(d + ABYTES, gptr(Abl + so));
        }
        // B
        #pragma unroll
        for (int j = 0; j < 2; j++) {
            int idx = tid + j * 512;
            if (BNAT) {
                int row = idx >> 3, seg = idx & 7;      // 128 rows x 8 segs
                size_t so = (size_t)(bn + row) * ldb + k0 + seg * 8;
                uint32_t d = st + 2 * ABYTES + row * (RS * 2) + seg * 16;
                CP16(d, gptr(Bbh + so));
                CP16(d + BBYTES, gptr(Bbl + so));
            } else {
                int row = idx >> 4, seg = idx & 15;     // 64 rows x 16 segs
                size_t so = (size_t)(k0 + row) * ldb + bn + seg * 8;
                uint32_t d = st + 2 * ABYTES + row * (BRS * 2) + seg * 16;
                CP16(d, gptr(Bbh + so));
                CP16(d + BBYTES, gptr(Bbl + so));
            }
        }
    };

    #pragma unroll
    for (int s = 0; s < STAGES - 1; s++) {
        if (s < NC) issue(s, s);
        CP_COMMIT();
    }

    for (int c = 0; c < NC; c++) {
        CP_WAIT1();
        __syncthreads();
        {
            int cn = c + STAGES - 1;
            if (cn < NC) issue(cn, cn % STAGES);
            CP_COMMIT();
        }
        const uint32_t abh_ = sb + (c % STAGES) * STAGE;
        const uint32_t abl_ = abh_ + ABYTES;
        const uint32_t bbh_ = abh_ + 2 * ABYTES;
        const uint32_t bbl_ = bbh_ + BBYTES;
        #pragma unroll
        for (int ks = 0; ks < 4; ks++) {
            uint32_t afh[MT][4], afl[MT][4], bfh[NTL][2], bfl[NTL][2];
            #pragma unroll
            for (int mt = 0; mt < MT; mt++) {
                uint32_t off = ((wm * 32 + mt * 16 + (lane & 15)) * RS +
                                ks * 16 + ((lane >> 4) << 3)) << 1;
                LDSM_X4(afh[mt], abh_ + off);
                LDSM_X4(afl[mt], abl_ + off);
            }
            #pragma unroll
            for (int nt = 0; nt < NTL; nt++) {
                if (BNAT) {
                    uint32_t off = ((wn * WNC + nt * 8 + (lane & 7)) * RS +
                                    ks * 16 + (((lane >> 3) & 1) << 3)) << 1;
                    LDSM_X2(bfh[nt], bbh_ + off);
                    LDSM_X2(bfl[nt], bbl_ + off);
                } else {
                    uint32_t off = ((ks * 16 + (lane & 15)) * BRS +
                                    wn * WNC + nt * 8) << 1;
                    LDSM_X2T(bfh[nt], bbh_ + off);
                    LDSM_X2T(bfl[nt], bbl_ + off);
                }
            }
            #pragma unroll
            for (int nt = 0; nt < NTL; nt++)
                #pragma unroll
                for (int mt = 0; mt < MT; mt++) {
                    MMA16816(acc[mt][nt], afh[mt], bfh[nt]);
                    MMA16816(acc[mt][nt], afh[mt], bfl[nt]);
                    MMA16816(acc[mt][nt], afl[mt], bfh[nt]);
                }
        }
    }

    const int gid = lane >> 2, tig = lane & 3;
    #pragma unroll
    for (int mt = 0; mt < MT; mt++) {
        #pragma unroll
        for (int nt = 0; nt < NTL; nt++) {
            int r0  = bm + wm * 32 + mt * 16 + gid;
            int col = bn + wn * WNC + nt * 8 + tig * 2;
            float2 v0 = make_float2(acc[mt][nt][0] * scale, acc[mt][nt][1] * scale);
            float2 v1 = make_float2(acc[mt][nt][2] * scale, acc[mt][nt][3] * scale);
            if (EPI >= 1) {
                float2 bb = *reinterpret_cast<const float2*>(&bias[col]);
                v0.x += bb.x; v0.y += bb.y; v1.x += bb.x; v1.y += bb.y;
            }
            if (EPI == 2) {
                v0.x = gelu_f(v0.x); v0.y = gelu_f(v0.y);
                v1.x = gelu_f(v1.x); v1.y = gelu_f(v1.y);
            }
            if (EPI == 3) {
                float2 ra = *reinterpret_cast<const float2*>(
                    &res[(size_t)r0 * ldc + col]);
                float2 rb = *reinterpret_cast<const float2*>(
                    &res[(size_t)(r0 + 8) * ldc + col]);
                v0.x += ra.x; v0.y += ra.y; v1.x += rb.x; v1.y += rb.y;
            }
            size_t o0 = (size_t)r0 * ldc + col + (size_t)blockIdx.z * cz;
            size_t o1 = (size_t)(r0 + 8) * ldc + col + (size_t)blockIdx.z * cz;
            if (OUT & 1) {
                *reinterpret_cast<float2*>(&C[o0]) = v0;
                *reinterpret_cast<float2*>(&C[o1]) = v1;
            }
            if (OUT & 2) {
                float a0 = v0.x, a1 = v0.y, b0 = v1.x, b1 = v1.y;
                if (OUT & 4) {
                    a0 = gelu_f(a0); a1 = gelu_f(a1);
                    b0 = gelu_f(b0); b1 = gelu_f(b1);
                }
                uint32_t h, l;
                split2(a0, a1, h, l);
                *reinterpret_cast<uint32_t*>(&Ch[o0]) = h;
                *reinterpret_cast<uint32_t*>(&Cl[o0]) = l;
                split2(b0, b1, h, l);
                *reinterpret_cast<uint32_t*>(&Ch[o1]) = h;
                *reinterpret_cast<uint32_t*>(&Cl[o1]) = l;
            }
        }
    }
}

// ---------------------------------------------------------------------------
// Fused flash attention (split-bf16 mma). Unchanged from R7 (passing).
// ---------------------------------------------------------------------------
__global__ __launch_bounds__(256) void flash_attn(
    const uint16_t* __restrict__ qh, const uint16_t* __restrict__ ql,
    uint16_t* __restrict__ oh, uint16_t* __restrict__ ol)
{
    constexpr int RS = 72;
    constexpr int TB = 128 * RS * 2;
    constexpr int KVSTAGE = 4 * TB;
    extern __shared__ __align__(128) char smm[];
    const uint32_t sb  = smem_u32(smm);
    const uint32_t sQh = sb, sQl = sb + TB;
    const int tid = threadIdx.x, lane = tid & 31, w = tid >> 5;
    const int q0 = blockIdx.x * 128;
    const int h  = blockIdx.y;
    const int g = lane >> 2, t = lane & 3;

    #pragma unroll
    for (int j = 0; j < 4; j++) {
        int idx = tid + j * 256;
        int row = idx >> 3, seg = idx & 7;
        size_t so = (size_t)(q0 + row) * QKVW + h * 64 + seg * 8;
        uint32_t d = sb + row * (RS * 2) + seg * 16;
        CP16(d, gptr(qh + so));
        CP16(d + TB, gptr(ql + so));
    }
    auto issueKV = [&](int kt, int s) {
        uint32_t st = sb + 2 * TB + s * KVSTAGE;
        int tok0 = kt * 128;
        #pragma unroll
        for (int j = 0; j < 4; j++) {
            int idx = tid + j * 256;
            int row = idx >> 3, seg = idx & 7;
            size_t soK = (size_t)(tok0 + row) * QKVW + INNER + h * 64 + seg * 8;
            uint32_t dK = st + row * (RS * 2) + seg * 16;
            CP16(dK, gptr(qh + soK));
            CP16(dK + TB, gptr(ql + soK));
            size_t soV = soK + INNER;
            uint32_t dV = st + 2 * TB + row * (RS * 2) + seg * 16;
            CP16(dV, gptr(qh + soV));
            CP16(dV + TB, gptr(ql + soV));
        }
    };
    issueKV(0, 0);
    CP_COMMIT();

    float O[8][4];
    #pragma unroll
    for (int jt = 0; jt < 8; jt++)
        #pragma unroll
        for (int r = 0; r < 4; r++) O[jt][r] = 0.f;
    float m0 = -1e30f, m1 = -1e30f, l0 = 0.f, l1 = 0.f;

    for (int kt = 0; kt < NB / 128; kt++) {
        if (kt + 1 < NB / 128) {
            issueKV(kt + 1, (kt + 1) & 1);
            CP_COMMIT();
            CP_WAIT1();
        } else {
            CP_WAIT0();
        }
        __syncthreads();
        const uint32_t st  = sb + 2 * TB + (kt & 1) * KVSTAGE;
        const uint32_t sKh = st, sKl = st + TB;
        const uint32_t sVh = st + 2 * TB, sVl = st + 3 * TB;

        float sacc[16][4];
        #pragma unroll
        for (int j = 0; j < 16; j++)
            #pragma unroll
            for (int r = 0; r < 4; r++) sacc[j][r] = 0.f;

        #pragma unroll
        for (int kc = 0; kc < 4; kc++) {
            uint32_t aqh[4], aql[4];
            uint32_t aoff = ((w * 16 + (lane & 15)) * RS +
                             kc * 16 + ((lane >> 4) << 3)) << 1;
            LDSM_X4(aqh, sQh + aoff);
            LDSM_X4(aql, sQl + aoff);
            #pragma unroll
            for (int jp = 0; jp < 8; jp++) {
                uint32_t rh[4], rl[4];
                uint32_t boff = ((jp * 16 + (lane & 15)) * RS +
                                 kc * 16 + ((lane >> 4) << 3)) << 1;
                LDSM_X4(rh, sKh + boff);
                LDSM_X4(rl, sKl + boff);
                uint32_t bh0[2] = {rh[0], rh[2]}, bh1[2] = {rh[1], rh[3]};
                uint32_t bl0[2] = {rl[0], rl[2]}, bl1[2] = {rl[1], rl[3]};
                MMA16816(sacc[2 * jp],     aqh, bh0);
                MMA16816(sacc[2 * jp],     aqh, bl0);
                MMA16816(sacc[2 * jp],     aql, bh0);
                MMA16816(sacc[2 * jp + 1], aqh, bh1);
                MMA16816(sacc[2 * jp + 1], aqh, bl1);
                MMA16816(sacc[2 * jp + 1], aql, bh1);
            }
        }

        float mx0 = m0, mx1 = m1;
        #pragma unroll
        for (int j = 0; j < 16; j++) {
            sacc[j][0] *= 0.125f; sacc[j][1] *= 0.125f;
            sacc[j][2] *= 0.125f; sacc[j][3] *= 0.125f;
            mx0 = fmaxf(mx0, fmaxf(sacc[j][0], sacc[j][1]));
            mx1 = fmaxf(mx1, fmaxf(sacc[j][2], sacc[j][3]));
        }
        mx0 = fmaxf(mx0, __shfl_xor_sync(0xffffffffu, mx0, 1));
        mx0 = fmaxf(mx0, __shfl_xor_sync(0xffffffffu, mx0, 2));
        mx1 = fmaxf(mx1, __shfl_xor_sync(0xffffffffu, mx1, 1));
        mx1 = fmaxf(mx1, __shfl_xor_sync(0xffffffffu, mx1, 2));
        float a0 = __expf(m0 - mx0), a1 = __expf(m1 - mx1);
        m0 = mx0; m1 = mx1;
        float s0 = 0.f, s1 = 0.f;
        #pragma unroll
        for (int j = 0; j < 16; j++) {
            sacc[j][0] = __expf(sacc[j][0] - m0); s0 += sacc[j][0];
            sacc[j][1] = __expf(sacc[j][1] - m0); s0 += sacc[j][1];
            sacc[j][2] = __expf(sacc[j][2] - m1); s1 += sacc[j][2];
            sacc[j][3] = __expf(sacc[j][3] - m1); s1 += sacc[j][3];
        }
        s0 += __shfl_xor_sync(0xffffffffu, s0, 1);
        s0 += __shfl_xor_sync(0xffffffffu, s0, 2);
        s1 += __shfl_xor_sync(0xffffffffu, s1, 1);
        s1 += __shfl_xor_sync(0xffffffffu, s1, 2);
        l0 = l0 * a0 + s0;
        l1 = l1 * a1 + s1;
        #pragma unroll
        for (int jt = 0; jt < 8; jt++) {
            O[jt][0] *= a0; O[jt][1] *= a0;
            O[jt][2] *= a1; O[jt][3] *= a1;
        }

        #pragma unroll
        for (int kc = 0; kc < 8; kc++) {
            uint32_t ah[4], al[4];
            split2(sacc[2 * kc][0],     sacc[2 * kc][1],     ah[0], al[0]);
            split2(sacc[2 * kc][2],     sacc[2 * kc][3],     ah[1], al[1]);
            split2(sacc[2 * kc + 1][0], sacc[2 * kc + 1][1], ah[2], al[2]);
            split2(sacc[2 * kc + 1][2], sacc[2 * kc + 1][3], ah[3], al[3]);
            #pragma unroll
            for (int jp = 0; jp < 4; jp++) {
                uint32_t rh[4], rl[4];
                uint32_t boff = ((kc * 16 + (lane & 15)) * RS +
                                 jp * 16 + ((lane >> 4) << 3)) << 1;
                LDSM_X4T(rh, sVh + boff);
                LDSM_X4T(rl, sVl + boff);
                uint32_t bh0[2] = {rh[0], rh[1]}, bh1[2] = {rh[2], rh[3]};
                uint32_t bl0[2] = {rl[0], rl[1]}, bl1[2] = {rl[2], rl[3]};
                MMA16816(O[2 * jp],     ah, bh0);
                MMA16816(O[2 * jp],     ah, bl0);
                MMA16816(O[2 * jp],     al, bh0);
                MMA16816(O[2 * jp + 1], ah, bh1);
                MMA16816(O[2 * jp + 1], ah, bl1);
                MMA16816(O[2 * jp + 1], al, bh1);
            }
        }
        __syncthreads();
    }

    float i0 = 1.f / l0, i1 = 1.f / l1;
    #pragma unroll
    for (int jt = 0; jt < 8; jt++) {
        uint32_t hh, ll;
        size_t o0 = (size_t)(q0 + w * 16 + g) * INNER + h * 64 + jt * 8 + t * 2;
        split2(O[jt][0] * i0, O[jt][1] * i0, hh, ll);
        *reinterpret_cast<uint32_t*>(oh + o0) = hh;
        *reinterpret_cast<uint32_t*>(ol + o0) = ll;
        size_t o1 = o0 + (size_t)8 * INNER;
        split2(O[jt][2] * i1, O[jt][3] * i1, hh, ll);
        *reinterpret_cast<uint32_t*>(oh + o1) = hh;
        *reinterpret_cast<uint32_t*>(ol + o1) = ll;
    }
}

// ---------------------------------------------------------------------------
// Reductions
// ---------------------------------------------------------------------------
__device__ __forceinline__ float blk_sum256(float v, float* sh) {
    int t = threadIdx.x;
    sh[t] = v; __syncthreads();
    #pragma unroll
    for (int s = 128; s >= 1; s >>= 1) {
        if (t < s) sh[t] += sh[t + s];
        __syncthreads();
    }
    float r = sh[0]; __syncthreads();
    return r;
}
__device__ __forceinline__ float blk_max256(float v, float* sh) {
    int t = threadIdx.x;
    sh[t] = v; __syncthreads();
    #pragma unroll
    for (int s = 128; s >= 1; s >>= 1) {
        if (t < s) sh[t] = fmaxf(sh[t], sh[t + s]);
        __syncthreads();
    }
    float r = sh[0]; __syncthreads();
    return r;
}

// ---------------------------------------------------------------------------
// Elementwise kernels
// ---------------------------------------------------------------------------
__global__ __launch_bounds__(256) void conv_bf(
    const float* __restrict__ x, uint16_t* __restrict__ h,
    uint16_t* __restrict__ l, int n2)
{
    int i = blockIdx.x * 256 + threadIdx.x;
    if (i < n2) {
        float2 v = reinterpret_cast<const float2*>(x)[i];
        uint32_t hh, ll;
        split2(v.x, v.y, hh, ll);
        reinterpret_cast<uint32_t*>(h)[i] = hh;
        reinterpret_cast<uint32_t*>(l)[i] = ll;
    }
}

__global__ __launch_bounds__(256) void embed_kernel(
    const float* __restrict__ expr, const float* __restrict__ xt,
    const float* __restrict__ yt, const int* __restrict__ xi,
    const int* __restrict__ yi, float* __restrict__ out)
{
    int row = blockIdx.x;
    size_t xo = (size_t)xi[row] * SPOT;
    size_t yo = (size_t)yi[row] * SPOT;
    size_t ro = (size_t)row * SPOT;
    for (int j = threadIdx.x; j < SPOT; j += 256)
        out[ro + j] = expr[ro + j] + xt[xo + j] + yt[yo + j];
}

template<int N>
__global__ __launch_bounds__(256) void ln_bf(
    const float* __restrict__ x, const float* __restrict__ g,
    const float* __restrict__ b, uint16_t* __restrict__ oh,
    uint16_t* __restrict__ ol)
{
    __shared__ float sh[256];
    constexpr int NPAIR = N / 2;
    constexpr int NP = (NPAIR + 255) / 256;
    int row = blockIdx.x, tid = threadIdx.x;
    const float2* xr = reinterpret_cast<const float2*>(x + (size_t)row * N);
    float2 v[NP];
    float s = 0.f;
    #pragma unroll
    for (int i = 0; i < NP; i++) {
        int p = i * 256 + tid;
        if (p < NPAIR) { v[i] = xr[p]; s += v[i].x + v[i].y; }
        else v[i] = make_float2(0.f, 0.f);
    }
    s = blk_sum256(s, sh);
    float mean = s / N, ss = 0.f;
    #pragma unroll
    for (int i = 0; i < NP; i++) {
        int p = i * 256 + tid;
        if (p < NPAIR) {
            float dx = v[i].x - mean, dy = v[i].y - mean;
            ss += dx * dx + dy * dy;
        }
    }
    ss = blk_sum256(ss, sh);
    float rstd = rsqrtf(ss / N + 1e-5f);
    uint32_t* OH = reinterpret_cast<uint32_t*>(oh + (size_t)row * N);
    uint32_t* OL = reinterpret_cast<uint32_t*>(ol + (size_t)row * N);
    #pragma unroll
    for (int i = 0; i < NP; i++) {
        int p = i * 256 + tid;
        if (p < NPAIR) {
            float2 gg = reinterpret_cast<const float2*>(g)[p];
            float2 bb = reinterpret_cast<const float2*>(b)[p];
            float y0 = (v[i].x - mean) * rstd * gg.x + bb.x;
            float y1 = (v[i].y - mean) * rstd * gg.y + bb.y;
            uint32_t h, l;
            split2(y0, y1, h, l);
            OH[p] = h; OL[p] = l;
        }
    }
}

__global__ __launch_bounds__(256) void softmax_rows(float* __restrict__ x)
{
    __shared__ float sh[256];
    size_t row = blockIdx.x;
    int tid = threadIdx.x;
    float* r = x + row * NB;
    float v[8];
    float mx = -1e30f;
    #pragma unroll
    for (int i = 0; i < 8; i++) { v[i] = r[i * 256 + tid]; mx = fmaxf(mx, v[i]); }
    mx = blk_max256(mx, sh);
    float s = 0.f;
    #pragma unroll
    for (int i = 0; i < 8; i++) { v[i] = __expf(v[i] - mx); s += v[i]; }
    s = blk_sum256(s, sh);
    float inv = 1.f / s;
    #pragma unroll
    for (int i = 0; i < 8; i++) r[i * 256 + tid] = v[i] * inv;
}

__global__ __launch_bounds__(256) void pack_bf(
    const uint16_t* __restrict__ ih, const uint16_t* __restrict__ il,
    const uint16_t* __restrict__ eh, const uint16_t* __restrict__ el,
    uint16_t* __restrict__ ch, uint16_t* __restrict__ cl)
{
    int row = blockIdx.x, tid = threadIdx.x;
    const uint32_t* IH = reinterpret_cast<const uint32_t*>(ih + (size_t)row * PROJ);
    const uint32_t* IL = reinterpret_cast<const uint32_t*>(il + (size_t)row * PROJ);
    const uint32_t* EH = reinterpret_cast<const uint32_t*>(eh + (size_t)row * PROJ);
    const uint32_t* EL = reinterpret_cast<const uint32_t*>(el + (size_t)row * PROJ);
    uint32_t vh, vl;
    if (tid < 128) { vh = IH[tid]; vl = IL[tid]; }
    else           { vh = EH[tid - 128]; vl = EL[tid - 128]; }
    reinterpret_cast<uint32_t*>(ch + (size_t)row * 2 * PROJ)[tid] = vh;
    reinterpret_cast<uint32_t*>(cl + (size_t)row * 2 * PROJ)[tid] = vl;
}

__global__ __launch_bounds__(256) void rowloss_kernel(
    const float* __restrict__ logits, const float* __restrict__ tgt,
    float* __restrict__ rowp)
{
    __shared__ float sh[256];
    int row = blockIdx.x, tid = threadIdx.x;
    const float* lr = logits + (size_t)row * NB;
    const float* tr = tgt    + (size_t)row * NB;
    float lv[8], tv[8];
    float mx = -1e30f;
    #pragma unroll
    for (int i = 0; i < 8; i++) {
        lv[i] = lr[i * 256 + tid];
        tv[i] = tr[i * 256 + tid];
        mx = fmaxf(mx, lv[i]);
    }
    mx = blk_max256(mx, sh);
    float se = 0.f, dot = 0.f;
    #pragma unroll
    for (int i = 0; i < 8; i++) { se += __expf(lv[i] - mx); dot += tv[i] * lv[i]; }
    se  = blk_sum256(se, sh);
    dot = blk_sum256(dot, sh);
    if (tid == 0) rowp[row] = 0.5f * (mx + logf(se) - dot);
}

__global__ __launch_bounds__(256) void colloss_kernel(
    const float* __restrict__ logits, const float* __restrict__ tgt,
    float* __restrict__ colp)
{
    __shared__ float smx[256], sse[256], sts[256], stdot[256];
    int tid = threadIdx.x;
    int c = blockIdx.x * 64 + (tid & 63);
    int ry = tid >> 6;
    float mx = -1e30f, se = 0.f, ts = 0.f, td = 0.f;
    for (int r = ry; r < NB; r += 4) {
        float l = logits[(size_t)r * NB + c];
        float t = tgt   [(size_t)r * NB + c];
        if (l > mx) { se = se * __expf(mx - l) + 1.f; mx = l; }
        else        { se += __expf(l - mx); }
        ts += t;
        td += t * l;
    }
    smx[tid] = mx; sse[tid] = se; sts[tid] = ts; stdot[tid] = td;
    __syncthreads();
    if (ry == 0) {
        #pragma unroll
        for (int k = 1; k < 4; k++) {
            int o = tid + k * 64;
            float m2 = smx[o], s2 = sse[o];
            float m = fmaxf(mx, m2);
            se = se * __expf(mx - m) + s2 * __expf(m2 - m);
            mx = m;
            ts += sts[o];
            td += stdot[o];
        }
        colp[c] = 0.5f * (ts * (mx + logf(se)) - td);
    }
}

__global__ __launch_bounds__(256) void final_reduce(
    const float* __restrict__ a, const float* __restrict__ b,
    float* __restrict__ out)
{
    __shared__ float sh[256];
    int tid = threadIdx.x;
    float s = 0.f;
    for (int i = tid; i < NB; i += 256) s += a[i] + b[i];
    s = blk_sum256(s, sh);
    if (tid == 0) out[0] = s * (1.0f / NB);
}

// ---------------------------------------------------------------------------
// Host launch
// ---------------------------------------------------------------------------
namespace {
constexpr int SMEM_STD = 3 * (2 * 128 * 72 * 2 + 2 * 64 * 136 * 2);   // 215040
constexpr int SMEM_NAT = 3 * (2 * 128 * 72 * 2 + 2 * 128 * 72 * 2);   // 221184
constexpr int SMEM_FLASH = 2 * (128 * 72 * 2) + 2 * 4 * (128 * 72 * 2); // 184320
}

#define SYM(var, sym) cudaGetSymbolAddress((void**)&var, sym)

extern "C" void kernel_launch(void* const* d_in, const int* in_sizes, int n_in,
                              void* d_out, int out_size)
{
    (void)in_sizes; (void)n_in; (void)out_size;
    const float* image_features = (const float*)d_in[0];
    const float* expression     = (const float*)d_in[1];
    const float* x_table        = (const float*)d_in[2];
    const float* y_table        = (const float*)d_in[3];
    const float* ln1_g          = (const float*)d_in[4];
    const float* ln1_b          = (const float*)d_in[5];
    const float* w_qkv          = (const float*)d_in[6];
    const float* w_o            = (const float*)d_in[7];
    const float* b_o            = (const float*)d_in[8];
    const float* ln2_g          = (const float*)d_in[9];
    const float* ln2_b          = (const float*)d_in[10];
    const float* w1             = (const float*)d_in[11];
    const float* b1             = (const float*)d_in[12];
    const float* w2             = (const float*)d_in[13];
    const float* b2             = (const float*)d_in[14];
    const float* img_proj_w     = (const float*)d_in[15];
    const float* img_proj_b     = (const float*)d_in[16];
    const float* img_fc_w       = (const float*)d_in[17];
    const float* img_fc_b       = (const float*)d_in[18];
    const float* img_ln_g       = (const float*)d_in[19];
    const float* img_ln_b       = (const float*)d_in[20];
    const float* spot_proj_w    = (const float*)d_in[21];
    const float* spot_proj_b    = (const float*)d_in[22];
    const float* spot_fc_w      = (const float*)d_in[23];
    const float* spot_fc_b      = (const float*)d_in[24];
    const float* spot_ln_g      = (const float*)d_in[25];
    const float* spot_ln_b      = (const float*)d_in[26];
    const int*   x_idx          = (const int*)d_in[27];
    const int*   y_idx          = (const int*)d_in[28];
    float* out = (float*)d_out;

    float *spot, *tmp, *pimg, *pspot, *logits, *tgt, *rowp, *colp;
    SYM(spot, g_spot); SYM(tmp, g_tmp);
    SYM(pimg, g_pimg); SYM(pspot, g_pspot);
    SYM(logits, g_logits); SYM(tgt, g_tgt); SYM(rowp, g_rowp); SYM(colp, g_colp);

    uint16_t *hbh, *hbl, *qkh, *qkl, *ath, *atl, *mph, *mpl;
    uint16_t *eih, *eil, *esh, *esl, *pgh, *pgl, *cth, *ctl, *ifh, *ifl;
    SYM(hbh, g_hbuf_h); SYM(hbl, g_hbuf_l);
    SYM(qkh, g_qkv_h);  SYM(qkl, g_qkv_l);
    SYM(ath, g_attn_h); SYM(atl, g_attn_l);
    SYM(mph, g_mlp_h);  SYM(mpl, g_mlp_l);
    SYM(eih, g_eimg_h); SYM(eil, g_eimg_l);
    SYM(esh, g_espot_h); SYM(esl, g_espot_l);
    SYM(pgh, g_pg_h);   SYM(pgl, g_pg_l);
    SYM(cth, g_cat_h);  SYM(ctl, g_cat_l);
    SYM(ifh, g_imgf_h); SYM(ifl, g_imgf_l);

    uint16_t *wqh, *wql, *woh, *wol, *w1h, *w1l, *w2h, *w2l;
    uint16_t *iph, *ipl, *ifch, *ifcl, *sph, *spl, *sfh, *sfl;
    SYM(wqh, g_wqkv_h); SYM(wql, g_wqkv_l);
    SYM(woh, g_wo_h);   SYM(wol, g_wo_l);
    SYM(w1h, g_w1_h);   SYM(w1l, g_w1_l);
    SYM(w2h, g_w2_h);   SYM(w2l, g_w2_l);
    SYM(iph, g_wip_h);  SYM(ipl, g_wip_l);
    SYM(ifch, g_wif_h); SYM(ifcl, g_wif_l);
    SYM(sph, g_wsp_h);  SYM(spl, g_wsp_l);
    SYM(sfh, g_wsf_h);  SYM(sfl, g_wsf_l);

    auto kQKV  = gemm_bf<128, false, 0, 2>;
    auto kSqk  = gemm_bf<128, true,  0, 1>;
    auto kRes  = gemm_bf<128, false, 3, 1>;
    auto kResO = gemm_bf<128, false, 3, 3>;   // fp32 + bf16 split out
    auto kMlp1 = gemm_bf<128, false, 2, 2>;
    auto kProj = gemm_bf<128, false, 1, 7>;
    cudaFuncSetAttribute(kQKV,  cudaFuncAttributeMaxDynamicSharedMemorySize, SMEM_STD);
    cudaFuncSetAttribute(kSqk,  cudaFuncAttributeMaxDynamicSharedMemorySize, SMEM_NAT);
    cudaFuncSetAttribute(kRes,  cudaFuncAttributeMaxDynamicSharedMemorySize, SMEM_STD);
    cudaFuncSetAttribute(kResO, cudaFuncAttributeMaxDynamicSharedMemorySize, SMEM_STD);
    cudaFuncSetAttribute(kMlp1, cudaFuncAttributeMaxDynamicSharedMemorySize, SMEM_STD);
    cudaFuncSetAttribute(kProj, cudaFuncAttributeMaxDynamicSharedMemorySize, SMEM_STD);
    cudaFuncSetAttribute(flash_attn,
                         cudaFuncAttributeMaxDynamicSharedMemorySize, SMEM_FLASH);

    auto CONV = [&](const float* src, uint16_t* h, uint16_t* l, int n) {
        conv_bf<<<(n / 2 + 255) / 256, 256>>>(src, h, l, n / 2);
    };
    CONV(w_qkv, wqh, wql, NL * SPOT * QKVW);
    CONV(w_o,   woh, wol, NL * INNER * SPOT);
    CONV(w1,    w1h, w1l, NL * SPOT * MLPD);
    CONV(w2,    w2h, w2l, NL * MLPD * SPOT);
    CONV(img_proj_w, iph, ipl, IMG * PROJ);
    CONV(img_fc_w, ifch, ifcl, PROJ * PROJ);
    CONV(spot_proj_w, sph, spl, SPOT * PROJ);
    CONV(spot_fc_w, sfh, sfl, PROJ * PROJ);
    CONV(image_features, ifh, ifl, NB * IMG);

    embed_kernel<<<NB, 256>>>(expression, x_table, y_table, x_idx, y_idx, spot);

    for (int l = 0; l < NL; l++) {
        uint16_t* wqh_l = wqh + (size_t)l * SPOT * QKVW;
        uint16_t* wql_l = wql + (size_t)l * SPOT * QKVW;
        uint16_t* woh_l = woh + (size_t)l * INNER * SPOT;
        uint16_t* wol_l = wol + (size_t)l * INNER * SPOT;
        uint16_t* w1h_l = w1h + (size_t)l * SPOT * MLPD;
        uint16_t* w1l_l = w1l + (size_t)l * SPOT * MLPD;
        uint16_t* w2h_l = w2h + (size_t)l * MLPD * SPOT;
        uint16_t* w2l_l = w2l + (size_t)l * MLPD * SPOT;

        ln_bf<SPOT><<<NB, 256>>>(spot, ln1_g + l * SPOT, ln1_b + l * SPOT, hbh, hbl);
        kQKV<<<dim3(QKVW / 128, NB / 128, 1), 512, SMEM_STD>>>(
            hbh, hbl, SPOT, 0, wqh_l, wql_l, QKVW, 0, nullptr, nullptr,
            nullptr, qkh, qkl, QKVW, 0, SPOT, 1.f);
        flash_attn<<<dim3(NB / 128, NH), 256, SMEM_FLASH>>>(qkh, qkl, ath, atl);
        kRes<<<dim3(SPOT / 128, NB / 128, 1), 512, SMEM_STD>>>(
            ath, atl, INNER, 0, woh_l, wol_l, SPOT, 0,
            b_o + l * SPOT, spot, spot, nullptr, nullptr, SPOT, 0, INNER, 1.f);
        ln_bf<SPOT><<<NB, 256>>>(spot, ln2_g + l * SPOT, ln2_b + l * SPOT, hbh, hbl);
        kMlp1<<<dim3(MLPD / 128, NB / 128, 1), 512, SMEM_STD>>>(
            hbh, hbl, SPOT, 0, w1h_l, w1l_l, MLPD, 0,
            b1 + l * MLPD, nullptr, nullptr, mph, mpl, MLPD, 0, SPOT, 1.f);
        if (l == NL - 1) {
            // final residual also emits bf16 split of spot -> hbh/hbl
            kResO<<<dim3(SPOT / 128, NB / 128, 1), 512, SMEM_STD>>>(
                mph, mpl, MLPD, 0, w2h_l, w2l_l, SPOT, 0,
                b2 + l * SPOT, spot, spot, hbh, hbl, SPOT, 0, MLPD, 1.f);
        } else {
            kRes<<<dim3(SPOT / 128, NB / 128, 1), 512, SMEM_STD>>>(
                mph, mpl, MLPD, 0, w2h_l, w2l_l, SPOT, 0,
                b2 + l * SPOT, spot, spot, nullptr, nullptr, SPOT, 0, MLPD, 1.f);
        }
    }

    kProj<<<dim3(PROJ / 128, NB / 128, 1), 512, SMEM_STD>>>(
        ifh, ifl, IMG, 0, iph, ipl, PROJ, 0,
        img_proj_b, nullptr, pimg, pgh, pgl, PROJ, 0, IMG, 1.f);
    kRes<<<dim3(PROJ / 128, NB / 128, 1), 512, SMEM_STD>>>(
        pgh, pgl, PROJ, 0, ifch, ifcl, PROJ, 0,
        img_fc_b, pimg, tmp, nullptr, nullptr, PROJ, 0, PROJ, 1.f);
    ln_bf<PROJ><<<NB, 256>>>(tmp, img_ln_g, img_ln_b, eih, eil);

    // spot bf16 split already in hbh/hbl (from kResO)
    kProj<<<dim3(PROJ / 128, NB / 128, 1), 512, SMEM_STD>>>(
        hbh, hbl, SPOT, 0, sph, spl, PROJ, 0,
        spot_proj_b, nullptr, pspot, pgh, pgl, PROJ, 0, SPOT, 1.f);
    kRes<<<dim3(PROJ / 128, NB / 128, 1), 512, SMEM_STD>>>(
        pgh, pgl, PROJ, 0, sfh, sfl, PROJ, 0,
        spot_fc_b, pspot, tmp, nullptr, nullptr, PROJ, 0, PROJ, 1.f);
    ln_bf<PROJ><<<NB, 256>>>(tmp, spot_ln_g, spot_ln_b, esh, esl);

    pack_bf<<<NB, 256>>>(eih, eil, esh, esl, cth, ctl);
    kSqk<<<dim3(NB / 128, NB / 128, 1), 512, SMEM_NAT>>>(
        esh, esl, PROJ, 0, eih, eil, PROJ, 0,
        nullptr, nullptr, logits, nullptr, nullptr, NB, 0, PROJ, 1.f);
    kSqk<<<dim3(NB / 128, NB / 128, 1), 512, SMEM_NAT>>>(
        cth, ctl, 2 * PROJ, 0, cth, ctl, 2 * PROJ, 0,
        nullptr, nullptr, tgt, nullptr, nullptr, NB, 0, 2 * PROJ, 0.5f);
    softmax_rows<<<NB, 256>>>(tgt);
    rowloss_kernel<<<NB, 256>>>(logits, tgt, rowp);
    colloss_kernel<<<NB / 64, 256>>>(logits, tgt, colp);
    final_reduce<<<1, 256>>>(rowp, colp, out);
}

// round 9
// speedup vs baseline: 1.2938x; 1.0192x over previous
#include <cuda_runtime.h>
#include <cstdint>

// ---------------------------------------------------------------------------
// Problem constants
// ---------------------------------------------------------------------------
namespace {
constexpr int NB   = 2048;
constexpr int SPOT = 1024;
constexpr int IMG  = 1024;
constexpr int PROJ = 256;
constexpr int NH   = 8;
constexpr int DH   = 64;
constexpr int INNER = 512;
constexpr int MLPD = 2048;
constexpr int QKVW = 1536;
constexpr int NL   = 2;
}

// ---------------------------------------------------------------------------
// Scratch: fp32
// ---------------------------------------------------------------------------
__device__ float g_spot  [NB * SPOT];
__device__ float g_tmp   [NB * SPOT];
__device__ float g_pimg  [NB * PROJ];
__device__ float g_pspot [NB * PROJ];
__device__ float g_logits[NB * NB];
__device__ float g_tgt   [NB * NB];
__device__ float g_rowp  [NB];
__device__ float g_colp  [NB];

// ---------------------------------------------------------------------------
// Scratch: bf16 hi/lo
// ---------------------------------------------------------------------------
__device__ uint16_t g_hbuf_h[NB * SPOT],  g_hbuf_l[NB * SPOT];
__device__ uint16_t g_qkv_h [NB * QKVW],  g_qkv_l [NB * QKVW];
__device__ uint16_t g_attn_h[NB * INNER], g_attn_l[NB * INNER];
__device__ uint16_t g_mlp_h [NB * MLPD],  g_mlp_l [NB * MLPD];
__device__ uint16_t g_eimg_h [NB * PROJ], g_eimg_l [NB * PROJ];
__device__ uint16_t g_espot_h[NB * PROJ], g_espot_l[NB * PROJ];
__device__ uint16_t g_pg_h   [NB * PROJ], g_pg_l   [NB * PROJ];
__device__ uint16_t g_cat_h[NB * 2 * PROJ], g_cat_l[NB * 2 * PROJ];
__device__ uint16_t g_imgf_h[NB * IMG], g_imgf_l[NB * IMG];
// weights bf16
__device__ uint16_t g_wqkv_h[NL * SPOT * QKVW], g_wqkv_l[NL * SPOT * QKVW];
__device__ uint16_t g_wo_h  [NL * INNER * SPOT], g_wo_l [NL * INNER * SPOT];
__device__ uint16_t g_w1_h  [NL * SPOT * MLPD],  g_w1_l [NL * SPOT * MLPD];
__device__ uint16_t g_w2_h  [NL * MLPD * SPOT],  g_w2_l [NL * MLPD * SPOT];
__device__ uint16_t g_wip_h [IMG * PROJ],  g_wip_l[IMG * PROJ];
__device__ uint16_t g_wif_h [PROJ * PROJ], g_wif_l[PROJ * PROJ];
__device__ uint16_t g_wsp_h [SPOT * PROJ], g_wsp_l[SPOT * PROJ];
__device__ uint16_t g_wsf_h [PROJ * PROJ], g_wsf_l[PROJ * PROJ];

// ---------------------------------------------------------------------------
// Helpers
// ---------------------------------------------------------------------------
__device__ __forceinline__ uint32_t smem_u32(const void* p) {
    uint32_t a;
    asm("{ .reg .u64 t; cvta.to.shared.u64 t, %1; cvt.u32.u64 %0, t; }"
        : "=r"(a) : "l"(p));
    return a;
}
__device__ __forceinline__ unsigned long long gptr(const void* p) {
    return (unsigned long long)__cvta_generic_to_global(p);
}
__device__ __forceinline__ float gelu_f(float x) {
    return 0.5f * x * (1.0f + erff(x * 0.7071067811865475f));
}
__device__ __forceinline__ void split2(float f0, float f1, uint32_t& hi, uint32_t& lo) {
    asm("cvt.rn.bf16x2.f32 %0, %1, %2;" : "=r"(hi) : "f"(f1), "f"(f0));
    float h0 = __uint_as_float(hi << 16);
    float h1 = __uint_as_float(hi & 0xFFFF0000u);
    float l0 = f0 - h0, l1 = f1 - h1;
    asm("cvt.rn.bf16x2.f32 %0, %1, %2;" : "=r"(lo) : "f"(l1), "f"(l0));
}

#define CP16(dst, src) \
    asm volatile("cp.async.cg.shared.global [%0], [%1], 16;" :: "r"(dst), "l"(src))
#define CP_COMMIT() asm volatile("cp.async.commit_group;" ::: "memory")
#define CP_WAIT1()  asm volatile("cp.async.wait_group 1;" ::: "memory")
#define CP_WAIT0()  asm volatile("cp.async.wait_group 0;" ::: "memory")

#define LDSM_X4(r, a)                                                          \
    asm volatile("ldmatrix.sync.aligned.m8n8.x4.shared.b16 {%0,%1,%2,%3}, [%4];" \
        : "=r"((r)[0]), "=r"((r)[1]), "=r"((r)[2]), "=r"((r)[3]) : "r"(a))
#define LDSM_X4T(r, a)                                                         \
    asm volatile("ldmatrix.sync.aligned.m8n8.x4.trans.shared.b16 {%0,%1,%2,%3}, [%4];" \
        : "=r"((r)[0]), "=r"((r)[1]), "=r"((r)[2]), "=r"((r)[3]) : "r"(a))
#define MMA16816(d, a, b)                                                      \
    asm volatile("mma.sync.aligned.m16n8k16.row.col.f32.bf16.bf16.f32 "        \
        "{%0,%1,%2,%3}, {%4,%5,%6,%7}, {%8,%9}, {%0,%1,%2,%3};"                \
        : "+f"((d)[0]), "+f"((d)[1]), "+f"((d)[2]), "+f"((d)[3])               \
        : "r"((a)[0]), "r"((a)[1]), "r"((a)[2]), "r"((a)[3]),                  \
          "r"((b)[0]), "r"((b)[1]))

// ---------------------------------------------------------------------------
// Pure-bf16 split GEMM. 512 threads (16 warps, warp grid 4x4, warp tile 32x32),
// BK=64 chunks, 3-stage cp.async pipeline. B fragments loaded pairwise via x4.
// ---------------------------------------------------------------------------
template<int NT, bool BNAT, int EPI, int OUT>
__global__ __launch_bounds__(512) void gemm_bf(
    const uint16_t* __restrict__ Ah, const uint16_t* __restrict__ Al,
    int lda, long long az,
    const uint16_t* __restrict__ Bh, const uint16_t* __restrict__ Bl,
    int ldb, long long bz,
    const float* __restrict__ bias, const float* __restrict__ res,
    float* __restrict__ C, uint16_t* __restrict__ Ch, uint16_t* __restrict__ Cl,
    int ldc, long long cz, int K, float scale)
{
    constexpr int WNC = NT / 4;                // 32
    constexpr int NTL = WNC / 8;               // 4
    constexpr int MT  = 2;
    constexpr int RS  = 72;
    constexpr int ABYTES = 128 * RS * 2;
    constexpr int BRS  = BNAT ? RS : (NT + 8);
    constexpr int BROWS = BNAT ? NT : 64;
    constexpr int BBYTES = BROWS * BRS * 2;
    constexpr int STAGE  = 2 * ABYTES + 2 * BBYTES;
    constexpr int STAGES = 3;

    extern __shared__ __align__(128) char smm[];
    const uint32_t sb = smem_u32(smm);
    const int tid = threadIdx.x, lane = tid & 31, wid = tid >> 5;
    const int wm = wid >> 2, wn = wid & 3;
    const int bm = blockIdx.y * 128, bn = blockIdx.x * NT;

    const uint16_t* Abh = Ah + (size_t)blockIdx.z * az + (size_t)bm * lda;
    const uint16_t* Abl = Al + (size_t)blockIdx.z * az + (size_t)bm * lda;
    const uint16_t* Bbh = Bh + (size_t)blockIdx.z * bz;
    const uint16_t* Bbl = Bl + (size_t)blockIdx.z * bz;

    float acc[MT][NTL][4];
    #pragma unroll
    for (int mt = 0; mt < MT; mt++)
        #pragma unroll
        for (int nt = 0; nt < NTL; nt++)
            #pragma unroll
            for (int r = 0; r < 4; r++) acc[mt][nt][r] = 0.f;

    const int NC = K >> 6;

    auto issue = [&](int c, int s) {
        const uint32_t st = sb + s * STAGE;
        const int k0 = c << 6;
        #pragma unroll
        for (int j = 0; j < 2; j++) {
            int idx = tid + j * 512;
            int row = idx >> 3, seg = idx & 7;
            size_t so = (size_t)row * lda + k0 + seg * 8;
            uint32_t d = st + row * (RS * 2) + seg * 16;
            CP16(d, gptr(Abh + so));
            CP16(d + ABYTES, gptr(Abl + so));
        }
        #pragma unroll
        for (int j = 0; j < 2; j++) {
            int idx = tid + j * 512;
            if (BNAT) {
                int row = idx >> 3, seg = idx & 7;
                size_t so = (size_t)(bn + row) * ldb + k0 + seg * 8;
                uint32_t d = st + 2 * ABYTES + row * (RS * 2) + seg * 16;
                CP16(d, gptr(Bbh + so));
                CP16(d + BBYTES, gptr(Bbl + so));
            } else {
                int row = idx >> 4, seg = idx & 15;
                size_t so = (size_t)(k0 + row) * ldb + bn + seg * 8;
                uint32_t d = st + 2 * ABYTES + row * (BRS * 2) + seg * 16;
                CP16(d, gptr(Bbh + so));
                CP16(d + BBYTES, gptr(Bbl + so));
            }
        }
    };

    #pragma unroll
    for (int s = 0; s < STAGES - 1; s++) {
        if (s < NC) issue(s, s);
        CP_COMMIT();
    }

    for (int c = 0; c < NC; c++) {
        CP_WAIT1();
        __syncthreads();
        {
            int cn = c + STAGES - 1;
            if (cn < NC) issue(cn, cn % STAGES);
            CP_COMMIT();
        }
        const uint32_t abh_ = sb + (c % STAGES) * STAGE;
        const uint32_t abl_ = abh_ + ABYTES;
        const uint32_t bbh_ = abh_ + 2 * ABYTES;
        const uint32_t bbl_ = bbh_ + BBYTES;
        #pragma unroll
        for (int ks = 0; ks < 4; ks++) {
            uint32_t afh[MT][4], afl[MT][4], bfh[NTL][2], bfl[NTL][2];
            #pragma unroll
            for (int mt = 0; mt < MT; mt++) {
                uint32_t off = ((wm * 32 + mt * 16 + (lane & 15)) * RS +
                                ks * 16 + ((lane >> 4) << 3)) << 1;
                LDSM_X4(afh[mt], abh_ + off);
                LDSM_X4(afl[mt], abl_ + off);
            }
            // B fragments: pair two n-tiles per x4 load
            #pragma unroll
            for (int p = 0; p < NTL / 2; p++) {
                uint32_t rh[4], rl[4];
                if (BNAT) {
                    int grp = lane >> 3;
                    int row = wn * WNC + p * 16 + (grp >> 1) * 8 + (lane & 7);
                    int koff = ks * 16 + (grp & 1) * 8;
                    uint32_t off = ((uint32_t)(row * RS + koff)) << 1;
                    LDSM_X4(rh, bbh_ + off);
                    LDSM_X4(rl, bbl_ + off);
                    // m0=(2p,k0) m1=(2p,k8) m2=(2p+1,k0) m3=(2p+1,k8)
                    bfh[2 * p][0] = rh[0]; bfh[2 * p][1] = rh[1];
                    bfh[2 * p + 1][0] = rh[2]; bfh[2 * p + 1][1] = rh[3];
                    bfl[2 * p][0] = rl[0]; bfl[2 * p][1] = rl[1];
                    bfl[2 * p + 1][0] = rl[2]; bfl[2 * p + 1][1] = rl[3];
                } else {
                    int row = ks * 16 + (lane & 15);
                    int col = wn * WNC + p * 16 + ((lane >> 4) << 3);
                    uint32_t off = ((uint32_t)(row * BRS + col)) << 1;
                    LDSM_X4T(rh, bbh_ + off);
                    LDSM_X4T(rl, bbl_ + off);
                    // m0=(n0,k0) m1=(n0,k8) m2=(n1,k0) m3=(n1,k8)
                    bfh[2 * p][0] = rh[0]; bfh[2 * p][1] = rh[1];
                    bfh[2 * p + 1][0] = rh[2]; bfh[2 * p + 1][1] = rh[3];
                    bfl[2 * p][0] = rl[0]; bfl[2 * p][1] = rl[1];
                    bfl[2 * p + 1][0] = rl[2]; bfl[2 * p + 1][1] = rl[3];
                }
            }
            #pragma unroll
            for (int nt = 0; nt < NTL; nt++)
                #pragma unroll
                for (int mt = 0; mt < MT; mt++) {
                    MMA16816(acc[mt][nt], afh[mt], bfh[nt]);
                    MMA16816(acc[mt][nt], afh[mt], bfl[nt]);
                    MMA16816(acc[mt][nt], afl[mt], bfh[nt]);
                }
        }
    }

    const int gid = lane >> 2, tig = lane & 3;
    #pragma unroll
    for (int mt = 0; mt < MT; mt++) {
        #pragma unroll
        for (int nt = 0; nt < NTL; nt++) {
            int r0  = bm + wm * 32 + mt * 16 + gid;
            int col = bn + wn * WNC + nt * 8 + tig * 2;
            float2 v0 = make_float2(acc[mt][nt][0] * scale, acc[mt][nt][1] * scale);
            float2 v1 = make_float2(acc[mt][nt][2] * scale, acc[mt][nt][3] * scale);
            if (EPI >= 1) {
                float2 bb = *reinterpret_cast<const float2*>(&bias[col]);
                v0.x += bb.x; v0.y += bb.y; v1.x += bb.x; v1.y += bb.y;
            }
            if (EPI == 2) {
                v0.x = gelu_f(v0.x); v0.y = gelu_f(v0.y);
                v1.x = gelu_f(v1.x); v1.y = gelu_f(v1.y);
            }
            if (EPI == 3) {
                float2 ra = *reinterpret_cast<const float2*>(
                    &res[(size_t)r0 * ldc + col]);
                float2 rb = *reinterpret_cast<const float2*>(
                    &res[(size_t)(r0 + 8) * ldc + col]);
                v0.x += ra.x; v0.y += ra.y; v1.x += rb.x; v1.y += rb.y;
            }
            size_t o0 = (size_t)r0 * ldc + col + (size_t)blockIdx.z * cz;
            size_t o1 = (size_t)(r0 + 8) * ldc + col + (size_t)blockIdx.z * cz;
            if (OUT & 1) {
                *reinterpret_cast<float2*>(&C[o0]) = v0;
                *reinterpret_cast<float2*>(&C[o1]) = v1;
            }
            if (OUT & 2) {
                float a0 = v0.x, a1 = v0.y, b0 = v1.x, b1 = v1.y;
                if (OUT & 4) {
                    a0 = gelu_f(a0); a1 = gelu_f(a1);
                    b0 = gelu_f(b0); b1 = gelu_f(b1);
                }
                uint32_t h, l;
                split2(a0, a1, h, l);
                *reinterpret_cast<uint32_t*>(&Ch[o0]) = h;
                *reinterpret_cast<uint32_t*>(&Cl[o0]) = l;
                split2(b0, b1, h, l);
                *reinterpret_cast<uint32_t*>(&Ch[o1]) = h;
                *reinterpret_cast<uint32_t*>(&Cl[o1]) = l;
            }
        }
    }
}

// ---------------------------------------------------------------------------
// Fused flash attention v2: 512 threads (16 warps, 4/SMSP). Warp pair
// (wq, wq+8) shares 16 query rows; each half handles 64 of 128 keys.
// Per-tile only the row max is exchanged (smem); partial l and O combine
// exactly once at the end (identical max sequence on both halves).
// ---------------------------------------------------------------------------
__global__ __launch_bounds__(512) void flash_attn(
    const uint16_t* __restrict__ qh, const uint16_t* __restrict__ ql,
    uint16_t* __restrict__ oh, uint16_t* __restrict__ ol)
{
    constexpr int RS = 72;
    constexpr int TB = 128 * RS * 2;      // 18432
    constexpr int KVSTAGE = 4 * TB;
    constexpr int PM_OFF = 2 * TB + 2 * KVSTAGE;
    extern __shared__ __align__(128) char smm[];
    const uint32_t sb  = smem_u32(smm);
    const uint32_t sQh = sb, sQl = sb + TB;
    float* pm = reinterpret_cast<float*>(smm + PM_OFF);   // 256 floats
    const int tid = threadIdx.x, lane = tid & 31, w = tid >> 5;
    const int wq = w & 7, h2 = w >> 3;
    const int q0 = blockIdx.x * 128;
    const int h  = blockIdx.y;
    const int g = lane >> 2, t = lane & 3;

    // Q tile: 128 rows x 8 segs per buffer (1024 segs, 2 per thread)
    #pragma unroll
    for (int j = 0; j < 2; j++) {
        int idx = tid + j * 512;
        int row = idx >> 3, seg = idx & 7;
        size_t so = (size_t)(q0 + row) * QKVW + h * 64 + seg * 8;
        uint32_t d = sb + row * (RS * 2) + seg * 16;
        CP16(d, gptr(qh + so));
        CP16(d + TB, gptr(ql + so));
    }
    auto issueKV = [&](int kt, int s) {
        uint32_t st = sb + 2 * TB + s * KVSTAGE;
        int tok0 = kt * 128;
        #pragma unroll
        for (int j = 0; j < 2; j++) {
            int idx = tid + j * 512;
            int row = idx >> 3, seg = idx & 7;
            size_t soK = (size_t)(tok0 + row) * QKVW + INNER + h * 64 + seg * 8;
            uint32_t dK = st + row * (RS * 2) + seg * 16;
            CP16(dK, gptr(qh + soK));
            CP16(dK + TB, gptr(ql + soK));
            size_t soV = soK + INNER;
            uint32_t dV = st + 2 * TB + row * (RS * 2) + seg * 16;
            CP16(dV, gptr(qh + soV));
            CP16(dV + TB, gptr(ql + soV));
        }
    };
    issueKV(0, 0);
    CP_COMMIT();

    float O[8][4];
    #pragma unroll
    for (int jt = 0; jt < 8; jt++)
        #pragma unroll
        for (int r = 0; r < 4; r++) O[jt][r] = 0.f;
    float m0 = -1e30f, m1 = -1e30f, l0 = 0.f, l1 = 0.f;

    for (int kt = 0; kt < NB / 128; kt++) {
        if (kt + 1 < NB / 128) {
            issueKV(kt + 1, (kt + 1) & 1);
            CP_COMMIT();
            CP_WAIT1();
        } else {
            CP_WAIT0();
        }
        __syncthreads();
        const uint32_t st  = sb + 2 * TB + (kt & 1) * KVSTAGE;
        const uint32_t sKh = st, sKl = st + TB;
        const uint32_t sVh = st + 2 * TB, sVl = st + 3 * TB;

        // ---- S partial: 16 queries x 64 keys (this warp's half)
        float sacc[8][4];
        #pragma unroll
        for (int j = 0; j < 8; j++)
            #pragma unroll
            for (int r = 0; r < 4; r++) sacc[j][r] = 0.f;

        #pragma unroll
        for (int kc = 0; kc < 4; kc++) {
            uint32_t aqh[4], aql[4];
            uint32_t aoff = ((wq * 16 + (lane & 15)) * RS +
                             kc * 16 + ((lane >> 4) << 3)) << 1;
            LDSM_X4(aqh, sQh + aoff);
            LDSM_X4(aql, sQl + aoff);
            #pragma unroll
            for (int jp = 0; jp < 4; jp++) {
                uint32_t rh[4], rl[4];
                uint32_t boff = ((h2 * 64 + jp * 16 + (lane & 15)) * RS +
                                 kc * 16 + ((lane >> 4) << 3)) << 1;
                LDSM_X4(rh, sKh + boff);   // {n0k0, n1k0, n0k8, n1k8}
                LDSM_X4(rl, sKl + boff);
                uint32_t bh0[2] = {rh[0], rh[2]}, bh1[2] = {rh[1], rh[3]};
                uint32_t bl0[2] = {rl[0], rl[2]}, bl1[2] = {rl[1], rl[3]};
                MMA16816(sacc[2 * jp],     aqh, bh0);
                MMA16816(sacc[2 * jp],     aqh, bl0);
                MMA16816(sacc[2 * jp],     aql, bh0);
                MMA16816(sacc[2 * jp + 1], aqh, bh1);
                MMA16816(sacc[2 * jp + 1], aqh, bl1);
                MMA16816(sacc[2 * jp + 1], aql, bh1);
            }
        }

        // ---- partial row max over this half's 64 keys
        float mx0 = -1e30f, mx1 = -1e30f;
        #pragma unroll
        for (int j = 0; j < 8; j++) {
            sacc[j][0] *= 0.125f; sacc[j][1] *= 0.125f;
            sacc[j][2] *= 0.125f; sacc[j][3] *= 0.125f;
            mx0 = fmaxf(mx0, fmaxf(sacc[j][0], sacc[j][1]));
            mx1 = fmaxf(mx1, fmaxf(sacc[j][2], sacc[j][3]));
        }
        mx0 = fmaxf(mx0, __shfl_xor_sync(0xffffffffu, mx0, 1));
        mx0 = fmaxf(mx0, __shfl_xor_sync(0xffffffffu, mx0, 2));
        mx1 = fmaxf(mx1, __shfl_xor_sync(0xffffffffu, mx1, 1));
        mx1 = fmaxf(mx1, __shfl_xor_sync(0xffffffffu, mx1, 2));
        // exchange max with partner half
        if (t == 0) {
            pm[h2 * 128 + wq * 16 + g]     = mx0;
            pm[h2 * 128 + wq * 16 + g + 8] = mx1;
        }
        __syncthreads();
        float ox0 = pm[(1 - h2) * 128 + wq * 16 + g];
        float ox1 = pm[(1 - h2) * 128 + wq * 16 + g + 8];
        float nm0 = fmaxf(m0, fmaxf(mx0, ox0));
        float nm1 = fmaxf(m1, fmaxf(mx1, ox1));
        float a0 = __expf(m0 - nm0), a1 = __expf(m1 - nm1);
        m0 = nm0; m1 = nm1;
        float s0 = 0.f, s1 = 0.f;
        #pragma unroll
        for (int j = 0; j < 8; j++) {
            sacc[j][0] = __expf(sacc[j][0] - m0); s0 += sacc[j][0];
            sacc[j][1] = __expf(sacc[j][1] - m0); s0 += sacc[j][1];
            sacc[j][2] = __expf(sacc[j][2] - m1); s1 += sacc[j][2];
            sacc[j][3] = __expf(sacc[j][3] - m1); s1 += sacc[j][3];
        }
        s0 += __shfl_xor_sync(0xffffffffu, s0, 1);
        s0 += __shfl_xor_sync(0xffffffffu, s0, 2);
        s1 += __shfl_xor_sync(0xffffffffu, s1, 1);
        s1 += __shfl_xor_sync(0xffffffffu, s1, 2);
        l0 = l0 * a0 + s0;       // partial l over this half's keys
        l1 = l1 * a1 + s1;
        #pragma unroll
        for (int jt = 0; jt < 8; jt++) {
            O[jt][0] *= a0; O[jt][1] *= a0;
            O[jt][2] *= a1; O[jt][3] *= a1;
        }

        // ---- O += P @ V over this half's 64 keys
        #pragma unroll
        for (int kc = 0; kc < 4; kc++) {
            uint32_t ah[4], al[4];
            split2(sacc[2 * kc][0],     sacc[2 * kc][1],     ah[0], al[0]);
            split2(sacc[2 * kc][2],     sacc[2 * kc][3],     ah[1], al[1]);
            split2(sacc[2 * kc + 1][0], sacc[2 * kc + 1][1], ah[2], al[2]);
            split2(sacc[2 * kc + 1][2], sacc[2 * kc + 1][3], ah[3], al[3]);
            #pragma unroll
            for (int jp = 0; jp < 4; jp++) {
                uint32_t rh[4], rl[4];
                uint32_t boff = ((h2 * 64 + kc * 16 + (lane & 15)) * RS +
                                 jp * 16 + ((lane >> 4) << 3)) << 1;
                LDSM_X4T(rh, sVh + boff);  // {n0k0, n0k8, n1k0, n1k8}
                LDSM_X4T(rl, sVl + boff);
                uint32_t bh0[2] = {rh[0], rh[1]}, bh1[2] = {rh[2], rh[3]};
                uint32_t bl0[2] = {rl[0], rl[1]}, bl1[2] = {rl[2], rl[3]};
                MMA16816(O[2 * jp],     ah, bh0);
                MMA16816(O[2 * jp],     ah, bl0);
                MMA16816(O[2 * jp],     al, bh0);
                MMA16816(O[2 * jp + 1], ah, bh1);
                MMA16816(O[2 * jp + 1], ah, bl1);
                MMA16816(O[2 * jp + 1], al, bh1);
            }
        }
        __syncthreads();
    }

    // ---- combine halves: h2==1 stages O and l, h2==0 adds + stores
    __syncthreads();
    float* Ost = reinterpret_cast<float*>(smm + 2 * TB);   // alias KV area
    float* lst = Ost + 128 * 66;
    if (h2 == 1) {
        #pragma unroll
        for (int jt = 0; jt < 8; jt++) {
            int c = jt * 8 + t * 2;
            Ost[(wq * 16 + g) * 66 + c]         = O[jt][0];
            Ost[(wq * 16 + g) * 66 + c + 1]     = O[jt][1];
            Ost[(wq * 16 + g + 8) * 66 + c]     = O[jt][2];
            Ost[(wq * 16 + g + 8) * 66 + c + 1] = O[jt][3];
        }
        if (t == 0) {
            lst[wq * 16 + g]     = l0;
            lst[wq * 16 + g + 8] = l1;
        }
    }
    __syncthreads();
    if (h2 == 0) {
        float i0 = 1.f / (l0 + lst[wq * 16 + g]);
        float i1 = 1.f / (l1 + lst[wq * 16 + g + 8]);
        #pragma unroll
        for (int jt = 0; jt < 8; jt++) {
            int c = jt * 8 + t * 2;
            float o00 = O[jt][0] + Ost[(wq * 16 + g) * 66 + c];
            float o01 = O[jt][1] + Ost[(wq * 16 + g) * 66 + c + 1];
            float o10 = O[jt][2] + Ost[(wq * 16 + g + 8) * 66 + c];
            float o11 = O[jt][3] + Ost[(wq * 16 + g + 8) * 66 + c + 1];
            uint32_t hh, ll;
            size_t o0 = (size_t)(q0 + wq * 16 + g) * INNER + h * 64 + c;
            split2(o00 * i0, o01 * i0, hh, ll);
            *reinterpret_cast<uint32_t*>(oh + o0) = hh;
            *reinterpret_cast<uint32_t*>(ol + o0) = ll;
            size_t o1 = o0 + (size_t)8 * INNER;
            split2(o10 * i1, o11 * i1, hh, ll);
            *reinterpret_cast<uint32_t*>(oh + o1) = hh;
            *reinterpret_cast<uint32_t*>(ol + o1) = ll;
        }
    }
}

// ---------------------------------------------------------------------------
// Reductions
// ---------------------------------------------------------------------------
__device__ __forceinline__ float blk_sum256(float v, float* sh) {
    int t = threadIdx.x;
    sh[t] = v; __syncthreads();
    #pragma unroll
    for (int s = 128; s >= 1; s >>= 1) {
        if (t < s) sh[t] += sh[t + s];
        __syncthreads();
    }
    float r = sh[0]; __syncthreads();
    return r;
}
__device__ __forceinline__ float blk_max256(float v, float* sh) {
    int t = threadIdx.x;
    sh[t] = v; __syncthreads();
    #pragma unroll
    for (int s = 128; s >= 1; s >>= 1) {
        if (t < s) sh[t] = fmaxf(sh[t], sh[t + s]);
        __syncthreads();
    }
    float r = sh[0]; __syncthreads();
    return r;
}

// ---------------------------------------------------------------------------
// Elementwise kernels
// ---------------------------------------------------------------------------
__global__ __launch_bounds__(256) void conv_bf(
    const float* __restrict__ x, uint16_t* __restrict__ h,
    uint16_t* __restrict__ l, int n2)
{
    int i = blockIdx.x * 256 + threadIdx.x;
    if (i < n2) {
        float2 v = reinterpret_cast<const float2*>(x)[i];
        uint32_t hh, ll;
        split2(v.x, v.y, hh, ll);
        reinterpret_cast<uint32_t*>(h)[i] = hh;
        reinterpret_cast<uint32_t*>(l)[i] = ll;
    }
}

__global__ __launch_bounds__(256) void embed_kernel(
    const float* __restrict__ expr, const float* __restrict__ xt,
    const float* __restrict__ yt, const int* __restrict__ xi,
    const int* __restrict__ yi, float* __restrict__ out)
{
    int row = blockIdx.x;
    size_t xo = (size_t)xi[row] * SPOT;
    size_t yo = (size_t)yi[row] * SPOT;
    size_t ro = (size_t)row * SPOT;
    for (int j = threadIdx.x; j < SPOT; j += 256)
        out[ro + j] = expr[ro + j] + xt[xo + j] + yt[yo + j];
}

template<int N>
__global__ __launch_bounds__(256) void ln_bf(
    const float* __restrict__ x, const float* __restrict__ g,
    const float* __restrict__ b, uint16_t* __restrict__ oh,
    uint16_t* __restrict__ ol)
{
    __shared__ float sh[256];
    constexpr int NPAIR = N / 2;
    constexpr int NP = (NPAIR + 255) / 256;
    int row = blockIdx.x, tid = threadIdx.x;
    const float2* xr = reinterpret_cast<const float2*>(x + (size_t)row * N);
    float2 v[NP];
    float s = 0.f;
    #pragma unroll
    for (int i = 0; i < NP; i++) {
        int p = i * 256 + tid;
        if (p < NPAIR) { v[i] = xr[p]; s += v[i].x + v[i].y; }
        else v[i] = make_float2(0.f, 0.f);
    }
    s = blk_sum256(s, sh);
    float mean = s / N, ss = 0.f;
    #pragma unroll
    for (int i = 0; i < NP; i++) {
        int p = i * 256 + tid;
        if (p < NPAIR) {
            float dx = v[i].x - mean, dy = v[i].y - mean;
            ss += dx * dx + dy * dy;
        }
    }
    ss = blk_sum256(ss, sh);
    float rstd = rsqrtf(ss / N + 1e-5f);
    uint32_t* OH = reinterpret_cast<uint32_t*>(oh + (size_t)row * N);
    uint32_t* OL = reinterpret_cast<uint32_t*>(ol + (size_t)row * N);
    #pragma unroll
    for (int i = 0; i < NP; i++) {
        int p = i * 256 + tid;
        if (p < NPAIR) {
            float2 gg = reinterpret_cast<const float2*>(g)[p];
            float2 bb = reinterpret_cast<const float2*>(b)[p];
            float y0 = (v[i].x - mean) * rstd * gg.x + bb.x;
            float y1 = (v[i].y - mean) * rstd * gg.y + bb.y;
            uint32_t h, l;
            split2(y0, y1, h, l);
            OH[p] = h; OL[p] = l;
        }
    }
}

__global__ __launch_bounds__(256) void softmax_rows(float* __restrict__ x)
{
    __shared__ float sh[256];
    size_t row = blockIdx.x;
    int tid = threadIdx.x;
    float* r = x + row * NB;
    float v[8];
    float mx = -1e30f;
    #pragma unroll
    for (int i = 0; i < 8; i++) { v[i] = r[i * 256 + tid]; mx = fmaxf(mx, v[i]); }
    mx = blk_max256(mx, sh);
    float s = 0.f;
    #pragma unroll
    for (int i = 0; i < 8; i++) { v[i] = __expf(v[i] - mx); s += v[i]; }
    s = blk_sum256(s, sh);
    float inv = 1.f / s;
    #pragma unroll
    for (int i = 0; i < 8; i++) r[i * 256 + tid] = v[i] * inv;
}

__global__ __launch_bounds__(256) void pack_bf(
    const uint16_t* __restrict__ ih, const uint16_t* __restrict__ il,
    const uint16_t* __restrict__ eh, const uint16_t* __restrict__ el,
    uint16_t* __restrict__ ch, uint16_t* __restrict__ cl)
{
    int row = blockIdx.x, tid = threadIdx.x;
    const uint32_t* IH = reinterpret_cast<const uint32_t*>(ih + (size_t)row * PROJ);
    const uint32_t* IL = reinterpret_cast<const uint32_t*>(il + (size_t)row * PROJ);
    const uint32_t* EH = reinterpret_cast<const uint32_t*>(eh + (size_t)row * PROJ);
    const uint32_t* EL = reinterpret_cast<const uint32_t*>(el + (size_t)row * PROJ);
    uint32_t vh, vl;
    if (tid < 128) { vh = IH[tid]; vl = IL[tid]; }
    else           { vh = EH[tid - 128]; vl = EL[tid - 128]; }
    reinterpret_cast<uint32_t*>(ch + (size_t)row * 2 * PROJ)[tid] = vh;
    reinterpret_cast<uint32_t*>(cl + (size_t)row * 2 * PROJ)[tid] = vl;
}

__global__ __launch_bounds__(256) void rowloss_kernel(
    const float* __restrict__ logits, const float* __restrict__ tgt,
    float* __restrict__ rowp)
{
    __shared__ float sh[256];
    int row = blockIdx.x, tid = threadIdx.x;
    const float* lr = logits + (size_t)row * NB;
    const float* tr = tgt    + (size_t)row * NB;
    float lv[8], tv[8];
    float mx = -1e30f;
    #pragma unroll
    for (int i = 0; i < 8; i++) {
        lv[i] = lr[i * 256 + tid];
        tv[i] = tr[i * 256 + tid];
        mx = fmaxf(mx, lv[i]);
    }
    mx = blk_max256(mx, sh);
    float se = 0.f, dot = 0.f;
    #pragma unroll
    for (int i = 0; i < 8; i++) { se += __expf(lv[i] - mx); dot += tv[i] * lv[i]; }
    se  = blk_sum256(se, sh);
    dot = blk_sum256(dot, sh);
    if (tid == 0) rowp[row] = 0.5f * (mx + logf(se) - dot);
}

__global__ __launch_bounds__(256) void colloss_kernel(
    const float* __restrict__ logits, const float* __restrict__ tgt,
    float* __restrict__ colp)
{
    __shared__ float smx[256], sse[256], sts[256], stdot[256];
    int tid = threadIdx.x;
    int c = blockIdx.x * 64 + (tid & 63);
    int ry = tid >> 6;
    float mx = -1e30f, se = 0.f, ts = 0.f, td = 0.f;
    for (int r = ry; r < NB; r += 4) {
        float l = logits[(size_t)r * NB + c];
        float t = tgt   [(size_t)r * NB + c];
        if (l > mx) { se = se * __expf(mx - l) + 1.f; mx = l; }
        else        { se += __expf(l - mx); }
        ts += t;
        td += t * l;
    }
    smx[tid] = mx; sse[tid] = se; sts[tid] = ts; stdot[tid] = td;
    __syncthreads();
    if (ry == 0) {
        #pragma unroll
        for (int k = 1; k < 4; k++) {
            int o = tid + k * 64;
            float m2 = smx[o], s2 = sse[o];
            float m = fmaxf(mx, m2);
            se = se * __expf(mx - m) + s2 * __expf(m2 - m);
            mx = m;
            ts += sts[o];
            td += stdot[o];
        }
        colp[c] = 0.5f * (ts * (mx + logf(se)) - td);
    }
}

__global__ __launch_bounds__(256) void final_reduce(
    const float* __restrict__ a, const float* __restrict__ b,
    float* __restrict__ out)
{
    __shared__ float sh[256];
    int tid = threadIdx.x;
    float s = 0.f;
    for (int i = tid; i < NB; i += 256) s += a[i] + b[i];
    s = blk_sum256(s, sh);
    if (tid == 0) out[0] = s * (1.0f / NB);
}

// ---------------------------------------------------------------------------
// Host launch
// ---------------------------------------------------------------------------
namespace {
constexpr int SMEM_STD = 3 * (2 * 128 * 72 * 2 + 2 * 64 * 136 * 2);   // 215040
constexpr int SMEM_NAT = 3 * (2 * 128 * 72 * 2 + 2 * 128 * 72 * 2);   // 221184
constexpr int SMEM_FLASH = 2 * (128 * 72 * 2) + 2 * 4 * (128 * 72 * 2)
                         + 256 * 4;                                    // 185344
}

#define SYM(var, sym) cudaGetSymbolAddress((void**)&var, sym)

extern "C" void kernel_launch(void* const* d_in, const int* in_sizes, int n_in,
                              void* d_out, int out_size)
{
    (void)in_sizes; (void)n_in; (void)out_size;
    const float* image_features = (const float*)d_in[0];
    const float* expression     = (const float*)d_in[1];
    const float* x_table        = (const float*)d_in[2];
    const float* y_table        = (const float*)d_in[3];
    const float* ln1_g          = (const float*)d_in[4];
    const float* ln1_b          = (const float*)d_in[5];
    const float* w_qkv          = (const float*)d_in[6];
    const float* w_o            = (const float*)d_in[7];
    const float* b_o            = (const float*)d_in[8];
    const float* ln2_g          = (const float*)d_in[9];
    const float* ln2_b          = (const float*)d_in[10];
    const float* w1             = (const float*)d_in[11];
    const float* b1             = (const float*)d_in[12];
    const float* w2             = (const float*)d_in[13];
    const float* b2             = (const float*)d_in[14];
    const float* img_proj_w     = (const float*)d_in[15];
    const float* img_proj_b     = (const float*)d_in[16];
    const float* img_fc_w       = (const float*)d_in[17];
    const float* img_fc_b       = (const float*)d_in[18];
    const float* img_ln_g       = (const float*)d_in[19];
    const float* img_ln_b       = (const float*)d_in[20];
    const float* spot_proj_w    = (const float*)d_in[21];
    const float* spot_proj_b    = (const float*)d_in[22];
    const float* spot_fc_w      = (const float*)d_in[23];
    const float* spot_fc_b      = (const float*)d_in[24];
    const float* spot_ln_g      = (const float*)d_in[25];
    const float* spot_ln_b      = (const float*)d_in[26];
    const int*   x_idx          = (const int*)d_in[27];
    const int*   y_idx          = (const int*)d_in[28];
    float* out = (float*)d_out;

    float *spot, *tmp, *pimg, *pspot, *logits, *tgt, *rowp, *colp;
    SYM(spot, g_spot); SYM(tmp, g_tmp);
    SYM(pimg, g_pimg); SYM(pspot, g_pspot);
    SYM(logits, g_logits); SYM(tgt, g_tgt); SYM(rowp, g_rowp); SYM(colp, g_colp);

    uint16_t *hbh, *hbl, *qkh, *qkl, *ath, *atl, *mph, *mpl;
    uint16_t *eih, *eil, *esh, *esl, *pgh, *pgl, *cth, *ctl, *ifh, *ifl;
    SYM(hbh, g_hbuf_h); SYM(hbl, g_hbuf_l);
    SYM(qkh, g_qkv_h);  SYM(qkl, g_qkv_l);
    SYM(ath, g_attn_h); SYM(atl, g_attn_l);
    SYM(mph, g_mlp_h);  SYM(mpl, g_mlp_l);
    SYM(eih, g_eimg_h); SYM(eil, g_eimg_l);
    SYM(esh, g_espot_h); SYM(esl, g_espot_l);
    SYM(pgh, g_pg_h);   SYM(pgl, g_pg_l);
    SYM(cth, g_cat_h);  SYM(ctl, g_cat_l);
    SYM(ifh, g_imgf_h); SYM(ifl, g_imgf_l);

    uint16_t *wqh, *wql, *woh, *wol, *w1h, *w1l, *w2h, *w2l;
    uint16_t *iph, *ipl, *ifch, *ifcl, *sph, *spl, *sfh, *sfl;
    SYM(wqh, g_wqkv_h); SYM(wql, g_wqkv_l);
    SYM(woh, g_wo_h);   SYM(wol, g_wo_l);
    SYM(w1h, g_w1_h);   SYM(w1l, g_w1_l);
    SYM(w2h, g_w2_h);   SYM(w2l, g_w2_l);
    SYM(iph, g_wip_h);  SYM(ipl, g_wip_l);
    SYM(ifch, g_wif_h); SYM(ifcl, g_wif_l);
    SYM(sph, g_wsp_h);  SYM(spl, g_wsp_l);
    SYM(sfh, g_wsf_h);  SYM(sfl, g_wsf_l);

    auto kQKV  = gemm_bf<128, false, 0, 2>;
    auto kSqk  = gemm_bf<128, true,  0, 1>;
    auto kRes  = gemm_bf<128, false, 3, 1>;
    auto kResO = gemm_bf<128, false, 3, 3>;
    auto kMlp1 = gemm_bf<128, false, 2, 2>;
    auto kProj = gemm_bf<128, false, 1, 7>;
    cudaFuncSetAttribute(kQKV,  cudaFuncAttributeMaxDynamicSharedMemorySize, SMEM_STD);
    cudaFuncSetAttribute(kSqk,  cudaFuncAttributeMaxDynamicSharedMemorySize, SMEM_NAT);
    cudaFuncSetAttribute(kRes,  cudaFuncAttributeMaxDynamicSharedMemorySize, SMEM_STD);
    cudaFuncSetAttribute(kResO, cudaFuncAttributeMaxDynamicSharedMemorySize, SMEM_STD);
    cudaFuncSetAttribute(kMlp1, cudaFuncAttributeMaxDynamicSharedMemorySize, SMEM_STD);
    cudaFuncSetAttribute(kProj, cudaFuncAttributeMaxDynamicSharedMemorySize, SMEM_STD);
    cudaFuncSetAttribute(flash_attn,
                         cudaFuncAttributeMaxDynamicSharedMemorySize, SMEM_FLASH);

    auto CONV = [&](const float* src, uint16_t* h, uint16_t* l, int n) {
        conv_bf<<<(n / 2 + 255) / 256, 256>>>(src, h, l, n / 2);
    };
    CONV(w_qkv, wqh, wql, NL * SPOT * QKVW);
    CONV(w_o,   woh, wol, NL * INNER * SPOT);
    CONV(w1,    w1h, w1l, NL * SPOT * MLPD);
    CONV(w2,    w2h, w2l, NL * MLPD * SPOT);
    CONV(img_proj_w, iph, ipl, IMG * PROJ);
    CONV(img_fc_w, ifch, ifcl, PROJ * PROJ);
    CONV(spot_proj_w, sph, spl, SPOT * PROJ);
    CONV(spot_fc_w, sfh, sfl, PROJ * PROJ);
    CONV(image_features, ifh, ifl, NB * IMG);

    embed_kernel<<<NB, 256>>>(expression, x_table, y_table, x_idx, y_idx, spot);

    for (int l = 0; l < NL; l++) {
        uint16_t* wqh_l = wqh + (size_t)l * SPOT * QKVW;
        uint16_t* wql_l = wql + (size_t)l * SPOT * QKVW;
        uint16_t* woh_l = woh + (size_t)l * INNER * SPOT;
        uint16_t* wol_l = wol + (size_t)l * INNER * SPOT;
        uint16_t* w1h_l = w1h + (size_t)l * SPOT * MLPD;
        uint16_t* w1l_l = w1l + (size_t)l * SPOT * MLPD;
        uint16_t* w2h_l = w2h + (size_t)l * MLPD * SPOT;
        uint16_t* w2l_l = w2l + (size_t)l * MLPD * SPOT;

        ln_bf<SPOT><<<NB, 256>>>(spot, ln1_g + l * SPOT, ln1_b + l * SPOT, hbh, hbl);
        kQKV<<<dim3(QKVW / 128, NB / 128, 1), 512, SMEM_STD>>>(
            hbh, hbl, SPOT, 0, wqh_l, wql_l, QKVW, 0, nullptr, nullptr,
            nullptr, qkh, qkl, QKVW, 0, SPOT, 1.f);
        flash_attn<<<dim3(NB / 128, NH), 512, SMEM_FLASH>>>(qkh, qkl, ath, atl);
        kRes<<<dim3(SPOT / 128, NB / 128, 1), 512, SMEM_STD>>>(
            ath, atl, INNER, 0, woh_l, wol_l, SPOT, 0,
            b_o + l * SPOT, spot, spot, nullptr, nullptr, SPOT, 0, INNER, 1.f);
        ln_bf<SPOT><<<NB, 256>>>(spot, ln2_g + l * SPOT, ln2_b + l * SPOT, hbh, hbl);
        kMlp1<<<dim3(MLPD / 128, NB / 128, 1), 512, SMEM_STD>>>(
            hbh, hbl, SPOT, 0, w1h_l, w1l_l, MLPD, 0,
            b1 + l * MLPD, nullptr, nullptr, mph, mpl, MLPD, 0, SPOT, 1.f);
        if (l == NL - 1) {
            kResO<<<dim3(SPOT / 128, NB / 128, 1), 512, SMEM_STD>>>(
                mph, mpl, MLPD, 0, w2h_l, w2l_l, SPOT, 0,
                b2 + l * SPOT, spot, spot, hbh, hbl, SPOT, 0, MLPD, 1.f);
        } else {
            kRes<<<dim3(SPOT / 128, NB / 128, 1), 512, SMEM_STD>>>(
                mph, mpl, MLPD, 0, w2h_l, w2l_l, SPOT, 0,
                b2 + l * SPOT, spot, spot, nullptr, nullptr, SPOT, 0, MLPD, 1.f);
        }
    }

    kProj<<<dim3(PROJ / 128, NB / 128, 1), 512, SMEM_STD>>>(
        ifh, ifl, IMG, 0, iph, ipl, PROJ, 0,
        img_proj_b, nullptr, pimg, pgh, pgl, PROJ, 0, IMG, 1.f);
    kRes<<<dim3(PROJ / 128, NB / 128, 1), 512, SMEM_STD>>>(
        pgh, pgl, PROJ, 0, ifch, ifcl, PROJ, 0,
        img_fc_b, pimg, tmp, nullptr, nullptr, PROJ, 0, PROJ, 1.f);
    ln_bf<PROJ><<<NB, 256>>>(tmp, img_ln_g, img_ln_b, eih, eil);

    kProj<<<dim3(PROJ / 128, NB / 128, 1), 512, SMEM_STD>>>(
        hbh, hbl, SPOT, 0, sph, spl, PROJ, 0,
        spot_proj_b, nullptr, pspot, pgh, pgl, PROJ, 0, SPOT, 1.f);
    kRes<<<dim3(PROJ / 128, NB / 128, 1), 512, SMEM_STD>>>(
        pgh, pgl, PROJ, 0, sfh, sfl, PROJ, 0,
        spot_fc_b, pspot, tmp, nullptr, nullptr, PROJ, 0, PROJ, 1.f);
    ln_bf<PROJ><<<NB, 256>>>(tmp, spot_ln_g, spot_ln_b, esh, esl);

    pack_bf<<<NB, 256>>>(eih, eil, esh, esl, cth, ctl);
    kSqk<<<dim3(NB / 128, NB / 128, 1), 512, SMEM_NAT>>>(
        esh, esl, PROJ, 0, eih, eil, PROJ, 0,
        nullptr, nullptr, logits, nullptr, nullptr, NB, 0, PROJ, 1.f);
    kSqk<<<dim3(NB / 128, NB / 128, 1), 512, SMEM_NAT>>>(
        cth, ctl, 2 * PROJ, 0, cth, ctl, 2 * PROJ, 0,
        nullptr, nullptr, tgt, nullptr, nullptr, NB, 0, 2 * PROJ, 0.5f);
    softmax_rows<<<NB, 256>>>(tgt);
    rowloss_kernel<<<NB, 256>>>(logits, tgt, rowp);
    colloss_kernel<<<NB / 64, 256>>>(logits, tgt, colp);
    final_reduce<<<1, 256>>>(rowp, colp, out);
}

// round 10
// speedup vs baseline: 1.3588x; 1.0502x over previous
#include <cuda_runtime.h>
#include <cstdint>

// ---------------------------------------------------------------------------
// Problem constants
// ---------------------------------------------------------------------------
namespace {
constexpr int NB   = 2048;
constexpr int SPOT = 1024;
constexpr int IMG  = 1024;
constexpr int PROJ = 256;
constexpr int NH   = 8;
constexpr int DH   = 64;
constexpr int INNER = 512;
constexpr int MLPD = 2048;
constexpr int QKVW = 1536;
constexpr int NL   = 2;
}

// ---------------------------------------------------------------------------
// Scratch: fp32
// ---------------------------------------------------------------------------
__device__ float g_spot  [NB * SPOT];
__device__ float g_tmp   [NB * SPOT];
__device__ float g_pimg  [NB * PROJ];
__device__ float g_pspot [NB * PROJ];
__device__ float g_logits[NB * NB];
__device__ float g_tgt   [NB * NB];
__device__ float g_rowp  [NB];
__device__ float g_colp  [NB];

// ---------------------------------------------------------------------------
// Scratch: bf16 hi/lo
// ---------------------------------------------------------------------------
__device__ uint16_t g_hbuf_h[NB * SPOT],  g_hbuf_l[NB * SPOT];
__device__ uint16_t g_qkv_h [NB * QKVW],  g_qkv_l [NB * QKVW];
__device__ uint16_t g_attn_h[NB * INNER], g_attn_l[NB * INNER];
__device__ uint16_t g_mlp_h [NB * MLPD],  g_mlp_l [NB * MLPD];
__device__ uint16_t g_eimg_h [NB * PROJ], g_eimg_l [NB * PROJ];
__device__ uint16_t g_espot_h[NB * PROJ], g_espot_l[NB * PROJ];
__device__ uint16_t g_pg_h   [NB * PROJ], g_pg_l   [NB * PROJ];
__device__ uint16_t g_cat_h[NB * 2 * PROJ], g_cat_l[NB * 2 * PROJ];
__device__ uint16_t g_imgf_h[NB * IMG], g_imgf_l[NB * IMG];
// weights bf16
__device__ uint16_t g_wqkv_h[NL * SPOT * QKVW], g_wqkv_l[NL * SPOT * QKVW];
__device__ uint16_t g_wo_h  [NL * INNER * SPOT], g_wo_l [NL * INNER * SPOT];
__device__ uint16_t g_w1_h  [NL * SPOT * MLPD],  g_w1_l [NL * SPOT * MLPD];
__device__ uint16_t g_w2_h  [NL * MLPD * SPOT],  g_w2_l [NL * MLPD * SPOT];
__device__ uint16_t g_wip_h [IMG * PROJ],  g_wip_l[IMG * PROJ];
__device__ uint16_t g_wif_h [PROJ * PROJ], g_wif_l[PROJ * PROJ];
__device__ uint16_t g_wsp_h [SPOT * PROJ], g_wsp_l[SPOT * PROJ];
__device__ uint16_t g_wsf_h [PROJ * PROJ], g_wsf_l[PROJ * PROJ];

// ---------------------------------------------------------------------------
// Helpers
// ---------------------------------------------------------------------------
__device__ __forceinline__ uint32_t smem_u32(const void* p) {
    uint32_t a;
    asm("{ .reg .u64 t; cvta.to.shared.u64 t, %1; cvt.u32.u64 %0, t; }"
        : "=r"(a) : "l"(p));
    return a;
}
__device__ __forceinline__ unsigned long long gptr(const void* p) {
    return (unsigned long long)__cvta_generic_to_global(p);
}
__device__ __forceinline__ float gelu_f(float x) {
    return 0.5f * x * (1.0f + erff(x * 0.7071067811865475f));
}
__device__ __forceinline__ void split2(float f0, float f1, uint32_t& hi, uint32_t& lo) {
    asm("cvt.rn.bf16x2.f32 %0, %1, %2;" : "=r"(hi) : "f"(f1), "f"(f0));
    float h0 = __uint_as_float(hi << 16);
    float h1 = __uint_as_float(hi & 0xFFFF0000u);
    float l0 = f0 - h0, l1 = f1 - h1;
    asm("cvt.rn.bf16x2.f32 %0, %1, %2;" : "=r"(lo) : "f"(l1), "f"(l0));
}

#define CP16(dst, src) \
    asm volatile("cp.async.cg.shared.global [%0], [%1], 16;" :: "r"(dst), "l"(src))
#define CP_COMMIT() asm volatile("cp.async.commit_group;" ::: "memory")
#define CP_WAIT1()  asm volatile("cp.async.wait_group 1;" ::: "memory")
#define CP_WAIT0()  asm volatile("cp.async.wait_group 0;" ::: "memory")

#define LDSM_X4(r, a)                                                          \
    asm volatile("ldmatrix.sync.aligned.m8n8.x4.shared.b16 {%0,%1,%2,%3}, [%4];" \
        : "=r"((r)[0]), "=r"((r)[1]), "=r"((r)[2]), "=r"((r)[3]) : "r"(a))
#define LDSM_X4T(r, a)                                                         \
    asm volatile("ldmatrix.sync.aligned.m8n8.x4.trans.shared.b16 {%0,%1,%2,%3}, [%4];" \
        : "=r"((r)[0]), "=r"((r)[1]), "=r"((r)[2]), "=r"((r)[3]) : "r"(a))
#define MMA16816(d, a, b)                                                      \
    asm volatile("mma.sync.aligned.m16n8k16.row.col.f32.bf16.bf16.f32 "        \
        "{%0,%1,%2,%3}, {%4,%5,%6,%7}, {%8,%9}, {%0,%1,%2,%3};"                \
        : "+f"((d)[0]), "+f"((d)[1]), "+f"((d)[2]), "+f"((d)[3])               \
        : "r"((a)[0]), "r"((a)[1]), "r"((a)[2]), "r"((a)[3]),                  \
          "r"((b)[0]), "r"((b)[1]))

// ---------------------------------------------------------------------------
// Pure-bf16 split GEMM. 512 threads (16 warps, warp grid 4x4), NT in {64,128},
// BK=64 chunks, 3-stage cp.async pipeline. B fragments loaded pairwise via x4.
// ---------------------------------------------------------------------------
template<int NT, bool BNAT, int EPI, int OUT>
__global__ __launch_bounds__(512) void gemm_bf(
    const uint16_t* __restrict__ Ah, const uint16_t* __restrict__ Al,
    int lda, long long az,
    const uint16_t* __restrict__ Bh, const uint16_t* __restrict__ Bl,
    int ldb, long long bz,
    const float* __restrict__ bias, const float* __restrict__ res,
    float* __restrict__ C, uint16_t* __restrict__ Ch, uint16_t* __restrict__ Cl,
    int ldc, long long cz, int K, float scale)
{
    constexpr int WNC = NT / 4;                // 32 or 16
    constexpr int NTL = WNC / 8;               // 4 or 2
    constexpr int MT  = 2;
    constexpr int RS  = 72;
    constexpr int ABYTES = 128 * RS * 2;
    constexpr int BRS  = BNAT ? RS : (NT + 8);
    constexpr int BROWS = BNAT ? NT : 64;
    constexpr int BBYTES = BROWS * BRS * 2;
    constexpr int STAGE  = 2 * ABYTES + 2 * BBYTES;
    constexpr int STAGES = 3;
    constexpr int BSEGROW = NT / 8;
    constexpr int BSEGS = BNAT ? NT * 8 : 64 * BSEGROW;
    constexpr int BIT = (BSEGS + 511) / 512;

    extern __shared__ __align__(128) char smm[];
    const uint32_t sb = smem_u32(smm);
    const int tid = threadIdx.x, lane = tid & 31, wid = tid >> 5;
    const int wm = wid >> 2, wn = wid & 3;
    const int bm = blockIdx.y * 128, bn = blockIdx.x * NT;

    const uint16_t* Abh = Ah + (size_t)blockIdx.z * az + (size_t)bm * lda;
    const uint16_t* Abl = Al + (size_t)blockIdx.z * az + (size_t)bm * lda;
    const uint16_t* Bbh = Bh + (size_t)blockIdx.z * bz;
    const uint16_t* Bbl = Bl + (size_t)blockIdx.z * bz;

    float acc[MT][NTL][4];
    #pragma unroll
    for (int mt = 0; mt < MT; mt++)
        #pragma unroll
        for (int nt = 0; nt < NTL; nt++)
            #pragma unroll
            for (int r = 0; r < 4; r++) acc[mt][nt][r] = 0.f;

    const int NC = K >> 6;

    auto issue = [&](int c, int s) {
        const uint32_t st = sb + s * STAGE;
        const int k0 = c << 6;
        #pragma unroll
        for (int j = 0; j < 2; j++) {
            int idx = tid + j * 512;
            int row = idx >> 3, seg = idx & 7;
            size_t so = (size_t)row * lda + k0 + seg * 8;
            uint32_t d = st + row * (RS * 2) + seg * 16;
            CP16(d, gptr(Abh + so));
            CP16(d + ABYTES, gptr(Abl + so));
        }
        #pragma unroll
        for (int j = 0; j < BIT; j++) {
            int idx = tid + j * 512;
            if (BSEGS >= 512 * (j + 1) || idx < BSEGS) {
                if (BNAT) {
                    int row = idx >> 3, seg = idx & 7;
                    size_t so = (size_t)(bn + row) * ldb + k0 + seg * 8;
                    uint32_t d = st + 2 * ABYTES + row * (RS * 2) + seg * 16;
                    CP16(d, gptr(Bbh + so));
                    CP16(d + BBYTES, gptr(Bbl + so));
                } else {
                    int row = idx / BSEGROW, seg = idx % BSEGROW;
                    size_t so = (size_t)(k0 + row) * ldb + bn + seg * 8;
                    uint32_t d = st + 2 * ABYTES + row * (BRS * 2) + seg * 16;
                    CP16(d, gptr(Bbh + so));
                    CP16(d + BBYTES, gptr(Bbl + so));
                }
            }
        }
    };

    #pragma unroll
    for (int s = 0; s < STAGES - 1; s++) {
        if (s < NC) issue(s, s);
        CP_COMMIT();
    }

    for (int c = 0; c < NC; c++) {
        CP_WAIT1();
        __syncthreads();
        {
            int cn = c + STAGES - 1;
            if (cn < NC) issue(cn, cn % STAGES);
            CP_COMMIT();
        }
        const uint32_t abh_ = sb + (c % STAGES) * STAGE;
        const uint32_t abl_ = abh_ + ABYTES;
        const uint32_t bbh_ = abh_ + 2 * ABYTES;
        const uint32_t bbl_ = bbh_ + BBYTES;
        #pragma unroll
        for (int ks = 0; ks < 4; ks++) {
            uint32_t afh[MT][4], afl[MT][4], bfh[NTL][2], bfl[NTL][2];
            #pragma unroll
            for (int mt = 0; mt < MT; mt++) {
                uint32_t off = ((wm * 32 + mt * 16 + (lane & 15)) * RS +
                                ks * 16 + ((lane >> 4) << 3)) << 1;
                LDSM_X4(afh[mt], abh_ + off);
                LDSM_X4(afl[mt], abl_ + off);
            }
            #pragma unroll
            for (int p = 0; p < NTL / 2; p++) {
                uint32_t rh[4], rl[4];
                if (BNAT) {
                    int grp = lane >> 3;
                    int row = wn * WNC + p * 16 + (grp >> 1) * 8 + (lane & 7);
                    int koff = ks * 16 + (grp & 1) * 8;
                    uint32_t off = ((uint32_t)(row * RS + koff)) << 1;
                    LDSM_X4(rh, bbh_ + off);
                    LDSM_X4(rl, bbl_ + off);
                    bfh[2 * p][0] = rh[0]; bfh[2 * p][1] = rh[1];
                    bfh[2 * p + 1][0] = rh[2]; bfh[2 * p + 1][1] = rh[3];
                    bfl[2 * p][0] = rl[0]; bfl[2 * p][1] = rl[1];
                    bfl[2 * p + 1][0] = rl[2]; bfl[2 * p + 1][1] = rl[3];
                } else {
                    int row = ks * 16 + (lane & 15);
                    int col = wn * WNC + p * 16 + ((lane >> 4) << 3);
                    uint32_t off = ((uint32_t)(row * BRS + col)) << 1;
                    LDSM_X4T(rh, bbh_ + off);
                    LDSM_X4T(rl, bbl_ + off);
                    bfh[2 * p][0] = rh[0]; bfh[2 * p][1] = rh[1];
                    bfh[2 * p + 1][0] = rh[2]; bfh[2 * p + 1][1] = rh[3];
                    bfl[2 * p][0] = rl[0]; bfl[2 * p][1] = rl[1];
                    bfl[2 * p + 1][0] = rl[2]; bfl[2 * p + 1][1] = rl[3];
                }
            }
            #pragma unroll
            for (int nt = 0; nt < NTL; nt++)
                #pragma unroll
                for (int mt = 0; mt < MT; mt++) {
                    MMA16816(acc[mt][nt], afh[mt], bfh[nt]);
                    MMA16816(acc[mt][nt], afh[mt], bfl[nt]);
                    MMA16816(acc[mt][nt], afl[mt], bfh[nt]);
                }
        }
    }

    const int gid = lane >> 2, tig = lane & 3;
    #pragma unroll
    for (int mt = 0; mt < MT; mt++) {
        #pragma unroll
        for (int nt = 0; nt < NTL; nt++) {
            int r0  = bm + wm * 32 + mt * 16 + gid;
            int col = bn + wn * WNC + nt * 8 + tig * 2;
            float2 v0 = make_float2(acc[mt][nt][0] * scale, acc[mt][nt][1] * scale);
            float2 v1 = make_float2(acc[mt][nt][2] * scale, acc[mt][nt][3] * scale);
            if (EPI >= 1) {
                float2 bb = *reinterpret_cast<const float2*>(&bias[col]);
                v0.x += bb.x; v0.y += bb.y; v1.x += bb.x; v1.y += bb.y;
            }
            if (EPI == 2) {
                v0.x = gelu_f(v0.x); v0.y = gelu_f(v0.y);
                v1.x = gelu_f(v1.x); v1.y = gelu_f(v1.y);
            }
            if (EPI == 3) {
                float2 ra = *reinterpret_cast<const float2*>(
                    &res[(size_t)r0 * ldc + col]);
                float2 rb = *reinterpret_cast<const float2*>(
                    &res[(size_t)(r0 + 8) * ldc + col]);
                v0.x += ra.x; v0.y += ra.y; v1.x += rb.x; v1.y += rb.y;
            }
            size_t o0 = (size_t)r0 * ldc + col + (size_t)blockIdx.z * cz;
            size_t o1 = (size_t)(r0 + 8) * ldc + col + (size_t)blockIdx.z * cz;
            if (OUT & 1) {
                *reinterpret_cast<float2*>(&C[o0]) = v0;
                *reinterpret_cast<float2*>(&C[o1]) = v1;
            }
            if (OUT & 2) {
                float a0 = v0.x, a1 = v0.y, b0 = v1.x, b1 = v1.y;
                if (OUT & 4) {
                    a0 = gelu_f(a0); a1 = gelu_f(a1);
                    b0 = gelu_f(b0); b1 = gelu_f(b1);
                }
                uint32_t h, l;
                split2(a0, a1, h, l);
                *reinterpret_cast<uint32_t*>(&Ch[o0]) = h;
                *reinterpret_cast<uint32_t*>(&Cl[o0]) = l;
                split2(b0, b1, h, l);
                *reinterpret_cast<uint32_t*>(&Ch[o1]) = h;
                *reinterpret_cast<uint32_t*>(&Cl[o1]) = l;
            }
        }
    }
}

// ---------------------------------------------------------------------------
// Fused flash attention v3: 512 threads; warp pair splits 128 keys.
// 2 syncthreads per KV tile (double-buffered pm; issue moved after sync).
// ---------------------------------------------------------------------------
__global__ __launch_bounds__(512) void flash_attn(
    const uint16_t* __restrict__ qh, const uint16_t* __restrict__ ql,
    uint16_t* __restrict__ oh, uint16_t* __restrict__ ol)
{
    constexpr int RS = 72;
    constexpr int TB = 128 * RS * 2;
    constexpr int KVSTAGE = 4 * TB;
    constexpr int PM_OFF = 2 * TB + 2 * KVSTAGE;
    extern __shared__ __align__(128) char smm[];
    const uint32_t sb  = smem_u32(smm);
    const uint32_t sQh = sb, sQl = sb + TB;
    float* pm = reinterpret_cast<float*>(smm + PM_OFF);   // 2 x 256 floats
    const int tid = threadIdx.x, lane = tid & 31, w = tid >> 5;
    const int wq = w & 7, h2 = w >> 3;
    const int q0 = blockIdx.x * 128;
    const int h  = blockIdx.y;
    const int g = lane >> 2, t = lane & 3;

    #pragma unroll
    for (int j = 0; j < 2; j++) {
        int idx = tid + j * 512;
        int row = idx >> 3, seg = idx & 7;
        size_t so = (size_t)(q0 + row) * QKVW + h * 64 + seg * 8;
        uint32_t d = sb + row * (RS * 2) + seg * 16;
        CP16(d, gptr(qh + so));
        CP16(d + TB, gptr(ql + so));
    }
    auto issueKV = [&](int kt, int s) {
        uint32_t st = sb + 2 * TB + s * KVSTAGE;
        int tok0 = kt * 128;
        #pragma unroll
        for (int j = 0; j < 2; j++) {
            int idx = tid + j * 512;
            int row = idx >> 3, seg = idx & 7;
            size_t soK = (size_t)(tok0 + row) * QKVW + INNER + h * 64 + seg * 8;
            uint32_t dK = st + row * (RS * 2) + seg * 16;
            CP16(dK, gptr(qh + soK));
            CP16(dK + TB, gptr(ql + soK));
            size_t soV = soK + INNER;
            uint32_t dV = st + 2 * TB + row * (RS * 2) + seg * 16;
            CP16(dV, gptr(qh + soV));
            CP16(dV + TB, gptr(ql + soV));
        }
    };
    issueKV(0, 0);
    CP_COMMIT();

    float O[8][4];
    #pragma unroll
    for (int jt = 0; jt < 8; jt++)
        #pragma unroll
        for (int r = 0; r < 4; r++) O[jt][r] = 0.f;
    float m0 = -1e30f, m1 = -1e30f, l0 = 0.f, l1 = 0.f;

    for (int kt = 0; kt < NB / 128; kt++) {
        CP_WAIT0();
        __syncthreads();
        if (kt + 1 < NB / 128) {
            issueKV(kt + 1, (kt + 1) & 1);
            CP_COMMIT();
        }
        const uint32_t st  = sb + 2 * TB + (kt & 1) * KVSTAGE;
        const uint32_t sKh = st, sKl = st + TB;
        const uint32_t sVh = st + 2 * TB, sVl = st + 3 * TB;

        float sacc[8][4];
        #pragma unroll
        for (int j = 0; j < 8; j++)
            #pragma unroll
            for (int r = 0; r < 4; r++) sacc[j][r] = 0.f;

        #pragma unroll
        for (int kc = 0; kc < 4; kc++) {
            uint32_t aqh[4], aql[4];
            uint32_t aoff = ((wq * 16 + (lane & 15)) * RS +
                             kc * 16 + ((lane >> 4) << 3)) << 1;
            LDSM_X4(aqh, sQh + aoff);
            LDSM_X4(aql, sQl + aoff);
            #pragma unroll
            for (int jp = 0; jp < 4; jp++) {
                uint32_t rh[4], rl[4];
                uint32_t boff = ((h2 * 64 + jp * 16 + (lane & 15)) * RS +
                                 kc * 16 + ((lane >> 4) << 3)) << 1;
                LDSM_X4(rh, sKh + boff);
                LDSM_X4(rl, sKl + boff);
                uint32_t bh0[2] = {rh[0], rh[2]}, bh1[2] = {rh[1], rh[3]};
                uint32_t bl0[2] = {rl[0], rl[2]}, bl1[2] = {rl[1], rl[3]};
                MMA16816(sacc[2 * jp],     aqh, bh0);
                MMA16816(sacc[2 * jp],     aqh, bl0);
                MMA16816(sacc[2 * jp],     aql, bh0);
                MMA16816(sacc[2 * jp + 1], aqh, bh1);
                MMA16816(sacc[2 * jp + 1], aqh, bl1);
                MMA16816(sacc[2 * jp + 1], aql, bh1);
            }
        }

        float mx0 = -1e30f, mx1 = -1e30f;
        #pragma unroll
        for (int j = 0; j < 8; j++) {
            sacc[j][0] *= 0.125f; sacc[j][1] *= 0.125f;
            sacc[j][2] *= 0.125f; sacc[j][3] *= 0.125f;
            mx0 = fmaxf(mx0, fmaxf(sacc[j][0], sacc[j][1]));
            mx1 = fmaxf(mx1, fmaxf(sacc[j][2], sacc[j][3]));
        }
        mx0 = fmaxf(mx0, __shfl_xor_sync(0xffffffffu, mx0, 1));
        mx0 = fmaxf(mx0, __shfl_xor_sync(0xffffffffu, mx0, 2));
        mx1 = fmaxf(mx1, __shfl_xor_sync(0xffffffffu, mx1, 1));
        mx1 = fmaxf(mx1, __shfl_xor_sync(0xffffffffu, mx1, 2));
        float* pmc = pm + (kt & 1) * 256;
        if (t == 0) {
            pmc[h2 * 128 + wq * 16 + g]     = mx0;
            pmc[h2 * 128 + wq * 16 + g + 8] = mx1;
        }
        __syncthreads();
        float ox0 = pmc[(1 - h2) * 128 + wq * 16 + g];
        float ox1 = pmc[(1 - h2) * 128 + wq * 16 + g + 8];
        float nm0 = fmaxf(m0, fmaxf(mx0, ox0));
        float nm1 = fmaxf(m1, fmaxf(mx1, ox1));
        float a0 = __expf(m0 - nm0), a1 = __expf(m1 - nm1);
        m0 = nm0; m1 = nm1;
        float s0 = 0.f, s1 = 0.f;
        #pragma unroll
        for (int j = 0; j < 8; j++) {
            sacc[j][0] = __expf(sacc[j][0] - m0); s0 += sacc[j][0];
            sacc[j][1] = __expf(sacc[j][1] - m0); s0 += sacc[j][1];
            sacc[j][2] = __expf(sacc[j][2] - m1); s1 += sacc[j][2];
            sacc[j][3] = __expf(sacc[j][3] - m1); s1 += sacc[j][3];
        }
        s0 += __shfl_xor_sync(0xffffffffu, s0, 1);
        s0 += __shfl_xor_sync(0xffffffffu, s0, 2);
        s1 += __shfl_xor_sync(0xffffffffu, s1, 1);
        s1 += __shfl_xor_sync(0xffffffffu, s1, 2);
        l0 = l0 * a0 + s0;
        l1 = l1 * a1 + s1;
        #pragma unroll
        for (int jt = 0; jt < 8; jt++) {
            O[jt][0] *= a0; O[jt][1] *= a0;
            O[jt][2] *= a1; O[jt][3] *= a1;
        }

        #pragma unroll
        for (int kc = 0; kc < 4; kc++) {
            uint32_t ah[4], al[4];
            split2(sacc[2 * kc][0],     sacc[2 * kc][1],     ah[0], al[0]);
            split2(sacc[2 * kc][2],     sacc[2 * kc][3],     ah[1], al[1]);
            split2(sacc[2 * kc + 1][0], sacc[2 * kc + 1][1], ah[2], al[2]);
            split2(sacc[2 * kc + 1][2], sacc[2 * kc + 1][3], ah[3], al[3]);
            #pragma unroll
            for (int jp = 0; jp < 4; jp++) {
                uint32_t rh[4], rl[4];
                uint32_t boff = ((h2 * 64 + kc * 16 + (lane & 15)) * RS +
                                 jp * 16 + ((lane >> 4) << 3)) << 1;
                LDSM_X4T(rh, sVh + boff);
                LDSM_X4T(rl, sVl + boff);
                uint32_t bh0[2] = {rh[0], rh[1]}, bh1[2] = {rh[2], rh[3]};
                uint32_t bl0[2] = {rl[0], rl[1]}, bl1[2] = {rl[2], rl[3]};
                MMA16816(O[2 * jp],     ah, bh0);
                MMA16816(O[2 * jp],     ah, bl0);
                MMA16816(O[2 * jp],     al, bh0);
                MMA16816(O[2 * jp + 1], ah, bh1);
                MMA16816(O[2 * jp + 1], ah, bl1);
                MMA16816(O[2 * jp + 1], al, bh1);
            }
        }
    }

    // combine halves
    __syncthreads();
    float* Ost = reinterpret_cast<float*>(smm + 2 * TB);
    float* lst = Ost + 128 * 66;
    if (h2 == 1) {
        #pragma unroll
        for (int jt = 0; jt < 8; jt++) {
            int c = jt * 8 + t * 2;
            Ost[(wq * 16 + g) * 66 + c]         = O[jt][0];
            Ost[(wq * 16 + g) * 66 + c + 1]     = O[jt][1];
            Ost[(wq * 16 + g + 8) * 66 + c]     = O[jt][2];
            Ost[(wq * 16 + g + 8) * 66 + c + 1] = O[jt][3];
        }
        if (t == 0) {
            lst[wq * 16 + g]     = l0;
            lst[wq * 16 + g + 8] = l1;
        }
    }
    __syncthreads();
    if (h2 == 0) {
        float i0 = 1.f / (l0 + lst[wq * 16 + g]);
        float i1 = 1.f / (l1 + lst[wq * 16 + g + 8]);
        #pragma unroll
        for (int jt = 0; jt < 8; jt++) {
            int c = jt * 8 + t * 2;
            float o00 = O[jt][0] + Ost[(wq * 16 + g) * 66 + c];
            float o01 = O[jt][1] + Ost[(wq * 16 + g) * 66 + c + 1];
            float o10 = O[jt][2] + Ost[(wq * 16 + g + 8) * 66 + c];
            float o11 = O[jt][3] + Ost[(wq * 16 + g + 8) * 66 + c + 1];
            uint32_t hh, ll;
            size_t o0 = (size_t)(q0 + wq * 16 + g) * INNER + h * 64 + c;
            split2(o00 * i0, o01 * i0, hh, ll);
            *reinterpret_cast<uint32_t*>(oh + o0) = hh;
            *reinterpret_cast<uint32_t*>(ol + o0) = ll;
            size_t o1 = o0 + (size_t)8 * INNER;
            split2(o10 * i1, o11 * i1, hh, ll);
            *reinterpret_cast<uint32_t*>(oh + o1) = hh;
            *reinterpret_cast<uint32_t*>(ol + o1) = ll;
        }
    }
}

// ---------------------------------------------------------------------------
// Reductions
// ---------------------------------------------------------------------------
__device__ __forceinline__ float blk_sum256(float v, float* sh) {
    int t = threadIdx.x;
    sh[t] = v; __syncthreads();
    #pragma unroll
    for (int s = 128; s >= 1; s >>= 1) {
        if (t < s) sh[t] += sh[t + s];
        __syncthreads();
    }
    float r = sh[0]; __syncthreads();
    return r;
}
__device__ __forceinline__ float blk_max256(float v, float* sh) {
    int t = threadIdx.x;
    sh[t] = v; __syncthreads();
    #pragma unroll
    for (int s = 128; s >= 1; s >>= 1) {
        if (t < s) sh[t] = fmaxf(sh[t], sh[t + s]);
        __syncthreads();
    }
    float r = sh[0]; __syncthreads();
    return r;
}

// ---------------------------------------------------------------------------
// Elementwise kernels
// ---------------------------------------------------------------------------
__global__ __launch_bounds__(256) void conv_bf(
    const float* __restrict__ x, uint16_t* __restrict__ h,
    uint16_t* __restrict__ l, int n8)
{
    int i = blockIdx.x * 256 + threadIdx.x;
    if (i < n8) {
        const float4* x4 = reinterpret_cast<const float4*>(x);
        float4 a = x4[2 * i], b = x4[2 * i + 1];
        uint32_t h0, h1, h2, h3, l0, l1, l2, l3;
        split2(a.x, a.y, h0, l0);
        split2(a.z, a.w, h1, l1);
        split2(b.x, b.y, h2, l2);
        split2(b.z, b.w, h3, l3);
        reinterpret_cast<uint4*>(h)[i] = make_uint4(h0, h1, h2, h3);
        reinterpret_cast<uint4*>(l)[i] = make_uint4(l0, l1, l2, l3);
    }
}

__global__ __launch_bounds__(256) void embed_kernel(
    const float* __restrict__ expr, const float* __restrict__ xt,
    const float* __restrict__ yt, const int* __restrict__ xi,
    const int* __restrict__ yi, float* __restrict__ out)
{
    int row = blockIdx.x;
    size_t xo = (size_t)xi[row] * SPOT;
    size_t yo = (size_t)yi[row] * SPOT;
    size_t ro = (size_t)row * SPOT;
    for (int j = threadIdx.x; j < SPOT; j += 256)
        out[ro + j] = expr[ro + j] + xt[xo + j] + yt[yo + j];
}

template<int N>
__global__ __launch_bounds__(256) void ln_bf(
    const float* __restrict__ x, const float* __restrict__ g,
    const float* __restrict__ b, uint16_t* __restrict__ oh,
    uint16_t* __restrict__ ol)
{
    __shared__ float sh[256];
    constexpr int NPAIR = N / 2;
    constexpr int NP = (NPAIR + 255) / 256;
    int row = blockIdx.x, tid = threadIdx.x;
    const float2* xr = reinterpret_cast<const float2*>(x + (size_t)row * N);
    float2 v[NP];
    float s = 0.f;
    #pragma unroll
    for (int i = 0; i < NP; i++) {
        int p = i * 256 + tid;
        if (p < NPAIR) { v[i] = xr[p]; s += v[i].x + v[i].y; }
        else v[i] = make_float2(0.f, 0.f);
    }
    s = blk_sum256(s, sh);
    float mean = s / N, ss = 0.f;
    #pragma unroll
    for (int i = 0; i < NP; i++) {
        int p = i * 256 + tid;
        if (p < NPAIR) {
            float dx = v[i].x - mean, dy = v[i].y - mean;
            ss += dx * dx + dy * dy;
        }
    }
    ss = blk_sum256(ss, sh);
    float rstd = rsqrtf(ss / N + 1e-5f);
    uint32_t* OH = reinterpret_cast<uint32_t*>(oh + (size_t)row * N);
    uint32_t* OL = reinterpret_cast<uint32_t*>(ol + (size_t)row * N);
    #pragma unroll
    for (int i = 0; i < NP; i++) {
        int p = i * 256 + tid;
        if (p < NPAIR) {
            float2 gg = reinterpret_cast<const float2*>(g)[p];
            float2 bb = reinterpret_cast<const float2*>(b)[p];
            float y0 = (v[i].x - mean) * rstd * gg.x + bb.x;
            float y1 = (v[i].y - mean) * rstd * gg.y + bb.y;
            uint32_t h, l;
            split2(y0, y1, h, l);
            OH[p] = h; OL[p] = l;
        }
    }
}

// Fused: softmax(tgt row) in place + rowp = 0.5*(LSE(logits) - sum t*l)
__global__ __launch_bounds__(256) void softmax_rowloss(
    float* __restrict__ tgt, const float* __restrict__ logits,
    float* __restrict__ rowp)
{
    __shared__ float sh[256];
    size_t row = blockIdx.x;
    int tid = threadIdx.x;
    float* tr = tgt + row * NB;
    const float* lr = logits + row * NB;
    float tv[8], lv[8];
    float mt = -1e30f, ml = -1e30f;
    #pragma unroll
    for (int i = 0; i < 8; i++) {
        tv[i] = tr[i * 256 + tid];
        lv[i] = lr[i * 256 + tid];
        mt = fmaxf(mt, tv[i]);
        ml = fmaxf(ml, lv[i]);
    }
    mt = blk_max256(mt, sh);
    float st = 0.f;
    #pragma unroll
    for (int i = 0; i < 8; i++) { tv[i] = __expf(tv[i] - mt); st += tv[i]; }
    st = blk_sum256(st, sh);
    float inv = 1.f / st;
    ml = blk_max256(ml, sh);
    float se = 0.f, dot = 0.f;
    #pragma unroll
    for (int i = 0; i < 8; i++) {
        tv[i] *= inv;
        tr[i * 256 + tid] = tv[i];
        se += __expf(lv[i] - ml);
        dot += tv[i] * lv[i];
    }
    se  = blk_sum256(se, sh);
    dot = blk_sum256(dot, sh);
    if (tid == 0) rowp[row] = 0.5f * (ml + logf(se) - dot);
}

__global__ __launch_bounds__(256) void pack_bf(
    const uint16_t* __restrict__ ih, const uint16_t* __restrict__ il,
    const uint16_t* __restrict__ eh, const uint16_t* __restrict__ el,
    uint16_t* __restrict__ ch, uint16_t* __restrict__ cl)
{
    int row = blockIdx.x, tid = threadIdx.x;
    const uint32_t* IH = reinterpret_cast<const uint32_t*>(ih + (size_t)row * PROJ);
    const uint32_t* IL = reinterpret_cast<const uint32_t*>(il + (size_t)row * PROJ);
    const uint32_t* EH = reinterpret_cast<const uint32_t*>(eh + (size_t)row * PROJ);
    const uint32_t* EL = reinterpret_cast<const uint32_t*>(el + (size_t)row * PROJ);
    uint32_t vh, vl;
    if (tid < 128) { vh = IH[tid]; vl = IL[tid]; }
    else           { vh = EH[tid - 128]; vl = EL[tid - 128]; }
    reinterpret_cast<uint32_t*>(ch + (size_t)row * 2 * PROJ)[tid] = vh;
    reinterpret_cast<uint32_t*>(cl + (size_t)row * 2 * PROJ)[tid] = vl;
}

__global__ __launch_bounds__(256) void colloss_kernel(
    const float* __restrict__ logits, const float* __restrict__ tgt,
    float* __restrict__ colp)
{
    __shared__ float smx[256], sse[256], sts[256], stdot[256];
    int tid = threadIdx.x;
    int c = blockIdx.x * 64 + (tid & 63);
    int ry = tid >> 6;
    float mx = -1e30f, se = 0.f, ts = 0.f, td = 0.f;
    for (int r = ry; r < NB; r += 4) {
        float l = logits[(size_t)r * NB + c];
        float t = tgt   [(size_t)r * NB + c];
        if (l > mx) { se = se * __expf(mx - l) + 1.f; mx = l; }
        else        { se += __expf(l - mx); }
        ts += t;
        td += t * l;
    }
    smx[tid] = mx; sse[tid] = se; sts[tid] = ts; stdot[tid] = td;
    __syncthreads();
    if (ry == 0) {
        #pragma unroll
        for (int k = 1; k < 4; k++) {
            int o = tid + k * 64;
            float m2 = smx[o], s2 = sse[o];
            float m = fmaxf(mx, m2);
            se = se * __expf(mx - m) + s2 * __expf(m2 - m);
            mx = m;
            ts += sts[o];
            td += stdot[o];
        }
        colp[c] = 0.5f * (ts * (mx + logf(se)) - td);
    }
}

__global__ __launch_bounds__(256) void final_reduce(
    const float* __restrict__ a, const float* __restrict__ b,
    float* __restrict__ out)
{
    __shared__ float sh[256];
    int tid = threadIdx.x;
    float s = 0.f;
    for (int i = tid; i < NB; i += 256) s += a[i] + b[i];
    s = blk_sum256(s, sh);
    if (tid == 0) out[0] = s * (1.0f / NB);
}

// ---------------------------------------------------------------------------
// Host launch
// ---------------------------------------------------------------------------
namespace {
constexpr int SMEM_STD = 3 * (2 * 128 * 72 * 2 + 2 * 64 * 136 * 2);   // 215040
constexpr int SMEM_NAT = 3 * (2 * 128 * 72 * 2 + 2 * 128 * 72 * 2);   // 221184
constexpr int SMEM_64  = 3 * (2 * 128 * 72 * 2 + 2 * 64 * 72 * 2);    // 165888
constexpr int SMEM_FLASH = 2 * (128 * 72 * 2) + 2 * 4 * (128 * 72 * 2)
                         + 2 * 256 * 4;                                // 186368
}

#define SYM(var, sym) cudaGetSymbolAddress((void**)&var, sym)

extern "C" void kernel_launch(void* const* d_in, const int* in_sizes, int n_in,
                              void* d_out, int out_size)
{
    (void)in_sizes; (void)n_in; (void)out_size;
    const float* image_features = (const float*)d_in[0];
    const float* expression     = (const float*)d_in[1];
    const float* x_table        = (const float*)d_in[2];
    const float* y_table        = (const float*)d_in[3];
    const float* ln1_g          = (const float*)d_in[4];
    const float* ln1_b          = (const float*)d_in[5];
    const float* w_qkv          = (const float*)d_in[6];
    const float* w_o            = (const float*)d_in[7];
    const float* b_o            = (const float*)d_in[8];
    const float* ln2_g          = (const float*)d_in[9];
    const float* ln2_b          = (const float*)d_in[10];
    const float* w1             = (const float*)d_in[11];
    const float* b1             = (const float*)d_in[12];
    const float* w2             = (const float*)d_in[13];
    const float* b2             = (const float*)d_in[14];
    const float* img_proj_w     = (const float*)d_in[15];
    const float* img_proj_b     = (const float*)d_in[16];
    const float* img_fc_w       = (const float*)d_in[17];
    const float* img_fc_b       = (const float*)d_in[18];
    const float* img_ln_g       = (const float*)d_in[19];
    const float* img_ln_b       = (const float*)d_in[20];
    const float* spot_proj_w    = (const float*)d_in[21];
    const float* spot_proj_b    = (const float*)d_in[22];
    const float* spot_fc_w      = (const float*)d_in[23];
    const float* spot_fc_b      = (const float*)d_in[24];
    const float* spot_ln_g      = (const float*)d_in[25];
    const float* spot_ln_b      = (const float*)d_in[26];
    const int*   x_idx          = (const int*)d_in[27];
    const int*   y_idx          = (const int*)d_in[28];
    float* out = (float*)d_out;

    float *spot, *tmp, *pimg, *pspot, *logits, *tgt, *rowp, *colp;
    SYM(spot, g_spot); SYM(tmp, g_tmp);
    SYM(pimg, g_pimg); SYM(pspot, g_pspot);
    SYM(logits, g_logits); SYM(tgt, g_tgt); SYM(rowp, g_rowp); SYM(colp, g_colp);

    uint16_t *hbh, *hbl, *qkh, *qkl, *ath, *atl, *mph, *mpl;
    uint16_t *eih, *eil, *esh, *esl, *pgh, *pgl, *cth, *ctl, *ifh, *ifl;
    SYM(hbh, g_hbuf_h); SYM(hbl, g_hbuf_l);
    SYM(qkh, g_qkv_h);  SYM(qkl, g_qkv_l);
    SYM(ath, g_attn_h); SYM(atl, g_attn_l);
    SYM(mph, g_mlp_h);  SYM(mpl, g_mlp_l);
    SYM(eih, g_eimg_h); SYM(eil, g_eimg_l);
    SYM(esh, g_espot_h); SYM(esl, g_espot_l);
    SYM(pgh, g_pg_h);   SYM(pgl, g_pg_l);
    SYM(cth, g_cat_h);  SYM(ctl, g_cat_l);
    SYM(ifh, g_imgf_h); SYM(ifl, g_imgf_l);

    uint16_t *wqh, *wql, *woh, *wol, *w1h, *w1l, *w2h, *w2l;
    uint16_t *iph, *ipl, *ifch, *ifcl, *sph, *spl, *sfh, *sfl;
    SYM(wqh, g_wqkv_h); SYM(wql, g_wqkv_l);
    SYM(woh, g_wo_h);   SYM(wol, g_wo_l);
    SYM(w1h, g_w1_h);   SYM(w1l, g_w1_l);
    SYM(w2h, g_w2_h);   SYM(w2l, g_w2_l);
    SYM(iph, g_wip_h);  SYM(ipl, g_wip_l);
    SYM(ifch, g_wif_h); SYM(ifcl, g_wif_l);
    SYM(sph, g_wsp_h);  SYM(spl, g_wsp_l);
    SYM(sfh, g_wsf_h);  SYM(sfl, g_wsf_l);

    auto kQKV  = gemm_bf<128, false, 0, 2>;
    auto kSqk  = gemm_bf<128, true,  0, 1>;
    auto kRes  = gemm_bf<128, false, 3, 1>;
    auto kResO = gemm_bf<128, false, 3, 3>;
    auto kMlp1 = gemm_bf<128, false, 2, 2>;
    auto kProj = gemm_bf<64,  false, 1, 7>;    // NT=64: 64 CTAs
    auto kResP = gemm_bf<64,  false, 3, 1>;    // NT=64: 64 CTAs
    cudaFuncSetAttribute(kQKV,  cudaFuncAttributeMaxDynamicSharedMemorySize, SMEM_STD);
    cudaFuncSetAttribute(kSqk,  cudaFuncAttributeMaxDynamicSharedMemorySize, SMEM_NAT);
    cudaFuncSetAttribute(kRes,  cudaFuncAttributeMaxDynamicSharedMemorySize, SMEM_STD);
    cudaFuncSetAttribute(kResO, cudaFuncAttributeMaxDynamicSharedMemorySize, SMEM_STD);
    cudaFuncSetAttribute(kMlp1, cudaFuncAttributeMaxDynamicSharedMemorySize, SMEM_STD);
    cudaFuncSetAttribute(kProj, cudaFuncAttributeMaxDynamicSharedMemorySize, SMEM_64);
    cudaFuncSetAttribute(kResP, cudaFuncAttributeMaxDynamicSharedMemorySize, SMEM_64);
    cudaFuncSetAttribute(flash_attn,
                         cudaFuncAttributeMaxDynamicSharedMemorySize, SMEM_FLASH);

    auto CONV = [&](const float* src, uint16_t* h, uint16_t* l, int n) {
        int n8 = n / 8;
        conv_bf<<<(n8 + 255) / 256, 256>>>(src, h, l, n8);
    };
    CONV(w_qkv, wqh, wql, NL * SPOT * QKVW);
    CONV(w_o,   woh, wol, NL * INNER * SPOT);
    CONV(w1,    w1h, w1l, NL * SPOT * MLPD);
    CONV(w2,    w2h, w2l, NL * MLPD * SPOT);
    CONV(img_proj_w, iph, ipl, IMG * PROJ);
    CONV(img_fc_w, ifch, ifcl, PROJ * PROJ);
    CONV(spot_proj_w, sph, spl, SPOT * PROJ);
    CONV(spot_fc_w, sfh, sfl, PROJ * PROJ);
    CONV(image_features, ifh, ifl, NB * IMG);

    embed_kernel<<<NB, 256>>>(expression, x_table, y_table, x_idx, y_idx, spot);

    for (int l = 0; l < NL; l++) {
        uint16_t* wqh_l = wqh + (size_t)l * SPOT * QKVW;
        uint16_t* wql_l = wql + (size_t)l * SPOT * QKVW;
        uint16_t* woh_l = woh + (size_t)l * INNER * SPOT;
        uint16_t* wol_l = wol + (size_t)l * INNER * SPOT;
        uint16_t* w1h_l = w1h + (size_t)l * SPOT * MLPD;
        uint16_t* w1l_l = w1l + (size_t)l * SPOT * MLPD;
        uint16_t* w2h_l = w2h + (size_t)l * MLPD * SPOT;
        uint16_t* w2l_l = w2l + (size_t)l * MLPD * SPOT;

        ln_bf<SPOT><<<NB, 256>>>(spot, ln1_g + l * SPOT, ln1_b + l * SPOT, hbh, hbl);
        kQKV<<<dim3(QKVW / 128, NB / 128, 1), 512, SMEM_STD>>>(
            hbh, hbl, SPOT, 0, wqh_l, wql_l, QKVW, 0, nullptr, nullptr,
            nullptr, qkh, qkl, QKVW, 0, SPOT, 1.f);
        flash_attn<<<dim3(NB / 128, NH), 512, SMEM_FLASH>>>(qkh, qkl, ath, atl);
        kRes<<<dim3(SPOT / 128, NB / 128, 1), 512, SMEM_STD>>>(
            ath, atl, INNER, 0, woh_l, wol_l, SPOT, 0,
            b_o + l * SPOT, spot, spot, nullptr, nullptr, SPOT, 0, INNER, 1.f);
        ln_bf<SPOT><<<NB, 256>>>(spot, ln2_g + l * SPOT, ln2_b + l * SPOT, hbh, hbl);
        kMlp1<<<dim3(MLPD / 128, NB / 128, 1), 512, SMEM_STD>>>(
            hbh, hbl, SPOT, 0, w1h_l, w1l_l, MLPD, 0,
            b1 + l * MLPD, nullptr, nullptr, mph, mpl, MLPD, 0, SPOT, 1.f);
        if (l == NL - 1) {
            kResO<<<dim3(SPOT / 128, NB / 128, 1), 512, SMEM_STD>>>(
                mph, mpl, MLPD, 0, w2h_l, w2l_l, SPOT, 0,
                b2 + l * SPOT, spot, spot, hbh, hbl, SPOT, 0, MLPD, 1.f);
        } else {
            kRes<<<dim3(SPOT / 128, NB / 128, 1), 512, SMEM_STD>>>(
                mph, mpl, MLPD, 0, w2h_l, w2l_l, SPOT, 0,
                b2 + l * SPOT, spot, spot, nullptr, nullptr, SPOT, 0, MLPD, 1.f);
        }
    }

    kProj<<<dim3(PROJ / 64, NB / 128, 1), 512, SMEM_64>>>(
        ifh, ifl, IMG, 0, iph, ipl, PROJ, 0,
        img_proj_b, nullptr, pimg, pgh, pgl, PROJ, 0, IMG, 1.f);
    kResP<<<dim3(PROJ / 64, NB / 128, 1), 512, SMEM_64>>>(
        pgh, pgl, PROJ, 0, ifch, ifcl, PROJ, 0,
        img_fc_b, pimg, tmp, nullptr, nullptr, PROJ, 0, PROJ, 1.f);
    ln_bf<PROJ><<<NB, 256>>>(tmp, img_ln_g, img_ln_b, eih, eil);

    kProj<<<dim3(PROJ / 64, NB / 128, 1), 512, SMEM_64>>>(
        hbh, hbl, SPOT, 0, sph, spl, PROJ, 0,
        spot_proj_b, nullptr, pspot, pgh, pgl, PROJ, 0, SPOT, 1.f);
    kResP<<<dim3(PROJ / 64, NB / 128, 1), 512, SMEM_64>>>(
        pgh, pgl, PROJ, 0, sfh, sfl, PROJ, 0,
        spot_fc_b, pspot, tmp, nullptr, nullptr, PROJ, 0, PROJ, 1.f);
    ln_bf<PROJ><<<NB, 256>>>(tmp, spot_ln_g, spot_ln_b, esh, esl);

    pack_bf<<<NB, 256>>>(eih, eil, esh, esl, cth, ctl);
    kSqk<<<dim3(NB / 128, NB / 128, 1), 512, SMEM_NAT>>>(
        esh, esl, PROJ, 0, eih, eil, PROJ, 0,
        nullptr, nullptr, logits, nullptr, nullptr, NB, 0, PROJ, 1.f);
    kSqk<<<dim3(NB / 128, NB / 128, 1), 512, SMEM_NAT>>>(
        cth, ctl, 2 * PROJ, 0, cth, ctl, 2 * PROJ, 0,
        nullptr, nullptr, tgt, nullptr, nullptr, NB, 0, 2 * PROJ, 0.5f);
    softmax_rowloss<<<NB, 256>>>(tgt, logits, rowp);
    colloss_kernel<<<NB / 64, 256>>>(logits, tgt, colp);
    final_reduce<<<1, 256>>>(rowp, colp, out);
}

// round 11
// speedup vs baseline: 1.4098x; 1.0376x over previous
#include <cuda_runtime.h>
#include <cstdint>

// ---------------------------------------------------------------------------
// Problem constants
// ---------------------------------------------------------------------------
namespace {
constexpr int NB   = 2048;
constexpr int SPOT = 1024;
constexpr int IMG  = 1024;
constexpr int PROJ = 256;
constexpr int NH   = 8;
constexpr int DH   = 64;
constexpr int INNER = 512;
constexpr int MLPD = 2048;
constexpr int QKVW = 1536;
constexpr int NL   = 2;
}

// ---------------------------------------------------------------------------
// Scratch: fp32
// ---------------------------------------------------------------------------
__device__ float g_spot  [NB * SPOT];
__device__ float g_pp    [2 * NB * PROJ];      // proj fp32 (img, spot)
__device__ float g_tmp2  [2 * NB * PROJ];      // pre-LN fp32 (img, spot)
__device__ float g_logits[NB * NB];
__device__ float g_tgt   [NB * NB];
__device__ float g_rowp  [NB];
__device__ float g_colp  [NB];
__device__ float g_pb    [2 * PROJ];           // proj biases (img, spot)
__device__ float g_pfb   [2 * PROJ];           // fc biases
__device__ float g_lng   [2 * PROJ];           // ln gains
__device__ float g_lnb   [2 * PROJ];           // ln biases

// ---------------------------------------------------------------------------
// Scratch: bf16 hi/lo
// ---------------------------------------------------------------------------
__device__ uint16_t g_hbuf_h[NB * SPOT],  g_hbuf_l[NB * SPOT];
__device__ uint16_t g_qkv_h [NB * QKVW],  g_qkv_l [NB * QKVW];
__device__ uint16_t g_attn_h[NB * INNER], g_attn_l[NB * INNER];
__device__ uint16_t g_mlp_h [NB * MLPD],  g_mlp_l [NB * MLPD];
__device__ uint16_t g_pin_h[2 * NB * 1024], g_pin_l[2 * NB * 1024]; // head A
__device__ uint16_t g_pg_h [2 * NB * PROJ], g_pg_l [2 * NB * PROJ]; // gelu(p)
__device__ uint16_t g_e_h  [2 * NB * PROJ], g_e_l  [2 * NB * PROJ]; // embeds
__device__ uint16_t g_cat_h[NB * 2 * PROJ], g_cat_l[NB * 2 * PROJ];
// weights bf16
__device__ uint16_t g_wqkv_h[NL * SPOT * QKVW], g_wqkv_l[NL * SPOT * QKVW];
__device__ uint16_t g_wo_h  [NL * INNER * SPOT], g_wo_l [NL * INNER * SPOT];
__device__ uint16_t g_w1_h  [NL * SPOT * MLPD],  g_w1_l [NL * SPOT * MLPD];
__device__ uint16_t g_w2_h  [NL * MLPD * SPOT],  g_w2_l [NL * MLPD * SPOT];
__device__ uint16_t g_pw_h [2 * 1024 * PROJ], g_pw_l [2 * 1024 * PROJ];
__device__ uint16_t g_pfw_h[2 * PROJ * PROJ], g_pfw_l[2 * PROJ * PROJ];

// ---------------------------------------------------------------------------
// Helpers
// ---------------------------------------------------------------------------
__device__ __forceinline__ uint32_t smem_u32(const void* p) {
    uint32_t a;
    asm("{ .reg .u64 t; cvta.to.shared.u64 t, %1; cvt.u32.u64 %0, t; }"
        : "=r"(a) : "l"(p));
    return a;
}
__device__ __forceinline__ unsigned long long gptr(const void* p) {
    return (unsigned long long)__cvta_generic_to_global(p);
}
__device__ __forceinline__ float gelu_f(float x) {
    return 0.5f * x * (1.0f + erff(x * 0.7071067811865475f));
}
__device__ __forceinline__ void split2(float f0, float f1, uint32_t& hi, uint32_t& lo) {
    asm("cvt.rn.bf16x2.f32 %0, %1, %2;" : "=r"(hi) : "f"(f1), "f"(f0));
    float h0 = __uint_as_float(hi << 16);
    float h1 = __uint_as_float(hi & 0xFFFF0000u);
    float l0 = f0 - h0, l1 = f1 - h1;
    asm("cvt.rn.bf16x2.f32 %0, %1, %2;" : "=r"(lo) : "f"(l1), "f"(l0));
}

#define CP16(dst, src) \
    asm volatile("cp.async.cg.shared.global [%0], [%1], 16;" :: "r"(dst), "l"(src))
#define CP_COMMIT() asm volatile("cp.async.commit_group;" ::: "memory")
#define CP_WAIT1()  asm volatile("cp.async.wait_group 1;" ::: "memory")
#define CP_WAIT0()  asm volatile("cp.async.wait_group 0;" ::: "memory")

#define LDSM_X4(r, a)                                                          \
    asm volatile("ldmatrix.sync.aligned.m8n8.x4.shared.b16 {%0,%1,%2,%3}, [%4];" \
        : "=r"((r)[0]), "=r"((r)[1]), "=r"((r)[2]), "=r"((r)[3]) : "r"(a))
#define LDSM_X4T(r, a)                                                         \
    asm volatile("ldmatrix.sync.aligned.m8n8.x4.trans.shared.b16 {%0,%1,%2,%3}, [%4];" \
        : "=r"((r)[0]), "=r"((r)[1]), "=r"((r)[2]), "=r"((r)[3]) : "r"(a))
#define MMA16816(d, a, b)                                                      \
    asm volatile("mma.sync.aligned.m16n8k16.row.col.f32.bf16.bf16.f32 "        \
        "{%0,%1,%2,%3}, {%4,%5,%6,%7}, {%8,%9}, {%0,%1,%2,%3};"                \
        : "+f"((d)[0]), "+f"((d)[1]), "+f"((d)[2]), "+f"((d)[3])               \
        : "r"((a)[0]), "r"((a)[1]), "r"((a)[2]), "r"((a)[3]),                  \
          "r"((b)[0]), "r"((b)[1]))

// ---------------------------------------------------------------------------
// Pure-bf16 split GEMM. 512 threads (16 warps, warp grid 4x4), NT in {64,128},
// BK=64 chunks, 3-stage cp.async pipeline. z-strides on A/B/C/bias/res.
// ---------------------------------------------------------------------------
template<int NT, bool BNAT, int EPI, int OUT>
__global__ __launch_bounds__(512) void gemm_bf(
    const uint16_t* __restrict__ Ah, const uint16_t* __restrict__ Al,
    int lda, long long az,
    const uint16_t* __restrict__ Bh, const uint16_t* __restrict__ Bl,
    int ldb, long long bz,
    const float* __restrict__ bias, long long biasz,
    const float* __restrict__ res, long long resz,
    float* __restrict__ C, uint16_t* __restrict__ Ch, uint16_t* __restrict__ Cl,
    int ldc, long long cz, int K, float scale)
{
    constexpr int WNC = NT / 4;
    constexpr int NTL = WNC / 8;
    constexpr int MT  = 2;
    constexpr int RS  = 72;
    constexpr int ABYTES = 128 * RS * 2;
    constexpr int BRS  = BNAT ? RS : (NT + 8);
    constexpr int BROWS = BNAT ? NT : 64;
    constexpr int BBYTES = BROWS * BRS * 2;
    constexpr int STAGE  = 2 * ABYTES + 2 * BBYTES;
    constexpr int STAGES = 3;
    constexpr int BSEGROW = NT / 8;
    constexpr int BSEGS = BNAT ? NT * 8 : 64 * BSEGROW;
    constexpr int BIT = (BSEGS + 511) / 512;

    extern __shared__ __align__(128) char smm[];
    const uint32_t sb = smem_u32(smm);
    const int tid = threadIdx.x, lane = tid & 31, wid = tid >> 5;
    const int wm = wid >> 2, wn = wid & 3;
    const int bm = blockIdx.y * 128, bn = blockIdx.x * NT;

    const uint16_t* Abh = Ah + (size_t)blockIdx.z * az + (size_t)bm * lda;
    const uint16_t* Abl = Al + (size_t)blockIdx.z * az + (size_t)bm * lda;
    const uint16_t* Bbh = Bh + (size_t)blockIdx.z * bz;
    const uint16_t* Bbl = Bl + (size_t)blockIdx.z * bz;
    const float* biasb = bias ? bias + (size_t)blockIdx.z * biasz : nullptr;
    const float* resb  = res  ? res  + (size_t)blockIdx.z * resz  : nullptr;

    float acc[MT][NTL][4];
    #pragma unroll
    for (int mt = 0; mt < MT; mt++)
        #pragma unroll
        for (int nt = 0; nt < NTL; nt++)
            #pragma unroll
            for (int r = 0; r < 4; r++) acc[mt][nt][r] = 0.f;

    const int NC = K >> 6;

    auto issue = [&](int c, int s) {
        const uint32_t st = sb + s * STAGE;
        const int k0 = c << 6;
        #pragma unroll
        for (int j = 0; j < 2; j++) {
            int idx = tid + j * 512;
            int row = idx >> 3, seg = idx & 7;
            size_t so = (size_t)row * lda + k0 + seg * 8;
            uint32_t d = st + row * (RS * 2) + seg * 16;
            CP16(d, gptr(Abh + so));
            CP16(d + ABYTES, gptr(Abl + so));
        }
        #pragma unroll
        for (int j = 0; j < BIT; j++) {
            int idx = tid + j * 512;
            if (BSEGS >= 512 * (j + 1) || idx < BSEGS) {
                if (BNAT) {
                    int row = idx >> 3, seg = idx & 7;
                    size_t so = (size_t)(bn + row) * ldb + k0 + seg * 8;
                    uint32_t d = st + 2 * ABYTES + row * (RS * 2) + seg * 16;
                    CP16(d, gptr(Bbh + so));
                    CP16(d + BBYTES, gptr(Bbl + so));
                } else {
                    int row = idx / BSEGROW, seg = idx % BSEGROW;
                    size_t so = (size_t)(k0 + row) * ldb + bn + seg * 8;
                    uint32_t d = st + 2 * ABYTES + row * (BRS * 2) + seg * 16;
                    CP16(d, gptr(Bbh + so));
                    CP16(d + BBYTES, gptr(Bbl + so));
                }
            }
        }
    };

    #pragma unroll
    for (int s = 0; s < STAGES - 1; s++) {
        if (s < NC) issue(s, s);
        CP_COMMIT();
    }

    for (int c = 0; c < NC; c++) {
        CP_WAIT1();
        __syncthreads();
        {
            int cn = c + STAGES - 1;
            if (cn < NC) issue(cn, cn % STAGES);
            CP_COMMIT();
        }
        const uint32_t abh_ = sb + (c % STAGES) * STAGE;
        const uint32_t abl_ = abh_ + ABYTES;
        const uint32_t bbh_ = abh_ + 2 * ABYTES;
        const uint32_t bbl_ = bbh_ + BBYTES;
        #pragma unroll
        for (int ks = 0; ks < 4; ks++) {
            uint32_t afh[MT][4], afl[MT][4], bfh[NTL][2], bfl[NTL][2];
            #pragma unroll
            for (int mt = 0; mt < MT; mt++) {
                uint32_t off = ((wm * 32 + mt * 16 + (lane & 15)) * RS +
                                ks * 16 + ((lane >> 4) << 3)) << 1;
                LDSM_X4(afh[mt], abh_ + off);
                LDSM_X4(afl[mt], abl_ + off);
            }
            #pragma unroll
            for (int p = 0; p < NTL / 2; p++) {
                uint32_t rh[4], rl[4];
                if (BNAT) {
                    int grp = lane >> 3;
                    int row = wn * WNC + p * 16 + (grp >> 1) * 8 + (lane & 7);
                    int koff = ks * 16 + (grp & 1) * 8;
                    uint32_t off = ((uint32_t)(row * RS + koff)) << 1;
                    LDSM_X4(rh, bbh_ + off);
                    LDSM_X4(rl, bbl_ + off);
                    bfh[2 * p][0] = rh[0]; bfh[2 * p][1] = rh[1];
                    bfh[2 * p + 1][0] = rh[2]; bfh[2 * p + 1][1] = rh[3];
                    bfl[2 * p][0] = rl[0]; bfl[2 * p][1] = rl[1];
                    bfl[2 * p + 1][0] = rl[2]; bfl[2 * p + 1][1] = rl[3];
                } else {
                    int row = ks * 16 + (lane & 15);
                    int col = wn * WNC + p * 16 + ((lane >> 4) << 3);
                    uint32_t off = ((uint32_t)(row * BRS + col)) << 1;
                    LDSM_X4T(rh, bbh_ + off);
                    LDSM_X4T(rl, bbl_ + off);
                    bfh[2 * p][0] = rh[0]; bfh[2 * p][1] = rh[1];
                    bfh[2 * p + 1][0] = rh[2]; bfh[2 * p + 1][1] = rh[3];
                    bfl[2 * p][0] = rl[0]; bfl[2 * p][1] = rl[1];
                    bfl[2 * p + 1][0] = rl[2]; bfl[2 * p + 1][1] = rl[3];
                }
            }
            #pragma unroll
            for (int nt = 0; nt < NTL; nt++)
                #pragma unroll
                for (int mt = 0; mt < MT; mt++) {
                    MMA16816(acc[mt][nt], afh[mt], bfh[nt]);
                    MMA16816(acc[mt][nt], afh[mt], bfl[nt]);
                    MMA16816(acc[mt][nt], afl[mt], bfh[nt]);
                }
        }
    }

    const int gid = lane >> 2, tig = lane & 3;
    #pragma unroll
    for (int mt = 0; mt < MT; mt++) {
        #pragma unroll
        for (int nt = 0; nt < NTL; nt++) {
            int r0  = bm + wm * 32 + mt * 16 + gid;
            int col = bn + wn * WNC + nt * 8 + tig * 2;
            float2 v0 = make_float2(acc[mt][nt][0] * scale, acc[mt][nt][1] * scale);
            float2 v1 = make_float2(acc[mt][nt][2] * scale, acc[mt][nt][3] * scale);
            if (EPI >= 1) {
                float2 bb = *reinterpret_cast<const float2*>(&biasb[col]);
                v0.x += bb.x; v0.y += bb.y; v1.x += bb.x; v1.y += bb.y;
            }
            if (EPI == 2) {
                v0.x = gelu_f(v0.x); v0.y = gelu_f(v0.y);
                v1.x = gelu_f(v1.x); v1.y = gelu_f(v1.y);
            }
            if (EPI == 3) {
                float2 ra = *reinterpret_cast<const float2*>(
                    &resb[(size_t)r0 * ldc + col]);
                float2 rb = *reinterpret_cast<const float2*>(
                    &resb[(size_t)(r0 + 8) * ldc + col]);
                v0.x += ra.x; v0.y += ra.y; v1.x += rb.x; v1.y += rb.y;
            }
            size_t o0 = (size_t)r0 * ldc + col + (size_t)blockIdx.z * cz;
            size_t o1 = (size_t)(r0 + 8) * ldc + col + (size_t)blockIdx.z * cz;
            if (OUT & 1) {
                *reinterpret_cast<float2*>(&C[o0]) = v0;
                *reinterpret_cast<float2*>(&C[o1]) = v1;
            }
            if (OUT & 2) {
                float a0 = v0.x, a1 = v0.y, b0 = v1.x, b1 = v1.y;
                if (OUT & 4) {
                    a0 = gelu_f(a0); a1 = gelu_f(a1);
                    b0 = gelu_f(b0); b1 = gelu_f(b1);
                }
                uint32_t h, l;
                split2(a0, a1, h, l);
                *reinterpret_cast<uint32_t*>(&Ch[o0]) = h;
                *reinterpret_cast<uint32_t*>(&Cl[o0]) = l;
                split2(b0, b1, h, l);
                *reinterpret_cast<uint32_t*>(&Ch[o1]) = h;
                *reinterpret_cast<uint32_t*>(&Cl[o1]) = l;
            }
        }
    }
}

// ---------------------------------------------------------------------------
// Fused flash attention v3 (unchanged from R10).
// ---------------------------------------------------------------------------
__global__ __launch_bounds__(512) void flash_attn(
    const uint16_t* __restrict__ qh, const uint16_t* __restrict__ ql,
    uint16_t* __restrict__ oh, uint16_t* __restrict__ ol)
{
    constexpr int RS = 72;
    constexpr int TB = 128 * RS * 2;
    constexpr int KVSTAGE = 4 * TB;
    constexpr int PM_OFF = 2 * TB + 2 * KVSTAGE;
    extern __shared__ __align__(128) char smm[];
    const uint32_t sb  = smem_u32(smm);
    const uint32_t sQh = sb, sQl = sb + TB;
    float* pm = reinterpret_cast<float*>(smm + PM_OFF);
    const int tid = threadIdx.x, lane = tid & 31, w = tid >> 5;
    const int wq = w & 7, h2 = w >> 3;
    const int q0 = blockIdx.x * 128;
    const int h  = blockIdx.y;
    const int g = lane >> 2, t = lane & 3;

    #pragma unroll
    for (int j = 0; j < 2; j++) {
        int idx = tid + j * 512;
        int row = idx >> 3, seg = idx & 7;
        size_t so = (size_t)(q0 + row) * QKVW + h * 64 + seg * 8;
        uint32_t d = sb + row * (RS * 2) + seg * 16;
        CP16(d, gptr(qh + so));
        CP16(d + TB, gptr(ql + so));
    }
    auto issueKV = [&](int kt, int s) {
        uint32_t st = sb + 2 * TB + s * KVSTAGE;
        int tok0 = kt * 128;
        #pragma unroll
        for (int j = 0; j < 2; j++) {
            int idx = tid + j * 512;
            int row = idx >> 3, seg = idx & 7;
            size_t soK = (size_t)(tok0 + row) * QKVW + INNER + h * 64 + seg * 8;
            uint32_t dK = st + row * (RS * 2) + seg * 16;
            CP16(dK, gptr(qh + soK));
            CP16(dK + TB, gptr(ql + soK));
            size_t soV = soK + INNER;
            uint32_t dV = st + 2 * TB + row * (RS * 2) + seg * 16;
            CP16(dV, gptr(qh + soV));
            CP16(dV + TB, gptr(ql + soV));
        }
    };
    issueKV(0, 0);
    CP_COMMIT();

    float O[8][4];
    #pragma unroll
    for (int jt = 0; jt < 8; jt++)
        #pragma unroll
        for (int r = 0; r < 4; r++) O[jt][r] = 0.f;
    float m0 = -1e30f, m1 = -1e30f, l0 = 0.f, l1 = 0.f;

    for (int kt = 0; kt < NB / 128; kt++) {
        CP_WAIT0();
        __syncthreads();
        if (kt + 1 < NB / 128) {
            issueKV(kt + 1, (kt + 1) & 1);
            CP_COMMIT();
        }
        const uint32_t st  = sb + 2 * TB + (kt & 1) * KVSTAGE;
        const uint32_t sKh = st, sKl = st + TB;
        const uint32_t sVh = st + 2 * TB, sVl = st + 3 * TB;

        float sacc[8][4];
        #pragma unroll
        for (int j = 0; j < 8; j++)
            #pragma unroll
            for (int r = 0; r < 4; r++) sacc[j][r] = 0.f;

        #pragma unroll
        for (int kc = 0; kc < 4; kc++) {
            uint32_t aqh[4], aql[4];
            uint32_t aoff = ((wq * 16 + (lane & 15)) * RS +
                             kc * 16 + ((lane >> 4) << 3)) << 1;
            LDSM_X4(aqh, sQh + aoff);
            LDSM_X4(aql, sQl + aoff);
            #pragma unroll
            for (int jp = 0; jp < 4; jp++) {
                uint32_t rh[4], rl[4];
                uint32_t boff = ((h2 * 64 + jp * 16 + (lane & 15)) * RS +
                                 kc * 16 + ((lane >> 4) << 3)) << 1;
                LDSM_X4(rh, sKh + boff);
                LDSM_X4(rl, sKl + boff);
                uint32_t bh0[2] = {rh[0], rh[2]}, bh1[2] = {rh[1], rh[3]};
                uint32_t bl0[2] = {rl[0], rl[2]}, bl1[2] = {rl[1], rl[3]};
                MMA16816(sacc[2 * jp],     aqh, bh0);
                MMA16816(sacc[2 * jp],     aqh, bl0);
                MMA16816(sacc[2 * jp],     aql, bh0);
                MMA16816(sacc[2 * jp + 1], aqh, bh1);
                MMA16816(sacc[2 * jp + 1], aqh, bl1);
                MMA16816(sacc[2 * jp + 1], aql, bh1);
            }
        }

        float mx0 = -1e30f, mx1 = -1e30f;
        #pragma unroll
        for (int j = 0; j < 8; j++) {
            sacc[j][0] *= 0.125f; sacc[j][1] *= 0.125f;
            sacc[j][2] *= 0.125f; sacc[j][3] *= 0.125f;
            mx0 = fmaxf(mx0, fmaxf(sacc[j][0], sacc[j][1]));
            mx1 = fmaxf(mx1, fmaxf(sacc[j][2], sacc[j][3]));
        }
        mx0 = fmaxf(mx0, __shfl_xor_sync(0xffffffffu, mx0, 1));
        mx0 = fmaxf(mx0, __shfl_xor_sync(0xffffffffu, mx0, 2));
        mx1 = fmaxf(mx1, __shfl_xor_sync(0xffffffffu, mx1, 1));
        mx1 = fmaxf(mx1, __shfl_xor_sync(0xffffffffu, mx1, 2));
        float* pmc = pm + (kt & 1) * 256;
        if (t == 0) {
            pmc[h2 * 128 + wq * 16 + g]     = mx0;
            pmc[h2 * 128 + wq * 16 + g + 8] = mx1;
        }
        __syncthreads();
        float ox0 = pmc[(1 - h2) * 128 + wq * 16 + g];
        float ox1 = pmc[(1 - h2) * 128 + wq * 16 + g + 8];
        float nm0 = fmaxf(m0, fmaxf(mx0, ox0));
        float nm1 = fmaxf(m1, fmaxf(mx1, ox1));
        float a0 = __expf(m0 - nm0), a1 = __expf(m1 - nm1);
        m0 = nm0; m1 = nm1;
        float s0 = 0.f, s1 = 0.f;
        #pragma unroll
        for (int j = 0; j < 8; j++) {
            sacc[j][0] = __expf(sacc[j][0] - m0); s0 += sacc[j][0];
            sacc[j][1] = __expf(sacc[j][1] - m0); s0 += sacc[j][1];
            sacc[j][2] = __expf(sacc[j][2] - m1); s1 += sacc[j][2];
            sacc[j][3] = __expf(sacc[j][3] - m1); s1 += sacc[j][3];
        }
        s0 += __shfl_xor_sync(0xffffffffu, s0, 1);
        s0 += __shfl_xor_sync(0xffffffffu, s0, 2);
        s1 += __shfl_xor_sync(0xffffffffu, s1, 1);
        s1 += __shfl_xor_sync(0xffffffffu, s1, 2);
        l0 = l0 * a0 + s0;
        l1 = l1 * a1 + s1;
        #pragma unroll
        for (int jt = 0; jt < 8; jt++) {
            O[jt][0] *= a0; O[jt][1] *= a0;
            O[jt][2] *= a1; O[jt][3] *= a1;
        }

        #pragma unroll
        for (int kc = 0; kc < 4; kc++) {
            uint32_t ah[4], al[4];
            split2(sacc[2 * kc][0],     sacc[2 * kc][1],     ah[0], al[0]);
            split2(sacc[2 * kc][2],     sacc[2 * kc][3],     ah[1], al[1]);
            split2(sacc[2 * kc + 1][0], sacc[2 * kc + 1][1], ah[2], al[2]);
            split2(sacc[2 * kc + 1][2], sacc[2 * kc + 1][3], ah[3], al[3]);
            #pragma unroll
            for (int jp = 0; jp < 4; jp++) {
                uint32_t rh[4], rl[4];
                uint32_t boff = ((h2 * 64 + kc * 16 + (lane & 15)) * RS +
                                 jp * 16 + ((lane >> 4) << 3)) << 1;
                LDSM_X4T(rh, sVh + boff);
                LDSM_X4T(rl, sVl + boff);
                uint32_t bh0[2] = {rh[0], rh[1]}, bh1[2] = {rh[2], rh[3]};
                uint32_t bl0[2] = {rl[0], rl[1]}, bl1[2] = {rl[2], rl[3]};
                MMA16816(O[2 * jp],     ah, bh0);
                MMA16816(O[2 * jp],     ah, bl0);
                MMA16816(O[2 * jp],     al, bh0);
                MMA16816(O[2 * jp + 1], ah, bh1);
                MMA16816(O[2 * jp + 1], ah, bl1);
                MMA16816(O[2 * jp + 1], al, bh1);
            }
        }
    }

    __syncthreads();
    float* Ost = reinterpret_cast<float*>(smm + 2 * TB);
    float* lst = Ost + 128 * 66;
    if (h2 == 1) {
        #pragma unroll
        for (int jt = 0; jt < 8; jt++) {
            int c = jt * 8 + t * 2;
            Ost[(wq * 16 + g) * 66 + c]         = O[jt][0];
            Ost[(wq * 16 + g) * 66 + c + 1]     = O[jt][1];
            Ost[(wq * 16 + g + 8) * 66 + c]     = O[jt][2];
            Ost[(wq * 16 + g + 8) * 66 + c + 1] = O[jt][3];
        }
        if (t == 0) {
            lst[wq * 16 + g]     = l0;
            lst[wq * 16 + g + 8] = l1;
        }
    }
    __syncthreads();
    if (h2 == 0) {
        float i0 = 1.f / (l0 + lst[wq * 16 + g]);
        float i1 = 1.f / (l1 + lst[wq * 16 + g + 8]);
        #pragma unroll
        for (int jt = 0; jt < 8; jt++) {
            int c = jt * 8 + t * 2;
            float o00 = O[jt][0] + Ost[(wq * 16 + g) * 66 + c];
            float o01 = O[jt][1] + Ost[(wq * 16 + g) * 66 + c + 1];
            float o10 = O[jt][2] + Ost[(wq * 16 + g + 8) * 66 + c];
            float o11 = O[jt][3] + Ost[(wq * 16 + g + 8) * 66 + c + 1];
            uint32_t hh, ll;
            size_t o0 = (size_t)(q0 + wq * 16 + g) * INNER + h * 64 + c;
            split2(o00 * i0, o01 * i0, hh, ll);
            *reinterpret_cast<uint32_t*>(oh + o0) = hh;
            *reinterpret_cast<uint32_t*>(ol + o0) = ll;
            size_t o1 = o0 + (size_t)8 * INNER;
            split2(o10 * i1, o11 * i1, hh, ll);
            *reinterpret_cast<uint32_t*>(oh + o1) = hh;
            *reinterpret_cast<uint32_t*>(ol + o1) = ll;
        }
    }
}

// ---------------------------------------------------------------------------
// Reductions
// ---------------------------------------------------------------------------
__device__ __forceinline__ float blk_sum256(float v, float* sh) {
    int t = threadIdx.x;
    sh[t] = v; __syncthreads();
    #pragma unroll
    for (int s = 128; s >= 1; s >>= 1) {
        if (t < s) sh[t] += sh[t + s];
        __syncthreads();
    }
    float r = sh[0]; __syncthreads();
    return r;
}
__device__ __forceinline__ float blk_max256(float v, float* sh) {
    int t = threadIdx.x;
    sh[t] = v; __syncthreads();
    #pragma unroll
    for (int s = 128; s >= 1; s >>= 1) {
        if (t < s) sh[t] = fmaxf(sh[t], sh[t + s]);
        __syncthreads();
    }
    float r = sh[0]; __syncthreads();
    return r;
}

// ---------------------------------------------------------------------------
// Elementwise kernels
// ---------------------------------------------------------------------------
__global__ __launch_bounds__(256) void conv_bf(
    const float* __restrict__ x, uint16_t* __restrict__ h,
    uint16_t* __restrict__ l, int n8)
{
    int i = blockIdx.x * 256 + threadIdx.x;
    if (i < n8) {
        const float4* x4 = reinterpret_cast<const float4*>(x);
        float4 a = x4[2 * i], b = x4[2 * i + 1];
        uint32_t h0, h1, h2, h3, l0, l1, l2, l3;
        split2(a.x, a.y, h0, l0);
        split2(a.z, a.w, h1, l1);
        split2(b.x, b.y, h2, l2);
        split2(b.z, b.w, h3, l3);
        reinterpret_cast<uint4*>(h)[i] = make_uint4(h0, h1, h2, h3);
        reinterpret_cast<uint4*>(l)[i] = make_uint4(l0, l1, l2, l3);
    }
}

// Pack per-head params: pb=[imgP,spotP], pfb=[imgF,spotF], lng/lnb
__global__ __launch_bounds__(256) void pack_params(
    const float* __restrict__ ipb, const float* __restrict__ spb,
    const float* __restrict__ ifb, const float* __restrict__ sfb,
    const float* __restrict__ ig,  const float* __restrict__ sg,
    const float* __restrict__ ib,  const float* __restrict__ sb,
    float* __restrict__ pb, float* __restrict__ pfb,
    float* __restrict__ lng, float* __restrict__ lnb)
{
    int t = threadIdx.x;
    pb [t]        = ipb[t];  pb [t + PROJ] = spb[t];
    pfb[t]        = ifb[t];  pfb[t + PROJ] = sfb[t];
    lng[t]        = ig[t];   lng[t + PROJ] = sg[t];
    lnb[t]        = ib[t];   lnb[t + PROJ] = sb[t];
}

__global__ __launch_bounds__(256) void embed_kernel(
    const float* __restrict__ expr, const float* __restrict__ xt,
    const float* __restrict__ yt, const int* __restrict__ xi,
    const int* __restrict__ yi, float* __restrict__ out)
{
    int row = blockIdx.x;
    size_t xo = (size_t)xi[row] * SPOT;
    size_t yo = (size_t)yi[row] * SPOT;
    size_t ro = (size_t)row * SPOT;
    for (int j = threadIdx.x; j < SPOT; j += 256)
        out[ro + j] = expr[ro + j] + xt[xo + j] + yt[yo + j];
}

template<int N>
__global__ __launch_bounds__(256) void ln_bf(
    const float* __restrict__ x, const float* __restrict__ g,
    const float* __restrict__ b, uint16_t* __restrict__ oh,
    uint16_t* __restrict__ ol)
{
    __shared__ float sh[256];
    constexpr int NPAIR = N / 2;
    constexpr int NP = (NPAIR + 255) / 256;
    int row = blockIdx.x, tid = threadIdx.x;
    const float2* xr = reinterpret_cast<const float2*>(x + (size_t)row * N);
    float2 v[NP];
    float s = 0.f;
    #pragma unroll
    for (int i = 0; i < NP; i++) {
        int p = i * 256 + tid;
        if (p < NPAIR) { v[i] = xr[p]; s += v[i].x + v[i].y; }
        else v[i] = make_float2(0.f, 0.f);
    }
    s = blk_sum256(s, sh);
    float mean = s / N, ss = 0.f;
    #pragma unroll
    for (int i = 0; i < NP; i++) {
        int p = i * 256 + tid;
        if (p < NPAIR) {
            float dx = v[i].x - mean, dy = v[i].y - mean;
            ss += dx * dx + dy * dy;
        }
    }
    ss = blk_sum256(ss, sh);
    float rstd = rsqrtf(ss / N + 1e-5f);
    uint32_t* OH = reinterpret_cast<uint32_t*>(oh + (size_t)row * N);
    uint32_t* OL = reinterpret_cast<uint32_t*>(ol + (size_t)row * N);
    #pragma unroll
    for (int i = 0; i < NP; i++) {
        int p = i * 256 + tid;
        if (p < NPAIR) {
            float2 gg = reinterpret_cast<const float2*>(g)[p];
            float2 bb = reinterpret_cast<const float2*>(b)[p];
            float y0 = (v[i].x - mean) * rstd * gg.x + bb.x;
            float y1 = (v[i].y - mean) * rstd * gg.y + bb.y;
            uint32_t h, l;
            split2(y0, y1, h, l);
            OH[p] = h; OL[p] = l;
        }
    }
}

// LN for batched heads: N=PROJ, grid 2*NB; g/b indexed by slot = row/NB.
__global__ __launch_bounds__(256) void ln_bf2(
    const float* __restrict__ x, const float* __restrict__ g,
    const float* __restrict__ b, uint16_t* __restrict__ oh,
    uint16_t* __restrict__ ol)
{
    __shared__ float sh[256];
    constexpr int N = PROJ;
    int row = blockIdx.x, tid = threadIdx.x;
    int slot = row >> 11;                     // row / NB
    const float* gs = g + slot * PROJ;
    const float* bs = b + slot * PROJ;
    const float2* xr = reinterpret_cast<const float2*>(x + (size_t)row * N);
    float2 v = make_float2(0.f, 0.f);
    if (tid < N / 2) v = xr[tid];
    float s = blk_sum256(v.x + v.y, sh);
    float mean = s / N;
    float ss = 0.f;
    if (tid < N / 2) {
        float dx = v.x - mean, dy = v.y - mean;
        ss = dx * dx + dy * dy;
    }
    ss = blk_sum256(ss, sh);
    float rstd = rsqrtf(ss / N + 1e-5f);
    if (tid < N / 2) {
        float2 gg = reinterpret_cast<const float2*>(gs)[tid];
        float2 bb = reinterpret_cast<const float2*>(bs)[tid];
        float y0 = (v.x - mean) * rstd * gg.x + bb.x;
        float y1 = (v.y - mean) * rstd * gg.y + bb.y;
        uint32_t h, l;
        split2(y0, y1, h, l);
        reinterpret_cast<uint32_t*>(oh + (size_t)row * N)[tid] = h;
        reinterpret_cast<uint32_t*>(ol + (size_t)row * N)[tid] = l;
    }
}

// Fused: softmax(tgt row) in place + rowp
__global__ __launch_bounds__(256) void softmax_rowloss(
    float* __restrict__ tgt, const float* __restrict__ logits,
    float* __restrict__ rowp)
{
    __shared__ float sh[256];
    size_t row = blockIdx.x;
    int tid = threadIdx.x;
    float* tr = tgt + row * NB;
    const float* lr = logits + row * NB;
    float tv[8], lv[8];
    float mt = -1e30f, ml = -1e30f;
    #pragma unroll
    for (int i = 0; i < 8; i++) {
        tv[i] = tr[i * 256 + tid];
        lv[i] = lr[i * 256 + tid];
        mt = fmaxf(mt, tv[i]);
        ml = fmaxf(ml, lv[i]);
    }
    mt = blk_max256(mt, sh);
    float st = 0.f;
    #pragma unroll
    for (int i = 0; i < 8; i++) { tv[i] = __expf(tv[i] - mt); st += tv[i]; }
    st = blk_sum256(st, sh);
    float inv = 1.f / st;
    ml = blk_max256(ml, sh);
    float se = 0.f, dot = 0.f;
    #pragma unroll
    for (int i = 0; i < 8; i++) {
        tv[i] *= inv;
        tr[i * 256 + tid] = tv[i];
        se += __expf(lv[i] - ml);
        dot += tv[i] * lv[i];
    }
    se  = blk_sum256(se, sh);
    dot = blk_sum256(dot, sh);
    if (tid == 0) rowp[row] = 0.5f * (ml + logf(se) - dot);
}

__global__ __launch_bounds__(256) void pack_bf(
    const uint16_t* __restrict__ ih, const uint16_t* __restrict__ il,
    const uint16_t* __restrict__ eh, const uint16_t* __restrict__ el,
    uint16_t* __restrict__ ch, uint16_t* __restrict__ cl)
{
    int row = blockIdx.x, tid = threadIdx.x;
    const uint32_t* IH = reinterpret_cast<const uint32_t*>(ih + (size_t)row * PROJ);
    const uint32_t* IL = reinterpret_cast<const uint32_t*>(il + (size_t)row * PROJ);
    const uint32_t* EH = reinterpret_cast<const uint32_t*>(eh + (size_t)row * PROJ);
    const uint32_t* EL = reinterpret_cast<const uint32_t*>(el + (size_t)row * PROJ);
    uint32_t vh, vl;
    if (tid < 128) { vh = IH[tid]; vl = IL[tid]; }
    else           { vh = EH[tid - 128]; vl = EL[tid - 128]; }
    reinterpret_cast<uint32_t*>(ch + (size_t)row * 2 * PROJ)[tid] = vh;
    reinterpret_cast<uint32_t*>(cl + (size_t)row * 2 * PROJ)[tid] = vl;
}

__global__ __launch_bounds__(256) void colloss_kernel(
    const float* __restrict__ logits, const float* __restrict__ tgt,
    float* __restrict__ colp)
{
    __shared__ float smx[256], sse[256], sts[256], stdot[256];
    int tid = threadIdx.x;
    int c = blockIdx.x * 64 + (tid & 63);
    int ry = tid >> 6;
    float mx = -1e30f, se = 0.f, ts = 0.f, td = 0.f;
    for (int r = ry; r < NB; r += 4) {
        float l = logits[(size_t)r * NB + c];
        float t = tgt   [(size_t)r * NB + c];
        if (l > mx) { se = se * __expf(mx - l) + 1.f; mx = l; }
        else        { se += __expf(l - mx); }
        ts += t;
        td += t * l;
    }
    smx[tid] = mx; sse[tid] = se; sts[tid] = ts; stdot[tid] = td;
    __syncthreads();
    if (ry == 0) {
        #pragma unroll
        for (int k = 1; k < 4; k++) {
            int o = tid + k * 64;
            float m2 = smx[o], s2 = sse[o];
            float m = fmaxf(mx, m2);
            se = se * __expf(mx - m) + s2 * __expf(m2 - m);
            mx = m;
            ts += sts[o];
            td += stdot[o];
        }
        colp[c] = 0.5f * (ts * (mx + logf(se)) - td);
    }
}

__global__ __launch_bounds__(256) void final_reduce(
    const float* __restrict__ a, const float* __restrict__ b,
    float* __restrict__ out)
{
    __shared__ float sh[256];
    int tid = threadIdx.x;
    float s = 0.f;
    for (int i = tid; i < NB; i += 256) s += a[i] + b[i];
    s = blk_sum256(s, sh);
    if (tid == 0) out[0] = s * (1.0f / NB);
}

// ---------------------------------------------------------------------------
// Host launch
// ---------------------------------------------------------------------------
namespace {
constexpr int SMEM_STD = 3 * (2 * 128 * 72 * 2 + 2 * 64 * 136 * 2);   // 215040
constexpr int SMEM_NAT = 3 * (2 * 128 * 72 * 2 + 2 * 128 * 72 * 2);   // 221184
constexpr int SMEM_64  = 3 * (2 * 128 * 72 * 2 + 2 * 64 * 72 * 2);    // 165888
constexpr int SMEM_FLASH = 2 * (128 * 72 * 2) + 2 * 4 * (128 * 72 * 2)
                         + 2 * 256 * 4;                                // 186368
}

#define SYM(var, sym) cudaGetSymbolAddress((void**)&var, sym)

extern "C" void kernel_launch(void* const* d_in, const int* in_sizes, int n_in,
                              void* d_out, int out_size)
{
    (void)in_sizes; (void)n_in; (void)out_size;
    const float* image_features = (const float*)d_in[0];
    const float* expression     = (const float*)d_in[1];
    const float* x_table        = (const float*)d_in[2];
    const float* y_table        = (const float*)d_in[3];
    const float* ln1_g          = (const float*)d_in[4];
    const float* ln1_b          = (const float*)d_in[5];
    const float* w_qkv          = (const float*)d_in[6];
    const float* w_o            = (const float*)d_in[7];
    const float* b_o            = (const float*)d_in[8];
    const float* ln2_g          = (const float*)d_in[9];
    const float* ln2_b          = (const float*)d_in[10];
    const float* w1             = (const float*)d_in[11];
    const float* b1             = (const float*)d_in[12];
    const float* w2             = (const float*)d_in[13];
    const float* b2             = (const float*)d_in[14];
    const float* img_proj_w     = (const float*)d_in[15];
    const float* img_proj_b     = (const float*)d_in[16];
    const float* img_fc_w       = (const float*)d_in[17];
    const float* img_fc_b       = (const float*)d_in[18];
    const float* img_ln_g       = (const float*)d_in[19];
    const float* img_ln_b       = (const float*)d_in[20];
    const float* spot_proj_w    = (const float*)d_in[21];
    const float* spot_proj_b    = (const float*)d_in[22];
    const float* spot_fc_w      = (const float*)d_in[23];
    const float* spot_fc_b      = (const float*)d_in[24];
    const float* spot_ln_g      = (const float*)d_in[25];
    const float* spot_ln_b      = (const float*)d_in[26];
    const int*   x_idx          = (const int*)d_in[27];
    const int*   y_idx          = (const int*)d_in[28];
    float* out = (float*)d_out;

    float *spot, *pp, *tmp2, *logits, *tgt, *rowp, *colp, *pb, *pfb, *lng, *lnb;
    SYM(spot, g_spot); SYM(pp, g_pp); SYM(tmp2, g_tmp2);
    SYM(logits, g_logits); SYM(tgt, g_tgt); SYM(rowp, g_rowp); SYM(colp, g_colp);
    SYM(pb, g_pb); SYM(pfb, g_pfb); SYM(lng, g_lng); SYM(lnb, g_lnb);

    uint16_t *hbh, *hbl, *qkh, *qkl, *ath, *atl, *mph, *mpl;
    uint16_t *pinh, *pinl, *pgh, *pgl, *eh, *el, *cth, *ctl;
    SYM(hbh, g_hbuf_h); SYM(hbl, g_hbuf_l);
    SYM(qkh, g_qkv_h);  SYM(qkl, g_qkv_l);
    SYM(ath, g_attn_h); SYM(atl, g_attn_l);
    SYM(mph, g_mlp_h);  SYM(mpl, g_mlp_l);
    SYM(pinh, g_pin_h); SYM(pinl, g_pin_l);
    SYM(pgh, g_pg_h);   SYM(pgl, g_pg_l);
    SYM(eh, g_e_h);     SYM(el, g_e_l);
    SYM(cth, g_cat_h);  SYM(ctl, g_cat_l);

    uint16_t *wqh, *wql, *woh, *wol, *w1h, *w1l, *w2h, *w2l;
    uint16_t *pwh, *pwl, *pfwh, *pfwl;
    SYM(wqh, g_wqkv_h); SYM(wql, g_wqkv_l);
    SYM(woh, g_wo_h);   SYM(wol, g_wo_l);
    SYM(w1h, g_w1_h);   SYM(w1l, g_w1_l);
    SYM(w2h, g_w2_h);   SYM(w2l, g_w2_l);
    SYM(pwh, g_pw_h);   SYM(pwl, g_pw_l);
    SYM(pfwh, g_pfw_h); SYM(pfwl, g_pfw_l);

    auto kQKV  = gemm_bf<128, false, 0, 2>;
    auto kSqk  = gemm_bf<128, true,  0, 1>;
    auto kRes  = gemm_bf<128, false, 3, 1>;
    auto kResO = gemm_bf<128, false, 3, 3>;
    auto kMlp1 = gemm_bf<128, false, 2, 2>;
    auto kProj = gemm_bf<64,  false, 1, 7>;
    auto kResP = gemm_bf<64,  false, 3, 1>;
    cudaFuncSetAttribute(kQKV,  cudaFuncAttributeMaxDynamicSharedMemorySize, SMEM_STD);
    cudaFuncSetAttribute(kSqk,  cudaFuncAttributeMaxDynamicSharedMemorySize, SMEM_NAT);
    cudaFuncSetAttribute(kRes,  cudaFuncAttributeMaxDynamicSharedMemorySize, SMEM_STD);
    cudaFuncSetAttribute(kResO, cudaFuncAttributeMaxDynamicSharedMemorySize, SMEM_STD);
    cudaFuncSetAttribute(kMlp1, cudaFuncAttributeMaxDynamicSharedMemorySize, SMEM_STD);
    cudaFuncSetAttribute(kProj, cudaFuncAttributeMaxDynamicSharedMemorySize, SMEM_64);
    cudaFuncSetAttribute(kResP, cudaFuncAttributeMaxDynamicSharedMemorySize, SMEM_64);
    cudaFuncSetAttribute(flash_attn,
                         cudaFuncAttributeMaxDynamicSharedMemorySize, SMEM_FLASH);

    auto CONV = [&](const float* src, uint16_t* h, uint16_t* l, int n) {
        int n8 = n / 8;
        conv_bf<<<(n8 + 255) / 256, 256>>>(src, h, l, n8);
    };
    CONV(w_qkv, wqh, wql, NL * SPOT * QKVW);
    CONV(w_o,   woh, wol, NL * INNER * SPOT);
    CONV(w1,    w1h, w1l, NL * SPOT * MLPD);
    CONV(w2,    w2h, w2l, NL * MLPD * SPOT);
    CONV(img_proj_w,  pwh, pwl, IMG * PROJ);                       // slot 0
    CONV(spot_proj_w, pwh + 1024 * PROJ, pwl + 1024 * PROJ, SPOT * PROJ);
    CONV(img_fc_w,  pfwh, pfwl, PROJ * PROJ);
    CONV(spot_fc_w, pfwh + PROJ * PROJ, pfwl + PROJ * PROJ, PROJ * PROJ);
    CONV(image_features, pinh, pinl, NB * IMG);                    // slot 0
    pack_params<<<1, 256>>>(img_proj_b, spot_proj_b, img_fc_b, spot_fc_b,
                            img_ln_g, spot_ln_g, img_ln_b, spot_ln_b,
                            pb, pfb, lng, lnb);

    embed_kernel<<<NB, 256>>>(expression, x_table, y_table, x_idx, y_idx, spot);

    for (int l = 0; l < NL; l++) {
        uint16_t* wqh_l = wqh + (size_t)l * SPOT * QKVW;
        uint16_t* wql_l = wql + (size_t)l * SPOT * QKVW;
        uint16_t* woh_l = woh + (size_t)l * INNER * SPOT;
        uint16_t* wol_l = wol + (size_t)l * INNER * SPOT;
        uint16_t* w1h_l = w1h + (size_t)l * SPOT * MLPD;
        uint16_t* w1l_l = w1l + (size_t)l * SPOT * MLPD;
        uint16_t* w2h_l = w2h + (size_t)l * MLPD * SPOT;
        uint16_t* w2l_l = w2l + (size_t)l * MLPD * SPOT;

        ln_bf<SPOT><<<NB, 256>>>(spot, ln1_g + l * SPOT, ln1_b + l * SPOT, hbh, hbl);
        kQKV<<<dim3(QKVW / 128, NB / 128, 1), 512, SMEM_STD>>>(
            hbh, hbl, SPOT, 0, wqh_l, wql_l, QKVW, 0,
            nullptr, 0, nullptr, 0,
            nullptr, qkh, qkl, QKVW, 0, SPOT, 1.f);
        flash_attn<<<dim3(NB / 128, NH), 512, SMEM_FLASH>>>(qkh, qkl, ath, atl);
        kRes<<<dim3(SPOT / 128, NB / 128, 1), 512, SMEM_STD>>>(
            ath, atl, INNER, 0, woh_l, wol_l, SPOT, 0,
            b_o + l * SPOT, 0, spot, 0,
            spot, nullptr, nullptr, SPOT, 0, INNER, 1.f);
        ln_bf<SPOT><<<NB, 256>>>(spot, ln2_g + l * SPOT, ln2_b + l * SPOT, hbh, hbl);
        kMlp1<<<dim3(MLPD / 128, NB / 128, 1), 512, SMEM_STD>>>(
            hbh, hbl, SPOT, 0, w1h_l, w1l_l, MLPD, 0,
            b1 + l * MLPD, 0, nullptr, 0,
            nullptr, mph, mpl, MLPD, 0, SPOT, 1.f);
        if (l == NL - 1) {
            // final residual also emits bf16 split into head-input slot 1
            kResO<<<dim3(SPOT / 128, NB / 128, 1), 512, SMEM_STD>>>(
                mph, mpl, MLPD, 0, w2h_l, w2l_l, SPOT, 0,
                b2 + l * SPOT, 0, spot, 0,
                spot, pinh + (size_t)NB * 1024, pinl + (size_t)NB * 1024,
                SPOT, 0, MLPD, 1.f);
        } else {
            kRes<<<dim3(SPOT / 128, NB / 128, 1), 512, SMEM_STD>>>(
                mph, mpl, MLPD, 0, w2h_l, w2l_l, SPOT, 0,
                b2 + l * SPOT, 0, spot, 0,
                spot, nullptr, nullptr, SPOT, 0, MLPD, 1.f);
        }
    }

    // ---- batched projection heads (z = 0:img, 1:spot)
    kProj<<<dim3(PROJ / 64, NB / 128, 2), 512, SMEM_64>>>(
        pinh, pinl, 1024, (long long)NB * 1024,
        pwh, pwl, PROJ, (long long)1024 * PROJ,
        pb, PROJ, nullptr, 0,
        pp, pgh, pgl, PROJ, (long long)NB * PROJ, 1024, 1.f);
    kResP<<<dim3(PROJ / 64, NB / 128, 2), 512, SMEM_64>>>(
        pgh, pgl, PROJ, (long long)NB * PROJ,
        pfwh, pfwl, PROJ, (long long)PROJ * PROJ,
        pfb, PROJ, pp, (long long)NB * PROJ,
        tmp2, nullptr, nullptr, PROJ, (long long)NB * PROJ, PROJ, 1.f);
    ln_bf2<<<2 * NB, 256>>>(tmp2, lng, lnb, eh, el);

    // ---- loss
    pack_bf<<<NB, 256>>>(eh, el, eh + (size_t)NB * PROJ, el + (size_t)NB * PROJ,
                         cth, ctl);
    kSqk<<<dim3(NB / 128, NB / 128, 1), 512, SMEM_NAT>>>(
        eh + (size_t)NB * PROJ, el + (size_t)NB * PROJ, PROJ, 0,
        eh, el, PROJ, 0,
        nullptr, 0, nullptr, 0,
        logits, nullptr, nullptr, NB, 0, PROJ, 1.f);
    kSqk<<<dim3(NB / 128, NB / 128, 1), 512, SMEM_NAT>>>(
        cth, ctl, 2 * PROJ, 0, cth, ctl, 2 * PROJ, 0,
        nullptr, 0, nullptr, 0,
        tgt, nullptr, nullptr, NB, 0, 2 * PROJ, 0.5f);
    softmax_rowloss<<<NB, 256>>>(tgt, logits, rowp);
    colloss_kernel<<<NB / 64, 256>>>(logits, tgt, colp);
    final_reduce<<<1, 256>>>(rowp, colp, out);
}

// round 12
// speedup vs baseline: 1.4510x; 1.0292x over previous
#include <cuda_runtime.h>
#include <cstdint>

// ---------------------------------------------------------------------------
// Problem constants
// ---------------------------------------------------------------------------
namespace {
constexpr int NB   = 2048;
constexpr int SPOT = 1024;
constexpr int IMG  = 1024;
constexpr int PROJ = 256;
constexpr int NH   = 8;
constexpr int DH   = 64;
constexpr int INNER = 512;
constexpr int MLPD = 2048;
constexpr int QKVW = 1536;
constexpr int NL   = 2;
}

// ---------------------------------------------------------------------------
// Scratch: fp32
// ---------------------------------------------------------------------------
__device__ float g_spot  [NB * SPOT];
__device__ float g_pp    [2 * NB * PROJ];
__device__ float g_tmp2  [2 * NB * PROJ];
__device__ float g_logits[NB * NB];
__device__ float g_tgt   [NB * NB];
__device__ float g_rowp  [NB];
__device__ float g_colp  [NB];
__device__ float g_pb    [2 * PROJ];
__device__ float g_pfb   [2 * PROJ];
__device__ float g_lng   [2 * PROJ];
__device__ float g_lnb   [2 * PROJ];

// ---------------------------------------------------------------------------
// Scratch: bf16 hi/lo
// ---------------------------------------------------------------------------
__device__ uint16_t g_hbuf_h[NB * SPOT],  g_hbuf_l[NB * SPOT];
__device__ uint16_t g_qkv_h [NB * QKVW],  g_qkv_l [NB * QKVW];
__device__ uint16_t g_attn_h[NB * INNER], g_attn_l[NB * INNER];
__device__ uint16_t g_mlp_h [NB * MLPD],  g_mlp_l [NB * MLPD];
__device__ uint16_t g_pin_h[2 * NB * 1024], g_pin_l[2 * NB * 1024];
__device__ uint16_t g_pg_h [2 * NB * PROJ], g_pg_l [2 * NB * PROJ];
__device__ uint16_t g_e_h  [2 * NB * PROJ], g_e_l  [2 * NB * PROJ];
__device__ uint16_t g_cat_h[NB * 2 * PROJ], g_cat_l[NB * 2 * PROJ];
// weights bf16
__device__ uint16_t g_wqkv_h[NL * SPOT * QKVW], g_wqkv_l[NL * SPOT * QKVW];
__device__ uint16_t g_wo_h  [NL * INNER * SPOT], g_wo_l [NL * INNER * SPOT];
__device__ uint16_t g_w1_h  [NL * SPOT * MLPD],  g_w1_l [NL * SPOT * MLPD];
__device__ uint16_t g_w2_h  [NL * MLPD * SPOT],  g_w2_l [NL * MLPD * SPOT];
__device__ uint16_t g_pw_h [2 * 1024 * PROJ], g_pw_l [2 * 1024 * PROJ];
__device__ uint16_t g_pfw_h[2 * PROJ * PROJ], g_pfw_l[2 * PROJ * PROJ];

// ---------------------------------------------------------------------------
// Helpers
// ---------------------------------------------------------------------------
__device__ __forceinline__ uint32_t smem_u32(const void* p) {
    uint32_t a;
    asm("{ .reg .u64 t; cvta.to.shared.u64 t, %1; cvt.u32.u64 %0, t; }"
        : "=r"(a) : "l"(p));
    return a;
}
__device__ __forceinline__ unsigned long long gptr(const void* p) {
    return (unsigned long long)__cvta_generic_to_global(p);
}
__device__ __forceinline__ float gelu_f(float x) {
    return 0.5f * x * (1.0f + erff(x * 0.7071067811865475f));
}
__device__ __forceinline__ void split2(float f0, float f1, uint32_t& hi, uint32_t& lo) {
    asm("cvt.rn.bf16x2.f32 %0, %1, %2;" : "=r"(hi) : "f"(f1), "f"(f0));
    float h0 = __uint_as_float(hi << 16);
    float h1 = __uint_as_float(hi & 0xFFFF0000u);
    float l0 = f0 - h0, l1 = f1 - h1;
    asm("cvt.rn.bf16x2.f32 %0, %1, %2;" : "=r"(lo) : "f"(l1), "f"(l0));
}

#define CP16(dst, src) \
    asm volatile("cp.async.cg.shared.global [%0], [%1], 16;" :: "r"(dst), "l"(src))
#define CP_COMMIT() asm volatile("cp.async.commit_group;" ::: "memory")
#define CP_WAIT1()  asm volatile("cp.async.wait_group 1;" ::: "memory")
#define CP_WAIT0()  asm volatile("cp.async.wait_group 0;" ::: "memory")

#define LDSM_X4(r, a)                                                          \
    asm volatile("ldmatrix.sync.aligned.m8n8.x4.shared.b16 {%0,%1,%2,%3}, [%4];" \
        : "=r"((r)[0]), "=r"((r)[1]), "=r"((r)[2]), "=r"((r)[3]) : "r"(a))
#define LDSM_X4T(r, a)                                                         \
    asm volatile("ldmatrix.sync.aligned.m8n8.x4.trans.shared.b16 {%0,%1,%2,%3}, [%4];" \
        : "=r"((r)[0]), "=r"((r)[1]), "=r"((r)[2]), "=r"((r)[3]) : "r"(a))
#define MMA16816(d, a, b)                                                      \
    asm volatile("mma.sync.aligned.m16n8k16.row.col.f32.bf16.bf16.f32 "        \
        "{%0,%1,%2,%3}, {%4,%5,%6,%7}, {%8,%9}, {%0,%1,%2,%3};"                \
        : "+f"((d)[0]), "+f"((d)[1]), "+f"((d)[2]), "+f"((d)[3])               \
        : "r"((a)[0]), "r"((a)[1]), "r"((a)[2]), "r"((a)[3]),                  \
          "r"((b)[0]), "r"((b)[1]))

// ---------------------------------------------------------------------------
// Pure-bf16 split GEMM. 512 threads (16 warps, warp grid 4x4), NT in {64,128},
// BK=64, 3-stage cp.async. SYMW: symmetric output (C=Cᵀ) — compute only
// blocks with bx>=by and mirror-write the transpose.
// ---------------------------------------------------------------------------
template<int NT, bool BNAT, int EPI, int OUT, bool SYMW = false>
__global__ __launch_bounds__(512) void gemm_bf(
    const uint16_t* __restrict__ Ah, const uint16_t* __restrict__ Al,
    int lda, long long az,
    const uint16_t* __restrict__ Bh, const uint16_t* __restrict__ Bl,
    int ldb, long long bz,
    const float* __restrict__ bias, long long biasz,
    const float* __restrict__ res, long long resz,
    float* __restrict__ C, uint16_t* __restrict__ Ch, uint16_t* __restrict__ Cl,
    int ldc, long long cz, int K, float scale)
{
    if (SYMW && (int)blockIdx.x < (int)blockIdx.y) return;

    constexpr int WNC = NT / 4;
    constexpr int NTL = WNC / 8;
    constexpr int MT  = 2;
    constexpr int RS  = 72;
    constexpr int ABYTES = 128 * RS * 2;
    constexpr int BRS  = BNAT ? RS : (NT + 8);
    constexpr int BROWS = BNAT ? NT : 64;
    constexpr int BBYTES = BROWS * BRS * 2;
    constexpr int STAGE  = 2 * ABYTES + 2 * BBYTES;
    constexpr int STAGES = 3;
    constexpr int BSEGROW = NT / 8;
    constexpr int BSEGS = BNAT ? NT * 8 : 64 * BSEGROW;
    constexpr int BIT = (BSEGS + 511) / 512;

    extern __shared__ __align__(128) char smm[];
    const uint32_t sb = smem_u32(smm);
    const int tid = threadIdx.x, lane = tid & 31, wid = tid >> 5;
    const int wm = wid >> 2, wn = wid & 3;
    const int bm = blockIdx.y * 128, bn = blockIdx.x * NT;

    const uint16_t* Abh = Ah + (size_t)blockIdx.z * az + (size_t)bm * lda;
    const uint16_t* Abl = Al + (size_t)blockIdx.z * az + (size_t)bm * lda;
    const uint16_t* Bbh = Bh + (size_t)blockIdx.z * bz;
    const uint16_t* Bbl = Bl + (size_t)blockIdx.z * bz;
    const float* biasb = bias ? bias + (size_t)blockIdx.z * biasz : nullptr;
    const float* resb  = res  ? res  + (size_t)blockIdx.z * resz  : nullptr;

    float acc[MT][NTL][4];
    #pragma unroll
    for (int mt = 0; mt < MT; mt++)
        #pragma unroll
        for (int nt = 0; nt < NTL; nt++)
            #pragma unroll
            for (int r = 0; r < 4; r++) acc[mt][nt][r] = 0.f;

    const int NC = K >> 6;

    auto issue = [&](int c, int s) {
        const uint32_t st = sb + s * STAGE;
        const int k0 = c << 6;
        #pragma unroll
        for (int j = 0; j < 2; j++) {
            int idx = tid + j * 512;
            int row = idx >> 3, seg = idx & 7;
            size_t so = (size_t)row * lda + k0 + seg * 8;
            uint32_t d = st + row * (RS * 2) + seg * 16;
            CP16(d, gptr(Abh + so));
            CP16(d + ABYTES, gptr(Abl + so));
        }
        #pragma unroll
        for (int j = 0; j < BIT; j++) {
            int idx = tid + j * 512;
            if (BSEGS >= 512 * (j + 1) || idx < BSEGS) {
                if (BNAT) {
                    int row = idx >> 3, seg = idx & 7;
                    size_t so = (size_t)(bn + row) * ldb + k0 + seg * 8;
                    uint32_t d = st + 2 * ABYTES + row * (RS * 2) + seg * 16;
                    CP16(d, gptr(Bbh + so));
                    CP16(d + BBYTES, gptr(Bbl + so));
                } else {
                    int row = idx / BSEGROW, seg = idx % BSEGROW;
                    size_t so = (size_t)(k0 + row) * ldb + bn + seg * 8;
                    uint32_t d = st + 2 * ABYTES + row * (BRS * 2) + seg * 16;
                    CP16(d, gptr(Bbh + so));
                    CP16(d + BBYTES, gptr(Bbl + so));
                }
            }
        }
    };

    #pragma unroll
    for (int s = 0; s < STAGES - 1; s++) {
        if (s < NC) issue(s, s);
        CP_COMMIT();
    }

    for (int c = 0; c < NC; c++) {
        CP_WAIT1();
        __syncthreads();
        {
            int cn = c + STAGES - 1;
            if (cn < NC) issue(cn, cn % STAGES);
            CP_COMMIT();
        }
        const uint32_t abh_ = sb + (c % STAGES) * STAGE;
        const uint32_t abl_ = abh_ + ABYTES;
        const uint32_t bbh_ = abh_ + 2 * ABYTES;
        const uint32_t bbl_ = bbh_ + BBYTES;
        #pragma unroll
        for (int ks = 0; ks < 4; ks++) {
            uint32_t afh[MT][4], afl[MT][4], bfh[NTL][2], bfl[NTL][2];
            #pragma unroll
            for (int mt = 0; mt < MT; mt++) {
                uint32_t off = ((wm * 32 + mt * 16 + (lane & 15)) * RS +
                                ks * 16 + ((lane >> 4) << 3)) << 1;
                LDSM_X4(afh[mt], abh_ + off);
                LDSM_X4(afl[mt], abl_ + off);
            }
            #pragma unroll
            for (int p = 0; p < NTL / 2; p++) {
                uint32_t rh[4], rl[4];
                if (BNAT) {
                    int grp = lane >> 3;
                    int row = wn * WNC + p * 16 + (grp >> 1) * 8 + (lane & 7);
                    int koff = ks * 16 + (grp & 1) * 8;
                    uint32_t off = ((uint32_t)(row * RS + koff)) << 1;
                    LDSM_X4(rh, bbh_ + off);
                    LDSM_X4(rl, bbl_ + off);
                    bfh[2 * p][0] = rh[0]; bfh[2 * p][1] = rh[1];
                    bfh[2 * p + 1][0] = rh[2]; bfh[2 * p + 1][1] = rh[3];
                    bfl[2 * p][0] = rl[0]; bfl[2 * p][1] = rl[1];
                    bfl[2 * p + 1][0] = rl[2]; bfl[2 * p + 1][1] = rl[3];
                } else {
                    int row = ks * 16 + (lane & 15);
                    int col = wn * WNC + p * 16 + ((lane >> 4) << 3);
                    uint32_t off = ((uint32_t)(row * BRS + col)) << 1;
                    LDSM_X4T(rh, bbh_ + off);
                    LDSM_X4T(rl, bbl_ + off);
                    bfh[2 * p][0] = rh[0]; bfh[2 * p][1] = rh[1];
                    bfh[2 * p + 1][0] = rh[2]; bfh[2 * p + 1][1] = rh[3];
                    bfl[2 * p][0] = rl[0]; bfl[2 * p][1] = rl[1];
                    bfl[2 * p + 1][0] = rl[2]; bfl[2 * p + 1][1] = rl[3];
                }
            }
            #pragma unroll
            for (int nt = 0; nt < NTL; nt++)
                #pragma unroll
                for (int mt = 0; mt < MT; mt++) {
                    MMA16816(acc[mt][nt], afh[mt], bfh[nt]);
                    MMA16816(acc[mt][nt], afh[mt], bfl[nt]);
                    MMA16816(acc[mt][nt], afl[mt], bfh[nt]);
                }
        }
    }

    const int gid = lane >> 2, tig = lane & 3;
    #pragma unroll
    for (int mt = 0; mt < MT; mt++) {
        #pragma unroll
        for (int nt = 0; nt < NTL; nt++) {
            int r0  = bm + wm * 32 + mt * 16 + gid;
            int col = bn + wn * WNC + nt * 8 + tig * 2;
            float2 v0 = make_float2(acc[mt][nt][0] * scale, acc[mt][nt][1] * scale);
            float2 v1 = make_float2(acc[mt][nt][2] * scale, acc[mt][nt][3] * scale);
            if (EPI >= 1) {
                float2 bb = *reinterpret_cast<const float2*>(&biasb[col]);
                v0.x += bb.x; v0.y += bb.y; v1.x += bb.x; v1.y += bb.y;
            }
            if (EPI == 2) {
                v0.x = gelu_f(v0.x); v0.y = gelu_f(v0.y);
                v1.x = gelu_f(v1.x); v1.y = gelu_f(v1.y);
            }
            if (EPI == 3) {
                float2 ra = *reinterpret_cast<const float2*>(
                    &resb[(size_t)r0 * ldc + col]);
                float2 rb = *reinterpret_cast<const float2*>(
                    &resb[(size_t)(r0 + 8) * ldc + col]);
                v0.x += ra.x; v0.y += ra.y; v1.x += rb.x; v1.y += rb.y;
            }
            size_t o0 = (size_t)r0 * ldc + col + (size_t)blockIdx.z * cz;
            size_t o1 = (size_t)(r0 + 8) * ldc + col + (size_t)blockIdx.z * cz;
            if (OUT & 1) {
                *reinterpret_cast<float2*>(&C[o0]) = v0;
                *reinterpret_cast<float2*>(&C[o1]) = v1;
                if (SYMW) {
                    // mirror write (values bitwise-identical by symmetry)
                    C[(size_t)col * ldc + r0]           = v0.x;
                    C[(size_t)(col + 1) * ldc + r0]     = v0.y;
                    C[(size_t)col * ldc + r0 + 8]       = v1.x;
                    C[(size_t)(col + 1) * ldc + r0 + 8] = v1.y;
                }
            }
            if (OUT & 2) {
                float a0 = v0.x, a1 = v0.y, b0 = v1.x, b1 = v1.y;
                if (OUT & 4) {
                    a0 = gelu_f(a0); a1 = gelu_f(a1);
                    b0 = gelu_f(b0); b1 = gelu_f(b1);
                }
                uint32_t h, l;
                split2(a0, a1, h, l);
                *reinterpret_cast<uint32_t*>(&Ch[o0]) = h;
                *reinterpret_cast<uint32_t*>(&Cl[o0]) = l;
                split2(b0, b1, h, l);
                *reinterpret_cast<uint32_t*>(&Ch[o1]) = h;
                *reinterpret_cast<uint32_t*>(&Cl[o1]) = l;
            }
        }
    }
}

// ---------------------------------------------------------------------------
// Fused flash attention v3 (unchanged).
// ---------------------------------------------------------------------------
__global__ __launch_bounds__(512) void flash_attn(
    const uint16_t* __restrict__ qh, const uint16_t* __restrict__ ql,
    uint16_t* __restrict__ oh, uint16_t* __restrict__ ol)
{
    constexpr int RS = 72;
    constexpr int TB = 128 * RS * 2;
    constexpr int KVSTAGE = 4 * TB;
    constexpr int PM_OFF = 2 * TB + 2 * KVSTAGE;
    extern __shared__ __align__(128) char smm[];
    const uint32_t sb  = smem_u32(smm);
    const uint32_t sQh = sb, sQl = sb + TB;
    float* pm = reinterpret_cast<float*>(smm + PM_OFF);
    const int tid = threadIdx.x, lane = tid & 31, w = tid >> 5;
    const int wq = w & 7, h2 = w >> 3;
    const int q0 = blockIdx.x * 128;
    const int h  = blockIdx.y;
    const int g = lane >> 2, t = lane & 3;

    #pragma unroll
    for (int j = 0; j < 2; j++) {
        int idx = tid + j * 512;
        int row = idx >> 3, seg = idx & 7;
        size_t so = (size_t)(q0 + row) * QKVW + h * 64 + seg * 8;
        uint32_t d = sb + row * (RS * 2) + seg * 16;
        CP16(d, gptr(qh + so));
        CP16(d + TB, gptr(ql + so));
    }
    auto issueKV = [&](int kt, int s) {
        uint32_t st = sb + 2 * TB + s * KVSTAGE;
        int tok0 = kt * 128;
        #pragma unroll
        for (int j = 0; j < 2; j++) {
            int idx = tid + j * 512;
            int row = idx >> 3, seg = idx & 7;
            size_t soK = (size_t)(tok0 + row) * QKVW + INNER + h * 64 + seg * 8;
            uint32_t dK = st + row * (RS * 2) + seg * 16;
            CP16(dK, gptr(qh + soK));
            CP16(dK + TB, gptr(ql + soK));
            size_t soV = soK + INNER;
            uint32_t dV = st + 2 * TB + row * (RS * 2) + seg * 16;
            CP16(dV, gptr(qh + soV));
            CP16(dV + TB, gptr(ql + soV));
        }
    };
    issueKV(0, 0);
    CP_COMMIT();

    float O[8][4];
    #pragma unroll
    for (int jt = 0; jt < 8; jt++)
        #pragma unroll
        for (int r = 0; r < 4; r++) O[jt][r] = 0.f;
    float m0 = -1e30f, m1 = -1e30f, l0 = 0.f, l1 = 0.f;

    for (int kt = 0; kt < NB / 128; kt++) {
        CP_WAIT0();
        __syncthreads();
        if (kt + 1 < NB / 128) {
            issueKV(kt + 1, (kt + 1) & 1);
            CP_COMMIT();
        }
        const uint32_t st  = sb + 2 * TB + (kt & 1) * KVSTAGE;
        const uint32_t sKh = st, sKl = st + TB;
        const uint32_t sVh = st + 2 * TB, sVl = st + 3 * TB;

        float sacc[8][4];
        #pragma unroll
        for (int j = 0; j < 8; j++)
            #pragma unroll
            for (int r = 0; r < 4; r++) sacc[j][r] = 0.f;

        #pragma unroll
        for (int kc = 0; kc < 4; kc++) {
            uint32_t aqh[4], aql[4];
            uint32_t aoff = ((wq * 16 + (lane & 15)) * RS +
                             kc * 16 + ((lane >> 4) << 3)) << 1;
            LDSM_X4(aqh, sQh + aoff);
            LDSM_X4(aql, sQl + aoff);
            #pragma unroll
            for (int jp = 0; jp < 4; jp++) {
                uint32_t rh[4], rl[4];
                uint32_t boff = ((h2 * 64 + jp * 16 + (lane & 15)) * RS +
                                 kc * 16 + ((lane >> 4) << 3)) << 1;
                LDSM_X4(rh, sKh + boff);
                LDSM_X4(rl, sKl + boff);
                uint32_t bh0[2] = {rh[0], rh[2]}, bh1[2] = {rh[1], rh[3]};
                uint32_t bl0[2] = {rl[0], rl[2]}, bl1[2] = {rl[1], rl[3]};
                MMA16816(sacc[2 * jp],     aqh, bh0);
                MMA16816(sacc[2 * jp],     aqh, bl0);
                MMA16816(sacc[2 * jp],     aql, bh0);
                MMA16816(sacc[2 * jp + 1], aqh, bh1);
                MMA16816(sacc[2 * jp + 1], aqh, bl1);
                MMA16816(sacc[2 * jp + 1], aql, bh1);
            }
        }

        float mx0 = -1e30f, mx1 = -1e30f;
        #pragma unroll
        for (int j = 0; j < 8; j++) {
            sacc[j][0] *= 0.125f; sacc[j][1] *= 0.125f;
            sacc[j][2] *= 0.125f; sacc[j][3] *= 0.125f;
            mx0 = fmaxf(mx0, fmaxf(sacc[j][0], sacc[j][1]));
            mx1 = fmaxf(mx1, fmaxf(sacc[j][2], sacc[j][3]));
        }
        mx0 = fmaxf(mx0, __shfl_xor_sync(0xffffffffu, mx0, 1));
        mx0 = fmaxf(mx0, __shfl_xor_sync(0xffffffffu, mx0, 2));
        mx1 = fmaxf(mx1, __shfl_xor_sync(0xffffffffu, mx1, 1));
        mx1 = fmaxf(mx1, __shfl_xor_sync(0xffffffffu, mx1, 2));
        float* pmc = pm + (kt & 1) * 256;
        if (t == 0) {
            pmc[h2 * 128 + wq * 16 + g]     = mx0;
            pmc[h2 * 128 + wq * 16 + g + 8] = mx1;
        }
        __syncthreads();
        float ox0 = pmc[(1 - h2) * 128 + wq * 16 + g];
        float ox1 = pmc[(1 - h2) * 128 + wq * 16 + g + 8];
        float nm0 = fmaxf(m0, fmaxf(mx0, ox0));
        float nm1 = fmaxf(m1, fmaxf(mx1, ox1));
        float a0 = __expf(m0 - nm0), a1 = __expf(m1 - nm1);
        m0 = nm0; m1 = nm1;
        float s0 = 0.f, s1 = 0.f;
        #pragma unroll
        for (int j = 0; j < 8; j++) {
            sacc[j][0] = __expf(sacc[j][0] - m0); s0 += sacc[j][0];
            sacc[j][1] = __expf(sacc[j][1] - m0); s0 += sacc[j][1];
            sacc[j][2] = __expf(sacc[j][2] - m1); s1 += sacc[j][2];
            sacc[j][3] = __expf(sacc[j][3] - m1); s1 += sacc[j][3];
        }
        s0 += __shfl_xor_sync(0xffffffffu, s0, 1);
        s0 += __shfl_xor_sync(0xffffffffu, s0, 2);
        s1 += __shfl_xor_sync(0xffffffffu, s1, 1);
        s1 += __shfl_xor_sync(0xffffffffu, s1, 2);
        l0 = l0 * a0 + s0;
        l1 = l1 * a1 + s1;
        #pragma unroll
        for (int jt = 0; jt < 8; jt++) {
            O[jt][0] *= a0; O[jt][1] *= a0;
            O[jt][2] *= a1; O[jt][3] *= a1;
        }

        #pragma unroll
        for (int kc = 0; kc < 4; kc++) {
            uint32_t ah[4], al[4];
            split2(sacc[2 * kc][0],     sacc[2 * kc][1],     ah[0], al[0]);
            split2(sacc[2 * kc][2],     sacc[2 * kc][3],     ah[1], al[1]);
            split2(sacc[2 * kc + 1][0], sacc[2 * kc + 1][1], ah[2], al[2]);
            split2(sacc[2 * kc + 1][2], sacc[2 * kc + 1][3], ah[3], al[3]);
            #pragma unroll
            for (int jp = 0; jp < 4; jp++) {
                uint32_t rh[4], rl[4];
                uint32_t boff = ((h2 * 64 + kc * 16 + (lane & 15)) * RS +
                                 jp * 16 + ((lane >> 4) << 3)) << 1;
                LDSM_X4T(rh, sVh + boff);
                LDSM_X4T(rl, sVl + boff);
                uint32_t bh0[2] = {rh[0], rh[1]}, bh1[2] = {rh[2], rh[3]};
                uint32_t bl0[2] = {rl[0], rl[1]}, bl1[2] = {rl[2], rl[3]};
                MMA16816(O[2 * jp],     ah, bh0);
                MMA16816(O[2 * jp],     ah, bl0);
                MMA16816(O[2 * jp],     al, bh0);
                MMA16816(O[2 * jp + 1], ah, bh1);
                MMA16816(O[2 * jp + 1], ah, bl1);
                MMA16816(O[2 * jp + 1], al, bh1);
            }
        }
    }

    __syncthreads();
    float* Ost = reinterpret_cast<float*>(smm + 2 * TB);
    float* lst = Ost + 128 * 66;
    if (h2 == 1) {
        #pragma unroll
        for (int jt = 0; jt < 8; jt++) {
            int c = jt * 8 + t * 2;
            Ost[(wq * 16 + g) * 66 + c]         = O[jt][0];
            Ost[(wq * 16 + g) * 66 + c + 1]     = O[jt][1];
            Ost[(wq * 16 + g + 8) * 66 + c]     = O[jt][2];
            Ost[(wq * 16 + g + 8) * 66 + c + 1] = O[jt][3];
        }
        if (t == 0) {
            lst[wq * 16 + g]     = l0;
            lst[wq * 16 + g + 8] = l1;
        }
    }
    __syncthreads();
    if (h2 == 0) {
        float i0 = 1.f / (l0 + lst[wq * 16 + g]);
        float i1 = 1.f / (l1 + lst[wq * 16 + g + 8]);
        #pragma unroll
        for (int jt = 0; jt < 8; jt++) {
            int c = jt * 8 + t * 2;
            float o00 = O[jt][0] + Ost[(wq * 16 + g) * 66 + c];
            float o01 = O[jt][1] + Ost[(wq * 16 + g) * 66 + c + 1];
            float o10 = O[jt][2] + Ost[(wq * 16 + g + 8) * 66 + c];
            float o11 = O[jt][3] + Ost[(wq * 16 + g + 8) * 66 + c + 1];
            uint32_t hh, ll;
            size_t o0 = (size_t)(q0 + wq * 16 + g) * INNER + h * 64 + c;
            split2(o00 * i0, o01 * i0, hh, ll);
            *reinterpret_cast<uint32_t*>(oh + o0) = hh;
            *reinterpret_cast<uint32_t*>(ol + o0) = ll;
            size_t o1 = o0 + (size_t)8 * INNER;
            split2(o10 * i1, o11 * i1, hh, ll);
            *reinterpret_cast<uint32_t*>(oh + o1) = hh;
            *reinterpret_cast<uint32_t*>(ol + o1) = ll;
        }
    }
}

// ---------------------------------------------------------------------------
// Reductions
// ---------------------------------------------------------------------------
__device__ __forceinline__ float blk_sum256(float v, float* sh) {
    int t = threadIdx.x;
    sh[t] = v; __syncthreads();
    #pragma unroll
    for (int s = 128; s >= 1; s >>= 1) {
        if (t < s) sh[t] += sh[t + s];
        __syncthreads();
    }
    float r = sh[0]; __syncthreads();
    return r;
}
__device__ __forceinline__ float blk_max256(float v, float* sh) {
    int t = threadIdx.x;
    sh[t] = v; __syncthreads();
    #pragma unroll
    for (int s = 128; s >= 1; s >>= 1) {
        if (t < s) sh[t] = fmaxf(sh[t], sh[t + s]);
        __syncthreads();
    }
    float r = sh[0]; __syncthreads();
    return r;
}

// ---------------------------------------------------------------------------
// Elementwise kernels
// ---------------------------------------------------------------------------
__global__ __launch_bounds__(256) void conv_bf(
    const float* __restrict__ x, uint16_t* __restrict__ h,
    uint16_t* __restrict__ l, int n8)
{
    int i = blockIdx.x * 256 + threadIdx.x;
    if (i < n8) {
        const float4* x4 = reinterpret_cast<const float4*>(x);
        float4 a = x4[2 * i], b = x4[2 * i + 1];
        uint32_t h0, h1, h2, h3, l0, l1, l2, l3;
        split2(a.x, a.y, h0, l0);
        split2(a.z, a.w, h1, l1);
        split2(b.x, b.y, h2, l2);
        split2(b.z, b.w, h3, l3);
        reinterpret_cast<uint4*>(h)[i] = make_uint4(h0, h1, h2, h3);
        reinterpret_cast<uint4*>(l)[i] = make_uint4(l0, l1, l2, l3);
    }
}

__global__ __launch_bounds__(256) void pack_params(
    const float* __restrict__ ipb, const float* __restrict__ spb,
    const float* __restrict__ ifb, const float* __restrict__ sfb,
    const float* __restrict__ ig,  const float* __restrict__ sg,
    const float* __restrict__ ib,  const float* __restrict__ sb,
    float* __restrict__ pb, float* __restrict__ pfb,
    float* __restrict__ lng, float* __restrict__ lnb)
{
    int t = threadIdx.x;
    pb [t]        = ipb[t];  pb [t + PROJ] = spb[t];
    pfb[t]        = ifb[t];  pfb[t + PROJ] = sfb[t];
    lng[t]        = ig[t];   lng[t + PROJ] = sg[t];
    lnb[t]        = ib[t];   lnb[t + PROJ] = sb[t];
}

__global__ __launch_bounds__(256) void embed_kernel(
    const float* __restrict__ expr, const float* __restrict__ xt,
    const float* __restrict__ yt, const int* __restrict__ xi,
    const int* __restrict__ yi, float* __restrict__ out)
{
    int row = blockIdx.x;
    size_t xo = (size_t)xi[row] * SPOT;
    size_t yo = (size_t)yi[row] * SPOT;
    size_t ro = (size_t)row * SPOT;
    for (int j = threadIdx.x; j < SPOT; j += 256)
        out[ro + j] = expr[ro + j] + xt[xo + j] + yt[yo + j];
}

template<int N>
__global__ __launch_bounds__(256) void ln_bf(
    const float* __restrict__ x, const float* __restrict__ g,
    const float* __restrict__ b, uint16_t* __restrict__ oh,
    uint16_t* __restrict__ ol)
{
    __shared__ float sh[256];
    constexpr int NPAIR = N / 2;
    constexpr int NP = (NPAIR + 255) / 256;
    int row = blockIdx.x, tid = threadIdx.x;
    const float2* xr = reinterpret_cast<const float2*>(x + (size_t)row * N);
    float2 v[NP];
    float s = 0.f;
    #pragma unroll
    for (int i = 0; i < NP; i++) {
        int p = i * 256 + tid;
        if (p < NPAIR) { v[i] = xr[p]; s += v[i].x + v[i].y; }
        else v[i] = make_float2(0.f, 0.f);
    }
    s = blk_sum256(s, sh);
    float mean = s / N, ss = 0.f;
    #pragma unroll
    for (int i = 0; i < NP; i++) {
        int p = i * 256 + tid;
        if (p < NPAIR) {
            float dx = v[i].x - mean, dy = v[i].y - mean;
            ss += dx * dx + dy * dy;
        }
    }
    ss = blk_sum256(ss, sh);
    float rstd = rsqrtf(ss / N + 1e-5f);
    uint32_t* OH = reinterpret_cast<uint32_t*>(oh + (size_t)row * N);
    uint32_t* OL = reinterpret_cast<uint32_t*>(ol + (size_t)row * N);
    #pragma unroll
    for (int i = 0; i < NP; i++) {
        int p = i * 256 + tid;
        if (p < NPAIR) {
            float2 gg = reinterpret_cast<const float2*>(g)[p];
            float2 bb = reinterpret_cast<const float2*>(b)[p];
            float y0 = (v[i].x - mean) * rstd * gg.x + bb.x;
            float y1 = (v[i].y - mean) * rstd * gg.y + bb.y;
            uint32_t h, l;
            split2(y0, y1, h, l);
            OH[p] = h; OL[p] = l;
        }
    }
}

__global__ __launch_bounds__(256) void ln_bf2(
    const float* __restrict__ x, const float* __restrict__ g,
    const float* __restrict__ b, uint16_t* __restrict__ oh,
    uint16_t* __restrict__ ol)
{
    __shared__ float sh[256];
    constexpr int N = PROJ;
    int row = blockIdx.x, tid = threadIdx.x;
    int slot = row >> 11;
    const float* gs = g + slot * PROJ;
    const float* bs = b + slot * PROJ;
    const float2* xr = reinterpret_cast<const float2*>(x + (size_t)row * N);
    float2 v = make_float2(0.f, 0.f);
    if (tid < N / 2) v = xr[tid];
    float s = blk_sum256(v.x + v.y, sh);
    float mean = s / N;
    float ss = 0.f;
    if (tid < N / 2) {
        float dx = v.x - mean, dy = v.y - mean;
        ss = dx * dx + dy * dy;
    }
    ss = blk_sum256(ss, sh);
    float rstd = rsqrtf(ss / N + 1e-5f);
    if (tid < N / 2) {
        float2 gg = reinterpret_cast<const float2*>(gs)[tid];
        float2 bb = reinterpret_cast<const float2*>(bs)[tid];
        float y0 = (v.x - mean) * rstd * gg.x + bb.x;
        float y1 = (v.y - mean) * rstd * gg.y + bb.y;
        uint32_t h, l;
        split2(y0, y1, h, l);
        reinterpret_cast<uint32_t*>(oh + (size_t)row * N)[tid] = h;
        reinterpret_cast<uint32_t*>(ol + (size_t)row * N)[tid] = l;
    }
}

__global__ __launch_bounds__(256) void softmax_rowloss(
    float* __restrict__ tgt, const float* __restrict__ logits,
    float* __restrict__ rowp)
{
    __shared__ float sh[256];
    size_t row = blockIdx.x;
    int tid = threadIdx.x;
    float* tr = tgt + row * NB;
    const float* lr = logits + row * NB;
    float tv[8], lv[8];
    float mt = -1e30f, ml = -1e30f;
    #pragma unroll
    for (int i = 0; i < 8; i++) {
        tv[i] = tr[i * 256 + tid];
        lv[i] = lr[i * 256 + tid];
        mt = fmaxf(mt, tv[i]);
        ml = fmaxf(ml, lv[i]);
    }
    mt = blk_max256(mt, sh);
    float st = 0.f;
    #pragma unroll
    for (int i = 0; i < 8; i++) { tv[i] = __expf(tv[i] - mt); st += tv[i]; }
    st = blk_sum256(st, sh);
    float inv = 1.f / st;
    ml = blk_max256(ml, sh);
    float se = 0.f, dot = 0.f;
    #pragma unroll
    for (int i = 0; i < 8; i++) {
        tv[i] *= inv;
        tr[i * 256 + tid] = tv[i];
        se += __expf(lv[i] - ml);
        dot += tv[i] * lv[i];
    }
    se  = blk_sum256(se, sh);
    dot = blk_sum256(dot, sh);
    if (tid == 0) rowp[row] = 0.5f * (ml + logf(se) - dot);
}

__global__ __launch_bounds__(256) void pack_bf(
    const uint16_t* __restrict__ ih, const uint16_t* __restrict__ il,
    const uint16_t* __restrict__ eh, const uint16_t* __restrict__ el,
    uint16_t* __restrict__ ch, uint16_t* __restrict__ cl)
{
    int row = blockIdx.x, tid = threadIdx.x;
    const uint32_t* IH = reinterpret_cast<const uint32_t*>(ih + (size_t)row * PROJ);
    const uint32_t* IL = reinterpret_cast<const uint32_t*>(il + (size_t)row * PROJ);
    const uint32_t* EH = reinterpret_cast<const uint32_t*>(eh + (size_t)row * PROJ);
    const uint32_t* EL = reinterpret_cast<const uint32_t*>(el + (size_t)row * PROJ);
    uint32_t vh, vl;
    if (tid < 128) { vh = IH[tid]; vl = IL[tid]; }
    else           { vh = EH[tid - 128]; vl = EL[tid - 128]; }
    reinterpret_cast<uint32_t*>(ch + (size_t)row * 2 * PROJ)[tid] = vh;
    reinterpret_cast<uint32_t*>(cl + (size_t)row * 2 * PROJ)[tid] = vl;
}

__global__ __launch_bounds__(256) void colloss_kernel(
    const float* __restrict__ logits, const float* __restrict__ tgt,
    float* __restrict__ colp)
{
    __shared__ float smx[256], sse[256], sts[256], stdot[256];
    int tid = threadIdx.x;
    int c = blockIdx.x * 64 + (tid & 63);
    int ry = tid >> 6;
    float mx = -1e30f, se = 0.f, ts = 0.f, td = 0.f;
    for (int r = ry; r < NB; r += 4) {
        float l = logits[(size_t)r * NB + c];
        float t = tgt   [(size_t)r * NB + c];
        if (l > mx) { se = se * __expf(mx - l) + 1.f; mx = l; }
        else        { se += __expf(l - mx); }
        ts += t;
        td += t * l;
    }
    smx[tid] = mx; sse[tid] = se; sts[tid] = ts; stdot[tid] = td;
    __syncthreads();
    if (ry == 0) {
        #pragma unroll
        for (int k = 1; k < 4; k++) {
            int o = tid + k * 64;
            float m2 = smx[o], s2 = sse[o];
            float m = fmaxf(mx, m2);
            se = se * __expf(mx - m) + s2 * __expf(m2 - m);
            mx = m;
            ts += sts[o];
            td += stdot[o];
        }
        colp[c] = 0.5f * (ts * (mx + logf(se)) - td);
    }
}

__global__ __launch_bounds__(256) void final_reduce(
    const float* __restrict__ a, const float* __restrict__ b,
    float* __restrict__ out)
{
    __shared__ float sh[256];
    int tid = threadIdx.x;
    float s = 0.f;
    for (int i = tid; i < NB; i += 256) s += a[i] + b[i];
    s = blk_sum256(s, sh);
    if (tid == 0) out[0] = s * (1.0f / NB);
}

// ---------------------------------------------------------------------------
// Host launch
// ---------------------------------------------------------------------------
namespace {
constexpr int SMEM_STD = 3 * (2 * 128 * 72 * 2 + 2 * 64 * 136 * 2);   // 215040
constexpr int SMEM_NAT = 3 * (2 * 128 * 72 * 2 + 2 * 128 * 72 * 2);   // 221184
constexpr int SMEM_64  = 3 * (2 * 128 * 72 * 2 + 2 * 64 * 72 * 2);    // 165888
constexpr int SMEM_FLASH = 2 * (128 * 72 * 2) + 2 * 4 * (128 * 72 * 2)
                         + 2 * 256 * 4;                                // 186368
}

#define SYM(var, sym) cudaGetSymbolAddress((void**)&var, sym)

extern "C" void kernel_launch(void* const* d_in, const int* in_sizes, int n_in,
                              void* d_out, int out_size)
{
    (void)in_sizes; (void)n_in; (void)out_size;
    const float* image_features = (const float*)d_in[0];
    const float* expression     = (const float*)d_in[1];
    const float* x_table        = (const float*)d_in[2];
    const float* y_table        = (const float*)d_in[3];
    const float* ln1_g          = (const float*)d_in[4];
    const float* ln1_b          = (const float*)d_in[5];
    const float* w_qkv          = (const float*)d_in[6];
    const float* w_o            = (const float*)d_in[7];
    const float* b_o            = (const float*)d_in[8];
    const float* ln2_g          = (const float*)d_in[9];
    const float* ln2_b          = (const float*)d_in[10];
    const float* w1             = (const float*)d_in[11];
    const float* b1             = (const float*)d_in[12];
    const float* w2             = (const float*)d_in[13];
    const float* b2             = (const float*)d_in[14];
    const float* img_proj_w     = (const float*)d_in[15];
    const float* img_proj_b     = (const float*)d_in[16];
    const float* img_fc_w       = (const float*)d_in[17];
    const float* img_fc_b       = (const float*)d_in[18];
    const float* img_ln_g       = (const float*)d_in[19];
    const float* img_ln_b       = (const float*)d_in[20];
    const float* spot_proj_w    = (const float*)d_in[21];
    const float* spot_proj_b    = (const float*)d_in[22];
    const float* spot_fc_w      = (const float*)d_in[23];
    const float* spot_fc_b      = (const float*)d_in[24];
    const float* spot_ln_g      = (const float*)d_in[25];
    const float* spot_ln_b      = (const float*)d_in[26];
    const int*   x_idx          = (const int*)d_in[27];
    const int*   y_idx          = (const int*)d_in[28];
    float* out = (float*)d_out;

    float *spot, *pp, *tmp2, *logits, *tgt, *rowp, *colp, *pb, *pfb, *lng, *lnb;
    SYM(spot, g_spot); SYM(pp, g_pp); SYM(tmp2, g_tmp2);
    SYM(logits, g_logits); SYM(tgt, g_tgt); SYM(rowp, g_rowp); SYM(colp, g_colp);
    SYM(pb, g_pb); SYM(pfb, g_pfb); SYM(lng, g_lng); SYM(lnb, g_lnb);

    uint16_t *hbh, *hbl, *qkh, *qkl, *ath, *atl, *mph, *mpl;
    uint16_t *pinh, *pinl, *pgh, *pgl, *eh, *el, *cth, *ctl;
    SYM(hbh, g_hbuf_h); SYM(hbl, g_hbuf_l);
    SYM(qkh, g_qkv_h);  SYM(qkl, g_qkv_l);
    SYM(ath, g_attn_h); SYM(atl, g_attn_l);
    SYM(mph, g_mlp_h);  SYM(mpl, g_mlp_l);
    SYM(pinh, g_pin_h); SYM(pinl, g_pin_l);
    SYM(pgh, g_pg_h);   SYM(pgl, g_pg_l);
    SYM(eh, g_e_h);     SYM(el, g_e_l);
    SYM(cth, g_cat_h);  SYM(ctl, g_cat_l);

    uint16_t *wqh, *wql, *woh, *wol, *w1h, *w1l, *w2h, *w2l;
    uint16_t *pwh, *pwl, *pfwh, *pfwl;
    SYM(wqh, g_wqkv_h); SYM(wql, g_wqkv_l);
    SYM(woh, g_wo_h);   SYM(wol, g_wo_l);
    SYM(w1h, g_w1_h);   SYM(w1l, g_w1_l);
    SYM(w2h, g_w2_h);   SYM(w2l, g_w2_l);
    SYM(pwh, g_pw_h);   SYM(pwl, g_pw_l);
    SYM(pfwh, g_pfw_h); SYM(pfwl, g_pfw_l);

    auto kQKV  = gemm_bf<64,  false, 0, 2>;        // NT=64: 384 CTAs
    auto kSqk  = gemm_bf<128, true,  0, 1>;
    auto kSymG = gemm_bf<128, true,  0, 1, true>;  // symmetric gram
    auto kRes  = gemm_bf<128, false, 3, 1>;
    auto kResO = gemm_bf<128, false, 3, 3>;
    auto kMlp1 = gemm_bf<128, false, 2, 2>;
    auto kProj = gemm_bf<64,  false, 1, 7>;
    auto kResP = gemm_bf<64,  false, 3, 1>;
    cudaFuncSetAttribute(kQKV,  cudaFuncAttributeMaxDynamicSharedMemorySize, SMEM_64);
    cudaFuncSetAttribute(kSqk,  cudaFuncAttributeMaxDynamicSharedMemorySize, SMEM_NAT);
    cudaFuncSetAttribute(kSymG, cudaFuncAttributeMaxDynamicSharedMemorySize, SMEM_NAT);
    cudaFuncSetAttribute(kRes,  cudaFuncAttributeMaxDynamicSharedMemorySize, SMEM_STD);
    cudaFuncSetAttribute(kResO, cudaFuncAttributeMaxDynamicSharedMemorySize, SMEM_STD);
    cudaFuncSetAttribute(kMlp1, cudaFuncAttributeMaxDynamicSharedMemorySize, SMEM_STD);
    cudaFuncSetAttribute(kProj, cudaFuncAttributeMaxDynamicSharedMemorySize, SMEM_64);
    cudaFuncSetAttribute(kResP, cudaFuncAttributeMaxDynamicSharedMemorySize, SMEM_64);
    cudaFuncSetAttribute(flash_attn,
                         cudaFuncAttributeMaxDynamicSharedMemorySize, SMEM_FLASH);

    auto CONV = [&](const float* src, uint16_t* h, uint16_t* l, int n) {
        int n8 = n / 8;
        conv_bf<<<(n8 + 255) / 256, 256>>>(src, h, l, n8);
    };
    CONV(w_qkv, wqh, wql, NL * SPOT * QKVW);
    CONV(w_o,   woh, wol, NL * INNER * SPOT);
    CONV(w1,    w1h, w1l, NL * SPOT * MLPD);
    CONV(w2,    w2h, w2l, NL * MLPD * SPOT);
    CONV(img_proj_w,  pwh, pwl, IMG * PROJ);
    CONV(spot_proj_w, pwh + 1024 * PROJ, pwl + 1024 * PROJ, SPOT * PROJ);
    CONV(img_fc_w,  pfwh, pfwl, PROJ * PROJ);
    CONV(spot_fc_w, pfwh + PROJ * PROJ, pfwl + PROJ * PROJ, PROJ * PROJ);
    CONV(image_features, pinh, pinl, NB * IMG);
    pack_params<<<1, 256>>>(img_proj_b, spot_proj_b, img_fc_b, spot_fc_b,
                            img_ln_g, spot_ln_g, img_ln_b, spot_ln_b,
                            pb, pfb, lng, lnb);

    embed_kernel<<<NB, 256>>>(expression, x_table, y_table, x_idx, y_idx, spot);

    for (int l = 0; l < NL; l++) {
        uint16_t* wqh_l = wqh + (size_t)l * SPOT * QKVW;
        uint16_t* wql_l = wql + (size_t)l * SPOT * QKVW;
        uint16_t* woh_l = woh + (size_t)l * INNER * SPOT;
        uint16_t* wol_l = wol + (size_t)l * INNER * SPOT;
        uint16_t* w1h_l = w1h + (size_t)l * SPOT * MLPD;
        uint16_t* w1l_l = w1l + (size_t)l * SPOT * MLPD;
        uint16_t* w2h_l = w2h + (size_t)l * MLPD * SPOT;
        uint16_t* w2l_l = w2l + (size_t)l * MLPD * SPOT;

        ln_bf<SPOT><<<NB, 256>>>(spot, ln1_g + l * SPOT, ln1_b + l * SPOT, hbh, hbl);
        kQKV<<<dim3(QKVW / 64, NB / 128, 1), 512, SMEM_64>>>(
            hbh, hbl, SPOT, 0, wqh_l, wql_l, QKVW, 0,
            nullptr, 0, nullptr, 0,
            nullptr, qkh, qkl, QKVW, 0, SPOT, 1.f);
        flash_attn<<<dim3(NB / 128, NH), 512, SMEM_FLASH>>>(qkh, qkl, ath, atl);
        kRes<<<dim3(SPOT / 128, NB / 128, 1), 512, SMEM_STD>>>(
            ath, atl, INNER, 0, woh_l, wol_l, SPOT, 0,
            b_o + l * SPOT, 0, spot, 0,
            spot, nullptr, nullptr, SPOT, 0, INNER, 1.f);
        ln_bf<SPOT><<<NB, 256>>>(spot, ln2_g + l * SPOT, ln2_b + l * SPOT, hbh, hbl);
        kMlp1<<<dim3(MLPD / 128, NB / 128, 1), 512, SMEM_STD>>>(
            hbh, hbl, SPOT, 0, w1h_l, w1l_l, MLPD, 0,
            b1 + l * MLPD, 0, nullptr, 0,
            nullptr, mph, mpl, MLPD, 0, SPOT, 1.f);
        if (l == NL - 1) {
            kResO<<<dim3(SPOT / 128, NB / 128, 1), 512, SMEM_STD>>>(
                mph, mpl, MLPD, 0, w2h_l, w2l_l, SPOT, 0,
                b2 + l * SPOT, 0, spot, 0,
                spot, pinh + (size_t)NB * 1024, pinl + (size_t)NB * 1024,
                SPOT, 0, MLPD, 1.f);
        } else {
            kRes<<<dim3(SPOT / 128, NB / 128, 1), 512, SMEM_STD>>>(
                mph, mpl, MLPD, 0, w2h_l, w2l_l, SPOT, 0,
                b2 + l * SPOT, 0, spot, 0,
                spot, nullptr, nullptr, SPOT, 0, MLPD, 1.f);
        }
    }

    // ---- batched projection heads (z = 0:img, 1:spot)
    kProj<<<dim3(PROJ / 64, NB / 128, 2), 512, SMEM_64>>>(
        pinh, pinl, 1024, (long long)NB * 1024,
        pwh, pwl, PROJ, (long long)1024 * PROJ,
        pb, PROJ, nullptr, 0,
        pp, pgh, pgl, PROJ, (long long)NB * PROJ, 1024, 1.f);
    kResP<<<dim3(PROJ / 64, NB / 128, 2), 512, SMEM_64>>>(
        pgh, pgl, PROJ, (long long)NB * PROJ,
        pfwh, pfwl, PROJ, (long long)PROJ * PROJ,
        pfb, PROJ, pp, (long long)NB * PROJ,
        tmp2, nullptr, nullptr, PROJ, (long long)NB * PROJ, PROJ, 1.f);
    ln_bf2<<<2 * NB, 256>>>(tmp2, lng, lnb, eh, el);

    // ---- loss
    pack_bf<<<NB, 256>>>(eh, el, eh + (size_t)NB * PROJ, el + (size_t)NB * PROJ,
                         cth, ctl);
    kSqk<<<dim3(NB / 128, NB / 128, 1), 512, SMEM_NAT>>>(
        eh + (size_t)NB * PROJ, el + (size_t)NB * PROJ, PROJ, 0,
        eh, el, PROJ, 0,
        nullptr, 0, nullptr, 0,
        logits, nullptr, nullptr, NB, 0, PROJ, 1.f);
    kSymG<<<dim3(NB / 128, NB / 128, 1), 512, SMEM_NAT>>>(
        cth, ctl, 2 * PROJ, 0, cth, ctl, 2 * PROJ, 0,
        nullptr, 0, nullptr, 0,
        tgt, nullptr, nullptr, NB, 0, 2 * PROJ, 0.5f);
    softmax_rowloss<<<NB, 256>>>(tgt, logits, rowp);
    colloss_kernel<<<NB / 64, 256>>>(logits, tgt, colp);
    final_reduce<<<1, 256>>>(rowp, colp, out);
}

// round 13
// speedup vs baseline: 1.5281x; 1.0531x over previous
#include <cuda_runtime.h>
#include <cstdint>

// ---------------------------------------------------------------------------
// Problem constants
// ---------------------------------------------------------------------------
namespace {
constexpr int NB   = 2048;
constexpr int SPOT = 1024;
constexpr int IMG  = 1024;
constexpr int PROJ = 256;
constexpr int NH   = 8;
constexpr int DH   = 64;
constexpr int INNER = 512;
constexpr int MLPD = 2048;
constexpr int QKVW = 1536;
constexpr int NL   = 2;
}

// ---------------------------------------------------------------------------
// Scratch: fp32
// ---------------------------------------------------------------------------
__device__ float g_spot  [NB * SPOT];
__device__ float g_pp    [2 * NB * PROJ];
__device__ float g_tmp2  [2 * NB * PROJ];
__device__ float g_logits[NB * NB];
__device__ float g_tgt   [NB * NB];
__device__ float g_rowp  [NB];
__device__ float g_colp  [NB];
__device__ float g_pb    [2 * PROJ];
__device__ float g_pfb   [2 * PROJ];
__device__ float g_lng   [2 * PROJ];
__device__ float g_lnb   [2 * PROJ];
__device__ float g_cmx [8 * NB], g_cse [8 * NB];
__device__ float g_cts [8 * NB], g_ctd [8 * NB];

// ---------------------------------------------------------------------------
// Scratch: bf16 hi/lo
// ---------------------------------------------------------------------------
__device__ uint16_t g_hbuf_h[NB * SPOT],  g_hbuf_l[NB * SPOT];
__device__ uint16_t g_qkv_h [NB * QKVW],  g_qkv_l [NB * QKVW];
__device__ uint16_t g_attn_h[NB * INNER], g_attn_l[NB * INNER];
__device__ uint16_t g_mlp_h [NB * MLPD],  g_mlp_l [NB * MLPD];
__device__ uint16_t g_pin_h[2 * NB * 1024], g_pin_l[2 * NB * 1024];
__device__ uint16_t g_pg_h [2 * NB * PROJ], g_pg_l [2 * NB * PROJ];
__device__ uint16_t g_e_h  [2 * NB * PROJ], g_e_l  [2 * NB * PROJ];
__device__ uint16_t g_cat_h[NB * 2 * PROJ], g_cat_l[NB * 2 * PROJ];
// weights bf16
__device__ uint16_t g_wqkv_h[NL * SPOT * QKVW], g_wqkv_l[NL * SPOT * QKVW];
__device__ uint16_t g_wo_h  [NL * INNER * SPOT], g_wo_l [NL * INNER * SPOT];
__device__ uint16_t g_w1_h  [NL * SPOT * MLPD],  g_w1_l [NL * SPOT * MLPD];
__device__ uint16_t g_w2_h  [NL * MLPD * SPOT],  g_w2_l [NL * MLPD * SPOT];
__device__ uint16_t g_pw_h [2 * 1024 * PROJ], g_pw_l [2 * 1024 * PROJ];
__device__ uint16_t g_pfw_h[2 * PROJ * PROJ], g_pfw_l[2 * PROJ * PROJ];

// ---------------------------------------------------------------------------
// Helpers
// ---------------------------------------------------------------------------
__device__ __forceinline__ uint32_t smem_u32(const void* p) {
    uint32_t a;
    asm("{ .reg .u64 t; cvta.to.shared.u64 t, %1; cvt.u32.u64 %0, t; }"
        : "=r"(a) : "l"(p));
    return a;
}
__device__ __forceinline__ unsigned long long gptr(const void* p) {
    return (unsigned long long)__cvta_generic_to_global(p);
}
__device__ __forceinline__ float gelu_f(float x) {
    return 0.5f * x * (1.0f + erff(x * 0.7071067811865475f));
}
__device__ __forceinline__ void split2(float f0, float f1, uint32_t& hi, uint32_t& lo) {
    asm("cvt.rn.bf16x2.f32 %0, %1, %2;" : "=r"(hi) : "f"(f1), "f"(f0));
    float h0 = __uint_as_float(hi << 16);
    float h1 = __uint_as_float(hi & 0xFFFF0000u);
    float l0 = f0 - h0, l1 = f1 - h1;
    asm("cvt.rn.bf16x2.f32 %0, %1, %2;" : "=r"(lo) : "f"(l1), "f"(l0));
}

#define CP16(dst, src) \
    asm volatile("cp.async.cg.shared.global [%0], [%1], 16;" :: "r"(dst), "l"(src))
#define CP_COMMIT() asm volatile("cp.async.commit_group;" ::: "memory")
#define CP_WAIT1()  asm volatile("cp.async.wait_group 1;" ::: "memory")
#define CP_WAIT0()  asm volatile("cp.async.wait_group 0;" ::: "memory")

#define LDSM_X4(r, a)                                                          \
    asm volatile("ldmatrix.sync.aligned.m8n8.x4.shared.b16 {%0,%1,%2,%3}, [%4];" \
        : "=r"((r)[0]), "=r"((r)[1]), "=r"((r)[2]), "=r"((r)[3]) : "r"(a))
#define LDSM_X4T(r, a)                                                         \
    asm volatile("ldmatrix.sync.aligned.m8n8.x4.trans.shared.b16 {%0,%1,%2,%3}, [%4];" \
        : "=r"((r)[0]), "=r"((r)[1]), "=r"((r)[2]), "=r"((r)[3]) : "r"(a))
#define MMA16816(d, a, b)                                                      \
    asm volatile("mma.sync.aligned.m16n8k16.row.col.f32.bf16.bf16.f32 "        \
        "{%0,%1,%2,%3}, {%4,%5,%6,%7}, {%8,%9}, {%0,%1,%2,%3};"                \
        : "+f"((d)[0]), "+f"((d)[1]), "+f"((d)[2]), "+f"((d)[3])               \
        : "r"((a)[0]), "r"((a)[1]), "r"((a)[2]), "r"((a)[3]),                  \
          "r"((b)[0]), "r"((b)[1]))

// ---------------------------------------------------------------------------
// Pure-bf16 split GEMM (unchanged from R12).
// ---------------------------------------------------------------------------
template<int NT, bool BNAT, int EPI, int OUT, bool SYMW = false>
__global__ __launch_bounds__(512) void gemm_bf(
    const uint16_t* __restrict__ Ah, const uint16_t* __restrict__ Al,
    int lda, long long az,
    const uint16_t* __restrict__ Bh, const uint16_t* __restrict__ Bl,
    int ldb, long long bz,
    const float* __restrict__ bias, long long biasz,
    const float* __restrict__ res, long long resz,
    float* __restrict__ C, uint16_t* __restrict__ Ch, uint16_t* __restrict__ Cl,
    int ldc, long long cz, int K, float scale)
{
    if (SYMW && (int)blockIdx.x < (int)blockIdx.y) return;

    constexpr int WNC = NT / 4;
    constexpr int NTL = WNC / 8;
    constexpr int MT  = 2;
    constexpr int RS  = 72;
    constexpr int ABYTES = 128 * RS * 2;
    constexpr int BRS  = BNAT ? RS : (NT + 8);
    constexpr int BROWS = BNAT ? NT : 64;
    constexpr int BBYTES = BROWS * BRS * 2;
    constexpr int STAGE  = 2 * ABYTES + 2 * BBYTES;
    constexpr int STAGES = 3;
    constexpr int BSEGROW = NT / 8;
    constexpr int BSEGS = BNAT ? NT * 8 : 64 * BSEGROW;
    constexpr int BIT = (BSEGS + 511) / 512;

    extern __shared__ __align__(128) char smm[];
    const uint32_t sb = smem_u32(smm);
    const int tid = threadIdx.x, lane = tid & 31, wid = tid >> 5;
    const int wm = wid >> 2, wn = wid & 3;
    const int bm = blockIdx.y * 128, bn = blockIdx.x * NT;

    const uint16_t* Abh = Ah + (size_t)blockIdx.z * az + (size_t)bm * lda;
    const uint16_t* Abl = Al + (size_t)blockIdx.z * az + (size_t)bm * lda;
    const uint16_t* Bbh = Bh + (size_t)blockIdx.z * bz;
    const uint16_t* Bbl = Bl + (size_t)blockIdx.z * bz;
    const float* biasb = bias ? bias + (size_t)blockIdx.z * biasz : nullptr;
    const float* resb  = res  ? res  + (size_t)blockIdx.z * resz  : nullptr;

    float acc[MT][NTL][4];
    #pragma unroll
    for (int mt = 0; mt < MT; mt++)
        #pragma unroll
        for (int nt = 0; nt < NTL; nt++)
            #pragma unroll
            for (int r = 0; r < 4; r++) acc[mt][nt][r] = 0.f;

    const int NC = K >> 6;

    auto issue = [&](int c, int s) {
        const uint32_t st = sb + s * STAGE;
        const int k0 = c << 6;
        #pragma unroll
        for (int j = 0; j < 2; j++) {
            int idx = tid + j * 512;
            int row = idx >> 3, seg = idx & 7;
            size_t so = (size_t)row * lda + k0 + seg * 8;
            uint32_t d = st + row * (RS * 2) + seg * 16;
            CP16(d, gptr(Abh + so));
            CP16(d + ABYTES, gptr(Abl + so));
        }
        #pragma unroll
        for (int j = 0; j < BIT; j++) {
            int idx = tid + j * 512;
            if (BSEGS >= 512 * (j + 1) || idx < BSEGS) {
                if (BNAT) {
                    int row = idx >> 3, seg = idx & 7;
                    size_t so = (size_t)(bn + row) * ldb + k0 + seg * 8;
                    uint32_t d = st + 2 * ABYTES + row * (RS * 2) + seg * 16;
                    CP16(d, gptr(Bbh + so));
                    CP16(d + BBYTES, gptr(Bbl + so));
                } else {
                    int row = idx / BSEGROW, seg = idx % BSEGROW;
                    size_t so = (size_t)(k0 + row) * ldb + bn + seg * 8;
                    uint32_t d = st + 2 * ABYTES + row * (BRS * 2) + seg * 16;
                    CP16(d, gptr(Bbh + so));
                    CP16(d + BBYTES, gptr(Bbl + so));
                }
            }
        }
    };

    #pragma unroll
    for (int s = 0; s < STAGES - 1; s++) {
        if (s < NC) issue(s, s);
        CP_COMMIT();
    }

    for (int c = 0; c < NC; c++) {
        CP_WAIT1();
        __syncthreads();
        {
            int cn = c + STAGES - 1;
            if (cn < NC) issue(cn, cn % STAGES);
            CP_COMMIT();
        }
        const uint32_t abh_ = sb + (c % STAGES) * STAGE;
        const uint32_t abl_ = abh_ + ABYTES;
        const uint32_t bbh_ = abh_ + 2 * ABYTES;
        const uint32_t bbl_ = bbh_ + BBYTES;
        #pragma unroll
        for (int ks = 0; ks < 4; ks++) {
            uint32_t afh[MT][4], afl[MT][4], bfh[NTL][2], bfl[NTL][2];
            #pragma unroll
            for (int mt = 0; mt < MT; mt++) {
                uint32_t off = ((wm * 32 + mt * 16 + (lane & 15)) * RS +
                                ks * 16 + ((lane >> 4) << 3)) << 1;
                LDSM_X4(afh[mt], abh_ + off);
                LDSM_X4(afl[mt], abl_ + off);
            }
            #pragma unroll
            for (int p = 0; p < NTL / 2; p++) {
                uint32_t rh[4], rl[4];
                if (BNAT) {
                    int grp = lane >> 3;
                    int row = wn * WNC + p * 16 + (grp >> 1) * 8 + (lane & 7);
                    int koff = ks * 16 + (grp & 1) * 8;
                    uint32_t off = ((uint32_t)(row * RS + koff)) << 1;
                    LDSM_X4(rh, bbh_ + off);
                    LDSM_X4(rl, bbl_ + off);
                    bfh[2 * p][0] = rh[0]; bfh[2 * p][1] = rh[1];
                    bfh[2 * p + 1][0] = rh[2]; bfh[2 * p + 1][1] = rh[3];
                    bfl[2 * p][0] = rl[0]; bfl[2 * p][1] = rl[1];
                    bfl[2 * p + 1][0] = rl[2]; bfl[2 * p + 1][1] = rl[3];
                } else {
                    int row = ks * 16 + (lane & 15);
                    int col = wn * WNC + p * 16 + ((lane >> 4) << 3);
                    uint32_t off = ((uint32_t)(row * BRS + col)) << 1;
                    LDSM_X4T(rh, bbh_ + off);
                    LDSM_X4T(rl, bbl_ + off);
                    bfh[2 * p][0] = rh[0]; bfh[2 * p][1] = rh[1];
                    bfh[2 * p + 1][0] = rh[2]; bfh[2 * p + 1][1] = rh[3];
                    bfl[2 * p][0] = rl[0]; bfl[2 * p][1] = rl[1];
                    bfl[2 * p + 1][0] = rl[2]; bfl[2 * p + 1][1] = rl[3];
                }
            }
            #pragma unroll
            for (int nt = 0; nt < NTL; nt++)
                #pragma unroll
                for (int mt = 0; mt < MT; mt++) {
                    MMA16816(acc[mt][nt], afh[mt], bfh[nt]);
                    MMA16816(acc[mt][nt], afh[mt], bfl[nt]);
                    MMA16816(acc[mt][nt], afl[mt], bfh[nt]);
                }
        }
    }

    const int gid = lane >> 2, tig = lane & 3;
    #pragma unroll
    for (int mt = 0; mt < MT; mt++) {
        #pragma unroll
        for (int nt = 0; nt < NTL; nt++) {
            int r0  = bm + wm * 32 + mt * 16 + gid;
            int col = bn + wn * WNC + nt * 8 + tig * 2;
            float2 v0 = make_float2(acc[mt][nt][0] * scale, acc[mt][nt][1] * scale);
            float2 v1 = make_float2(acc[mt][nt][2] * scale, acc[mt][nt][3] * scale);
            if (EPI >= 1) {
                float2 bb = *reinterpret_cast<const float2*>(&biasb[col]);
                v0.x += bb.x; v0.y += bb.y; v1.x += bb.x; v1.y += bb.y;
            }
            if (EPI == 2) {
                v0.x = gelu_f(v0.x); v0.y = gelu_f(v0.y);
                v1.x = gelu_f(v1.x); v1.y = gelu_f(v1.y);
            }
            if (EPI == 3) {
                float2 ra = *reinterpret_cast<const float2*>(
                    &resb[(size_t)r0 * ldc + col]);
                float2 rb = *reinterpret_cast<const float2*>(
                    &resb[(size_t)(r0 + 8) * ldc + col]);
                v0.x += ra.x; v0.y += ra.y; v1.x += rb.x; v1.y += rb.y;
            }
            size_t o0 = (size_t)r0 * ldc + col + (size_t)blockIdx.z * cz;
            size_t o1 = (size_t)(r0 + 8) * ldc + col + (size_t)blockIdx.z * cz;
            if (OUT & 1) {
                *reinterpret_cast<float2*>(&C[o0]) = v0;
                *reinterpret_cast<float2*>(&C[o1]) = v1;
                if (SYMW) {
                    C[(size_t)col * ldc + r0]           = v0.x;
                    C[(size_t)(col + 1) * ldc + r0]     = v0.y;
                    C[(size_t)col * ldc + r0 + 8]       = v1.x;
                    C[(size_t)(col + 1) * ldc + r0 + 8] = v1.y;
                }
            }
            if (OUT & 2) {
                float a0 = v0.x, a1 = v0.y, b0 = v1.x, b1 = v1.y;
                if (OUT & 4) {
                    a0 = gelu_f(a0); a1 = gelu_f(a1);
                    b0 = gelu_f(b0); b1 = gelu_f(b1);
                }
                uint32_t h, l;
                split2(a0, a1, h, l);
                *reinterpret_cast<uint32_t*>(&Ch[o0]) = h;
                *reinterpret_cast<uint32_t*>(&Cl[o0]) = l;
                split2(b0, b1, h, l);
                *reinterpret_cast<uint32_t*>(&Ch[o1]) = h;
                *reinterpret_cast<uint32_t*>(&Cl[o1]) = l;
            }
        }
    }
}

// ---------------------------------------------------------------------------
// Fused flash attention v3 (unchanged).
// ---------------------------------------------------------------------------
__global__ __launch_bounds__(512) void flash_attn(
    const uint16_t* __restrict__ qh, const uint16_t* __restrict__ ql,
    uint16_t* __restrict__ oh, uint16_t* __restrict__ ol)
{
    constexpr int RS = 72;
    constexpr int TB = 128 * RS * 2;
    constexpr int KVSTAGE = 4 * TB;
    constexpr int PM_OFF = 2 * TB + 2 * KVSTAGE;
    extern __shared__ __align__(128) char smm[];
    const uint32_t sb  = smem_u32(smm);
    const uint32_t sQh = sb, sQl = sb + TB;
    float* pm = reinterpret_cast<float*>(smm + PM_OFF);
    const int tid = threadIdx.x, lane = tid & 31, w = tid >> 5;
    const int wq = w & 7, h2 = w >> 3;
    const int q0 = blockIdx.x * 128;
    const int h  = blockIdx.y;
    const int g = lane >> 2, t = lane & 3;

    #pragma unroll
    for (int j = 0; j < 2; j++) {
        int idx = tid + j * 512;
        int row = idx >> 3, seg = idx & 7;
        size_t so = (size_t)(q0 + row) * QKVW + h * 64 + seg * 8;
        uint32_t d = sb + row * (RS * 2) + seg * 16;
        CP16(d, gptr(qh + so));
        CP16(d + TB, gptr(ql + so));
    }
    auto issueKV = [&](int kt, int s) {
        uint32_t st = sb + 2 * TB + s * KVSTAGE;
        int tok0 = kt * 128;
        #pragma unroll
        for (int j = 0; j < 2; j++) {
            int idx = tid + j * 512;
            int row = idx >> 3, seg = idx & 7;
            size_t soK = (size_t)(tok0 + row) * QKVW + INNER + h * 64 + seg * 8;
            uint32_t dK = st + row * (RS * 2) + seg * 16;
            CP16(dK, gptr(qh + soK));
            CP16(dK + TB, gptr(ql + soK));
            size_t soV = soK + INNER;
            uint32_t dV = st + 2 * TB + row * (RS * 2) + seg * 16;
            CP16(dV, gptr(qh + soV));
            CP16(dV + TB, gptr(ql + soV));
        }
    };
    issueKV(0, 0);
    CP_COMMIT();

    float O[8][4];
    #pragma unroll
    for (int jt = 0; jt < 8; jt++)
        #pragma unroll
        for (int r = 0; r < 4; r++) O[jt][r] = 0.f;
    float m0 = -1e30f, m1 = -1e30f, l0 = 0.f, l1 = 0.f;

    for (int kt = 0; kt < NB / 128; kt++) {
        CP_WAIT0();
        __syncthreads();
        if (kt + 1 < NB / 128) {
            issueKV(kt + 1, (kt + 1) & 1);
            CP_COMMIT();
        }
        const uint32_t st  = sb + 2 * TB + (kt & 1) * KVSTAGE;
        const uint32_t sKh = st, sKl = st + TB;
        const uint32_t sVh = st + 2 * TB, sVl = st + 3 * TB;

        float sacc[8][4];
        #pragma unroll
        for (int j = 0; j < 8; j++)
            #pragma unroll
            for (int r = 0; r < 4; r++) sacc[j][r] = 0.f;

        #pragma unroll
        for (int kc = 0; kc < 4; kc++) {
            uint32_t aqh[4], aql[4];
            uint32_t aoff = ((wq * 16 + (lane & 15)) * RS +
                             kc * 16 + ((lane >> 4) << 3)) << 1;
            LDSM_X4(aqh, sQh + aoff);
            LDSM_X4(aql, sQl + aoff);
            #pragma unroll
            for (int jp = 0; jp < 4; jp++) {
                uint32_t rh[4], rl[4];
                uint32_t boff = ((h2 * 64 + jp * 16 + (lane & 15)) * RS +
                                 kc * 16 + ((lane >> 4) << 3)) << 1;
                LDSM_X4(rh, sKh + boff);
                LDSM_X4(rl, sKl + boff);
                uint32_t bh0[2] = {rh[0], rh[2]}, bh1[2] = {rh[1], rh[3]};
                uint32_t bl0[2] = {rl[0], rl[2]}, bl1[2] = {rl[1], rl[3]};
                MMA16816(sacc[2 * jp],     aqh, bh0);
                MMA16816(sacc[2 * jp],     aqh, bl0);
                MMA16816(sacc[2 * jp],     aql, bh0);
                MMA16816(sacc[2 * jp + 1], aqh, bh1);
                MMA16816(sacc[2 * jp + 1], aqh, bl1);
                MMA16816(sacc[2 * jp + 1], aql, bh1);
            }
        }

        float mx0 = -1e30f, mx1 = -1e30f;
        #pragma unroll
        for (int j = 0; j < 8; j++) {
            sacc[j][0] *= 0.125f; sacc[j][1] *= 0.125f;
            sacc[j][2] *= 0.125f; sacc[j][3] *= 0.125f;
            mx0 = fmaxf(mx0, fmaxf(sacc[j][0], sacc[j][1]));
            mx1 = fmaxf(mx1, fmaxf(sacc[j][2], sacc[j][3]));
        }
        mx0 = fmaxf(mx0, __shfl_xor_sync(0xffffffffu, mx0, 1));
        mx0 = fmaxf(mx0, __shfl_xor_sync(0xffffffffu, mx0, 2));
        mx1 = fmaxf(mx1, __shfl_xor_sync(0xffffffffu, mx1, 1));
        mx1 = fmaxf(mx1, __shfl_xor_sync(0xffffffffu, mx1, 2));
        float* pmc = pm + (kt & 1) * 256;
        if (t == 0) {
            pmc[h2 * 128 + wq * 16 + g]     = mx0;
            pmc[h2 * 128 + wq * 16 + g + 8] = mx1;
        }
        __syncthreads();
        float ox0 = pmc[(1 - h2) * 128 + wq * 16 + g];
        float ox1 = pmc[(1 - h2) * 128 + wq * 16 + g + 8];
        float nm0 = fmaxf(m0, fmaxf(mx0, ox0));
        float nm1 = fmaxf(m1, fmaxf(mx1, ox1));
        float a0 = __expf(m0 - nm0), a1 = __expf(m1 - nm1);
        m0 = nm0; m1 = nm1;
        float s0 = 0.f, s1 = 0.f;
        #pragma unroll
        for (int j = 0; j < 8; j++) {
            sacc[j][0] = __expf(sacc[j][0] - m0); s0 += sacc[j][0];
            sacc[j][1] = __expf(sacc[j][1] - m0); s0 += sacc[j][1];
            sacc[j][2] = __expf(sacc[j][2] - m1); s1 += sacc[j][2];
            sacc[j][3] = __expf(sacc[j][3] - m1); s1 += sacc[j][3];
        }
        s0 += __shfl_xor_sync(0xffffffffu, s0, 1);
        s0 += __shfl_xor_sync(0xffffffffu, s0, 2);
        s1 += __shfl_xor_sync(0xffffffffu, s1, 1);
        s1 += __shfl_xor_sync(0xffffffffu, s1, 2);
        l0 = l0 * a0 + s0;
        l1 = l1 * a1 + s1;
        #pragma unroll
        for (int jt = 0; jt < 8; jt++) {
            O[jt][0] *= a0; O[jt][1] *= a0;
            O[jt][2] *= a1; O[jt][3] *= a1;
        }

        #pragma unroll
        for (int kc = 0; kc < 4; kc++) {
            uint32_t ah[4], al[4];
            split2(sacc[2 * kc][0],     sacc[2 * kc][1],     ah[0], al[0]);
            split2(sacc[2 * kc][2],     sacc[2 * kc][3],     ah[1], al[1]);
            split2(sacc[2 * kc + 1][0], sacc[2 * kc + 1][1], ah[2], al[2]);
            split2(sacc[2 * kc + 1][2], sacc[2 * kc + 1][3], ah[3], al[3]);
            #pragma unroll
            for (int jp = 0; jp < 4; jp++) {
                uint32_t rh[4], rl[4];
                uint32_t boff = ((h2 * 64 + kc * 16 + (lane & 15)) * RS +
                                 jp * 16 + ((lane >> 4) << 3)) << 1;
                LDSM_X4T(rh, sVh + boff);
                LDSM_X4T(rl, sVl + boff);
                uint32_t bh0[2] = {rh[0], rh[1]}, bh1[2] = {rh[2], rh[3]};
                uint32_t bl0[2] = {rl[0], rl[1]}, bl1[2] = {rl[2], rl[3]};
                MMA16816(O[2 * jp],     ah, bh0);
                MMA16816(O[2 * jp],     ah, bl0);
                MMA16816(O[2 * jp],     al, bh0);
                MMA16816(O[2 * jp + 1], ah, bh1);
                MMA16816(O[2 * jp + 1], ah, bl1);
                MMA16816(O[2 * jp + 1], al, bh1);
            }
        }
    }

    __syncthreads();
    float* Ost = reinterpret_cast<float*>(smm + 2 * TB);
    float* lst = Ost + 128 * 66;
    if (h2 == 1) {
        #pragma unroll
        for (int jt = 0; jt < 8; jt++) {
            int c = jt * 8 + t * 2;
            Ost[(wq * 16 + g) * 66 + c]         = O[jt][0];
            Ost[(wq * 16 + g) * 66 + c + 1]     = O[jt][1];
            Ost[(wq * 16 + g + 8) * 66 + c]     = O[jt][2];
            Ost[(wq * 16 + g + 8) * 66 + c + 1] = O[jt][3];
        }
        if (t == 0) {
            lst[wq * 16 + g]     = l0;
            lst[wq * 16 + g + 8] = l1;
        }
    }
    __syncthreads();
    if (h2 == 0) {
        float i0 = 1.f / (l0 + lst[wq * 16 + g]);
        float i1 = 1.f / (l1 + lst[wq * 16 + g + 8]);
        #pragma unroll
        for (int jt = 0; jt < 8; jt++) {
            int c = jt * 8 + t * 2;
            float o00 = O[jt][0] + Ost[(wq * 16 + g) * 66 + c];
            float o01 = O[jt][1] + Ost[(wq * 16 + g) * 66 + c + 1];
            float o10 = O[jt][2] + Ost[(wq * 16 + g + 8) * 66 + c];
            float o11 = O[jt][3] + Ost[(wq * 16 + g + 8) * 66 + c + 1];
            uint32_t hh, ll;
            size_t o0 = (size_t)(q0 + wq * 16 + g) * INNER + h * 64 + c;
            split2(o00 * i0, o01 * i0, hh, ll);
            *reinterpret_cast<uint32_t*>(oh + o0) = hh;
            *reinterpret_cast<uint32_t*>(ol + o0) = ll;
            size_t o1 = o0 + (size_t)8 * INNER;
            split2(o10 * i1, o11 * i1, hh, ll);
            *reinterpret_cast<uint32_t*>(oh + o1) = hh;
            *reinterpret_cast<uint32_t*>(ol + o1) = ll;
        }
    }
}

// ---------------------------------------------------------------------------
// Reductions
// ---------------------------------------------------------------------------
__device__ __forceinline__ float blk_sum256(float v, float* sh) {
    int t = threadIdx.x;
    sh[t] = v; __syncthreads();
    #pragma unroll
    for (int s = 128; s >= 1; s >>= 1) {
        if (t < s) sh[t] += sh[t + s];
        __syncthreads();
    }
    float r = sh[0]; __syncthreads();
    return r;
}
__device__ __forceinline__ float blk_max256(float v, float* sh) {
    int t = threadIdx.x;
    sh[t] = v; __syncthreads();
    #pragma unroll
    for (int s = 128; s >= 1; s >>= 1) {
        if (t < s) sh[t] = fmaxf(sh[t], sh[t + s]);
        __syncthreads();
    }
    float r = sh[0]; __syncthreads();
    return r;
}

// ---------------------------------------------------------------------------
// Elementwise kernels
// ---------------------------------------------------------------------------
struct ConvSegs {
    const float* src[10];
    uint16_t* h[10];
    uint16_t* l[10];
    int base[11];   // prefix sums in 8-element units
};

__global__ __launch_bounds__(256) void conv_multi(ConvSegs s, int total8)
{
    int i = blockIdx.x * 256 + threadIdx.x;
    if (i >= total8) return;
    int k = 0;
    while (i >= s.base[k + 1]) k++;
    int off = i - s.base[k];
    const float4* x4 = reinterpret_cast<const float4*>(s.src[k]);
    float4 a = x4[2 * off], b = x4[2 * off + 1];
    uint32_t h0, h1, h2, h3, l0, l1, l2, l3;
    split2(a.x, a.y, h0, l0);
    split2(a.z, a.w, h1, l1);
    split2(b.x, b.y, h2, l2);
    split2(b.z, b.w, h3, l3);
    reinterpret_cast<uint4*>(s.h[k])[off] = make_uint4(h0, h1, h2, h3);
    reinterpret_cast<uint4*>(s.l[k])[off] = make_uint4(l0, l1, l2, l3);
}

__global__ __launch_bounds__(256) void pack_params(
    const float* __restrict__ ipb, const float* __restrict__ spb,
    const float* __restrict__ ifb, const float* __restrict__ sfb,
    const float* __restrict__ ig,  const float* __restrict__ sg,
    const float* __restrict__ ib,  const float* __restrict__ sb,
    float* __restrict__ pb, float* __restrict__ pfb,
    float* __restrict__ lng, float* __restrict__ lnb)
{
    int t = threadIdx.x;
    pb [t]        = ipb[t];  pb [t + PROJ] = spb[t];
    pfb[t]        = ifb[t];  pfb[t + PROJ] = sfb[t];
    lng[t]        = ig[t];   lng[t + PROJ] = sg[t];
    lnb[t]        = ib[t];   lnb[t + PROJ] = sb[t];
}

__global__ __launch_bounds__(256) void embed_kernel(
    const float* __restrict__ expr, const float* __restrict__ xt,
    const float* __restrict__ yt, const int* __restrict__ xi,
    const int* __restrict__ yi, float* __restrict__ out)
{
    int row = blockIdx.x, tid = threadIdx.x;
    const float4* e4 = reinterpret_cast<const float4*>(expr + (size_t)row * SPOT);
    const float4* x4 = reinterpret_cast<const float4*>(xt + (size_t)xi[row] * SPOT);
    const float4* y4 = reinterpret_cast<const float4*>(yt + (size_t)yi[row] * SPOT);
    float4 e = e4[tid], x = x4[tid], y = y4[tid];
    e.x += x.x + y.x; e.y += x.y + y.y;
    e.z += x.z + y.z; e.w += x.w + y.w;
    reinterpret_cast<float4*>(out + (size_t)row * SPOT)[tid] = e;
}

template<int N>
__global__ __launch_bounds__(256) void ln_bf(
    const float* __restrict__ x, const float* __restrict__ g,
    const float* __restrict__ b, uint16_t* __restrict__ oh,
    uint16_t* __restrict__ ol)
{
    __shared__ float sh[256];
    constexpr int NPAIR = N / 2;
    constexpr int NP = (NPAIR + 255) / 256;
    int row = blockIdx.x, tid = threadIdx.x;
    const float2* xr = reinterpret_cast<const float2*>(x + (size_t)row * N);
    float2 v[NP];
    float s = 0.f;
    #pragma unroll
    for (int i = 0; i < NP; i++) {
        int p = i * 256 + tid;
        if (p < NPAIR) { v[i] = xr[p]; s += v[i].x + v[i].y; }
        else v[i] = make_float2(0.f, 0.f);
    }
    s = blk_sum256(s, sh);
    float mean = s / N, ss = 0.f;
    #pragma unroll
    for (int i = 0; i < NP; i++) {
        int p = i * 256 + tid;
        if (p < NPAIR) {
            float dx = v[i].x - mean, dy = v[i].y - mean;
            ss += dx * dx + dy * dy;
        }
    }
    ss = blk_sum256(ss, sh);
    float rstd = rsqrtf(ss / N + 1e-5f);
    uint32_t* OH = reinterpret_cast<uint32_t*>(oh + (size_t)row * N);
    uint32_t* OL = reinterpret_cast<uint32_t*>(ol + (size_t)row * N);
    #pragma unroll
    for (int i = 0; i < NP; i++) {
        int p = i * 256 + tid;
        if (p < NPAIR) {
            float2 gg = reinterpret_cast<const float2*>(g)[p];
            float2 bb = reinterpret_cast<const float2*>(b)[p];
            float y0 = (v[i].x - mean) * rstd * gg.x + bb.x;
            float y1 = (v[i].y - mean) * rstd * gg.y + bb.y;
            uint32_t h, l;
            split2(y0, y1, h, l);
            OH[p] = h; OL[p] = l;
        }
    }
}

__global__ __launch_bounds__(256) void ln_bf2(
    const float* __restrict__ x, const float* __restrict__ g,
    const float* __restrict__ b, uint16_t* __restrict__ oh,
    uint16_t* __restrict__ ol)
{
    __shared__ float sh[256];
    constexpr int N = PROJ;
    int row = blockIdx.x, tid = threadIdx.x;
    int slot = row >> 11;
    const float* gs = g + slot * PROJ;
    const float* bs = b + slot * PROJ;
    const float2* xr = reinterpret_cast<const float2*>(x + (size_t)row * N);
    float2 v = make_float2(0.f, 0.f);
    if (tid < N / 2) v = xr[tid];
    float s = blk_sum256(v.x + v.y, sh);
    float mean = s / N;
    float ss = 0.f;
    if (tid < N / 2) {
        float dx = v.x - mean, dy = v.y - mean;
        ss = dx * dx + dy * dy;
    }
    ss = blk_sum256(ss, sh);
    float rstd = rsqrtf(ss / N + 1e-5f);
    if (tid < N / 2) {
        float2 gg = reinterpret_cast<const float2*>(gs)[tid];
        float2 bb = reinterpret_cast<const float2*>(bs)[tid];
        float y0 = (v.x - mean) * rstd * gg.x + bb.x;
        float y1 = (v.y - mean) * rstd * gg.y + bb.y;
        uint32_t h, l;
        split2(y0, y1, h, l);
        reinterpret_cast<uint32_t*>(oh + (size_t)row * N)[tid] = h;
        reinterpret_cast<uint32_t*>(ol + (size_t)row * N)[tid] = l;
    }
}

__global__ __launch_bounds__(256) void softmax_rowloss(
    float* __restrict__ tgt, const float* __restrict__ logits,
    float* __restrict__ rowp)
{
    __shared__ float sh[256];
    size_t row = blockIdx.x;
    int tid = threadIdx.x;
    float* tr = tgt + row * NB;
    const float* lr = logits + row * NB;
    float tv[8], lv[8];
    float mt = -1e30f, ml = -1e30f;
    #pragma unroll
    for (int i = 0; i < 8; i++) {
        tv[i] = tr[i * 256 + tid];
        lv[i] = lr[i * 256 + tid];
        mt = fmaxf(mt, tv[i]);
        ml = fmaxf(ml, lv[i]);
    }
    mt = blk_max256(mt, sh);
    float st = 0.f;
    #pragma unroll
    for (int i = 0; i < 8; i++) { tv[i] = __expf(tv[i] - mt); st += tv[i]; }
    st = blk_sum256(st, sh);
    float inv = 1.f / st;
    ml = blk_max256(ml, sh);
    float se = 0.f, dot = 0.f;
    #pragma unroll
    for (int i = 0; i < 8; i++) {
        tv[i] *= inv;
        tr[i * 256 + tid] = tv[i];
        se += __expf(lv[i] - ml);
        dot += tv[i] * lv[i];
    }
    se  = blk_sum256(se, sh);
    dot = blk_sum256(dot, sh);
    if (tid == 0) rowp[row] = 0.5f * (ml + logf(se) - dot);
}

__global__ __launch_bounds__(256) void pack_bf(
    const uint16_t* __restrict__ ih, const uint16_t* __restrict__ il,
    const uint16_t* __restrict__ eh, const uint16_t* __restrict__ el,
    uint16_t* __restrict__ ch, uint16_t* __restrict__ cl)
{
    int row = blockIdx.x, tid = threadIdx.x;
    const uint32_t* IH = reinterpret_cast<const uint32_t*>(ih + (size_t)row * PROJ);
    const uint32_t* IL = reinterpret_cast<const uint32_t*>(il + (size_t)row * PROJ);
    const uint32_t* EH = reinterpret_cast<const uint32_t*>(eh + (size_t)row * PROJ);
    const uint32_t* EL = reinterpret_cast<const uint32_t*>(el + (size_t)row * PROJ);
    uint32_t vh, vl;
    if (tid < 128) { vh = IH[tid]; vl = IL[tid]; }
    else           { vh = EH[tid - 128]; vl = EL[tid - 128]; }
    reinterpret_cast<uint32_t*>(ch + (size_t)row * 2 * PROJ)[tid] = vh;
    reinterpret_cast<uint32_t*>(cl + (size_t)row * 2 * PROJ)[tid] = vl;
}

// Column loss, phase 1: grid (NB/64, 8). Each block: 64 cols x 256 rows.
__global__ __launch_bounds__(256) void colloss_part(
    const float* __restrict__ logits, const float* __restrict__ tgt,
    float* __restrict__ cmx, float* __restrict__ cse,
    float* __restrict__ cts, float* __restrict__ ctd)
{
    __shared__ float smx[256], sse[256], sts[256], stdot[256];
    int tid = threadIdx.x;
    int c = blockIdx.x * 64 + (tid & 63);
    int ry = tid >> 6;
    int r0 = blockIdx.y * 256;
    float mx = -1e30f, se = 0.f, ts = 0.f, td = 0.f;
    for (int r = r0 + ry; r < r0 + 256; r += 4) {
        float l = logits[(size_t)r * NB + c];
        float t = tgt   [(size_t)r * NB + c];
        if (l > mx) { se = se * __expf(mx - l) + 1.f; mx = l; }
        else        { se += __expf(l - mx); }
        ts += t;
        td += t * l;
    }
    smx[tid] = mx; sse[tid] = se; sts[tid] = ts; stdot[tid] = td;
    __syncthreads();
    if (ry == 0) {
        #pragma unroll
        for (int k = 1; k < 4; k++) {
            int o = tid + k * 64;
            float m2 = smx[o], s2 = sse[o];
            float m = fmaxf(mx, m2);
            se = se * __expf(mx - m) + s2 * __expf(m2 - m);
            mx = m;
            ts += sts[o];
            td += stdot[o];
        }
        size_t idx = (size_t)blockIdx.y * NB + c;
        cmx[idx] = mx; cse[idx] = se; cts[idx] = ts; ctd[idx] = td;
    }
}

// Column loss, phase 2: deterministic merge of 8 partials per column.
__global__ __launch_bounds__(256) void colloss_fin(
    const float* __restrict__ cmx, const float* __restrict__ cse,
    const float* __restrict__ cts, const float* __restrict__ ctd,
    float* __restrict__ colp)
{
    int c = blockIdx.x * 256 + threadIdx.x;
    float mx = cmx[c], se = cse[c], ts = cts[c], td = ctd[c];
    #pragma unroll
    for (int k = 1; k < 8; k++) {
        size_t idx = (size_t)k * NB + c;
        float m2 = cmx[idx], s2 = cse[idx];
        float m = fmaxf(mx, m2);
        se = se * __expf(mx - m) + s2 * __expf(m2 - m);
        mx = m;
        ts += cts[idx];
        td += ctd[idx];
    }
    colp[c] = 0.5f * (ts * (mx + logf(se)) - td);
}

__global__ __launch_bounds__(256) void final_reduce(
    const float* __restrict__ a, const float* __restrict__ b,
    float* __restrict__ out)
{
    __shared__ float sh[256];
    int tid = threadIdx.x;
    float s = 0.f;
    for (int i = tid; i < NB; i += 256) s += a[i] + b[i];
    s = blk_sum256(s, sh);
    if (tid == 0) out[0] = s * (1.0f / NB);
}

// ---------------------------------------------------------------------------
// Host launch
// ---------------------------------------------------------------------------
namespace {
constexpr int SMEM_STD = 3 * (2 * 128 * 72 * 2 + 2 * 64 * 136 * 2);   // 215040
constexpr int SMEM_NAT = 3 * (2 * 128 * 72 * 2 + 2 * 128 * 72 * 2);   // 221184
constexpr int SMEM_64  = 3 * (2 * 128 * 72 * 2 + 2 * 64 * 72 * 2);    // 165888
constexpr int SMEM_FLASH = 2 * (128 * 72 * 2) + 2 * 4 * (128 * 72 * 2)
                         + 2 * 256 * 4;                                // 186368
}

#define SYM(var, sym) cudaGetSymbolAddress((void**)&var, sym)

extern "C" void kernel_launch(void* const* d_in, const int* in_sizes, int n_in,
                              void* d_out, int out_size)
{
    (void)in_sizes; (void)n_in; (void)out_size;
    const float* image_features = (const float*)d_in[0];
    const float* expression     = (const float*)d_in[1];
    const float* x_table        = (const float*)d_in[2];
    const float* y_table        = (const float*)d_in[3];
    const float* ln1_g          = (const float*)d_in[4];
    const float* ln1_b          = (const float*)d_in[5];
    const float* w_qkv          = (const float*)d_in[6];
    const float* w_o            = (const float*)d_in[7];
    const float* b_o            = (const float*)d_in[8];
    const float* ln2_g          = (const float*)d_in[9];
    const float* ln2_b          = (const float*)d_in[10];
    const float* w1             = (const float*)d_in[11];
    const float* b1             = (const float*)d_in[12];
    const float* w2             = (const float*)d_in[13];
    const float* b2             = (const float*)d_in[14];
    const float* img_proj_w     = (const float*)d_in[15];
    const float* img_proj_b     = (const float*)d_in[16];
    const float* img_fc_w       = (const float*)d_in[17];
    const float* img_fc_b       = (const float*)d_in[18];
    const float* img_ln_g       = (const float*)d_in[19];
    const float* img_ln_b       = (const float*)d_in[20];
    const float* spot_proj_w    = (const float*)d_in[21];
    const float* spot_proj_b    = (const float*)d_in[22];
    const float* spot_fc_w      = (const float*)d_in[23];
    const float* spot_fc_b      = (const float*)d_in[24];
    const float* spot_ln_g      = (const float*)d_in[25];
    const float* spot_ln_b      = (const float*)d_in[26];
    const int*   x_idx          = (const int*)d_in[27];
    const int*   y_idx          = (const int*)d_in[28];
    float* out = (float*)d_out;

    float *spot, *pp, *tmp2, *logits, *tgt, *rowp, *colp, *pb, *pfb, *lng, *lnb;
    float *cmx, *cse, *cts, *ctd;
    SYM(spot, g_spot); SYM(pp, g_pp); SYM(tmp2, g_tmp2);
    SYM(logits, g_logits); SYM(tgt, g_tgt); SYM(rowp, g_rowp); SYM(colp, g_colp);
    SYM(pb, g_pb); SYM(pfb, g_pfb); SYM(lng, g_lng); SYM(lnb, g_lnb);
    SYM(cmx, g_cmx); SYM(cse, g_cse); SYM(cts, g_cts); SYM(ctd, g_ctd);

    uint16_t *hbh, *hbl, *qkh, *qkl, *ath, *atl, *mph, *mpl;
    uint16_t *pinh, *pinl, *pgh, *pgl, *eh, *el, *cth, *ctl;
    SYM(hbh, g_hbuf_h); SYM(hbl, g_hbuf_l);
    SYM(qkh, g_qkv_h);  SYM(qkl, g_qkv_l);
    SYM(ath, g_attn_h); SYM(atl, g_attn_l);
    SYM(mph, g_mlp_h);  SYM(mpl, g_mlp_l);
    SYM(pinh, g_pin_h); SYM(pinl, g_pin_l);
    SYM(pgh, g_pg_h);   SYM(pgl, g_pg_l);
    SYM(eh, g_e_h);     SYM(el, g_e_l);
    SYM(cth, g_cat_h);  SYM(ctl, g_cat_l);

    uint16_t *wqh, *wql, *woh, *wol, *w1h, *w1l, *w2h, *w2l;
    uint16_t *pwh, *pwl, *pfwh, *pfwl;
    SYM(wqh, g_wqkv_h); SYM(wql, g_wqkv_l);
    SYM(woh, g_wo_h);   SYM(wol, g_wo_l);
    SYM(w1h, g_w1_h);   SYM(w1l, g_w1_l);
    SYM(w2h, g_w2_h);   SYM(w2l, g_w2_l);
    SYM(pwh, g_pw_h);   SYM(pwl, g_pw_l);
    SYM(pfwh, g_pfw_h); SYM(pfwl, g_pfw_l);

    auto kQKV  = gemm_bf<64,  false, 0, 2>;
    auto kSqk  = gemm_bf<128, true,  0, 1>;
    auto kSymG = gemm_bf<128, true,  0, 1, true>;
    auto kRes  = gemm_bf<128, false, 3, 1>;
    auto kResO = gemm_bf<128, false, 3, 3>;
    auto kMlp1 = gemm_bf<128, false, 2, 2>;
    auto kProj = gemm_bf<64,  false, 1, 7>;
    auto kResP = gemm_bf<64,  false, 3, 1>;
    cudaFuncSetAttribute(kQKV,  cudaFuncAttributeMaxDynamicSharedMemorySize, SMEM_64);
    cudaFuncSetAttribute(kSqk,  cudaFuncAttributeMaxDynamicSharedMemorySize, SMEM_NAT);
    cudaFuncSetAttribute(kSymG, cudaFuncAttributeMaxDynamicSharedMemorySize, SMEM_NAT);
    cudaFuncSetAttribute(kRes,  cudaFuncAttributeMaxDynamicSharedMemorySize, SMEM_STD);
    cudaFuncSetAttribute(kResO, cudaFuncAttributeMaxDynamicSharedMemorySize, SMEM_STD);
    cudaFuncSetAttribute(kMlp1, cudaFuncAttributeMaxDynamicSharedMemorySize, SMEM_STD);
    cudaFuncSetAttribute(kProj, cudaFuncAttributeMaxDynamicSharedMemorySize, SMEM_64);
    cudaFuncSetAttribute(kResP, cudaFuncAttributeMaxDynamicSharedMemorySize, SMEM_64);
    cudaFuncSetAttribute(flash_attn,
                         cudaFuncAttributeMaxDynamicSharedMemorySize, SMEM_FLASH);

    // ---- single batched weight/feature conversion
    {
        ConvSegs cs{};
        auto add = [&](int k, const float* s, uint16_t* h, uint16_t* l, int n) {
            cs.src[k] = s; cs.h[k] = h; cs.l[k] = l;
            cs.base[k + 1] = cs.base[k] + n / 8;
        };
        cs.base[0] = 0;
        add(0, w_qkv, wqh, wql, NL * SPOT * QKVW);
        add(1, w_o,   woh, wol, NL * INNER * SPOT);
        add(2, w1,    w1h, w1l, NL * SPOT * MLPD);
        add(3, w2,    w2h, w2l, NL * MLPD * SPOT);
        add(4, img_proj_w,  pwh, pwl, IMG * PROJ);
        add(5, spot_proj_w, pwh + 1024 * PROJ, pwl + 1024 * PROJ, SPOT * PROJ);
        add(6, img_fc_w,  pfwh, pfwl, PROJ * PROJ);
        add(7, spot_fc_w, pfwh + PROJ * PROJ, pfwl + PROJ * PROJ, PROJ * PROJ);
        add(8, image_features, pinh, pinl, NB * IMG);
        add(9, nullptr, nullptr, nullptr, 0);
        int total8 = cs.base[9];
        conv_multi<<<(total8 + 255) / 256, 256>>>(cs, total8);
    }
    pack_params<<<1, 256>>>(img_proj_b, spot_proj_b, img_fc_b, spot_fc_b,
                            img_ln_g, spot_ln_g, img_ln_b, spot_ln_b,
                            pb, pfb, lng, lnb);

    embed_kernel<<<NB, 256>>>(expression, x_table, y_table, x_idx, y_idx, spot);

    for (int l = 0; l < NL; l++) {
        uint16_t* wqh_l = wqh + (size_t)l * SPOT * QKVW;
        uint16_t* wql_l = wql + (size_t)l * SPOT * QKVW;
        uint16_t* woh_l = woh + (size_t)l * INNER * SPOT;
        uint16_t* wol_l = wol + (size_t)l * INNER * SPOT;
        uint16_t* w1h_l = w1h + (size_t)l * SPOT * MLPD;
        uint16_t* w1l_l = w1l + (size_t)l * SPOT * MLPD;
        uint16_t* w2h_l = w2h + (size_t)l * MLPD * SPOT;
        uint16_t* w2l_l = w2l + (size_t)l * MLPD * SPOT;

        ln_bf<SPOT><<<NB, 256>>>(spot, ln1_g + l * SPOT, ln1_b + l * SPOT, hbh, hbl);
        kQKV<<<dim3(QKVW / 64, NB / 128, 1), 512, SMEM_64>>>(
            hbh, hbl, SPOT, 0, wqh_l, wql_l, QKVW, 0,
            nullptr, 0, nullptr, 0,
            nullptr, qkh, qkl, QKVW, 0, SPOT, 1.f);
        flash_attn<<<dim3(NB / 128, NH), 512, SMEM_FLASH>>>(qkh, qkl, ath, atl);
        kRes<<<dim3(SPOT / 128, NB / 128, 1), 512, SMEM_STD>>>(
            ath, atl, INNER, 0, woh_l, wol_l, SPOT, 0,
            b_o + l * SPOT, 0, spot, 0,
            spot, nullptr, nullptr, SPOT, 0, INNER, 1.f);
        ln_bf<SPOT><<<NB, 256>>>(spot, ln2_g + l * SPOT, ln2_b + l * SPOT, hbh, hbl);
        kMlp1<<<dim3(MLPD / 128, NB / 128, 1), 512, SMEM_STD>>>(
            hbh, hbl, SPOT, 0, w1h_l, w1l_l, MLPD, 0,
            b1 + l * MLPD, 0, nullptr, 0,
            nullptr, mph, mpl, MLPD, 0, SPOT, 1.f);
        if (l == NL - 1) {
            kResO<<<dim3(SPOT / 128, NB / 128, 1), 512, SMEM_STD>>>(
                mph, mpl, MLPD, 0, w2h_l, w2l_l, SPOT, 0,
                b2 + l * SPOT, 0, spot, 0,
                spot, pinh + (size_t)NB * 1024, pinl + (size_t)NB * 1024,
                SPOT, 0, MLPD, 1.f);
        } else {
            kRes<<<dim3(SPOT / 128, NB / 128, 1), 512, SMEM_STD>>>(
                mph, mpl, MLPD, 0, w2h_l, w2l_l, SPOT, 0,
                b2 + l * SPOT, 0, spot, 0,
                spot, nullptr, nullptr, SPOT, 0, MLPD, 1.f);
        }
    }

    // ---- batched projection heads (z = 0:img, 1:spot)
    kProj<<<dim3(PROJ / 64, NB / 128, 2), 512, SMEM_64>>>(
        pinh, pinl, 1024, (long long)NB * 1024,
        pwh, pwl, PROJ, (long long)1024 * PROJ,
        pb, PROJ, nullptr, 0,
        pp, pgh, pgl, PROJ, (long long)NB * PROJ, 1024, 1.f);
    kResP<<<dim3(PROJ / 64, NB / 128, 2), 512, SMEM_64>>>(
        pgh, pgl, PROJ, (long long)NB * PROJ,
        pfwh, pfwl, PROJ, (long long)PROJ * PROJ,
        pfb, PROJ, pp, (long long)NB * PROJ,
        tmp2, nullptr, nullptr, PROJ, (long long)NB * PROJ, PROJ, 1.f);
    ln_bf2<<<2 * NB, 256>>>(tmp2, lng, lnb, eh, el);

    // ---- loss
    pack_bf<<<NB, 256>>>(eh, el, eh + (size_t)NB * PROJ, el + (size_t)NB * PROJ,
                         cth, ctl);
    kSqk<<<dim3(NB / 128, NB / 128, 1), 512, SMEM_NAT>>>(
        eh + (size_t)NB * PROJ, el + (size_t)NB * PROJ, PROJ, 0,
        eh, el, PROJ, 0,
        nullptr, 0, nullptr, 0,
        logits, nullptr, nullptr, NB, 0, PROJ, 1.f);
    kSymG<<<dim3(NB / 128, NB / 128, 1), 512, SMEM_NAT>>>(
        cth, ctl, 2 * PROJ, 0, cth, ctl, 2 * PROJ, 0,
        nullptr, 0, nullptr, 0,
        tgt, nullptr, nullptr, NB, 0, 2 * PROJ, 0.5f);
    softmax_rowloss<<<NB, 256>>>(tgt, logits, rowp);
    colloss_part<<<dim3(NB / 64, 8), 256>>>(logits, tgt, cmx, cse, cts, ctd);
    colloss_fin<<<NB / 256, 256>>>(cmx, cse, cts, ctd, colp);
    final_reduce<<<1, 256>>>(rowp, colp, out);
}

// round 14
// speedup vs baseline: 1.5679x; 1.0260x over previous
#include <cuda_runtime.h>
#include <cstdint>

// ---------------------------------------------------------------------------
// Problem constants
// ---------------------------------------------------------------------------
namespace {
constexpr int NB   = 2048;
constexpr int SPOT = 1024;
constexpr int IMG  = 1024;
constexpr int PROJ = 256;
constexpr int NH   = 8;
constexpr int DH   = 64;
constexpr int INNER = 512;
constexpr int MLPD = 2048;
constexpr int QKVW = 1536;
constexpr int NL   = 2;
}

// ---------------------------------------------------------------------------
// Scratch: fp32
// ---------------------------------------------------------------------------
__device__ float g_spot  [NB * SPOT];
__device__ float g_pp    [2 * NB * PROJ];
__device__ float g_tmp2  [2 * NB * PROJ];
__device__ float g_logits[NB * NB];
__device__ float g_tgt   [NB * NB];
__device__ float g_rowp  [NB];
__device__ float g_colp  [NB];
__device__ float g_pb    [2 * PROJ];
__device__ float g_pfb   [2 * PROJ];
__device__ float g_lng   [2 * PROJ];
__device__ float g_lnb   [2 * PROJ];
__device__ float g_cmx [8 * NB], g_cse [8 * NB];
__device__ float g_cts [8 * NB], g_ctd [8 * NB];

// ---------------------------------------------------------------------------
// Scratch: bf16 hi/lo
// ---------------------------------------------------------------------------
__device__ uint16_t g_hbuf_h[NB * SPOT],  g_hbuf_l[NB * SPOT];
__device__ uint16_t g_qkv_h [NB * QKVW],  g_qkv_l [NB * QKVW];
__device__ uint16_t g_attn_h[NB * INNER], g_attn_l[NB * INNER];
__device__ uint16_t g_mlp_h [NB * MLPD],  g_mlp_l [NB * MLPD];
__device__ uint16_t g_pin_h[2 * NB * 1024], g_pin_l[2 * NB * 1024];
__device__ uint16_t g_pg_h [2 * NB * PROJ], g_pg_l [2 * NB * PROJ];
__device__ uint16_t g_e_h  [2 * NB * PROJ], g_e_l  [2 * NB * PROJ];
__device__ uint16_t g_cat_h[NB * 2 * PROJ], g_cat_l[NB * 2 * PROJ];
// weights bf16
__device__ uint16_t g_wqkv_h[NL * SPOT * QKVW], g_wqkv_l[NL * SPOT * QKVW];
__device__ uint16_t g_wo_h  [NL * INNER * SPOT], g_wo_l [NL * INNER * SPOT];
__device__ uint16_t g_w1_h  [NL * SPOT * MLPD],  g_w1_l [NL * SPOT * MLPD];
__device__ uint16_t g_w2_h  [NL * MLPD * SPOT],  g_w2_l [NL * MLPD * SPOT];
__device__ uint16_t g_pw_h [2 * 1024 * PROJ], g_pw_l [2 * 1024 * PROJ];
__device__ uint16_t g_pfw_h[2 * PROJ * PROJ], g_pfw_l[2 * PROJ * PROJ];

// ---------------------------------------------------------------------------
// Helpers
// ---------------------------------------------------------------------------
__device__ __forceinline__ uint32_t smem_u32(const void* p) {
    uint32_t a;
    asm("{ .reg .u64 t; cvta.to.shared.u64 t, %1; cvt.u32.u64 %0, t; }"
        : "=r"(a) : "l"(p));
    return a;
}
__device__ __forceinline__ unsigned long long gptr(const void* p) {
    return (unsigned long long)__cvta_generic_to_global(p);
}
__device__ __forceinline__ float gelu_f(float x) {
    return 0.5f * x * (1.0f + erff(x * 0.7071067811865475f));
}
__device__ __forceinline__ void split2(float f0, float f1, uint32_t& hi, uint32_t& lo) {
    asm("cvt.rn.bf16x2.f32 %0, %1, %2;" : "=r"(hi) : "f"(f1), "f"(f0));
    float h0 = __uint_as_float(hi << 16);
    float h1 = __uint_as_float(hi & 0xFFFF0000u);
    float l0 = f0 - h0, l1 = f1 - h1;
    asm("cvt.rn.bf16x2.f32 %0, %1, %2;" : "=r"(lo) : "f"(l1), "f"(l0));
}

#define CP16(dst, src) \
    asm volatile("cp.async.cg.shared.global [%0], [%1], 16;" :: "r"(dst), "l"(src))
#define CP_COMMIT() asm volatile("cp.async.commit_group;" ::: "memory")
#define CP_WAIT1()  asm volatile("cp.async.wait_group 1;" ::: "memory")
#define CP_WAIT0()  asm volatile("cp.async.wait_group 0;" ::: "memory")

#define LDSM_X4(r, a)                                                          \
    asm volatile("ldmatrix.sync.aligned.m8n8.x4.shared.b16 {%0,%1,%2,%3}, [%4];" \
        : "=r"((r)[0]), "=r"((r)[1]), "=r"((r)[2]), "=r"((r)[3]) : "r"(a))
#define LDSM_X4T(r, a)                                                         \
    asm volatile("ldmatrix.sync.aligned.m8n8.x4.trans.shared.b16 {%0,%1,%2,%3}, [%4];" \
        : "=r"((r)[0]), "=r"((r)[1]), "=r"((r)[2]), "=r"((r)[3]) : "r"(a))
#define MMA16816(d, a, b)                                                      \
    asm volatile("mma.sync.aligned.m16n8k16.row.col.f32.bf16.bf16.f32 "        \
        "{%0,%1,%2,%3}, {%4,%5,%6,%7}, {%8,%9}, {%0,%1,%2,%3};"                \
        : "+f"((d)[0]), "+f"((d)[1]), "+f"((d)[2]), "+f"((d)[3])               \
        : "r"((a)[0]), "r"((a)[1]), "r"((a)[2]), "r"((a)[3]),                  \
          "r"((b)[0]), "r"((b)[1]))

// ---------------------------------------------------------------------------
// Pure-bf16 split GEMM (unchanged from R13).
// ---------------------------------------------------------------------------
template<int NT, bool BNAT, int EPI, int OUT, bool SYMW = false>
__global__ __launch_bounds__(512) void gemm_bf(
    const uint16_t* __restrict__ Ah, const uint16_t* __restrict__ Al,
    int lda, long long az,
    const uint16_t* __restrict__ Bh, const uint16_t* __restrict__ Bl,
    int ldb, long long bz,
    const float* __restrict__ bias, long long biasz,
    const float* __restrict__ res, long long resz,
    float* __restrict__ C, uint16_t* __restrict__ Ch, uint16_t* __restrict__ Cl,
    int ldc, long long cz, int K, float scale)
{
    if (SYMW && (int)blockIdx.x < (int)blockIdx.y) return;

    constexpr int WNC = NT / 4;
    constexpr int NTL = WNC / 8;
    constexpr int MT  = 2;
    constexpr int RS  = 72;
    constexpr int ABYTES = 128 * RS * 2;
    constexpr int BRS  = BNAT ? RS : (NT + 8);
    constexpr int BROWS = BNAT ? NT : 64;
    constexpr int BBYTES = BROWS * BRS * 2;
    constexpr int STAGE  = 2 * ABYTES + 2 * BBYTES;
    constexpr int STAGES = 3;
    constexpr int BSEGROW = NT / 8;
    constexpr int BSEGS = BNAT ? NT * 8 : 64 * BSEGROW;
    constexpr int BIT = (BSEGS + 511) / 512;

    extern __shared__ __align__(128) char smm[];
    const uint32_t sb = smem_u32(smm);
    const int tid = threadIdx.x, lane = tid & 31, wid = tid >> 5;
    const int wm = wid >> 2, wn = wid & 3;
    const int bm = blockIdx.y * 128, bn = blockIdx.x * NT;

    const uint16_t* Abh = Ah + (size_t)blockIdx.z * az + (size_t)bm * lda;
    const uint16_t* Abl = Al + (size_t)blockIdx.z * az + (size_t)bm * lda;
    const uint16_t* Bbh = Bh + (size_t)blockIdx.z * bz;
    const uint16_t* Bbl = Bl + (size_t)blockIdx.z * bz;
    const float* biasb = bias ? bias + (size_t)blockIdx.z * biasz : nullptr;
    const float* resb  = res  ? res  + (size_t)blockIdx.z * resz  : nullptr;

    float acc[MT][NTL][4];
    #pragma unroll
    for (int mt = 0; mt < MT; mt++)
        #pragma unroll
        for (int nt = 0; nt < NTL; nt++)
            #pragma unroll
            for (int r = 0; r < 4; r++) acc[mt][nt][r] = 0.f;

    const int NC = K >> 6;

    auto issue = [&](int c, int s) {
        const uint32_t st = sb + s * STAGE;
        const int k0 = c << 6;
        #pragma unroll
        for (int j = 0; j < 2; j++) {
            int idx = tid + j * 512;
            int row = idx >> 3, seg = idx & 7;
            size_t so = (size_t)row * lda + k0 + seg * 8;
            uint32_t d = st + row * (RS * 2) + seg * 16;
            CP16(d, gptr(Abh + so));
            CP16(d + ABYTES, gptr(Abl + so));
        }
        #pragma unroll
        for (int j = 0; j < BIT; j++) {
            int idx = tid + j * 512;
            if (BSEGS >= 512 * (j + 1) || idx < BSEGS) {
                if (BNAT) {
                    int row = idx >> 3, seg = idx & 7;
                    size_t so = (size_t)(bn + row) * ldb + k0 + seg * 8;
                    uint32_t d = st + 2 * ABYTES + row * (RS * 2) + seg * 16;
                    CP16(d, gptr(Bbh + so));
                    CP16(d + BBYTES, gptr(Bbl + so));
                } else {
                    int row = idx / BSEGROW, seg = idx % BSEGROW;
                    size_t so = (size_t)(k0 + row) * ldb + bn + seg * 8;
                    uint32_t d = st + 2 * ABYTES + row * (BRS * 2) + seg * 16;
                    CP16(d, gptr(Bbh + so));
                    CP16(d + BBYTES, gptr(Bbl + so));
                }
            }
        }
    };

    #pragma unroll
    for (int s = 0; s < STAGES - 1; s++) {
        if (s < NC) issue(s, s);
        CP_COMMIT();
    }

    for (int c = 0; c < NC; c++) {
        CP_WAIT1();
        __syncthreads();
        {
            int cn = c + STAGES - 1;
            if (cn < NC) issue(cn, cn % STAGES);
            CP_COMMIT();
        }
        const uint32_t abh_ = sb + (c % STAGES) * STAGE;
        const uint32_t abl_ = abh_ + ABYTES;
        const uint32_t bbh_ = abh_ + 2 * ABYTES;
        const uint32_t bbl_ = bbh_ + BBYTES;
        #pragma unroll
        for (int ks = 0; ks < 4; ks++) {
            uint32_t afh[MT][4], afl[MT][4], bfh[NTL][2], bfl[NTL][2];
            #pragma unroll
            for (int mt = 0; mt < MT; mt++) {
                uint32_t off = ((wm * 32 + mt * 16 + (lane & 15)) * RS +
                                ks * 16 + ((lane >> 4) << 3)) << 1;
                LDSM_X4(afh[mt], abh_ + off);
                LDSM_X4(afl[mt], abl_ + off);
            }
            #pragma unroll
            for (int p = 0; p < NTL / 2; p++) {
                uint32_t rh[4], rl[4];
                if (BNAT) {
                    int grp = lane >> 3;
                    int row = wn * WNC + p * 16 + (grp >> 1) * 8 + (lane & 7);
                    int koff = ks * 16 + (grp & 1) * 8;
                    uint32_t off = ((uint32_t)(row * RS + koff)) << 1;
                    LDSM_X4(rh, bbh_ + off);
                    LDSM_X4(rl, bbl_ + off);
                    bfh[2 * p][0] = rh[0]; bfh[2 * p][1] = rh[1];
                    bfh[2 * p + 1][0] = rh[2]; bfh[2 * p + 1][1] = rh[3];
                    bfl[2 * p][0] = rl[0]; bfl[2 * p][1] = rl[1];
                    bfl[2 * p + 1][0] = rl[2]; bfl[2 * p + 1][1] = rl[3];
                } else {
                    int row = ks * 16 + (lane & 15);
                    int col = wn * WNC + p * 16 + ((lane >> 4) << 3);
                    uint32_t off = ((uint32_t)(row * BRS + col)) << 1;
                    LDSM_X4T(rh, bbh_ + off);
                    LDSM_X4T(rl, bbl_ + off);
                    bfh[2 * p][0] = rh[0]; bfh[2 * p][1] = rh[1];
                    bfh[2 * p + 1][0] = rh[2]; bfh[2 * p + 1][1] = rh[3];
                    bfl[2 * p][0] = rl[0]; bfl[2 * p][1] = rl[1];
                    bfl[2 * p + 1][0] = rl[2]; bfl[2 * p + 1][1] = rl[3];
                }
            }
            #pragma unroll
            for (int nt = 0; nt < NTL; nt++)
                #pragma unroll
                for (int mt = 0; mt < MT; mt++) {
                    MMA16816(acc[mt][nt], afh[mt], bfh[nt]);
                    MMA16816(acc[mt][nt], afh[mt], bfl[nt]);
                    MMA16816(acc[mt][nt], afl[mt], bfh[nt]);
                }
        }
    }

    const int gid = lane >> 2, tig = lane & 3;
    #pragma unroll
    for (int mt = 0; mt < MT; mt++) {
        #pragma unroll
        for (int nt = 0; nt < NTL; nt++) {
            int r0  = bm + wm * 32 + mt * 16 + gid;
            int col = bn + wn * WNC + nt * 8 + tig * 2;
            float2 v0 = make_float2(acc[mt][nt][0] * scale, acc[mt][nt][1] * scale);
            float2 v1 = make_float2(acc[mt][nt][2] * scale, acc[mt][nt][3] * scale);
            if (EPI >= 1) {
                float2 bb = *reinterpret_cast<const float2*>(&biasb[col]);
                v0.x += bb.x; v0.y += bb.y; v1.x += bb.x; v1.y += bb.y;
            }
            if (EPI == 2) {
                v0.x = gelu_f(v0.x); v0.y = gelu_f(v0.y);
                v1.x = gelu_f(v1.x); v1.y = gelu_f(v1.y);
            }
            if (EPI == 3) {
                float2 ra = *reinterpret_cast<const float2*>(
                    &resb[(size_t)r0 * ldc + col]);
                float2 rb = *reinterpret_cast<const float2*>(
                    &resb[(size_t)(r0 + 8) * ldc + col]);
                v0.x += ra.x; v0.y += ra.y; v1.x += rb.x; v1.y += rb.y;
            }
            size_t o0 = (size_t)r0 * ldc + col + (size_t)blockIdx.z * cz;
            size_t o1 = (size_t)(r0 + 8) * ldc + col + (size_t)blockIdx.z * cz;
            if (OUT & 1) {
                *reinterpret_cast<float2*>(&C[o0]) = v0;
                *reinterpret_cast<float2*>(&C[o1]) = v1;
                if (SYMW) {
                    C[(size_t)col * ldc + r0]           = v0.x;
                    C[(size_t)(col + 1) * ldc + r0]     = v0.y;
                    C[(size_t)col * ldc + r0 + 8]       = v1.x;
                    C[(size_t)(col + 1) * ldc + r0 + 8] = v1.y;
                }
            }
            if (OUT & 2) {
                float a0 = v0.x, a1 = v0.y, b0 = v1.x, b1 = v1.y;
                if (OUT & 4) {
                    a0 = gelu_f(a0); a1 = gelu_f(a1);
                    b0 = gelu_f(b0); b1 = gelu_f(b1);
                }
                uint32_t h, l;
                split2(a0, a1, h, l);
                *reinterpret_cast<uint32_t*>(&Ch[o0]) = h;
                *reinterpret_cast<uint32_t*>(&Cl[o0]) = l;
                split2(b0, b1, h, l);
                *reinterpret_cast<uint32_t*>(&Ch[o1]) = h;
                *reinterpret_cast<uint32_t*>(&Cl[o1]) = l;
            }
        }
    }
}

// ---------------------------------------------------------------------------
// Fused flash attention v3 (unchanged).
// ---------------------------------------------------------------------------
__global__ __launch_bounds__(512) void flash_attn(
    const uint16_t* __restrict__ qh, const uint16_t* __restrict__ ql,
    uint16_t* __restrict__ oh, uint16_t* __restrict__ ol)
{
    constexpr int RS = 72;
    constexpr int TB = 128 * RS * 2;
    constexpr int KVSTAGE = 4 * TB;
    constexpr int PM_OFF = 2 * TB + 2 * KVSTAGE;
    extern __shared__ __align__(128) char smm[];
    const uint32_t sb  = smem_u32(smm);
    const uint32_t sQh = sb, sQl = sb + TB;
    float* pm = reinterpret_cast<float*>(smm + PM_OFF);
    const int tid = threadIdx.x, lane = tid & 31, w = tid >> 5;
    const int wq = w & 7, h2 = w >> 3;
    const int q0 = blockIdx.x * 128;
    const int h  = blockIdx.y;
    const int g = lane >> 2, t = lane & 3;

    #pragma unroll
    for (int j = 0; j < 2; j++) {
        int idx = tid + j * 512;
        int row = idx >> 3, seg = idx & 7;
        size_t so = (size_t)(q0 + row) * QKVW + h * 64 + seg * 8;
        uint32_t d = sb + row * (RS * 2) + seg * 16;
        CP16(d, gptr(qh + so));
        CP16(d + TB, gptr(ql + so));
    }
    auto issueKV = [&](int kt, int s) {
        uint32_t st = sb + 2 * TB + s * KVSTAGE;
        int tok0 = kt * 128;
        #pragma unroll
        for (int j = 0; j < 2; j++) {
            int idx = tid + j * 512;
            int row = idx >> 3, seg = idx & 7;
            size_t soK = (size_t)(tok0 + row) * QKVW + INNER + h * 64 + seg * 8;
            uint32_t dK = st + row * (RS * 2) + seg * 16;
            CP16(dK, gptr(qh + soK));
            CP16(dK + TB, gptr(ql + soK));
            size_t soV = soK + INNER;
            uint32_t dV = st + 2 * TB + row * (RS * 2) + seg * 16;
            CP16(dV, gptr(qh + soV));
            CP16(dV + TB, gptr(ql + soV));
        }
    };
    issueKV(0, 0);
    CP_COMMIT();

    float O[8][4];
    #pragma unroll
    for (int jt = 0; jt < 8; jt++)
        #pragma unroll
        for (int r = 0; r < 4; r++) O[jt][r] = 0.f;
    float m0 = -1e30f, m1 = -1e30f, l0 = 0.f, l1 = 0.f;

    for (int kt = 0; kt < NB / 128; kt++) {
        CP_WAIT0();
        __syncthreads();
        if (kt + 1 < NB / 128) {
            issueKV(kt + 1, (kt + 1) & 1);
            CP_COMMIT();
        }
        const uint32_t st  = sb + 2 * TB + (kt & 1) * KVSTAGE;
        const uint32_t sKh = st, sKl = st + TB;
        const uint32_t sVh = st + 2 * TB, sVl = st + 3 * TB;

        float sacc[8][4];
        #pragma unroll
        for (int j = 0; j < 8; j++)
            #pragma unroll
            for (int r = 0; r < 4; r++) sacc[j][r] = 0.f;

        #pragma unroll
        for (int kc = 0; kc < 4; kc++) {
            uint32_t aqh[4], aql[4];
            uint32_t aoff = ((wq * 16 + (lane & 15)) * RS +
                             kc * 16 + ((lane >> 4) << 3)) << 1;
            LDSM_X4(aqh, sQh + aoff);
            LDSM_X4(aql, sQl + aoff);
            #pragma unroll
            for (int jp = 0; jp < 4; jp++) {
                uint32_t rh[4], rl[4];
                uint32_t boff = ((h2 * 64 + jp * 16 + (lane & 15)) * RS +
                                 kc * 16 + ((lane >> 4) << 3)) << 1;
                LDSM_X4(rh, sKh + boff);
                LDSM_X4(rl, sKl + boff);
                uint32_t bh0[2] = {rh[0], rh[2]}, bh1[2] = {rh[1], rh[3]};
                uint32_t bl0[2] = {rl[0], rl[2]}, bl1[2] = {rl[1], rl[3]};
                MMA16816(sacc[2 * jp],     aqh, bh0);
                MMA16816(sacc[2 * jp],     aqh, bl0);
                MMA16816(sacc[2 * jp],     aql, bh0);
                MMA16816(sacc[2 * jp + 1], aqh, bh1);
                MMA16816(sacc[2 * jp + 1], aqh, bl1);
                MMA16816(sacc[2 * jp + 1], aql, bh1);
            }
        }

        float mx0 = -1e30f, mx1 = -1e30f;
        #pragma unroll
        for (int j = 0; j < 8; j++) {
            sacc[j][0] *= 0.125f; sacc[j][1] *= 0.125f;
            sacc[j][2] *= 0.125f; sacc[j][3] *= 0.125f;
            mx0 = fmaxf(mx0, fmaxf(sacc[j][0], sacc[j][1]));
            mx1 = fmaxf(mx1, fmaxf(sacc[j][2], sacc[j][3]));
        }
        mx0 = fmaxf(mx0, __shfl_xor_sync(0xffffffffu, mx0, 1));
        mx0 = fmaxf(mx0, __shfl_xor_sync(0xffffffffu, mx0, 2));
        mx1 = fmaxf(mx1, __shfl_xor_sync(0xffffffffu, mx1, 1));
        mx1 = fmaxf(mx1, __shfl_xor_sync(0xffffffffu, mx1, 2));
        float* pmc = pm + (kt & 1) * 256;
        if (t == 0) {
            pmc[h2 * 128 + wq * 16 + g]     = mx0;
            pmc[h2 * 128 + wq * 16 + g + 8] = mx1;
        }
        __syncthreads();
        float ox0 = pmc[(1 - h2) * 128 + wq * 16 + g];
        float ox1 = pmc[(1 - h2) * 128 + wq * 16 + g + 8];
        float nm0 = fmaxf(m0, fmaxf(mx0, ox0));
        float nm1 = fmaxf(m1, fmaxf(mx1, ox1));
        float a0 = __expf(m0 - nm0), a1 = __expf(m1 - nm1);
        m0 = nm0; m1 = nm1;
        float s0 = 0.f, s1 = 0.f;
        #pragma unroll
        for (int j = 0; j < 8; j++) {
            sacc[j][0] = __expf(sacc[j][0] - m0); s0 += sacc[j][0];
            sacc[j][1] = __expf(sacc[j][1] - m0); s0 += sacc[j][1];
            sacc[j][2] = __expf(sacc[j][2] - m1); s1 += sacc[j][2];
            sacc[j][3] = __expf(sacc[j][3] - m1); s1 += sacc[j][3];
        }
        s0 += __shfl_xor_sync(0xffffffffu, s0, 1);
        s0 += __shfl_xor_sync(0xffffffffu, s0, 2);
        s1 += __shfl_xor_sync(0xffffffffu, s1, 1);
        s1 += __shfl_xor_sync(0xffffffffu, s1, 2);
        l0 = l0 * a0 + s0;
        l1 = l1 * a1 + s1;
        #pragma unroll
        for (int jt = 0; jt < 8; jt++) {
            O[jt][0] *= a0; O[jt][1] *= a0;
            O[jt][2] *= a1; O[jt][3] *= a1;
        }

        #pragma unroll
        for (int kc = 0; kc < 4; kc++) {
            uint32_t ah[4], al[4];
            split2(sacc[2 * kc][0],     sacc[2 * kc][1],     ah[0], al[0]);
            split2(sacc[2 * kc][2],     sacc[2 * kc][3],     ah[1], al[1]);
            split2(sacc[2 * kc + 1][0], sacc[2 * kc + 1][1], ah[2], al[2]);
            split2(sacc[2 * kc + 1][2], sacc[2 * kc + 1][3], ah[3], al[3]);
            #pragma unroll
            for (int jp = 0; jp < 4; jp++) {
                uint32_t rh[4], rl[4];
                uint32_t boff = ((h2 * 64 + kc * 16 + (lane & 15)) * RS +
                                 jp * 16 + ((lane >> 4) << 3)) << 1;
                LDSM_X4T(rh, sVh + boff);
                LDSM_X4T(rl, sVl + boff);
                uint32_t bh0[2] = {rh[0], rh[1]}, bh1[2] = {rh[2], rh[3]};
                uint32_t bl0[2] = {rl[0], rl[1]}, bl1[2] = {rl[2], rl[3]};
                MMA16816(O[2 * jp],     ah, bh0);
                MMA16816(O[2 * jp],     ah, bl0);
                MMA16816(O[2 * jp],     al, bh0);
                MMA16816(O[2 * jp + 1], ah, bh1);
                MMA16816(O[2 * jp + 1], ah, bl1);
                MMA16816(O[2 * jp + 1], al, bh1);
            }
        }
    }

    __syncthreads();
    float* Ost = reinterpret_cast<float*>(smm + 2 * TB);
    float* lst = Ost + 128 * 66;
    if (h2 == 1) {
        #pragma unroll
        for (int jt = 0; jt < 8; jt++) {
            int c = jt * 8 + t * 2;
            Ost[(wq * 16 + g) * 66 + c]         = O[jt][0];
            Ost[(wq * 16 + g) * 66 + c + 1]     = O[jt][1];
            Ost[(wq * 16 + g + 8) * 66 + c]     = O[jt][2];
            Ost[(wq * 16 + g + 8) * 66 + c + 1] = O[jt][3];
        }
        if (t == 0) {
            lst[wq * 16 + g]     = l0;
            lst[wq * 16 + g + 8] = l1;
        }
    }
    __syncthreads();
    if (h2 == 0) {
        float i0 = 1.f / (l0 + lst[wq * 16 + g]);
        float i1 = 1.f / (l1 + lst[wq * 16 + g + 8]);
        #pragma unroll
        for (int jt = 0; jt < 8; jt++) {
            int c = jt * 8 + t * 2;
            float o00 = O[jt][0] + Ost[(wq * 16 + g) * 66 + c];
            float o01 = O[jt][1] + Ost[(wq * 16 + g) * 66 + c + 1];
            float o10 = O[jt][2] + Ost[(wq * 16 + g + 8) * 66 + c];
            float o11 = O[jt][3] + Ost[(wq * 16 + g + 8) * 66 + c + 1];
            uint32_t hh, ll;
            size_t o0 = (size_t)(q0 + wq * 16 + g) * INNER + h * 64 + c;
            split2(o00 * i0, o01 * i0, hh, ll);
            *reinterpret_cast<uint32_t*>(oh + o0) = hh;
            *reinterpret_cast<uint32_t*>(ol + o0) = ll;
            size_t o1 = o0 + (size_t)8 * INNER;
            split2(o10 * i1, o11 * i1, hh, ll);
            *reinterpret_cast<uint32_t*>(oh + o1) = hh;
            *reinterpret_cast<uint32_t*>(ol + o1) = ll;
        }
    }
}

// ---------------------------------------------------------------------------
// Fast block reductions (256 threads): warp shuffle + 8-way smem merge.
// Deterministic. sh must hold >= 16 floats.
// ---------------------------------------------------------------------------
__device__ __forceinline__ void red_sum2(float& a, float& b, float* sh) {
    #pragma unroll
    for (int o = 16; o >= 1; o >>= 1) {
        a += __shfl_xor_sync(0xffffffffu, a, o);
        b += __shfl_xor_sync(0xffffffffu, b, o);
    }
    int w = threadIdx.x >> 5;
    if ((threadIdx.x & 31) == 0) { sh[w] = a; sh[8 + w] = b; }
    __syncthreads();
    float ra = 0.f, rb = 0.f;
    #pragma unroll
    for (int i = 0; i < 8; i++) { ra += sh[i]; rb += sh[8 + i]; }
    a = ra; b = rb;
    __syncthreads();
}
__device__ __forceinline__ void red_max2(float& a, float& b, float* sh) {
    #pragma unroll
    for (int o = 16; o >= 1; o >>= 1) {
        a = fmaxf(a, __shfl_xor_sync(0xffffffffu, a, o));
        b = fmaxf(b, __shfl_xor_sync(0xffffffffu, b, o));
    }
    int w = threadIdx.x >> 5;
    if ((threadIdx.x & 31) == 0) { sh[w] = a; sh[8 + w] = b; }
    __syncthreads();
    float ra = -1e30f, rb = -1e30f;
    #pragma unroll
    for (int i = 0; i < 8; i++) { ra = fmaxf(ra, sh[i]); rb = fmaxf(rb, sh[8 + i]); }
    a = ra; b = rb;
    __syncthreads();
}
__device__ __forceinline__ float red_sum1(float a, float* sh) {
    #pragma unroll
    for (int o = 16; o >= 1; o >>= 1)
        a += __shfl_xor_sync(0xffffffffu, a, o);
    int w = threadIdx.x >> 5;
    if ((threadIdx.x & 31) == 0) sh[w] = a;
    __syncthreads();
    float r = 0.f;
    #pragma unroll
    for (int i = 0; i < 8; i++) r += sh[i];
    __syncthreads();
    return r;
}

// legacy helper for final_reduce
__device__ __forceinline__ float blk_sum256(float v, float* sh) {
    int t = threadIdx.x;
    sh[t] = v; __syncthreads();
    #pragma unroll
    for (int s = 128; s >= 1; s >>= 1) {
        if (t < s) sh[t] += sh[t + s];
        __syncthreads();
    }
    float r = sh[0]; __syncthreads();
    return r;
}

// ---------------------------------------------------------------------------
// Elementwise kernels
// ---------------------------------------------------------------------------
struct ConvSegs {
    const float* src[10];
    uint16_t* h[10];
    uint16_t* l[10];
    int base[11];
};

__global__ __launch_bounds__(256) void conv_multi(ConvSegs s, int total8)
{
    int i = blockIdx.x * 256 + threadIdx.x;
    if (i >= total8) return;
    int k = 0;
    while (i >= s.base[k + 1]) k++;
    int off = i - s.base[k];
    const float4* x4 = reinterpret_cast<const float4*>(s.src[k]);
    float4 a = x4[2 * off], b = x4[2 * off + 1];
    uint32_t h0, h1, h2, h3, l0, l1, l2, l3;
    split2(a.x, a.y, h0, l0);
    split2(a.z, a.w, h1, l1);
    split2(b.x, b.y, h2, l2);
    split2(b.z, b.w, h3, l3);
    reinterpret_cast<uint4*>(s.h[k])[off] = make_uint4(h0, h1, h2, h3);
    reinterpret_cast<uint4*>(s.l[k])[off] = make_uint4(l0, l1, l2, l3);
}

__global__ __launch_bounds__(256) void pack_params(
    const float* __restrict__ ipb, const float* __restrict__ spb,
    const float* __restrict__ ifb, const float* __restrict__ sfb,
    const float* __restrict__ ig,  const float* __restrict__ sg,
    const float* __restrict__ ib,  const float* __restrict__ sb,
    float* __restrict__ pb, float* __restrict__ pfb,
    float* __restrict__ lng, float* __restrict__ lnb)
{
    int t = threadIdx.x;
    pb [t]        = ipb[t];  pb [t + PROJ] = spb[t];
    pfb[t]        = ifb[t];  pfb[t + PROJ] = sfb[t];
    lng[t]        = ig[t];   lng[t + PROJ] = sg[t];
    lnb[t]        = ib[t];   lnb[t + PROJ] = sb[t];
}

__global__ __launch_bounds__(256) void embed_kernel(
    const float* __restrict__ expr, const float* __restrict__ xt,
    const float* __restrict__ yt, const int* __restrict__ xi,
    const int* __restrict__ yi, float* __restrict__ out)
{
    int row = blockIdx.x, tid = threadIdx.x;
    const float4* e4 = reinterpret_cast<const float4*>(expr + (size_t)row * SPOT);
    const float4* x4 = reinterpret_cast<const float4*>(xt + (size_t)xi[row] * SPOT);
    const float4* y4 = reinterpret_cast<const float4*>(yt + (size_t)yi[row] * SPOT);
    float4 e = e4[tid], x = x4[tid], y = y4[tid];
    e.x += x.x + y.x; e.y += x.y + y.y;
    e.z += x.z + y.z; e.w += x.w + y.w;
    reinterpret_cast<float4*>(out + (size_t)row * SPOT)[tid] = e;
}

// LayerNorm fp32 -> split bf16. Single pass: var = E[x^2] - mean^2.
template<int N>
__global__ __launch_bounds__(256) void ln_bf(
    const float* __restrict__ x, const float* __restrict__ g,
    const float* __restrict__ b, uint16_t* __restrict__ oh,
    uint16_t* __restrict__ ol)
{
    __shared__ float sh[16];
    constexpr int NPAIR = N / 2;
    constexpr int NP = (NPAIR + 255) / 256;
    int row = blockIdx.x, tid = threadIdx.x;
    const float2* xr = reinterpret_cast<const float2*>(x + (size_t)row * N);
    float2 v[NP];
    float s = 0.f, sq = 0.f;
    #pragma unroll
    for (int i = 0; i < NP; i++) {
        int p = i * 256 + tid;
        if (p < NPAIR) {
            v[i] = xr[p];
            s  += v[i].x + v[i].y;
            sq += v[i].x * v[i].x + v[i].y * v[i].y;
        } else v[i] = make_float2(0.f, 0.f);
    }
    red_sum2(s, sq, sh);
    float mean = s / N;
    float var = sq / N - mean * mean;
    float rstd = rsqrtf(var + 1e-5f);
    uint32_t* OH = reinterpret_cast<uint32_t*>(oh + (size_t)row * N);
    uint32_t* OL = reinterpret_cast<uint32_t*>(ol + (size_t)row * N);
    #pragma unroll
    for (int i = 0; i < NP; i++) {
        int p = i * 256 + tid;
        if (p < NPAIR) {
            float2 gg = reinterpret_cast<const float2*>(g)[p];
            float2 bb = reinterpret_cast<const float2*>(b)[p];
            float y0 = (v[i].x - mean) * rstd * gg.x + bb.x;
            float y1 = (v[i].y - mean) * rstd * gg.y + bb.y;
            uint32_t h, l;
            split2(y0, y1, h, l);
            OH[p] = h; OL[p] = l;
        }
    }
}

__global__ __launch_bounds__(256) void ln_bf2(
    const float* __restrict__ x, const float* __restrict__ g,
    const float* __restrict__ b, uint16_t* __restrict__ oh,
    uint16_t* __restrict__ ol)
{
    __shared__ float sh[16];
    constexpr int N = PROJ;
    int row = blockIdx.x, tid = threadIdx.x;
    int slot = row >> 11;
    const float* gs = g + slot * PROJ;
    const float* bs = b + slot * PROJ;
    const float2* xr = reinterpret_cast<const float2*>(x + (size_t)row * N);
    float2 v = make_float2(0.f, 0.f);
    if (tid < N / 2) v = xr[tid];
    float s = v.x + v.y, sq = v.x * v.x + v.y * v.y;
    red_sum2(s, sq, sh);
    float mean = s / N;
    float var = sq / N - mean * mean;
    float rstd = rsqrtf(var + 1e-5f);
    if (tid < N / 2) {
        float2 gg = reinterpret_cast<const float2*>(gs)[tid];
        float2 bb = reinterpret_cast<const float2*>(bs)[tid];
        float y0 = (v.x - mean) * rstd * gg.x + bb.x;
        float y1 = (v.y - mean) * rstd * gg.y + bb.y;
        uint32_t h, l;
        split2(y0, y1, h, l);
        reinterpret_cast<uint32_t*>(oh + (size_t)row * N)[tid] = h;
        reinterpret_cast<uint32_t*>(ol + (size_t)row * N)[tid] = l;
    }
}

__global__ __launch_bounds__(256) void softmax_rowloss(
    float* __restrict__ tgt, const float* __restrict__ logits,
    float* __restrict__ rowp)
{
    __shared__ float sh[16];
    size_t row = blockIdx.x;
    int tid = threadIdx.x;
    float* tr = tgt + row * NB;
    const float* lr = logits + row * NB;
    float tv[8], lv[8];
    float mt = -1e30f, ml = -1e30f;
    #pragma unroll
    for (int i = 0; i < 8; i++) {
        tv[i] = tr[i * 256 + tid];
        lv[i] = lr[i * 256 + tid];
        mt = fmaxf(mt, tv[i]);
        ml = fmaxf(ml, lv[i]);
    }
    red_max2(mt, ml, sh);
    float st = 0.f;
    #pragma unroll
    for (int i = 0; i < 8; i++) { tv[i] = __expf(tv[i] - mt); st += tv[i]; }
    st = red_sum1(st, sh);
    float inv = 1.f / st;
    float se = 0.f, dot = 0.f;
    #pragma unroll
    for (int i = 0; i < 8; i++) {
        tv[i] *= inv;
        tr[i * 256 + tid] = tv[i];
        se += __expf(lv[i] - ml);
        dot += tv[i] * lv[i];
    }
    red_sum2(se, dot, sh);
    if (tid == 0) rowp[row] = 0.5f * (ml + logf(se) - dot);
}

__global__ __launch_bounds__(256) void pack_bf(
    const uint16_t* __restrict__ ih, const uint16_t* __restrict__ il,
    const uint16_t* __restrict__ eh, const uint16_t* __restrict__ el,
    uint16_t* __restrict__ ch, uint16_t* __restrict__ cl)
{
    int row = blockIdx.x, tid = threadIdx.x;
    const uint32_t* IH = reinterpret_cast<const uint32_t*>(ih + (size_t)row * PROJ);
    const uint32_t* IL = reinterpret_cast<const uint32_t*>(il + (size_t)row * PROJ);
    const uint32_t* EH = reinterpret_cast<const uint32_t*>(eh + (size_t)row * PROJ);
    const uint32_t* EL = reinterpret_cast<const uint32_t*>(el + (size_t)row * PROJ);
    uint32_t vh, vl;
    if (tid < 128) { vh = IH[tid]; vl = IL[tid]; }
    else           { vh = EH[tid - 128]; vl = EL[tid - 128]; }
    reinterpret_cast<uint32_t*>(ch + (size_t)row * 2 * PROJ)[tid] = vh;
    reinterpret_cast<uint32_t*>(cl + (size_t)row * 2 * PROJ)[tid] = vl;
}

__global__ __launch_bounds__(256) void colloss_part(
    const float* __restrict__ logits, const float* __restrict__ tgt,
    float* __restrict__ cmx, float* __restrict__ cse,
    float* __restrict__ cts, float* __restrict__ ctd)
{
    __shared__ float smx[256], sse[256], sts[256], stdot[256];
    int tid = threadIdx.x;
    int c = blockIdx.x * 64 + (tid & 63);
    int ry = tid >> 6;
    int r0 = blockIdx.y * 256;
    float mx = -1e30f, se = 0.f, ts = 0.f, td = 0.f;
    for (int r = r0 + ry; r < r0 + 256; r += 4) {
        float l = logits[(size_t)r * NB + c];
        float t = tgt   [(size_t)r * NB + c];
        if (l > mx) { se = se * __expf(mx - l) + 1.f; mx = l; }
        else        { se += __expf(l - mx); }
        ts += t;
        td += t * l;
    }
    smx[tid] = mx; sse[tid] = se; sts[tid] = ts; stdot[tid] = td;
    __syncthreads();
    if (ry == 0) {
        #pragma unroll
        for (int k = 1; k < 4; k++) {
            int o = tid + k * 64;
            float m2 = smx[o], s2 = sse[o];
            float m = fmaxf(mx, m2);
            se = se * __expf(mx - m) + s2 * __expf(m2 - m);
            mx = m;
            ts += sts[o];
            td += stdot[o];
        }
        size_t idx = (size_t)blockIdx.y * NB + c;
        cmx[idx] = mx; cse[idx] = se; cts[idx] = ts; ctd[idx] = td;
    }
}

__global__ __launch_bounds__(256) void colloss_fin(
    const float* __restrict__ cmx, const float* __restrict__ cse,
    const float* __restrict__ cts, const float* __restrict__ ctd,
    float* __restrict__ colp)
{
    int c = blockIdx.x * 256 + threadIdx.x;
    float mx = cmx[c], se = cse[c], ts = cts[c], td = ctd[c];
    #pragma unroll
    for (int k = 1; k < 8; k++) {
        size_t idx = (size_t)k * NB + c;
        float m2 = cmx[idx], s2 = cse[idx];
        float m = fmaxf(mx, m2);
        se = se * __expf(mx - m) + s2 * __expf(m2 - m);
        mx = m;
        ts += cts[idx];
        td += ctd[idx];
    }
    colp[c] = 0.5f * (ts * (mx + logf(se)) - td);
}

__global__ __launch_bounds__(256) void final_reduce(
    const float* __restrict__ a, const float* __restrict__ b,
    float* __restrict__ out)
{
    __shared__ float sh[256];
    int tid = threadIdx.x;
    float s = 0.f;
    for (int i = tid; i < NB; i += 256) s += a[i] + b[i];
    s = blk_sum256(s, sh);
    if (tid == 0) out[0] = s * (1.0f / NB);
}

// ---------------------------------------------------------------------------
// Host launch
// ---------------------------------------------------------------------------
namespace {
constexpr int SMEM_STD = 3 * (2 * 128 * 72 * 2 + 2 * 64 * 136 * 2);   // 215040
constexpr int SMEM_NAT = 3 * (2 * 128 * 72 * 2 + 2 * 128 * 72 * 2);   // 221184
constexpr int SMEM_64  = 3 * (2 * 128 * 72 * 2 + 2 * 64 * 72 * 2);    // 165888
constexpr int SMEM_FLASH = 2 * (128 * 72 * 2) + 2 * 4 * (128 * 72 * 2)
                         + 2 * 256 * 4;                                // 186368
}

#define SYM(var, sym) cudaGetSymbolAddress((void**)&var, sym)

extern "C" void kernel_launch(void* const* d_in, const int* in_sizes, int n_in,
                              void* d_out, int out_size)
{
    (void)in_sizes; (void)n_in; (void)out_size;
    const float* image_features = (const float*)d_in[0];
    const float* expression     = (const float*)d_in[1];
    const float* x_table        = (const float*)d_in[2];
    const float* y_table        = (const float*)d_in[3];
    const float* ln1_g          = (const float*)d_in[4];
    const float* ln1_b          = (const float*)d_in[5];
    const float* w_qkv          = (const float*)d_in[6];
    const float* w_o            = (const float*)d_in[7];
    const float* b_o            = (const float*)d_in[8];
    const float* ln2_g          = (const float*)d_in[9];
    const float* ln2_b          = (const float*)d_in[10];
    const float* w1             = (const float*)d_in[11];
    const float* b1             = (const float*)d_in[12];
    const float* w2             = (const float*)d_in[13];
    const float* b2             = (const float*)d_in[14];
    const float* img_proj_w     = (const float*)d_in[15];
    const float* img_proj_b     = (const float*)d_in[16];
    const float* img_fc_w       = (const float*)d_in[17];
    const float* img_fc_b       = (const float*)d_in[18];
    const float* img_ln_g       = (const float*)d_in[19];
    const float* img_ln_b       = (const float*)d_in[20];
    const float* spot_proj_w    = (const float*)d_in[21];
    const float* spot_proj_b    = (const float*)d_in[22];
    const float* spot_fc_w      = (const float*)d_in[23];
    const float* spot_fc_b      = (const float*)d_in[24];
    const float* spot_ln_g      = (const float*)d_in[25];
    const float* spot_ln_b      = (const float*)d_in[26];
    const int*   x_idx          = (const int*)d_in[27];
    const int*   y_idx          = (const int*)d_in[28];
    float* out = (float*)d_out;

    float *spot, *pp, *tmp2, *logits, *tgt, *rowp, *colp, *pb, *pfb, *lng, *lnb;
    float *cmx, *cse, *cts, *ctd;
    SYM(spot, g_spot); SYM(pp, g_pp); SYM(tmp2, g_tmp2);
    SYM(logits, g_logits); SYM(tgt, g_tgt); SYM(rowp, g_rowp); SYM(colp, g_colp);
    SYM(pb, g_pb); SYM(pfb, g_pfb); SYM(lng, g_lng); SYM(lnb, g_lnb);
    SYM(cmx, g_cmx); SYM(cse, g_cse); SYM(cts, g_cts); SYM(ctd, g_ctd);

    uint16_t *hbh, *hbl, *qkh, *qkl, *ath, *atl, *mph, *mpl;
    uint16_t *pinh, *pinl, *pgh, *pgl, *eh, *el, *cth, *ctl;
    SYM(hbh, g_hbuf_h); SYM(hbl, g_hbuf_l);
    SYM(qkh, g_qkv_h);  SYM(qkl, g_qkv_l);
    SYM(ath, g_attn_h); SYM(atl, g_attn_l);
    SYM(mph, g_mlp_h);  SYM(mpl, g_mlp_l);
    SYM(pinh, g_pin_h); SYM(pinl, g_pin_l);
    SYM(pgh, g_pg_h);   SYM(pgl, g_pg_l);
    SYM(eh, g_e_h);     SYM(el, g_e_l);
    SYM(cth, g_cat_h);  SYM(ctl, g_cat_l);

    uint16_t *wqh, *wql, *woh, *wol, *w1h, *w1l, *w2h, *w2l;
    uint16_t *pwh, *pwl, *pfwh, *pfwl;
    SYM(wqh, g_wqkv_h); SYM(wql, g_wqkv_l);
    SYM(woh, g_wo_h);   SYM(wol, g_wo_l);
    SYM(w1h, g_w1_h);   SYM(w1l, g_w1_l);
    SYM(w2h, g_w2_h);   SYM(w2l, g_w2_l);
    SYM(pwh, g_pw_h);   SYM(pwl, g_pw_l);
    SYM(pfwh, g_pfw_h); SYM(pfwl, g_pfw_l);

    auto kQKV  = gemm_bf<64,  false, 0, 2>;
    auto kSqk  = gemm_bf<128, true,  0, 1>;
    auto kSymG = gemm_bf<128, true,  0, 1, true>;
    auto kRes  = gemm_bf<128, false, 3, 1>;
    auto kResO = gemm_bf<128, false, 3, 3>;
    auto kMlp1 = gemm_bf<128, false, 2, 2>;
    auto kProj = gemm_bf<64,  false, 1, 7>;
    auto kResP = gemm_bf<64,  false, 3, 1>;
    cudaFuncSetAttribute(kQKV,  cudaFuncAttributeMaxDynamicSharedMemorySize, SMEM_64);
    cudaFuncSetAttribute(kSqk,  cudaFuncAttributeMaxDynamicSharedMemorySize, SMEM_NAT);
    cudaFuncSetAttribute(kSymG, cudaFuncAttributeMaxDynamicSharedMemorySize, SMEM_NAT);
    cudaFuncSetAttribute(kRes,  cudaFuncAttributeMaxDynamicSharedMemorySize, SMEM_STD);
    cudaFuncSetAttribute(kResO, cudaFuncAttributeMaxDynamicSharedMemorySize, SMEM_STD);
    cudaFuncSetAttribute(kMlp1, cudaFuncAttributeMaxDynamicSharedMemorySize, SMEM_STD);
    cudaFuncSetAttribute(kProj, cudaFuncAttributeMaxDynamicSharedMemorySize, SMEM_64);
    cudaFuncSetAttribute(kResP, cudaFuncAttributeMaxDynamicSharedMemorySize, SMEM_64);
    cudaFuncSetAttribute(flash_attn,
                         cudaFuncAttributeMaxDynamicSharedMemorySize, SMEM_FLASH);

    {
        ConvSegs cs{};
        auto add = [&](int k, const float* s, uint16_t* h, uint16_t* l, int n) {
            cs.src[k] = s; cs.h[k] = h; cs.l[k] = l;
            cs.base[k + 1] = cs.base[k] + n / 8;
        };
        cs.base[0] = 0;
        add(0, w_qkv, wqh, wql, NL * SPOT * QKVW);
        add(1, w_o,   woh, wol, NL * INNER * SPOT);
        add(2, w1,    w1h, w1l, NL * SPOT * MLPD);
        add(3, w2,    w2h, w2l, NL * MLPD * SPOT);
        add(4, img_proj_w,  pwh, pwl, IMG * PROJ);
        add(5, spot_proj_w, pwh + 1024 * PROJ, pwl + 1024 * PROJ, SPOT * PROJ);
        add(6, img_fc_w,  pfwh, pfwl, PROJ * PROJ);
        add(7, spot_fc_w, pfwh + PROJ * PROJ, pfwl + PROJ * PROJ, PROJ * PROJ);
        add(8, image_features, pinh, pinl, NB * IMG);
        add(9, nullptr, nullptr, nullptr, 0);
        int total8 = cs.base[9];
        conv_multi<<<(total8 + 255) / 256, 256>>>(cs, total8);
    }
    pack_params<<<1, 256>>>(img_proj_b, spot_proj_b, img_fc_b, spot_fc_b,
                            img_ln_g, spot_ln_g, img_ln_b, spot_ln_b,
                            pb, pfb, lng, lnb);

    embed_kernel<<<NB, 256>>>(expression, x_table, y_table, x_idx, y_idx, spot);

    for (int l = 0; l < NL; l++) {
        uint16_t* wqh_l = wqh + (size_t)l * SPOT * QKVW;
        uint16_t* wql_l = wql + (size_t)l * SPOT * QKVW;
        uint16_t* woh_l = woh + (size_t)l * INNER * SPOT;
        uint16_t* wol_l = wol + (size_t)l * INNER * SPOT;
        uint16_t* w1h_l = w1h + (size_t)l * SPOT * MLPD;
        uint16_t* w1l_l = w1l + (size_t)l * SPOT * MLPD;
        uint16_t* w2h_l = w2h + (size_t)l * MLPD * SPOT;
        uint16_t* w2l_l = w2l + (size_t)l * MLPD * SPOT;

        ln_bf<SPOT><<<NB, 256>>>(spot, ln1_g + l * SPOT, ln1_b + l * SPOT, hbh, hbl);
        kQKV<<<dim3(QKVW / 64, NB / 128, 1), 512, SMEM_64>>>(
            hbh, hbl, SPOT, 0, wqh_l, wql_l, QKVW, 0,
            nullptr, 0, nullptr, 0,
            nullptr, qkh, qkl, QKVW, 0, SPOT, 1.f);
        flash_attn<<<dim3(NB / 128, NH), 512, SMEM_FLASH>>>(qkh, qkl, ath, atl);
        kRes<<<dim3(SPOT / 128, NB / 128, 1), 512, SMEM_STD>>>(
            ath, atl, INNER, 0, woh_l, wol_l, SPOT, 0,
            b_o + l * SPOT, 0, spot, 0,
            spot, nullptr, nullptr, SPOT, 0, INNER, 1.f);
        ln_bf<SPOT><<<NB, 256>>>(spot, ln2_g + l * SPOT, ln2_b + l * SPOT, hbh, hbl);
        kMlp1<<<dim3(MLPD / 128, NB / 128, 1), 512, SMEM_STD>>>(
            hbh, hbl, SPOT, 0, w1h_l, w1l_l, MLPD, 0,
            b1 + l * MLPD, 0, nullptr, 0,
            nullptr, mph, mpl, MLPD, 0, SPOT, 1.f);
        if (l == NL - 1) {
            kResO<<<dim3(SPOT / 128, NB / 128, 1), 512, SMEM_STD>>>(
                mph, mpl, MLPD, 0, w2h_l, w2l_l, SPOT, 0,
                b2 + l * SPOT, 0, spot, 0,
                spot, pinh + (size_t)NB * 1024, pinl + (size_t)NB * 1024,
                SPOT, 0, MLPD, 1.f);
        } else {
            kRes<<<dim3(SPOT / 128, NB / 128, 1), 512, SMEM_STD>>>(
                mph, mpl, MLPD, 0, w2h_l, w2l_l, SPOT, 0,
                b2 + l * SPOT, 0, spot, 0,
                spot, nullptr, nullptr, SPOT, 0, MLPD, 1.f);
        }
    }

    kProj<<<dim3(PROJ / 64, NB / 128, 2), 512, SMEM_64>>>(
        pinh, pinl, 1024, (long long)NB * 1024,
        pwh, pwl, PROJ, (long long)1024 * PROJ,
        pb, PROJ, nullptr, 0,
        pp, pgh, pgl, PROJ, (long long)NB * PROJ, 1024, 1.f);
    kResP<<<dim3(PROJ / 64, NB / 128, 2), 512, SMEM_64>>>(
        pgh, pgl, PROJ, (long long)NB * PROJ,
        pfwh, pfwl, PROJ, (long long)PROJ * PROJ,
        pfb, PROJ, pp, (long long)NB * PROJ,
        tmp2, nullptr, nullptr, PROJ, (long long)NB * PROJ, PROJ, 1.f);
    ln_bf2<<<2 * NB, 256>>>(tmp2, lng, lnb, eh, el);

    pack_bf<<<NB, 256>>>(eh, el, eh + (size_t)NB * PROJ, el + (size_t)NB * PROJ,
                         cth, ctl);
    kSqk<<<dim3(NB / 128, NB / 128, 1), 512, SMEM_NAT>>>(
        eh + (size_t)NB * PROJ, el + (size_t)NB * PROJ, PROJ, 0,
        eh, el, PROJ, 0,
        nullptr, 0, nullptr, 0,
        logits, nullptr, nullptr, NB, 0, PROJ, 1.f);
    kSymG<<<dim3(NB / 128, NB / 128, 1), 512, SMEM_NAT>>>(
        cth, ctl, 2 * PROJ, 0, cth, ctl, 2 * PROJ, 0,
        nullptr, 0, nullptr, 0,
        tgt, nullptr, nullptr, NB, 0, 2 * PROJ, 0.5f);
    softmax_rowloss<<<NB, 256>>>(tgt, logits, rowp);
    colloss_part<<<dim3(NB / 64, 8), 256>>>(logits, tgt, cmx, cse, cts, ctd);
    colloss_fin<<<NB / 256, 256>>>(cmx, cse, cts, ctd, colp);
    final_reduce<<<1, 256>>>(rowp, colp, out);
}